// round 1
// baseline (speedup 1.0000x reference)
#include <cuda_runtime.h>
#include <math.h>

#define B_ 8
#define N_ 2048
#define F_ 256
#define H_ 128
#define K_ 1025
#define OUTC 384

// ---------------- scratch (device globals; no allocation allowed) ----------
__device__ float g_NA[(size_t)B_*N_*N_];   // normalized adj, then S in-place
__device__ float g_T [(size_t)B_*N_*N_];   // T = A @ S
__device__ float g_A2[(size_t)B_*N_*N_];   // layer-1 output adjacency
__device__ float g_A3[(size_t)B_*N_*N_];   // layer-2 output adjacency
__device__ float g_xW [B_*N_*F_];
__device__ float g_x1 [B_*N_*H_];
__device__ float g_xa [B_*N_*H_];
__device__ float g_xb [B_*N_*H_];
__device__ float g_x2f[B_*N_*F_];
__device__ float g_v  [B_*N_];
__device__ float g_alp[B_*N_];
__device__ float g_dd [B_*N_];
__device__ float g_rnz[B_*N_];
__device__ float g_ca [B_*N_];
__device__ float g_cut[B_];

// ---------------- row stats --------------------------------------------------
// mode 0 (dense_gcn): d = rsqrt(max(sum - diag + 1, 1))
// mode 1 (normalize_batch_adj): d = rsqrt(max(sum + 1, 1)); rnz = (sum > 0)
__global__ void rowstats_kernel(const float* __restrict__ A, float* __restrict__ dout,
                                float* __restrict__ rnz, int mode) {
    int b = blockIdx.y, i = blockIdx.x, tid = threadIdx.x;
    const float* row = A + ((size_t)(b * N_ + i)) * N_;
    float s = 0.f;
    for (int j = tid; j < N_; j += 256) s += row[j];
    __shared__ float red[256];
    red[tid] = s; __syncthreads();
    for (int o = 128; o > 0; o >>= 1) { if (tid < o) red[tid] += red[tid + o]; __syncthreads(); }
    if (tid == 0) {
        float sum = red[0];
        if (mode == 0) {
            float rs = fmaxf(sum - row[i] + 1.f, 1.f);
            dout[b * N_ + i] = 1.f / sqrtf(rs);
        } else {
            float rs = fmaxf(sum + 1.f, 1.f);
            dout[b * N_ + i] = 1.f / sqrtf(rs);
            rnz[b * N_ + i] = (sum > 0.f) ? 1.f : 0.f;
        }
    }
}

// ---------------- build normalized adjacency --------------------------------
__global__ void buildNA_kernel(const float* __restrict__ A, const float* __restrict__ d,
                               const float* __restrict__ rnz, float* __restrict__ NA, int mode) {
    int b = blockIdx.z, i = blockIdx.y;
    int j = blockIdx.x * 256 + threadIdx.x;
    size_t idx = ((size_t)(b * N_ + i)) * N_ + j;
    float di = d[b * N_ + i], dj = d[b * N_ + j];
    float a = A[idx];
    float v;
    if (mode == 0) v = di * dj * ((i == j) ? 1.f : a);
    else           v = rnz[b * N_ + i] * di * dj * (a + ((i == j) ? 1.f : 0.f));
    NA[idx] = v;
}

// ---------------- v = x @ Watt + batt ----------------------------------------
__global__ void gemv_watt_kernel(const float* __restrict__ x, const float* __restrict__ Watt,
                                 const float* __restrict__ batt, float* __restrict__ v) {
    int w = blockIdx.x * 8 + (threadIdx.x >> 5);
    int lane = threadIdx.x & 31;
    if (w >= B_ * N_) return;
    const float* xr = x + (size_t)w * H_;
    float s = 0.f;
    #pragma unroll
    for (int c = lane; c < H_; c += 32) s += xr[c] * Watt[c];
    #pragma unroll
    for (int o = 16; o > 0; o >>= 1) s += __shfl_down_sync(0xffffffffu, s, o);
    if (lane == 0) v[w] = s + batt[0];
}

// ---------------- alpha = sigmoid((NA @ v)^2) --------------------------------
__global__ void alpha_kernel(const float* __restrict__ NA, const float* __restrict__ v,
                             float* __restrict__ alp) {
    int b = blockIdx.y, n = blockIdx.x, tid = threadIdx.x;
    const float* row = NA + ((size_t)(b * N_ + n)) * N_;
    const float* vb  = v + b * N_;
    float s = 0.f;
    for (int m = tid; m < N_; m += 256) s += row[m] * vb[m];
    __shared__ float red[256];
    red[tid] = s; __syncthreads();
    for (int o = 128; o > 0; o >>= 1) { if (tid < o) red[tid] += red[tid + o]; __syncthreads(); }
    if (tid == 0) {
        float r = red[0];
        float z = r * r;
        alp[b * N_ + n] = 1.f / (1.f + expf(-z));
    }
}

// ---------------- exact K-th largest via bitonic sort ------------------------
__global__ void topk_cut_kernel(const float* __restrict__ alp, float* __restrict__ cut) {
    __shared__ float s[N_];
    int b = blockIdx.x, t = threadIdx.x;   // 1024 threads
    s[t] = alp[b * N_ + t];
    s[t + 1024] = alp[b * N_ + t + 1024];
    __syncthreads();
    for (int k = 2; k <= N_; k <<= 1) {
        for (int j = k >> 1; j > 0; j >>= 1) {
            for (int i = t; i < N_; i += 1024) {
                int ixj = i ^ j;
                if (ixj > i) {
                    float a = s[i], c = s[ixj];
                    if (((i & k) == 0) ? (a > c) : (a < c)) { s[i] = c; s[ixj] = a; }
                }
            }
            __syncthreads();
        }
    }
    if (t == 0) cut[b] = s[N_ - K_];   // ascending sort: K-th largest
}

__global__ void ca_kernel(const float* __restrict__ alp, const float* __restrict__ cut,
                          float* __restrict__ ca) {
    int idx = blockIdx.x * 256 + threadIdx.x;
    int b = idx / N_;
    ca[idx] = fmaxf(alp[idx] + 1e-7f - cut[b], 0.f);
}

// ---------------- S = NA * ca[col], row-normalized (in place) ---------------
__global__ void buildS_kernel(float* __restrict__ NA, const float* __restrict__ ca) {
    __shared__ float prod[N_];
    __shared__ float red[256];
    int b = blockIdx.y, n = blockIdx.x, tid = threadIdx.x;
    float* row = NA + ((size_t)(b * N_ + n)) * N_;
    const float* cab = ca + b * N_;
    float s = 0.f;
    for (int m = tid; m < N_; m += 256) { float p = row[m] * cab[m]; prod[m] = p; s += p; }
    red[tid] = s; __syncthreads();
    for (int o = 128; o > 0; o >>= 1) { if (tid < o) red[tid] += red[tid + o]; __syncthreads(); }
    float denom = fmaxf(red[0], 1e-12f);
    for (int m = tid; m < N_; m += 256) row[m] = prod[m] / denom;
}

// ---------------- sparse (layer-1) kernels -----------------------------------
// T[b,i,:] = sum_j adj[b,i,j] * S[b,j,:]  (adj binary sparse, ~21 nnz/row)
__global__ void spmm_adjS_kernel(const float* __restrict__ adj, const float* __restrict__ S,
                                 float* __restrict__ T) {
    __shared__ float acc[N_];
    __shared__ int   lst[N_];
    __shared__ float lvl[N_];
    __shared__ int cnt;
    int b = blockIdx.y, i = blockIdx.x, tid = threadIdx.x;
    const float* arow = adj + ((size_t)(b * N_ + i)) * N_;
    if (tid == 0) cnt = 0;
    for (int c = tid; c < N_; c += 256) acc[c] = 0.f;
    __syncthreads();
    for (int j = tid; j < N_; j += 256) {
        float a = arow[j];
        if (a != 0.f) { int p = atomicAdd(&cnt, 1); lst[p] = j; lvl[p] = a; }
    }
    __syncthreads();
    int nn = cnt;
    for (int p = 0; p < nn; p++) {
        const float* srow = S + ((size_t)(b * N_ + lst[p])) * N_;
        float a = lvl[p];
        for (int c = tid; c < N_; c += 256) acc[c] = fmaf(a, srow[c], acc[c]);
    }
    __syncthreads();
    float* trow = T + ((size_t)(b * N_ + i)) * N_;
    for (int c = tid; c < N_; c += 256) trow[c] = acc[c];
}

// A2[b,m,:] = sum_n S[b,n,m] * T[b,n,:];  S col-m pattern = {adj[m,n]!=0} U {m}
// (adj symmetric). Epilogue: floor(x*1e4)/1e4.
__global__ void spmm_STT_kernel(const float* __restrict__ adj, const float* __restrict__ S,
                                const float* __restrict__ Tm, float* __restrict__ A2) {
    __shared__ float acc[N_];
    __shared__ int   lst[N_];
    __shared__ float svv[N_];
    __shared__ int cnt;
    int b = blockIdx.y, m = blockIdx.x, tid = threadIdx.x;
    const float* arow = adj + ((size_t)(b * N_ + m)) * N_;
    if (tid == 0) cnt = 0;
    for (int c = tid; c < N_; c += 256) acc[c] = 0.f;
    __syncthreads();
    for (int n = tid; n < N_; n += 256) {
        if (arow[n] != 0.f || n == m) {
            float s = S[((size_t)(b * N_ + n)) * N_ + m];
            if (s != 0.f) { int p = atomicAdd(&cnt, 1); lst[p] = n; svv[p] = s; }
        }
    }
    __syncthreads();
    int nn = cnt;
    for (int p = 0; p < nn; p++) {
        const float* trow = Tm + ((size_t)(b * N_ + lst[p])) * N_;
        float s = svv[p];
        for (int c = tid; c < N_; c += 256) acc[c] = fmaf(s, trow[c], acc[c]);
    }
    __syncthreads();
    float* orow = A2 + ((size_t)(b * N_ + m)) * N_;
    for (int c = tid; c < N_; c += 256) orow[c] = floorf(acc[c] * 10000.f) / 10000.f;
}

// ---------------- batched dense GEMM (fp32, 128x128x16, 8x8 microtile) ------
// TRANSA=0: C = A @ B, A is M x Kd.   TRANSA=1: C = A^T @ B, A is Kd x M.
// EPI: 0 none, 1 (+bias)*mask then relu, 2 (+bias)*mask, 3 floor-quant
template<int TRANSA, int EPI>
__global__ void __launch_bounds__(256, 2) gemm_kernel(
    const float* __restrict__ A, const float* __restrict__ Bm, float* __restrict__ C,
    int M, int Kd, int Nc, long sA, long sB, long sC,
    const float* __restrict__ bias, const float* __restrict__ mask) {
    __shared__ float As[16][128];
    __shared__ float Bs[16][128];
    const int b = blockIdx.z;
    A  += (size_t)b * sA;
    Bm += (size_t)b * sB;
    C  += (size_t)b * sC;
    const int n0 = blockIdx.x * 128, m0 = blockIdx.y * 128;
    const int tid = threadIdx.x, tx = tid & 15, ty = tid >> 4;
    float acc[8][8];
    #pragma unroll
    for (int i = 0; i < 8; i++)
        #pragma unroll
        for (int j = 0; j < 8; j++) acc[i][j] = 0.f;

    for (int k0 = 0; k0 < Kd; k0 += 16) {
        if (!TRANSA) {
            int r = tid >> 2, c4 = (tid & 3) * 4;
            #pragma unroll
            for (int rr = 0; rr < 128; rr += 64) {
                float4 va = *(const float4*)(A + (size_t)(m0 + r + rr) * Kd + k0 + c4);
                As[c4 + 0][r + rr] = va.x; As[c4 + 1][r + rr] = va.y;
                As[c4 + 2][r + rr] = va.z; As[c4 + 3][r + rr] = va.w;
            }
        } else {
            int r = tid >> 5, c4 = (tid & 31) * 4;
            #pragma unroll
            for (int rr = 0; rr < 16; rr += 8) {
                float4 va = *(const float4*)(A + (size_t)(k0 + r + rr) * M + m0 + c4);
                *(float4*)&As[r + rr][c4] = va;
            }
        }
        {
            int r = tid >> 5, c4 = (tid & 31) * 4;
            #pragma unroll
            for (int rr = 0; rr < 16; rr += 8) {
                float4 vb = *(const float4*)(Bm + (size_t)(k0 + r + rr) * Nc + n0 + c4);
                *(float4*)&Bs[r + rr][c4] = vb;
            }
        }
        __syncthreads();
        #pragma unroll
        for (int k = 0; k < 16; k++) {
            float a[8], bv[8];
            *(float4*)(a)      = *(const float4*)&As[k][ty * 8];
            *(float4*)(a + 4)  = *(const float4*)&As[k][ty * 8 + 4];
            *(float4*)(bv)     = *(const float4*)&Bs[k][tx * 8];
            *(float4*)(bv + 4) = *(const float4*)&Bs[k][tx * 8 + 4];
            #pragma unroll
            for (int i = 0; i < 8; i++)
                #pragma unroll
                for (int j = 0; j < 8; j++) acc[i][j] = fmaf(a[i], bv[j], acc[i][j]);
        }
        __syncthreads();
    }
    #pragma unroll
    for (int i = 0; i < 8; i++) {
        int m = m0 + ty * 8 + i;
        float mk = (EPI == 1 || EPI == 2) ? mask[(size_t)b * N_ + m] : 1.f;
        #pragma unroll
        for (int j = 0; j < 8; j++) {
            int n = n0 + tx * 8 + j;
            float v = acc[i][j];
            if (EPI == 1)      { v = (v + bias[n]) * mk; v = fmaxf(v, 0.f); }
            else if (EPI == 2) { v = (v + bias[n]) * mk; }
            else if (EPI == 3) { v = floorf(v * 10000.f) / 10000.f; }
            C[(size_t)m * Nc + n] = v;
        }
    }
}

// ---------------- output means -----------------------------------------------
__global__ void mean_kernel(const float* __restrict__ x1, const float* __restrict__ x2f,
                            float* __restrict__ out) {
    int b = blockIdx.x, c = threadIdx.x;   // 384 threads
    float s = 0.f;
    if (c < H_) {
        for (int n = 0; n < N_; n++) s += x1[((size_t)(b * N_ + n)) * H_ + c];
        out[b * OUTC + c] = s / (float)N_;
    } else {
        int cc = c - H_;
        for (int n = 0; n < N_; n++) s += x2f[((size_t)(b * N_ + n)) * F_ + cc];
        out[b * OUTC + c] = s / (float)N_;
    }
}

// ---------------- host-side dispatch -----------------------------------------
static void gemm(int transa, int epi, const float* A, const float* Bm, float* C,
                 int M, int Kd, int Nc, long sA, long sB, long sC,
                 const float* bias, const float* mask) {
    dim3 grid(Nc / 128, M / 128, B_), blk(256);
    if (!transa) {
        switch (epi) {
            case 0: gemm_kernel<0,0><<<grid,blk>>>(A,Bm,C,M,Kd,Nc,sA,sB,sC,bias,mask); break;
            case 1: gemm_kernel<0,1><<<grid,blk>>>(A,Bm,C,M,Kd,Nc,sA,sB,sC,bias,mask); break;
            case 2: gemm_kernel<0,2><<<grid,blk>>>(A,Bm,C,M,Kd,Nc,sA,sB,sC,bias,mask); break;
            default:gemm_kernel<0,3><<<grid,blk>>>(A,Bm,C,M,Kd,Nc,sA,sB,sC,bias,mask); break;
        }
    } else {
        switch (epi) {
            case 0: gemm_kernel<1,0><<<grid,blk>>>(A,Bm,C,M,Kd,Nc,sA,sB,sC,bias,mask); break;
            case 1: gemm_kernel<1,1><<<grid,blk>>>(A,Bm,C,M,Kd,Nc,sA,sB,sC,bias,mask); break;
            case 2: gemm_kernel<1,2><<<grid,blk>>>(A,Bm,C,M,Kd,Nc,sA,sB,sC,bias,mask); break;
            default:gemm_kernel<1,3><<<grid,blk>>>(A,Bm,C,M,Kd,Nc,sA,sB,sC,bias,mask); break;
        }
    }
}

extern "C" void kernel_launch(void* const* d_in, const int* in_sizes, int n_in,
                              void* d_out, int out_size) {
    const float* x    = (const float*)d_in[0];
    const float* adj  = (const float*)d_in[1];
    const float* mask = (const float*)d_in[2];
    const float* W1   = (const float*)d_in[3];
    const float* b1   = (const float*)d_in[4];
    const float* Watt = (const float*)d_in[5];
    const float* batt = (const float*)d_in[6];
    const float* W2   = (const float*)d_in[7];
    const float* b2   = (const float*)d_in[8];
    float* out = (float*)d_out;

    float *pNA,*pT,*pA2,*pA3,*pxW,*px1,*pxa,*pxb,*px2f,*pv,*palp,*pd,*prnz,*pca,*pcut;
    cudaGetSymbolAddress((void**)&pNA,  g_NA);
    cudaGetSymbolAddress((void**)&pT,   g_T);
    cudaGetSymbolAddress((void**)&pA2,  g_A2);
    cudaGetSymbolAddress((void**)&pA3,  g_A3);
    cudaGetSymbolAddress((void**)&pxW,  g_xW);
    cudaGetSymbolAddress((void**)&px1,  g_x1);
    cudaGetSymbolAddress((void**)&pxa,  g_xa);
    cudaGetSymbolAddress((void**)&pxb,  g_xb);
    cudaGetSymbolAddress((void**)&px2f, g_x2f);
    cudaGetSymbolAddress((void**)&pv,   g_v);
    cudaGetSymbolAddress((void**)&palp, g_alp);
    cudaGetSymbolAddress((void**)&pd,   g_dd);
    cudaGetSymbolAddress((void**)&prnz, g_rnz);
    cudaGetSymbolAddress((void**)&pca,  g_ca);
    cudaGetSymbolAddress((void**)&pcut, g_cut);

    // ---- GCN layer 1: x1 = relu((AN @ (x @ W1) + b1) * mask) ----
    gemm(0, 0, x, W1, pxW, N_, F_, H_, (long)N_ * F_, 0, (long)N_ * H_, nullptr, nullptr);
    rowstats_kernel<<<dim3(N_, B_), 256>>>(adj, pd, nullptr, 0);
    buildNA_kernel<<<dim3(N_ / 256, N_, B_), 256>>>(adj, pd, nullptr, pNA, 0);
    gemm(0, 1, pNA, pxW, px1, N_, N_, H_,
         (long)N_ * N_, (long)N_ * H_, (long)N_ * H_, b1, mask);

    // ---- two coarsening layers ----
    const float* xin = px1;
    const float* Ain = adj;
    float* xouts[2] = { pxa, pxb };
    float* Aouts[2] = { pA2, pA3 };
    for (int L = 0; L < 2; L++) {
        rowstats_kernel<<<dim3(N_, B_), 256>>>(Ain, pd, prnz, 1);
        buildNA_kernel<<<dim3(N_ / 256, N_, B_), 256>>>(Ain, pd, prnz, pNA, 1);
        gemv_watt_kernel<<<(B_ * N_) / 8, 256>>>(xin, Watt, batt, pv);
        alpha_kernel<<<dim3(N_, B_), 256>>>(pNA, pv, palp);
        topk_cut_kernel<<<B_, 1024>>>(palp, pcut);
        ca_kernel<<<(B_ * N_) / 256, 256>>>(palp, pcut, pca);
        buildS_kernel<<<dim3(N_, B_), 256>>>(pNA, pca);   // NA -> S in place
        // x_next = S^T @ x_in
        gemm(1, 0, pNA, xin, xouts[L], N_, N_, H_,
             (long)N_ * N_, (long)N_ * H_, (long)N_ * H_, nullptr, nullptr);
        if (L == 0) {
            // adj is binary & ~1% sparse: sparse path for both N^3 products
            spmm_adjS_kernel<<<dim3(N_, B_), 256>>>(Ain, pNA, pT);
            spmm_STT_kernel<<<dim3(N_, B_), 256>>>(Ain, pNA, pT, Aouts[L]);
        } else {
            gemm(0, 0, Ain, pNA, pT, N_, N_, N_,
                 (long)N_ * N_, (long)N_ * N_, (long)N_ * N_, nullptr, nullptr);
            gemm(1, 3, pNA, pT, Aouts[L], N_, N_, N_,
                 (long)N_ * N_, (long)N_ * N_, (long)N_ * N_, nullptr, nullptr);
        }
        xin = xouts[L];
        Ain = Aouts[L];
    }

    // ---- final GCN: x2 = (AN3 @ (x3 @ W2) + b2) * mask ----
    rowstats_kernel<<<dim3(N_, B_), 256>>>(Ain, pd, nullptr, 0);
    buildNA_kernel<<<dim3(N_ / 256, N_, B_), 256>>>(Ain, pd, nullptr, pNA, 0);
    gemm(0, 0, xin, W2, pxW, N_, H_, F_, (long)N_ * H_, 0, (long)N_ * F_, nullptr, nullptr);
    gemm(0, 2, pNA, pxW, px2f, N_, N_, F_,
         (long)N_ * N_, (long)N_ * F_, (long)N_ * F_, b2, mask);

    // ---- concat means ----
    mean_kernel<<<B_, OUTC>>>(px1, px2f, out);
}

// round 2
// speedup vs baseline: 2.5268x; 2.5268x over previous
#include <cuda_runtime.h>
#include <math.h>

#define B_ 8
#define N_ 2048
#define F_ 256
#define H_ 128
#define K_ 1025
#define OUTC 384

// ---------------- scratch (device globals; no allocation allowed) ----------
__device__ float g_NA[(size_t)B_*N_*N_];   // NA/S (layer1), NAc/S2c (layer2), NA3 (final)
__device__ float g_T [(size_t)B_*N_*N_];   // T = A @ S (layer1 full; layer2 compact)
__device__ float g_Ac[(size_t)B_*N_*N_];   // compacted A2
__device__ float g_A3[(size_t)B_*N_*N_];   // compacted A3
__device__ float g_xW [B_*N_*F_];
__device__ float g_x1 [B_*N_*H_];
__device__ float g_xc [B_*N_*H_];          // compacted x2
__device__ float g_x3 [B_*N_*H_];          // compacted x3
__device__ float g_x2f[B_*N_*F_];          // compacted final GCN output
__device__ float g_v  [B_*N_];
__device__ float g_alp[B_*N_];
__device__ float g_dd [B_*N_];
__device__ float g_rnz[B_*N_];
__device__ float g_ca [B_*N_];
__device__ float g_cut[B_];
__device__ float g_maskc[B_*N_];
__device__ float g_mrest[B_];
__device__ int   g_idx[B_*N_];
__device__ int   g_cnt[B_];

// ---------------- row stats --------------------------------------------------
// mode 0 (dense_gcn): d = rsqrt(max(sum - diag + 1, 1))
// mode 1 (normalize_batch_adj): d = rsqrt(max(sum + 1, 1)); rnz = (sum > 0)
__global__ void rowstats_kernel(const float* __restrict__ A, float* __restrict__ dout,
                                float* __restrict__ rnz, int mode) {
    int b = blockIdx.y, i = blockIdx.x, tid = threadIdx.x;
    const float* row = A + ((size_t)(b * N_ + i)) * N_;
    float s = 0.f;
    for (int j = tid; j < N_; j += 256) s += row[j];
    __shared__ float red[256];
    red[tid] = s; __syncthreads();
    for (int o = 128; o > 0; o >>= 1) { if (tid < o) red[tid] += red[tid + o]; __syncthreads(); }
    if (tid == 0) {
        float sum = red[0];
        if (mode == 0) {
            float rs = fmaxf(sum - row[i] + 1.f, 1.f);
            dout[b * N_ + i] = 1.f / sqrtf(rs);
        } else {
            float rs = fmaxf(sum + 1.f, 1.f);
            dout[b * N_ + i] = 1.f / sqrtf(rs);
            rnz[b * N_ + i] = (sum > 0.f) ? 1.f : 0.f;
        }
    }
}

// ---------------- build normalized adjacency --------------------------------
__global__ void buildNA_kernel(const float* __restrict__ A, const float* __restrict__ d,
                               const float* __restrict__ rnz, float* __restrict__ NA, int mode) {
    int b = blockIdx.z, i = blockIdx.y;
    int j = blockIdx.x * 256 + threadIdx.x;
    size_t idx = ((size_t)(b * N_ + i)) * N_ + j;
    float di = d[b * N_ + i], dj = d[b * N_ + j];
    float a = A[idx];
    float v;
    if (mode == 0) v = di * dj * ((i == j) ? 1.f : a);
    else           v = rnz[b * N_ + i] * di * dj * (a + ((i == j) ? 1.f : 0.f));
    NA[idx] = v;
}

// ---------------- v = x @ Watt + batt ----------------------------------------
__global__ void gemv_watt_kernel(const float* __restrict__ x, const float* __restrict__ Watt,
                                 const float* __restrict__ batt, float* __restrict__ v) {
    int w = blockIdx.x * 8 + (threadIdx.x >> 5);
    int lane = threadIdx.x & 31;
    if (w >= B_ * N_) return;
    const float* xr = x + (size_t)w * H_;
    float s = 0.f;
    #pragma unroll
    for (int c = lane; c < H_; c += 32) s += xr[c] * Watt[c];
    #pragma unroll
    for (int o = 16; o > 0; o >>= 1) s += __shfl_down_sync(0xffffffffu, s, o);
    if (lane == 0) v[w] = s + batt[0];
}

// ---------------- alpha = sigmoid((NA @ v)^2) --------------------------------
__global__ void alpha_kernel(const float* __restrict__ NA, const float* __restrict__ v,
                             float* __restrict__ alp) {
    int b = blockIdx.y, n = blockIdx.x, tid = threadIdx.x;
    const float* row = NA + ((size_t)(b * N_ + n)) * N_;
    const float* vb  = v + b * N_;
    float s = 0.f;
    for (int m = tid; m < N_; m += 256) s += row[m] * vb[m];
    __shared__ float red[256];
    red[tid] = s; __syncthreads();
    for (int o = 128; o > 0; o >>= 1) { if (tid < o) red[tid] += red[tid + o]; __syncthreads(); }
    if (tid == 0) {
        float r = red[0];
        float z = r * r;
        alp[b * N_ + n] = 1.f / (1.f + expf(-z));
    }
}

// ---------------- exact K-th largest via bitonic sort ------------------------
__global__ void topk_cut_kernel(const float* __restrict__ alp, float* __restrict__ cut) {
    __shared__ float s[N_];
    int b = blockIdx.x, t = threadIdx.x;   // 1024 threads
    s[t] = alp[b * N_ + t];
    s[t + 1024] = alp[b * N_ + t + 1024];
    __syncthreads();
    for (int k = 2; k <= N_; k <<= 1) {
        for (int j = k >> 1; j > 0; j >>= 1) {
            for (int i = t; i < N_; i += 1024) {
                int ixj = i ^ j;
                if (ixj > i) {
                    float a = s[i], c = s[ixj];
                    if (((i & k) == 0) ? (a > c) : (a < c)) { s[i] = c; s[ixj] = a; }
                }
            }
            __syncthreads();
        }
    }
    if (t == 0) cut[b] = s[N_ - K_];
}

__global__ void ca_kernel(const float* __restrict__ alp, const float* __restrict__ cut,
                          float* __restrict__ ca) {
    int idx = blockIdx.x * 256 + threadIdx.x;
    int b = idx / N_;
    ca[idx] = fmaxf(alp[idx] + 1e-7f - cut[b], 0.f);
}

// ---------------- S = NA * ca[col], row-normalized (in place) ---------------
__global__ void buildS_kernel(float* __restrict__ NA, const float* __restrict__ ca) {
    __shared__ float prod[N_];
    __shared__ float red[256];
    int b = blockIdx.y, n = blockIdx.x, tid = threadIdx.x;
    float* row = NA + ((size_t)(b * N_ + n)) * N_;
    const float* cab = ca + b * N_;
    float s = 0.f;
    for (int m = tid; m < N_; m += 256) { float p = row[m] * cab[m]; prod[m] = p; s += p; }
    red[tid] = s; __syncthreads();
    for (int o = 128; o > 0; o >>= 1) { if (tid < o) red[tid] += red[tid + o]; __syncthreads(); }
    float denom = fmaxf(red[0], 1e-12f);
    for (int m = tid; m < N_; m += 256) row[m] = prod[m] / denom;
}

// ---------------- deterministic kept-set compaction (prefix scan) -----------
__global__ void compact_kernel(const float* __restrict__ ca, int* __restrict__ idx,
                               int* __restrict__ cnt) {
    __shared__ int sc[1024];
    int b = blockIdx.x, t = threadIdx.x;   // 1024 threads
    int f0 = (ca[b * N_ + 2 * t]     > 0.f) ? 1 : 0;
    int f1 = (ca[b * N_ + 2 * t + 1] > 0.f) ? 1 : 0;
    int c = f0 + f1;
    sc[t] = c; __syncthreads();
    for (int o = 1; o < 1024; o <<= 1) {
        int v = (t >= o) ? sc[t - o] : 0; __syncthreads();
        sc[t] += v; __syncthreads();
    }
    int base = sc[t] - c;
    if (f0) { idx[b * N_ + base] = 2 * t; base++; }
    if (f1) { idx[b * N_ + base] = 2 * t + 1; }
    if (t == 1023) cnt[b] = sc[1023];
}

__global__ void compact_mask_kernel(const float* __restrict__ mask, const int* __restrict__ idx,
                                    const int* __restrict__ cnt, float* __restrict__ maskc,
                                    float* __restrict__ mrest) {
    __shared__ float red[256];
    int b = blockIdx.x, t = threadIdx.x;
    int c = cnt[b];
    float local = 0.f;
    for (int i = t; i < N_; i += 256) {
        float mv = 0.f;
        if (i < c) mv = mask[b * N_ + idx[b * N_ + i]];
        maskc[b * N_ + i] = mv;
        local += mask[b * N_ + i] - mv;
    }
    red[t] = local; __syncthreads();
    for (int o = 128; o > 0; o >>= 1) { if (t < o) red[t] += red[t + o]; __syncthreads(); }
    if (t == 0) mrest[b] = red[0];
}

// ---------------- sparse layer-1 kernels (deterministic list build) ---------
// x1 = relu((AN0 @ xW) + b1) * mask, AN0 from adj + d0 (mode0)
__global__ void spmm_gcn1_kernel(const float* __restrict__ adj, const float* __restrict__ d0,
                                 const float* __restrict__ xW, const float* __restrict__ b1,
                                 const float* __restrict__ mask, float* __restrict__ x1) {
    __shared__ int   lst[N_];
    __shared__ float cf [N_];
    __shared__ int   sc [256];
    int b = blockIdx.y, i = blockIdx.x, tid = threadIdx.x;
    const float* arow = adj + ((size_t)(b * N_ + i)) * N_;
    float di = d0[b * N_ + i];
    int c = 0;
    #pragma unroll
    for (int q = 0; q < 8; q++) { int j = tid + q * 256; if (arow[j] != 0.f && j != i) c++; }
    sc[tid] = c; __syncthreads();
    for (int o = 1; o < 256; o <<= 1) {
        int v = (tid >= o) ? sc[tid - o] : 0; __syncthreads();
        sc[tid] += v; __syncthreads();
    }
    int base = sc[tid] - c;
    #pragma unroll
    for (int q = 0; q < 8; q++) {
        int j = tid + q * 256; float a = arow[j];
        if (a != 0.f && j != i) { lst[base] = j; cf[base] = di * d0[b * N_ + j] * a; base++; }
    }
    __syncthreads();
    int nn = sc[255];
    if (tid < H_) {
        float acc = di * di * xW[((size_t)(b * N_ + i)) * H_ + tid];
        for (int p = 0; p < nn; p++)
            acc = fmaf(cf[p], xW[((size_t)(b * N_ + lst[p])) * H_ + tid], acc);
        float vv = (acc + b1[tid]) * mask[b * N_ + i];
        x1[((size_t)(b * N_ + i)) * H_ + tid] = fmaxf(vv, 0.f);
    }
}

// xc[ic,:] = sum_n S[n, idx[ic]] * x1[n,:]   (direct compacted x-update)
__global__ void spmm_xupd_kernel(const float* __restrict__ adj, const float* __restrict__ S,
                                 const float* __restrict__ x1, const int* __restrict__ idx,
                                 const int* __restrict__ cnt, float* __restrict__ xc) {
    __shared__ int   lst[N_];
    __shared__ float sv [N_];
    __shared__ int   sc [256];
    int b = blockIdx.y, ic = blockIdx.x, tid = threadIdx.x;
    int cn = cnt[b];
    size_t orow = ((size_t)(b * N_ + ic)) * H_;
    if (ic >= cn) { if (tid < H_) xc[orow + tid] = 0.f; return; }
    int m = idx[b * N_ + ic];
    const float* arow = adj + ((size_t)(b * N_ + m)) * N_;
    int c = 0;
    #pragma unroll
    for (int q = 0; q < 8; q++) { int n = tid + q * 256; if (arow[n] != 0.f || n == m) c++; }
    sc[tid] = c; __syncthreads();
    for (int o = 1; o < 256; o <<= 1) {
        int v = (tid >= o) ? sc[tid - o] : 0; __syncthreads();
        sc[tid] += v; __syncthreads();
    }
    int base = sc[tid] - c;
    #pragma unroll
    for (int q = 0; q < 8; q++) {
        int n = tid + q * 256;
        if (arow[n] != 0.f || n == m) { lst[base] = n; base++; }
    }
    __syncthreads();
    int nn = sc[255];
    for (int p = tid; p < nn; p += 256) sv[p] = S[((size_t)(b * N_ + lst[p])) * N_ + m];
    __syncthreads();
    if (tid < H_) {
        float acc = 0.f;
        for (int p = 0; p < nn; p++)
            acc = fmaf(sv[p], x1[((size_t)(b * N_ + lst[p])) * H_ + tid], acc);
        xc[orow + tid] = acc;
    }
}

// T[i,:] = sum_j adj[i,j] * S[j,:]
__global__ void spmm_adjS_kernel(const float* __restrict__ adj, const float* __restrict__ S,
                                 float* __restrict__ T) {
    __shared__ float acc[N_];
    __shared__ int   lst[N_];
    __shared__ float lvl[N_];
    __shared__ int   sc [256];
    int b = blockIdx.y, i = blockIdx.x, tid = threadIdx.x;
    const float* arow = adj + ((size_t)(b * N_ + i)) * N_;
    for (int c2 = tid; c2 < N_; c2 += 256) acc[c2] = 0.f;
    int c = 0;
    #pragma unroll
    for (int q = 0; q < 8; q++) { int j = tid + q * 256; if (arow[j] != 0.f) c++; }
    sc[tid] = c; __syncthreads();
    for (int o = 1; o < 256; o <<= 1) {
        int v = (tid >= o) ? sc[tid - o] : 0; __syncthreads();
        sc[tid] += v; __syncthreads();
    }
    int base = sc[tid] - c;
    #pragma unroll
    for (int q = 0; q < 8; q++) {
        int j = tid + q * 256; float a = arow[j];
        if (a != 0.f) { lst[base] = j; lvl[base] = a; base++; }
    }
    __syncthreads();
    int nn = sc[255];
    for (int p = 0; p < nn; p++) {
        const float* srow = S + ((size_t)(b * N_ + lst[p])) * N_;
        float a = lvl[p];
        for (int c2 = tid; c2 < N_; c2 += 256) acc[c2] = fmaf(a, srow[c2], acc[c2]);
    }
    __syncthreads();
    float* trow = T + ((size_t)(b * N_ + i)) * N_;
    for (int c2 = tid; c2 < N_; c2 += 256) trow[c2] = acc[c2];
}

// A2c[ic,jc] = floorq( sum_n S[n, idx[ic]] * T[n, idx[jc]] ), zero padding
__global__ void spmm_STT_kernel(const float* __restrict__ adj, const float* __restrict__ S,
                                const float* __restrict__ Tm, const int* __restrict__ idx,
                                const int* __restrict__ cnt, float* __restrict__ A2c) {
    __shared__ float acc[N_];
    __shared__ int   lst[N_];
    __shared__ float sv [N_];
    __shared__ int   sc [256];
    int b = blockIdx.y, ic = blockIdx.x, tid = threadIdx.x;
    int cn = cnt[b];
    float* orow = A2c + ((size_t)(b * N_ + ic)) * N_;
    if (ic >= cn) { for (int j = tid; j < N_; j += 256) orow[j] = 0.f; return; }
    int m = idx[b * N_ + ic];
    const float* arow = adj + ((size_t)(b * N_ + m)) * N_;
    for (int j = tid; j < N_; j += 256) acc[j] = 0.f;
    int c = 0;
    #pragma unroll
    for (int q = 0; q < 8; q++) { int n = tid + q * 256; if (arow[n] != 0.f || n == m) c++; }
    sc[tid] = c; __syncthreads();
    for (int o = 1; o < 256; o <<= 1) {
        int v = (tid >= o) ? sc[tid - o] : 0; __syncthreads();
        sc[tid] += v; __syncthreads();
    }
    int base = sc[tid] - c;
    #pragma unroll
    for (int q = 0; q < 8; q++) {
        int n = tid + q * 256;
        if (arow[n] != 0.f || n == m) { lst[base] = n; base++; }
    }
    __syncthreads();
    int nn = sc[255];
    for (int p = tid; p < nn; p += 256) sv[p] = S[((size_t)(b * N_ + lst[p])) * N_ + m];
    __syncthreads();
    for (int p = 0; p < nn; p++) {
        float s = sv[p];
        if (s != 0.f) {
            const float* trow = Tm + ((size_t)(b * N_ + lst[p])) * N_;
            for (int j = tid; j < N_; j += 256) acc[j] = fmaf(s, trow[j], acc[j]);
        }
    }
    __syncthreads();
    const int* idxb = idx + b * N_;
    for (int jc = tid; jc < N_; jc += 256) {
        float vv = 0.f;
        if (jc < cn) { float a = acc[idxb[jc]]; vv = floorf(a * 10000.f) / 10000.f; }
        orow[jc] = vv;
    }
}

// ---------------- dense GEMM, dynamic cnt-guard ------------------------------
// TRANSA=0: C = A @ B (A: M x K, lda). TRANSA=1: C = A^T @ B (A: K x M, lda).
// EPI: 0 none, 2 (+bias)*mask, 3 floor-quant
template<int TRANSA, int EPI>
__global__ void __launch_bounds__(256, 2) gemm_kernel(
    const float* __restrict__ A, const float* __restrict__ Bm, float* __restrict__ C,
    int M, int Kd, int Nc, int lda, int ldb, int ldc,
    long sA, long sB, long sC,
    const float* __restrict__ bias, const float* __restrict__ mask,
    const int* __restrict__ cnt, int dynM, int dynK, int dynN, int zfill) {
    __shared__ float As[16][128];
    __shared__ float Bs[16][128];
    const int b = blockIdx.z;
    int Mp = M, Kp = Kd, Np = Nc;
    if (cnt) {
        int cc = cnt[b]; int p = (cc + 127) & ~127;
        if (dynM) Mp = p; if (dynK) Kp = p; if (dynN) Np = p;
    }
    const int n0 = blockIdx.x * 128, m0 = blockIdx.y * 128;
    bool inside = (m0 < Mp) && (n0 < Np);
    if (!inside && !zfill) return;
    A  += (size_t)b * sA;
    Bm += (size_t)b * sB;
    C  += (size_t)b * sC;
    const int tid = threadIdx.x, tx = tid & 15, ty = tid >> 4;
    float acc[8][8];
    #pragma unroll
    for (int i = 0; i < 8; i++)
        #pragma unroll
        for (int j = 0; j < 8; j++) acc[i][j] = 0.f;

    if (inside) {
        for (int k0 = 0; k0 < Kp; k0 += 16) {
            if (!TRANSA) {
                int r = tid >> 2, c4 = (tid & 3) * 4;
                #pragma unroll
                for (int rr = 0; rr < 128; rr += 64) {
                    float4 va = *(const float4*)(A + (size_t)(m0 + r + rr) * lda + k0 + c4);
                    As[c4 + 0][r + rr] = va.x; As[c4 + 1][r + rr] = va.y;
                    As[c4 + 2][r + rr] = va.z; As[c4 + 3][r + rr] = va.w;
                }
            } else {
                int r = tid >> 5, c4 = (tid & 31) * 4;
                #pragma unroll
                for (int rr = 0; rr < 16; rr += 8) {
                    float4 va = *(const float4*)(A + (size_t)(k0 + r + rr) * lda + m0 + c4);
                    *(float4*)&As[r + rr][c4] = va;
                }
            }
            {
                int r = tid >> 5, c4 = (tid & 31) * 4;
                #pragma unroll
                for (int rr = 0; rr < 16; rr += 8) {
                    float4 vb = *(const float4*)(Bm + (size_t)(k0 + r + rr) * ldb + n0 + c4);
                    *(float4*)&Bs[r + rr][c4] = vb;
                }
            }
            __syncthreads();
            #pragma unroll
            for (int k = 0; k < 16; k++) {
                float a[8], bv[8];
                *(float4*)(a)      = *(const float4*)&As[k][ty * 8];
                *(float4*)(a + 4)  = *(const float4*)&As[k][ty * 8 + 4];
                *(float4*)(bv)     = *(const float4*)&Bs[k][tx * 8];
                *(float4*)(bv + 4) = *(const float4*)&Bs[k][tx * 8 + 4];
                #pragma unroll
                for (int i = 0; i < 8; i++)
                    #pragma unroll
                    for (int j = 0; j < 8; j++) acc[i][j] = fmaf(a[i], bv[j], acc[i][j]);
            }
            __syncthreads();
        }
    }
    #pragma unroll
    for (int i = 0; i < 8; i++) {
        int m = m0 + ty * 8 + i;
        float mk = (EPI == 2) ? mask[(size_t)b * N_ + m] : 1.f;
        #pragma unroll
        for (int j = 0; j < 8; j++) {
            int n = n0 + tx * 8 + j;
            float v = acc[i][j];
            if (EPI == 2)      { v = (v + bias[n]) * mk; }
            else if (EPI == 3) { v = floorf(v * 10000.f) / 10000.f; }
            C[(size_t)m * ldc + n] = v;
        }
    }
}

// ---------------- output means -----------------------------------------------
__global__ void mean_kernel(const float* __restrict__ x1, const float* __restrict__ x2f,
                            const float* __restrict__ b2, const int* __restrict__ cnt,
                            const float* __restrict__ mrest, float* __restrict__ out) {
    int b = blockIdx.x, c = threadIdx.x;   // 384 threads
    if (c < H_) {
        float s0 = 0.f, s1 = 0.f;
        for (int n = 0; n < N_; n += 2) {
            s0 += x1[((size_t)(b * N_ + n))     * H_ + c];
            s1 += x1[((size_t)(b * N_ + n + 1)) * H_ + c];
        }
        out[b * OUTC + c] = (s0 + s1) / (float)N_;
    } else {
        int cc = c - H_;
        int cn = cnt[b];
        float s = 0.f;
        for (int i = 0; i < cn; i++) s += x2f[((size_t)(b * N_ + i)) * F_ + cc];
        s += b2[cc] * mrest[b];
        out[b * OUTC + c] = s / (float)N_;
    }
}

extern "C" void kernel_launch(void* const* d_in, const int* in_sizes, int n_in,
                              void* d_out, int out_size) {
    const float* x    = (const float*)d_in[0];
    const float* adj  = (const float*)d_in[1];
    const float* mask = (const float*)d_in[2];
    const float* W1   = (const float*)d_in[3];
    const float* b1   = (const float*)d_in[4];
    const float* Watt = (const float*)d_in[5];
    const float* batt = (const float*)d_in[6];
    const float* W2   = (const float*)d_in[7];
    const float* b2   = (const float*)d_in[8];
    float* out = (float*)d_out;

    float *pNA,*pT,*pAc,*pA3,*pxW,*px1,*pxc,*px3,*px2f,*pv,*palp,*pd,*prnz,*pca,*pcut,*pmaskc,*pmrest;
    int *pidx,*pcnt;
    cudaGetSymbolAddress((void**)&pNA,  g_NA);
    cudaGetSymbolAddress((void**)&pT,   g_T);
    cudaGetSymbolAddress((void**)&pAc,  g_Ac);
    cudaGetSymbolAddress((void**)&pA3,  g_A3);
    cudaGetSymbolAddress((void**)&pxW,  g_xW);
    cudaGetSymbolAddress((void**)&px1,  g_x1);
    cudaGetSymbolAddress((void**)&pxc,  g_xc);
    cudaGetSymbolAddress((void**)&px3,  g_x3);
    cudaGetSymbolAddress((void**)&px2f, g_x2f);
    cudaGetSymbolAddress((void**)&pv,   g_v);
    cudaGetSymbolAddress((void**)&palp, g_alp);
    cudaGetSymbolAddress((void**)&pd,   g_dd);
    cudaGetSymbolAddress((void**)&prnz, g_rnz);
    cudaGetSymbolAddress((void**)&pca,  g_ca);
    cudaGetSymbolAddress((void**)&pcut, g_cut);
    cudaGetSymbolAddress((void**)&pmaskc, g_maskc);
    cudaGetSymbolAddress((void**)&pmrest, g_mrest);
    cudaGetSymbolAddress((void**)&pidx, g_idx);
    cudaGetSymbolAddress((void**)&pcnt, g_cnt);

    // ---- GCN layer 1: x1 = relu((AN0 @ (x @ W1) + b1) * mask)  (sparse agg) ----
    gemm_kernel<0,0><<<dim3(1,16,B_),256>>>(x, W1, pxW, N_, F_, H_, F_, H_, H_,
        (long)N_*F_, 0, (long)N_*H_, nullptr, nullptr, nullptr, 0,0,0,0);
    rowstats_kernel<<<dim3(N_, B_), 256>>>(adj, pd, nullptr, 0);
    spmm_gcn1_kernel<<<dim3(N_, B_), 256>>>(adj, pd, pxW, b1, mask, px1);

    // ---- coarsen layer 1 (full domain, sparse adj pattern) ----
    rowstats_kernel<<<dim3(N_, B_), 256>>>(adj, pd, prnz, 1);
    buildNA_kernel<<<dim3(N_/256, N_, B_), 256>>>(adj, pd, prnz, pNA, 1);
    gemv_watt_kernel<<<(B_*N_)/8, 256>>>(px1, Watt, batt, pv);
    alpha_kernel<<<dim3(N_, B_), 256>>>(pNA, pv, palp);
    topk_cut_kernel<<<B_, 1024>>>(palp, pcut);
    ca_kernel<<<(B_*N_)/256, 256>>>(palp, pcut, pca);
    compact_kernel<<<B_, 1024>>>(pca, pidx, pcnt);
    compact_mask_kernel<<<B_, 256>>>(mask, pidx, pcnt, pmaskc, pmrest);
    buildS_kernel<<<dim3(N_, B_), 256>>>(pNA, pca);                 // NA -> S1
    spmm_xupd_kernel<<<dim3(N_, B_), 256>>>(adj, pNA, px1, pidx, pcnt, pxc);
    spmm_adjS_kernel<<<dim3(N_, B_), 256>>>(adj, pNA, pT);
    spmm_STT_kernel <<<dim3(N_, B_), 256>>>(adj, pNA, pT, pidx, pcnt, pAc);

    // ---- coarsen layer 2 (compacted domain, dense guarded GEMMs) ----
    rowstats_kernel<<<dim3(N_, B_), 256>>>(pAc, pd, prnz, 1);
    buildNA_kernel<<<dim3(N_/256, N_, B_), 256>>>(pAc, pd, prnz, pNA, 1);
    gemv_watt_kernel<<<(B_*N_)/8, 256>>>(pxc, Watt, batt, pv);
    alpha_kernel<<<dim3(N_, B_), 256>>>(pNA, pv, palp);
    topk_cut_kernel<<<B_, 1024>>>(palp, pcut);
    ca_kernel<<<(B_*N_)/256, 256>>>(palp, pcut, pca);
    buildS_kernel<<<dim3(N_, B_), 256>>>(pNA, pca);                 // NA -> S2c
    // x3c = S2c^T @ xc
    gemm_kernel<1,0><<<dim3(1,16,B_),256>>>(pNA, pxc, px3, N_, N_, H_, N_, H_, H_,
        (long)N_*N_, (long)N_*H_, (long)N_*H_, nullptr, nullptr, pcnt, 1,1,0,0);
    // Tc = Ac @ S2c
    gemm_kernel<0,0><<<dim3(16,16,B_),256>>>(pAc, pNA, pT, N_, N_, N_, N_, N_, N_,
        (long)N_*N_, (long)N_*N_, (long)N_*N_, nullptr, nullptr, pcnt, 1,1,1,0);
    // A3c = S2c^T @ Tc, floor-quant, zero-fill outside (full-width write)
    gemm_kernel<1,3><<<dim3(16,16,B_),256>>>(pNA, pT, pA3, N_, N_, N_, N_, N_, N_,
        (long)N_*N_, (long)N_*N_, (long)N_*N_, nullptr, nullptr, pcnt, 1,1,1,1);

    // ---- final GCN (compacted): x2f = (NA3 @ (x3 @ W2) + b2) * maskc ----
    rowstats_kernel<<<dim3(N_, B_), 256>>>(pA3, pd, nullptr, 0);
    buildNA_kernel<<<dim3(N_/256, N_, B_), 256>>>(pA3, pd, nullptr, pNA, 0);
    gemm_kernel<0,0><<<dim3(2,16,B_),256>>>(px3, W2, pxW, N_, H_, F_, H_, F_, F_,
        (long)N_*H_, 0, (long)N_*F_, nullptr, nullptr, pcnt, 1,0,0,0);
    gemm_kernel<0,2><<<dim3(2,16,B_),256>>>(pNA, pxW, px2f, N_, N_, F_, N_, F_, F_,
        (long)N_*N_, (long)N_*F_, (long)N_*F_, b2, pmaskc, pcnt, 1,1,0,0);

    // ---- concat means ----
    mean_kernel<<<B_, OUTC>>>(px1, px2f, b2, pcnt, pmrest, out);
}

// round 3
// speedup vs baseline: 3.6653x; 1.4506x over previous
#include <cuda_runtime.h>
#include <math.h>

#define B_ 8
#define N_ 2048
#define F_ 256
#define H_ 128
#define K_ 1025
#define OUTC 384
#define CAP 256

// ---------------- scratch (device globals; no allocation allowed) ----------
__device__ float g_NA[(size_t)B_*N_*N_];   // layer2 NA/S2c, final NA3
__device__ float g_T [(size_t)B_*N_*N_];   // Tc (layer1, stride cnp) then T2 (layer2, stride N_)
__device__ float g_Ac[(size_t)B_*N_*N_];   // compacted A2 (stride N_)
__device__ float g_A3[(size_t)B_*N_*N_];   // compacted A3 (stride N_)
__device__ float g_Sc[(size_t)B_*N_*N_];   // compacted S (stride cnp)
__device__ float g_xW [B_*N_*F_];
__device__ float g_x1 [B_*N_*H_];
__device__ float g_xc [B_*N_*H_];
__device__ float g_x3 [B_*N_*H_];
__device__ float g_x2f[B_*N_*F_];
__device__ int   g_lst[(size_t)B_*N_*CAP];
__device__ int   g_deg[B_*N_];
__device__ int   g_hasd[B_*N_];
__device__ float g_d0[B_*N_], g_d1[B_*N_], g_rnz[B_*N_];
__device__ float g_d2[B_*N_], g_rz2[B_*N_];
__device__ float g_v[B_*N_], g_alp[B_*N_], g_ca[B_*N_], g_srec[B_*N_];
__device__ float g_cut[B_];
__device__ float g_maskc[B_*N_], g_mrest[B_];
__device__ int   g_idx[B_*N_], g_ginv[B_*N_], g_cnt[B_];
__device__ float g_p1[B_*4*H_], g_p2[B_*4*F_];

// ---------------- cp.async helpers ------------------------------------------
#define CP16(dst, src) { \
    unsigned _a = (unsigned)__cvta_generic_to_shared(dst); \
    asm volatile("cp.async.cg.shared.global [%0], [%1], 16;\n" :: "r"(_a), "l"(src)); }
#define CP_COMMIT() asm volatile("cp.async.commit_group;\n")
#define CP_WAIT0()  asm volatile("cp.async.wait_group 0;\n")

// ---------------- CSR build + degree stats (one adj scan) -------------------
__global__ void csr_build_kernel(const float* __restrict__ adj, int* __restrict__ lst,
                                 int* __restrict__ deg, int* __restrict__ hasd,
                                 float* __restrict__ d0, float* __restrict__ d1,
                                 float* __restrict__ rnz) {
    __shared__ int sc[256];
    __shared__ int hd;
    int b = blockIdx.y, i = blockIdx.x, tid = threadIdx.x;
    const float* arow = adj + ((size_t)(b * N_ + i)) * N_;
    if (tid == 0) hd = 0;
    __syncthreads();
    int flags[8];
    int c = 0;
    #pragma unroll
    for (int q = 0; q < 8; q++) {
        int j = tid + q * 256;
        int f = (arow[j] != 0.f) ? 1 : 0;
        flags[q] = f; c += f;
        if (f && j == i) hd = 1;
    }
    sc[tid] = c; __syncthreads();
    for (int o = 1; o < 256; o <<= 1) {
        int v = (tid >= o) ? sc[tid - o] : 0; __syncthreads();
        sc[tid] += v; __syncthreads();
    }
    int base = sc[tid] - c;
    int* l = lst + ((size_t)(b * N_ + i)) * CAP;
    #pragma unroll
    for (int q = 0; q < 8; q++) {
        int j = tid + q * 256;
        if (flags[q]) { if (base < CAP) l[base] = j; base++; }
    }
    __syncthreads();
    if (tid == 0) {
        int total = sc[255];
        deg[b * N_ + i] = (total > CAP) ? CAP : total;
        hasd[b * N_ + i] = hd;
        d0[b * N_ + i] = rsqrtf(fmaxf((float)(total - hd) + 1.f, 1.f));
        d1[b * N_ + i] = rsqrtf((float)total + 1.f);
        rnz[b * N_ + i] = (total > 0) ? 1.f : 0.f;
    }
}

// ---------------- GCN layer 1 sparse aggregation -----------------------------
__global__ void gcn1_kernel(const int* __restrict__ lst, const int* __restrict__ deg,
                            const float* __restrict__ d0, const float* __restrict__ xW,
                            const float* __restrict__ b1, const float* __restrict__ mask,
                            float* __restrict__ x1) {
    int b = blockIdx.y, i = blockIdx.x, c = threadIdx.x;   // 128 threads
    int dg = deg[b * N_ + i];
    const int* l = lst + ((size_t)(b * N_ + i)) * CAP;
    float di = d0[b * N_ + i];
    float acc = di * di * xW[((size_t)(b * N_ + i)) * H_ + c];
    for (int p = 0; p < dg; p++) {
        int j = l[p];
        if (j != i) acc = fmaf(di * d0[b * N_ + j], xW[((size_t)(b * N_ + j)) * H_ + c], acc);
    }
    float vv = (acc + b1[c]) * mask[b * N_ + i];
    x1[((size_t)(b * N_ + i)) * H_ + c] = fmaxf(vv, 0.f);
}

// ---------------- v = x @ Watt + batt ----------------------------------------
__global__ void gemv_watt_kernel(const float* __restrict__ x, const float* __restrict__ Watt,
                                 const float* __restrict__ batt, float* __restrict__ v) {
    int w = blockIdx.x * 8 + (threadIdx.x >> 5);
    int lane = threadIdx.x & 31;
    if (w >= B_ * N_) return;
    const float* xr = x + (size_t)w * H_;
    float s = 0.f;
    #pragma unroll
    for (int c = lane; c < H_; c += 32) s += xr[c] * Watt[c];
    #pragma unroll
    for (int o = 16; o > 0; o >>= 1) s += __shfl_down_sync(0xffffffffu, s, o);
    if (lane == 0) v[w] = s + batt[0];
}

// ---------------- layer-1 alpha (sparse) --------------------------------------
__global__ void alpha1_kernel(const int* __restrict__ lst, const int* __restrict__ deg,
                              const float* __restrict__ d1, const float* __restrict__ rnz,
                              const float* __restrict__ v, float* __restrict__ alp) {
    int b = blockIdx.y;
    int i = blockIdx.x * 8 + (threadIdx.x >> 5);
    int lane = threadIdx.x & 31;
    const int* l = lst + ((size_t)(b * N_ + i)) * CAP;
    int dg = deg[b * N_ + i];
    float s = 0.f;
    for (int p = lane; p < dg; p += 32) { int j = l[p]; s += d1[b * N_ + j] * v[b * N_ + j]; }
    #pragma unroll
    for (int o = 16; o > 0; o >>= 1) s += __shfl_down_sync(0xffffffffu, s, o);
    if (lane == 0) {
        float di = d1[b * N_ + i];
        float r = rnz[b * N_ + i] * di * (s + di * v[b * N_ + i]);
        float z = r * r;
        alp[b * N_ + i] = 1.f / (1.f + expf(-z));
    }
}

// ---------------- exact K-th largest via bitonic sort ------------------------
__global__ void topk_cut_kernel(const float* __restrict__ alp, float* __restrict__ cut) {
    __shared__ float s[N_];
    int b = blockIdx.x, t = threadIdx.x;   // 1024 threads
    s[t] = alp[b * N_ + t];
    s[t + 1024] = alp[b * N_ + t + 1024];
    __syncthreads();
    for (int k = 2; k <= N_; k <<= 1) {
        for (int j = k >> 1; j > 0; j >>= 1) {
            for (int i = t; i < N_; i += 1024) {
                int ixj = i ^ j;
                if (ixj > i) {
                    float a = s[i], c = s[ixj];
                    if (((i & k) == 0) ? (a > c) : (a < c)) { s[i] = c; s[ixj] = a; }
                }
            }
            __syncthreads();
        }
    }
    if (t == 0) cut[b] = s[N_ - K_];
}

__global__ void ca_kernel(const float* __restrict__ alp, const float* __restrict__ cut,
                          float* __restrict__ ca) {
    int idx = blockIdx.x * 256 + threadIdx.x;
    int b = idx / N_;
    ca[idx] = fmaxf(alp[idx] + 1e-7f - cut[b], 0.f);
}

// ---------------- deterministic kept-set compaction (prefix scan) -----------
__global__ void compact_kernel(const float* __restrict__ ca, int* __restrict__ idx,
                               int* __restrict__ ginv, int* __restrict__ cnt) {
    __shared__ int sc[1024];
    int b = blockIdx.x, t = threadIdx.x;   // 1024 threads
    int f0 = (ca[b * N_ + 2 * t]     > 0.f) ? 1 : 0;
    int f1 = (ca[b * N_ + 2 * t + 1] > 0.f) ? 1 : 0;
    ginv[b * N_ + 2 * t] = -1;
    ginv[b * N_ + 2 * t + 1] = -1;
    int c = f0 + f1;
    sc[t] = c; __syncthreads();
    for (int o = 1; o < 1024; o <<= 1) {
        int v = (t >= o) ? sc[t - o] : 0; __syncthreads();
        sc[t] += v; __syncthreads();
    }
    int base = sc[t] - c;
    if (f0) { idx[b * N_ + base] = 2 * t;     ginv[b * N_ + 2 * t]     = base; base++; }
    if (f1) { idx[b * N_ + base] = 2 * t + 1; ginv[b * N_ + 2 * t + 1] = base; }
    if (t == 1023) cnt[b] = sc[1023];
}

__global__ void compact_mask_kernel(const float* __restrict__ mask, const int* __restrict__ idx,
                                    const int* __restrict__ cnt, float* __restrict__ maskc,
                                    float* __restrict__ mrest) {
    __shared__ float red[256];
    int b = blockIdx.x, t = threadIdx.x;
    int c = cnt[b];
    float local = 0.f;
    for (int i = t; i < N_; i += 256) {
        float mv = 0.f;
        if (i < c) mv = mask[b * N_ + idx[b * N_ + i]];
        maskc[b * N_ + i] = mv;
        local += mask[b * N_ + i] - mv;
    }
    red[t] = local; __syncthreads();
    for (int o = 128; o > 0; o >>= 1) { if (t < o) red[t] += red[t + o]; __syncthreads(); }
    if (t == 0) mrest[b] = red[0];
}

// ---------------- layer-1 S row normalizer (sparse): srec = rnz*d1/max(rn,eps)
__global__ void srec_kernel(const int* __restrict__ lst, const int* __restrict__ deg,
                            const float* __restrict__ d1, const float* __restrict__ rnz,
                            const float* __restrict__ ca, float* __restrict__ srec) {
    int b = blockIdx.y;
    int i = blockIdx.x * 8 + (threadIdx.x >> 5);
    int lane = threadIdx.x & 31;
    const int* l = lst + ((size_t)(b * N_ + i)) * CAP;
    int dg = deg[b * N_ + i];
    float s = 0.f;
    for (int p = lane; p < dg; p += 32) { int j = l[p]; s += d1[b * N_ + j] * ca[b * N_ + j]; }
    #pragma unroll
    for (int o = 16; o > 0; o >>= 1) s += __shfl_down_sync(0xffffffffu, s, o);
    if (lane == 0) {
        float di = d1[b * N_ + i];
        float raw = rnz[b * N_ + i] * di * (s + di * ca[b * N_ + i]);
        srec[b * N_ + i] = rnz[b * N_ + i] * di / fmaxf(raw, 1e-12f);
    }
}

// ---------------- column-compacted S (stride cnp) ----------------------------
__global__ void buildSc_kernel(const int* __restrict__ lst, const int* __restrict__ deg,
                               const int* __restrict__ hasd, const float* __restrict__ d1,
                               const float* __restrict__ ca, const float* __restrict__ srec,
                               const int* __restrict__ ginv, const int* __restrict__ cnt,
                               float* __restrict__ Sc) {
    int b = blockIdx.y, n = blockIdx.x, tid = threadIdx.x;
    int cnp = (cnt[b] + 127) & ~127;
    float* srow = Sc + (size_t)b * N_ * N_ + (size_t)n * cnp;
    for (int jc = tid; jc < cnp; jc += 256) srow[jc] = 0.f;
    __syncthreads();
    int dg = deg[b * N_ + n];
    const int* l = lst + ((size_t)(b * N_ + n)) * CAP;
    float sr = srec[b * N_ + n];
    for (int p = tid; p < dg; p += 256) {
        int m = l[p];
        int jc = ginv[b * N_ + m];
        if (jc >= 0) {
            float coef = (m == n) ? 2.f : 1.f;
            srow[jc] = sr * d1[b * N_ + m] * ca[b * N_ + m] * coef;
        }
    }
    if (tid == 0 && !hasd[b * N_ + n]) {
        int jc = ginv[b * N_ + n];
        if (jc >= 0) srow[jc] = sr * d1[b * N_ + n] * ca[b * N_ + n];
    }
}

// ---------------- xc[ic,:] = sum_n S[n, idx[ic]] * x1[n,:] -------------------
__global__ void xupd_kernel(const int* __restrict__ lst, const int* __restrict__ deg,
                            const int* __restrict__ hasd, const float* __restrict__ d1,
                            const float* __restrict__ ca, const float* __restrict__ srec,
                            const int* __restrict__ idx, const int* __restrict__ cnt,
                            const float* __restrict__ x1, float* __restrict__ xc) {
    int b = blockIdx.y, ic = blockIdx.x, c = threadIdx.x;   // 128 threads
    int cn = cnt[b], cnp = (cn + 127) & ~127;
    if (ic >= cnp) return;
    float* orow = xc + ((size_t)(b * N_ + ic)) * H_;
    if (ic >= cn) { orow[c] = 0.f; return; }
    int m = idx[b * N_ + ic];
    float dmcam = d1[b * N_ + m] * ca[b * N_ + m];
    int dg = deg[b * N_ + m];
    const int* l = lst + ((size_t)(b * N_ + m)) * CAP;
    float acc = 0.f;
    for (int p = 0; p < dg; p++) {
        int n = l[p];
        float coef = (n == m) ? 2.f : 1.f;
        float sv = srec[b * N_ + n] * dmcam * coef;
        acc = fmaf(sv, x1[((size_t)(b * N_ + n)) * H_ + c], acc);
    }
    if (!hasd[b * N_ + m])
        acc = fmaf(srec[b * N_ + m] * dmcam, x1[((size_t)(b * N_ + m)) * H_ + c], acc);
    orow[c] = acc;
}

// ---------------- Tc[i,:] = sum_{j in list_i} Sc[j,:]  (adj binary) ----------
__global__ void adjS_kernel(const int* __restrict__ lst, const int* __restrict__ deg,
                            const int* __restrict__ cnt, const float* __restrict__ Sc,
                            float* __restrict__ Tc) {
    __shared__ float acc[N_];
    int b = blockIdx.y, i = blockIdx.x, tid = threadIdx.x;
    int cnp = (cnt[b] + 127) & ~127;
    for (int jc = tid; jc < cnp; jc += 256) acc[jc] = 0.f;
    __syncthreads();
    int dg = deg[b * N_ + i];
    const int* l = lst + ((size_t)(b * N_ + i)) * CAP;
    const float* Sb = Sc + (size_t)b * N_ * N_;
    for (int p = 0; p < dg; p++) {
        const float* srow = Sb + (size_t)l[p] * cnp;
        for (int jc = tid; jc < cnp; jc += 256) acc[jc] += srow[jc];
    }
    __syncthreads();
    float* trow = Tc + (size_t)b * N_ * N_ + (size_t)i * cnp;
    for (int jc = tid; jc < cnp; jc += 256) trow[jc] = acc[jc];
}

// ---------------- Ac[ic,:] = floorq(sum_n S[n,m] * Tc[n,:]) ------------------
__global__ void STT_kernel(const int* __restrict__ lst, const int* __restrict__ deg,
                           const int* __restrict__ hasd, const float* __restrict__ d1,
                           const float* __restrict__ ca, const float* __restrict__ srec,
                           const int* __restrict__ idx, const int* __restrict__ cnt,
                           const float* __restrict__ Tc, float* __restrict__ Ac) {
    __shared__ float acc[N_];
    int b = blockIdx.y, ic = blockIdx.x, tid = threadIdx.x;
    int cn = cnt[b], cnp = (cn + 127) & ~127;
    if (ic >= cnp) return;
    float* orow = Ac + ((size_t)(b * N_ + ic)) * N_;
    if (ic >= cn) { for (int jc = tid; jc < cnp; jc += 256) orow[jc] = 0.f; return; }
    int m = idx[b * N_ + ic];
    float dmcam = d1[b * N_ + m] * ca[b * N_ + m];
    for (int jc = tid; jc < cnp; jc += 256) acc[jc] = 0.f;
    __syncthreads();
    int dg = deg[b * N_ + m];
    const int* l = lst + ((size_t)(b * N_ + m)) * CAP;
    const float* Tb = Tc + (size_t)b * N_ * N_;
    for (int p = 0; p < dg; p++) {
        int n = l[p];
        float coef = (n == m) ? 2.f : 1.f;
        float sv = srec[b * N_ + n] * dmcam * coef;
        if (sv != 0.f) {
            const float* trow = Tb + (size_t)n * cnp;
            for (int jc = tid; jc < cnp; jc += 256) acc[jc] = fmaf(sv, trow[jc], acc[jc]);
        }
    }
    if (!hasd[b * N_ + m]) {
        float sv = srec[b * N_ + m] * dmcam;
        if (sv != 0.f) {
            const float* trow = Tb + (size_t)m * cnp;
            for (int jc = tid; jc < cnp; jc += 256) acc[jc] = fmaf(sv, trow[jc], acc[jc]);
        }
    }
    __syncthreads();
    for (int jc = tid; jc < cnp; jc += 256) orow[jc] = floorf(acc[jc] * 10000.f) / 10000.f;
}

// ---------------- width-restricted dense helpers (layer 2 / final) ----------
// mode 0: d = rsqrt(max(sum - diag + 1, 1));  mode 1: d = rsqrt(sum + 1), rnz
__global__ void rowstats_c_kernel(const float* __restrict__ A, const int* __restrict__ cnt,
                                  float* __restrict__ dout, float* __restrict__ rnz, int mode) {
    int b = blockIdx.y, i = blockIdx.x, tid = threadIdx.x;
    int cnp = (cnt[b] + 127) & ~127;
    if (i >= cnp) return;
    const float* row = A + ((size_t)(b * N_ + i)) * N_;
    float s = 0.f;
    for (int j = tid; j < cnp; j += 256) s += row[j];
    __shared__ float red[256];
    red[tid] = s; __syncthreads();
    for (int o = 128; o > 0; o >>= 1) { if (tid < o) red[tid] += red[tid + o]; __syncthreads(); }
    if (tid == 0) {
        float sum = red[0];
        if (mode == 0) {
            dout[b * N_ + i] = rsqrtf(fmaxf(sum - row[i] + 1.f, 1.f));
        } else {
            dout[b * N_ + i] = rsqrtf(fmaxf(sum + 1.f, 1.f));
            rnz[b * N_ + i] = (sum > 0.f) ? 1.f : 0.f;
        }
    }
}

__global__ void buildNA_c_kernel(const float* __restrict__ A, const float* __restrict__ d,
                                 const float* __restrict__ rnz, const int* __restrict__ cnt,
                                 float* __restrict__ NA, int mode) {
    int b = blockIdx.z, i = blockIdx.y;
    int j = blockIdx.x * 256 + threadIdx.x;
    int cnp = (cnt[b] + 127) & ~127;
    if (i >= cnp || j >= cnp) return;
    size_t idx = ((size_t)(b * N_ + i)) * N_ + j;
    float di = d[b * N_ + i], dj = d[b * N_ + j];
    float a = A[idx];
    float v;
    if (mode == 0) v = di * dj * ((i == j) ? 1.f : a);
    else           v = rnz[b * N_ + i] * di * dj * (a + ((i == j) ? 1.f : 0.f));
    NA[idx] = v;
}

__global__ void alpha2_kernel(const float* __restrict__ NA, const float* __restrict__ v,
                              const int* __restrict__ cnt, float* __restrict__ alp) {
    int b = blockIdx.y, n = blockIdx.x, tid = threadIdx.x;
    int cnp = (cnt[b] + 127) & ~127;
    if (n >= cnp) { if (tid == 0) alp[b * N_ + n] = 0.5f; return; }
    const float* row = NA + ((size_t)(b * N_ + n)) * N_;
    const float* vb  = v + b * N_;
    float s = 0.f;
    for (int m = tid; m < cnp; m += 256) s += row[m] * vb[m];
    __shared__ float red[256];
    red[tid] = s; __syncthreads();
    for (int o = 128; o > 0; o >>= 1) { if (tid < o) red[tid] += red[tid + o]; __syncthreads(); }
    if (tid == 0) {
        float r = red[0];
        float z = r * r;
        alp[b * N_ + n] = 1.f / (1.f + expf(-z));
    }
}

__global__ void buildS2_kernel(float* __restrict__ NA, const float* __restrict__ ca,
                               const int* __restrict__ cnt) {
    __shared__ float prod[N_];
    __shared__ float red[256];
    int b = blockIdx.y, n = blockIdx.x, tid = threadIdx.x;
    int cnp = (cnt[b] + 127) & ~127;
    if (n >= cnp) return;
    float* row = NA + ((size_t)(b * N_ + n)) * N_;
    const float* cab = ca + b * N_;
    float s = 0.f;
    for (int m = tid; m < cnp; m += 256) { float p = row[m] * cab[m]; prod[m] = p; s += p; }
    red[tid] = s; __syncthreads();
    for (int o = 128; o > 0; o >>= 1) { if (tid < o) red[tid] += red[tid + o]; __syncthreads(); }
    float denom = fmaxf(red[0], 1e-12f);
    for (int m = tid; m < cnp; m += 256) row[m] = prod[m] / denom;
}

// ---------------- double-buffered cp.async GEMM ------------------------------
// TRANSA=0: C = A @ B (A: M x K, lda). TRANSA=1: C = A^T @ B (A: K x M, lda).
// EPI: 0 none, 2 (+bias)*mask, 3 floor-quant
template<int TRANSA, int EPI>
__global__ void __launch_bounds__(256, 2) gemm2_kernel(
    const float* __restrict__ A, const float* __restrict__ Bm, float* __restrict__ C,
    int M, int Kd, int Nc, int lda, int ldb, int ldc,
    long sA, long sB, long sC,
    const float* __restrict__ bias, const float* __restrict__ mask,
    const int* __restrict__ cnt, int dynM, int dynK, int dynN) {
    __shared__ float As[2][128 * 16];   // TRANSA=0: [row][k]; TRANSA=1: [k][col]
    __shared__ float Bs[2][16 * 128];
    const int b = blockIdx.z;
    int Mp = M, Kp = Kd, Np = Nc;
    if (cnt) {
        int p = (cnt[b] + 127) & ~127;
        if (dynM) Mp = p; if (dynK) Kp = p; if (dynN) Np = p;
    }
    const int n0 = blockIdx.x * 128, m0 = blockIdx.y * 128;
    if (m0 >= Mp || n0 >= Np) return;
    A  += (size_t)b * sA;
    Bm += (size_t)b * sB;
    C  += (size_t)b * sC;
    const int tid = threadIdx.x, tx = tid & 15, ty = tid >> 4;
    float acc[8][8];
    #pragma unroll
    for (int i = 0; i < 8; i++)
        #pragma unroll
        for (int j = 0; j < 8; j++) acc[i][j] = 0.f;

    const int Kt = Kp >> 4;

    // stage loaders
    auto load_tiles = [&](int k0, int buf) {
        if (!TRANSA) {
            #pragma unroll
            for (int q = 0; q < 2; q++) {
                int c = tid + q * 256;
                int row = c >> 2, col4 = (c & 3) * 4;
                const float* src = A + (size_t)(m0 + row) * lda + k0 + col4;
                CP16(&As[buf][row * 16 + col4], src);
            }
        } else {
            #pragma unroll
            for (int q = 0; q < 2; q++) {
                int c = tid + q * 256;
                int row = c >> 5, col4 = (c & 31) * 4;
                const float* src = A + (size_t)(k0 + row) * lda + m0 + col4;
                CP16(&As[buf][row * 128 + col4], src);
            }
        }
        #pragma unroll
        for (int q = 0; q < 2; q++) {
            int c = tid + q * 256;
            int row = c >> 5, col4 = (c & 31) * 4;
            const float* src = Bm + (size_t)(k0 + row) * ldb + n0 + col4;
            CP16(&Bs[buf][row * 128 + col4], src);
        }
    };

    load_tiles(0, 0);
    CP_COMMIT();

    for (int t = 0; t < Kt; t++) {
        CP_WAIT0();
        __syncthreads();
        if (t + 1 < Kt) { load_tiles((t + 1) << 4, (t + 1) & 1); CP_COMMIT(); }
        const int buf = t & 1;
        #pragma unroll
        for (int k = 0; k < 16; k++) {
            float a[8], bv[8];
            if (!TRANSA) {
                #pragma unroll
                for (int i = 0; i < 8; i++) a[i] = As[buf][(ty * 8 + i) * 16 + k];
            } else {
                *(float4*)(a)     = *(const float4*)&As[buf][k * 128 + ty * 8];
                *(float4*)(a + 4) = *(const float4*)&As[buf][k * 128 + ty * 8 + 4];
            }
            *(float4*)(bv)     = *(const float4*)&Bs[buf][k * 128 + tx * 8];
            *(float4*)(bv + 4) = *(const float4*)&Bs[buf][k * 128 + tx * 8 + 4];
            #pragma unroll
            for (int i = 0; i < 8; i++)
                #pragma unroll
                for (int j = 0; j < 8; j++) acc[i][j] = fmaf(a[i], bv[j], acc[i][j]);
        }
        __syncthreads();
    }
    #pragma unroll
    for (int i = 0; i < 8; i++) {
        int m = m0 + ty * 8 + i;
        float mk = (EPI == 2) ? mask[(size_t)b * N_ + m] : 1.f;
        #pragma unroll
        for (int j = 0; j < 8; j++) {
            int n = n0 + tx * 8 + j;
            float v = acc[i][j];
            if (EPI == 2)      { v = (v + bias[n]) * mk; }
            else if (EPI == 3) { v = floorf(v * 10000.f) / 10000.f; }
            C[(size_t)m * ldc + n] = v;
        }
    }
}

// ---------------- output means (two-stage, deterministic) --------------------
__global__ void mean1_part_kernel(const float* __restrict__ x1, float* __restrict__ p1) {
    int b = blockIdx.y, q = blockIdx.x, c = threadIdx.x;   // 128 threads
    float s = 0.f;
    for (int n = q * 512; n < (q + 1) * 512; n++) s += x1[((size_t)(b * N_ + n)) * H_ + c];
    p1[(b * 4 + q) * H_ + c] = s;
}

__global__ void mean2_part_kernel(const float* __restrict__ x2f, const int* __restrict__ cnt,
                                  float* __restrict__ p2) {
    int b = blockIdx.y, q = blockIdx.x, c = threadIdx.x;   // 256 threads
    int cn = cnt[b];
    int lo = q * 512, hi = (q + 1) * 512; if (hi > cn) hi = cn;
    float s = 0.f;
    for (int n = lo; n < hi; n++) s += x2f[((size_t)(b * N_ + n)) * F_ + c];
    p2[(b * 4 + q) * F_ + c] = s;
}

__global__ void mean_combine_kernel(const float* __restrict__ p1, const float* __restrict__ p2,
                                    const float* __restrict__ b2, const float* __restrict__ mrest,
                                    float* __restrict__ out) {
    int b = blockIdx.x, c = threadIdx.x;   // 384 threads
    if (c < H_) {
        float s = 0.f;
        for (int q = 0; q < 4; q++) s += p1[(b * 4 + q) * H_ + c];
        out[b * OUTC + c] = s / (float)N_;
    } else {
        int cc = c - H_;
        float s = b2[cc] * mrest[b];
        for (int q = 0; q < 4; q++) s += p2[(b * 4 + q) * F_ + cc];
        out[b * OUTC + c] = s / (float)N_;
    }
}

extern "C" void kernel_launch(void* const* d_in, const int* in_sizes, int n_in,
                              void* d_out, int out_size) {
    const float* x    = (const float*)d_in[0];
    const float* adj  = (const float*)d_in[1];
    const float* mask = (const float*)d_in[2];
    const float* W1   = (const float*)d_in[3];
    const float* b1   = (const float*)d_in[4];
    const float* Watt = (const float*)d_in[5];
    const float* batt = (const float*)d_in[6];
    const float* W2   = (const float*)d_in[7];
    const float* b2   = (const float*)d_in[8];
    float* out = (float*)d_out;

    float *pNA,*pT,*pAc,*pA3,*pSc,*pxW,*px1,*pxc,*px3,*px2f;
    float *pv,*palp,*pca,*psrec,*pd0,*pd1,*prnz,*pd2,*prz2,*pcut,*pmaskc,*pmrest,*pp1,*pp2;
    int *plst,*pdeg,*phasd,*pidx,*pginv,*pcnt;
    cudaGetSymbolAddress((void**)&pNA,  g_NA);
    cudaGetSymbolAddress((void**)&pT,   g_T);
    cudaGetSymbolAddress((void**)&pAc,  g_Ac);
    cudaGetSymbolAddress((void**)&pA3,  g_A3);
    cudaGetSymbolAddress((void**)&pSc,  g_Sc);
    cudaGetSymbolAddress((void**)&pxW,  g_xW);
    cudaGetSymbolAddress((void**)&px1,  g_x1);
    cudaGetSymbolAddress((void**)&pxc,  g_xc);
    cudaGetSymbolAddress((void**)&px3,  g_x3);
    cudaGetSymbolAddress((void**)&px2f, g_x2f);
    cudaGetSymbolAddress((void**)&pv,   g_v);
    cudaGetSymbolAddress((void**)&palp, g_alp);
    cudaGetSymbolAddress((void**)&pca,  g_ca);
    cudaGetSymbolAddress((void**)&psrec,g_srec);
    cudaGetSymbolAddress((void**)&pd0,  g_d0);
    cudaGetSymbolAddress((void**)&pd1,  g_d1);
    cudaGetSymbolAddress((void**)&prnz, g_rnz);
    cudaGetSymbolAddress((void**)&pd2,  g_d2);
    cudaGetSymbolAddress((void**)&prz2, g_rz2);
    cudaGetSymbolAddress((void**)&pcut, g_cut);
    cudaGetSymbolAddress((void**)&pmaskc, g_maskc);
    cudaGetSymbolAddress((void**)&pmrest, g_mrest);
    cudaGetSymbolAddress((void**)&pp1,  g_p1);
    cudaGetSymbolAddress((void**)&pp2,  g_p2);
    cudaGetSymbolAddress((void**)&plst, g_lst);
    cudaGetSymbolAddress((void**)&pdeg, g_deg);
    cudaGetSymbolAddress((void**)&phasd,g_hasd);
    cudaGetSymbolAddress((void**)&pidx, g_idx);
    cudaGetSymbolAddress((void**)&pginv,g_ginv);
    cudaGetSymbolAddress((void**)&pcnt, g_cnt);

    // ---- CSR + degree stats (single adj scan) ----
    csr_build_kernel<<<dim3(N_, B_), 256>>>(adj, plst, pdeg, phasd, pd0, pd1, prnz);

    // ---- GCN layer 1 (sparse aggregation) ----
    gemm2_kernel<0,0><<<dim3(1,16,B_),256>>>(x, W1, pxW, N_, F_, H_, F_, H_, H_,
        (long)N_*F_, 0, (long)N_*H_, nullptr, nullptr, nullptr, 0,0,0);
    gcn1_kernel<<<dim3(N_, B_), 128>>>(plst, pdeg, pd0, pxW, b1, mask, px1);

    // ---- coarsen layer 1 (sparse, no dense NA/S) ----
    gemv_watt_kernel<<<(B_*N_)/8, 256>>>(px1, Watt, batt, pv);
    alpha1_kernel<<<dim3(N_/8, B_), 256>>>(plst, pdeg, pd1, prnz, pv, palp);
    topk_cut_kernel<<<B_, 1024>>>(palp, pcut);
    ca_kernel<<<(B_*N_)/256, 256>>>(palp, pcut, pca);
    compact_kernel<<<B_, 1024>>>(pca, pidx, pginv, pcnt);
    compact_mask_kernel<<<B_, 256>>>(mask, pidx, pcnt, pmaskc, pmrest);
    srec_kernel<<<dim3(N_/8, B_), 256>>>(plst, pdeg, pd1, prnz, pca, psrec);
    buildSc_kernel<<<dim3(N_, B_), 256>>>(plst, pdeg, phasd, pd1, pca, psrec, pginv, pcnt, pSc);
    xupd_kernel<<<dim3(N_, B_), 128>>>(plst, pdeg, phasd, pd1, pca, psrec, pidx, pcnt, px1, pxc);
    adjS_kernel<<<dim3(N_, B_), 256>>>(plst, pdeg, pcnt, pSc, pT);
    STT_kernel<<<dim3(N_, B_), 256>>>(plst, pdeg, phasd, pd1, pca, psrec, pidx, pcnt, pT, pAc);

    // ---- coarsen layer 2 (compacted dense) ----
    rowstats_c_kernel<<<dim3(N_, B_), 256>>>(pAc, pcnt, pd2, prz2, 1);
    buildNA_c_kernel<<<dim3(8, N_, B_), 256>>>(pAc, pd2, prz2, pcnt, pNA, 1);
    gemv_watt_kernel<<<(B_*N_)/8, 256>>>(pxc, Watt, batt, pv);
    alpha2_kernel<<<dim3(N_, B_), 256>>>(pNA, pv, pcnt, palp);
    topk_cut_kernel<<<B_, 1024>>>(palp, pcut);
    ca_kernel<<<(B_*N_)/256, 256>>>(palp, pcut, pca);
    buildS2_kernel<<<dim3(N_, B_), 256>>>(pNA, pca, pcnt);          // NA -> S2c in place
    // x3 = S2c^T @ xc
    gemm2_kernel<1,0><<<dim3(1,16,B_),256>>>(pNA, pxc, px3, N_, N_, H_, N_, H_, H_,
        (long)N_*N_, (long)N_*H_, (long)N_*H_, nullptr, nullptr, pcnt, 1,1,0);
    // T2 = Ac @ S2c
    gemm2_kernel<0,0><<<dim3(16,16,B_),256>>>(pAc, pNA, pT, N_, N_, N_, N_, N_, N_,
        (long)N_*N_, (long)N_*N_, (long)N_*N_, nullptr, nullptr, pcnt, 1,1,1);
    // A3 = S2c^T @ T2, floor-quant
    gemm2_kernel<1,3><<<dim3(16,16,B_),256>>>(pNA, pT, pA3, N_, N_, N_, N_, N_, N_,
        (long)N_*N_, (long)N_*N_, (long)N_*N_, nullptr, nullptr, pcnt, 1,1,1);

    // ---- final GCN (compacted): x2f = (NA3 @ (x3 @ W2) + b2) * maskc ----
    rowstats_c_kernel<<<dim3(N_, B_), 256>>>(pA3, pcnt, pd2, nullptr, 0);
    buildNA_c_kernel<<<dim3(8, N_, B_), 256>>>(pA3, pd2, nullptr, pcnt, pNA, 0);
    gemm2_kernel<0,0><<<dim3(2,16,B_),256>>>(px3, W2, pxW, N_, H_, F_, H_, F_, F_,
        (long)N_*H_, 0, (long)N_*F_, nullptr, nullptr, pcnt, 1,0,0);
    gemm2_kernel<0,2><<<dim3(2,16,B_),256>>>(pNA, pxW, px2f, N_, N_, F_, N_, F_, F_,
        (long)N_*N_, (long)N_*F_, (long)N_*F_, b2, pmaskc, pcnt, 1,1,0);

    // ---- concat means ----
    mean1_part_kernel<<<dim3(4, B_), 128>>>(px1, pp1);
    mean2_part_kernel<<<dim3(4, B_), 256>>>(px2f, pcnt, pp2);
    mean_combine_kernel<<<B_, 384>>>(pp1, pp2, b2, pmrest, out);
}

// round 4
// speedup vs baseline: 4.2830x; 1.1685x over previous
#include <cuda_runtime.h>
#include <cuda_bf16.h>
#include <math.h>
#include <stdint.h>

#define B_ 8
#define N_ 2048
#define F_ 256
#define H_ 128
#define K_ 1025
#define OUTC 384
#define CAP 256

// ---------------- scratch (device globals; no allocation allowed) ----------
__device__ float g_NA[(size_t)B_*N_*N_];   // layer2 NA/S2c, final NA3
__device__ float g_T [(size_t)B_*N_*N_];   // Tc (layer1, stride cnp) then T2 (layer2, stride N_)
__device__ float g_Ac[(size_t)B_*N_*N_];   // compacted A2 (stride N_)
__device__ float g_A3[(size_t)B_*N_*N_];   // compacted A3 (stride N_)
__device__ float g_Sc[(size_t)B_*N_*N_];   // compacted S (stride cnp)
__device__ __nv_bfloat16 g_Ahi[(size_t)B_*N_*N_], g_Alo[(size_t)B_*N_*N_];
__device__ __nv_bfloat16 g_SThi[(size_t)B_*N_*N_], g_STlo[(size_t)B_*N_*N_];
__device__ __nv_bfloat16 g_TThi[(size_t)B_*N_*N_], g_TTlo[(size_t)B_*N_*N_];
__device__ float g_xW [B_*N_*F_];
__device__ float g_x1 [B_*N_*H_];
__device__ float g_xc [B_*N_*H_];
__device__ float g_x3 [B_*N_*H_];
__device__ float g_x2f[B_*N_*F_];
__device__ int   g_lst[(size_t)B_*N_*CAP];
__device__ int   g_deg[B_*N_];
__device__ int   g_hasd[B_*N_];
__device__ float g_d0[B_*N_], g_d1[B_*N_], g_rnz[B_*N_];
__device__ float g_d2[B_*N_], g_rz2[B_*N_];
__device__ float g_v[B_*N_], g_alp[B_*N_], g_ca[B_*N_], g_srec[B_*N_];
__device__ float g_cut[B_];
__device__ float g_maskc[B_*N_], g_mrest[B_];
__device__ int   g_idx[B_*N_], g_ginv[B_*N_], g_cnt[B_];
__device__ float g_p1[B_*4*H_], g_p2[B_*4*F_];

// ---------------- cp.async helpers ------------------------------------------
#define CP16(dst, src) { \
    unsigned _a = (unsigned)__cvta_generic_to_shared(dst); \
    asm volatile("cp.async.cg.shared.global [%0], [%1], 16;\n" :: "r"(_a), "l"(src)); }
#define CP8(dst, src) { \
    unsigned _a = (unsigned)__cvta_generic_to_shared(dst); \
    asm volatile("cp.async.ca.shared.global [%0], [%1], 8;\n" :: "r"(_a), "l"(src)); }
#define CP_COMMIT() asm volatile("cp.async.commit_group;\n")
#define CP_WAIT0()  asm volatile("cp.async.wait_group 0;\n")

__device__ __forceinline__ void mma_bf16(float* c, const uint32_t* a, uint32_t b0, uint32_t b1) {
    asm volatile("mma.sync.aligned.m16n8k16.row.col.f32.bf16.bf16.f32 "
        "{%0,%1,%2,%3}, {%4,%5,%6,%7}, {%8,%9}, {%0,%1,%2,%3};"
        : "+f"(c[0]), "+f"(c[1]), "+f"(c[2]), "+f"(c[3])
        : "r"(a[0]), "r"(a[1]), "r"(a[2]), "r"(a[3]), "r"(b0), "r"(b1));
}

// ---------------- CSR build + degree stats (one adj scan) -------------------
__global__ void csr_build_kernel(const float* __restrict__ adj, int* __restrict__ lst,
                                 int* __restrict__ deg, int* __restrict__ hasd,
                                 float* __restrict__ d0, float* __restrict__ d1,
                                 float* __restrict__ rnz) {
    __shared__ int sc[256];
    __shared__ int hd;
    int b = blockIdx.y, i = blockIdx.x, tid = threadIdx.x;
    const float* arow = adj + ((size_t)(b * N_ + i)) * N_;
    if (tid == 0) hd = 0;
    __syncthreads();
    int flags[8];
    int c = 0;
    #pragma unroll
    for (int q = 0; q < 8; q++) {
        int j = tid + q * 256;
        int f = (arow[j] != 0.f) ? 1 : 0;
        flags[q] = f; c += f;
        if (f && j == i) hd = 1;
    }
    sc[tid] = c; __syncthreads();
    for (int o = 1; o < 256; o <<= 1) {
        int v = (tid >= o) ? sc[tid - o] : 0; __syncthreads();
        sc[tid] += v; __syncthreads();
    }
    int base = sc[tid] - c;
    int* l = lst + ((size_t)(b * N_ + i)) * CAP;
    #pragma unroll
    for (int q = 0; q < 8; q++) {
        int j = tid + q * 256;
        if (flags[q]) { if (base < CAP) l[base] = j; base++; }
    }
    __syncthreads();
    if (tid == 0) {
        int total = sc[255];
        deg[b * N_ + i] = (total > CAP) ? CAP : total;
        hasd[b * N_ + i] = hd;
        d0[b * N_ + i] = rsqrtf(fmaxf((float)(total - hd) + 1.f, 1.f));
        d1[b * N_ + i] = rsqrtf((float)total + 1.f);
        rnz[b * N_ + i] = (total > 0) ? 1.f : 0.f;
    }
}

// ---------------- GCN layer 1 sparse aggregation -----------------------------
__global__ void gcn1_kernel(const int* __restrict__ lst, const int* __restrict__ deg,
                            const float* __restrict__ d0, const float* __restrict__ xW,
                            const float* __restrict__ b1, const float* __restrict__ mask,
                            float* __restrict__ x1) {
    int b = blockIdx.y, i = blockIdx.x, c = threadIdx.x;   // 128 threads
    int dg = deg[b * N_ + i];
    const int* l = lst + ((size_t)(b * N_ + i)) * CAP;
    float di = d0[b * N_ + i];
    float acc = di * di * xW[((size_t)(b * N_ + i)) * H_ + c];
    for (int p = 0; p < dg; p++) {
        int j = l[p];
        if (j != i) acc = fmaf(di * d0[b * N_ + j], xW[((size_t)(b * N_ + j)) * H_ + c], acc);
    }
    float vv = (acc + b1[c]) * mask[b * N_ + i];
    x1[((size_t)(b * N_ + i)) * H_ + c] = fmaxf(vv, 0.f);
}

// ---------------- v = x @ Watt + batt ----------------------------------------
__global__ void gemv_watt_kernel(const float* __restrict__ x, const float* __restrict__ Watt,
                                 const float* __restrict__ batt, float* __restrict__ v) {
    int w = blockIdx.x * 8 + (threadIdx.x >> 5);
    int lane = threadIdx.x & 31;
    if (w >= B_ * N_) return;
    const float* xr = x + (size_t)w * H_;
    float s = 0.f;
    #pragma unroll
    for (int c = lane; c < H_; c += 32) s += xr[c] * Watt[c];
    #pragma unroll
    for (int o = 16; o > 0; o >>= 1) s += __shfl_down_sync(0xffffffffu, s, o);
    if (lane == 0) v[w] = s + batt[0];
}

// ---------------- layer-1 alpha (sparse) --------------------------------------
__global__ void alpha1_kernel(const int* __restrict__ lst, const int* __restrict__ deg,
                              const float* __restrict__ d1, const float* __restrict__ rnz,
                              const float* __restrict__ v, float* __restrict__ alp) {
    int b = blockIdx.y;
    int i = blockIdx.x * 8 + (threadIdx.x >> 5);
    int lane = threadIdx.x & 31;
    const int* l = lst + ((size_t)(b * N_ + i)) * CAP;
    int dg = deg[b * N_ + i];
    float s = 0.f;
    for (int p = lane; p < dg; p += 32) { int j = l[p]; s += d1[b * N_ + j] * v[b * N_ + j]; }
    #pragma unroll
    for (int o = 16; o > 0; o >>= 1) s += __shfl_down_sync(0xffffffffu, s, o);
    if (lane == 0) {
        float di = d1[b * N_ + i];
        float r = rnz[b * N_ + i] * di * (s + di * v[b * N_ + i]);
        float z = r * r;
        alp[b * N_ + i] = 1.f / (1.f + expf(-z));
    }
}

// ---------------- exact K-th largest via bitonic sort ------------------------
__global__ void topk_cut_kernel(const float* __restrict__ alp, float* __restrict__ cut) {
    __shared__ float s[N_];
    int b = blockIdx.x, t = threadIdx.x;   // 1024 threads
    s[t] = alp[b * N_ + t];
    s[t + 1024] = alp[b * N_ + t + 1024];
    __syncthreads();
    for (int k = 2; k <= N_; k <<= 1) {
        for (int j = k >> 1; j > 0; j >>= 1) {
            for (int i = t; i < N_; i += 1024) {
                int ixj = i ^ j;
                if (ixj > i) {
                    float a = s[i], c = s[ixj];
                    if (((i & k) == 0) ? (a > c) : (a < c)) { s[i] = c; s[ixj] = a; }
                }
            }
            __syncthreads();
        }
    }
    if (t == 0) cut[b] = s[N_ - K_];
}

__global__ void ca_kernel(const float* __restrict__ alp, const float* __restrict__ cut,
                          float* __restrict__ ca) {
    int idx = blockIdx.x * 256 + threadIdx.x;
    int b = idx / N_;
    ca[idx] = fmaxf(alp[idx] + 1e-7f - cut[b], 0.f);
}

// ---------------- deterministic kept-set compaction (prefix scan) -----------
__global__ void compact_kernel(const float* __restrict__ ca, int* __restrict__ idx,
                               int* __restrict__ ginv, int* __restrict__ cnt) {
    __shared__ int sc[1024];
    int b = blockIdx.x, t = threadIdx.x;   // 1024 threads
    int f0 = (ca[b * N_ + 2 * t]     > 0.f) ? 1 : 0;
    int f1 = (ca[b * N_ + 2 * t + 1] > 0.f) ? 1 : 0;
    ginv[b * N_ + 2 * t] = -1;
    ginv[b * N_ + 2 * t + 1] = -1;
    int c = f0 + f1;
    sc[t] = c; __syncthreads();
    for (int o = 1; o < 1024; o <<= 1) {
        int v = (t >= o) ? sc[t - o] : 0; __syncthreads();
        sc[t] += v; __syncthreads();
    }
    int base = sc[t] - c;
    if (f0) { idx[b * N_ + base] = 2 * t;     ginv[b * N_ + 2 * t]     = base; base++; }
    if (f1) { idx[b * N_ + base] = 2 * t + 1; ginv[b * N_ + 2 * t + 1] = base; }
    if (t == 1023) cnt[b] = sc[1023];
}

__global__ void compact_mask_kernel(const float* __restrict__ mask, const int* __restrict__ idx,
                                    const int* __restrict__ cnt, float* __restrict__ maskc,
                                    float* __restrict__ mrest) {
    __shared__ float red[256];
    int b = blockIdx.x, t = threadIdx.x;
    int c = cnt[b];
    float local = 0.f;
    for (int i = t; i < N_; i += 256) {
        float mv = 0.f;
        if (i < c) mv = mask[b * N_ + idx[b * N_ + i]];
        maskc[b * N_ + i] = mv;
        local += mask[b * N_ + i] - mv;
    }
    red[t] = local; __syncthreads();
    for (int o = 128; o > 0; o >>= 1) { if (t < o) red[t] += red[t + o]; __syncthreads(); }
    if (t == 0) mrest[b] = red[0];
}

// ---------------- layer-1 S row normalizer (sparse): srec = rnz*d1/max(rn,eps)
__global__ void srec_kernel(const int* __restrict__ lst, const int* __restrict__ deg,
                            const float* __restrict__ d1, const float* __restrict__ rnz,
                            const float* __restrict__ ca, float* __restrict__ srec) {
    int b = blockIdx.y;
    int i = blockIdx.x * 8 + (threadIdx.x >> 5);
    int lane = threadIdx.x & 31;
    const int* l = lst + ((size_t)(b * N_ + i)) * CAP;
    int dg = deg[b * N_ + i];
    float s = 0.f;
    for (int p = lane; p < dg; p += 32) { int j = l[p]; s += d1[b * N_ + j] * ca[b * N_ + j]; }
    #pragma unroll
    for (int o = 16; o > 0; o >>= 1) s += __shfl_down_sync(0xffffffffu, s, o);
    if (lane == 0) {
        float di = d1[b * N_ + i];
        float raw = rnz[b * N_ + i] * di * (s + di * ca[b * N_ + i]);
        srec[b * N_ + i] = rnz[b * N_ + i] * di / fmaxf(raw, 1e-12f);
    }
}

// ---------------- column-compacted S (stride cnp) ----------------------------
__global__ void buildSc_kernel(const int* __restrict__ lst, const int* __restrict__ deg,
                               const int* __restrict__ hasd, const float* __restrict__ d1,
                               const float* __restrict__ ca, const float* __restrict__ srec,
                               const int* __restrict__ ginv, const int* __restrict__ cnt,
                               float* __restrict__ Sc) {
    int b = blockIdx.y, n = blockIdx.x, tid = threadIdx.x;
    int cnp = (cnt[b] + 127) & ~127;
    float* srow = Sc + (size_t)b * N_ * N_ + (size_t)n * cnp;
    for (int jc = tid; jc < cnp; jc += 256) srow[jc] = 0.f;
    __syncthreads();
    int dg = deg[b * N_ + n];
    const int* l = lst + ((size_t)(b * N_ + n)) * CAP;
    float sr = srec[b * N_ + n];
    for (int p = tid; p < dg; p += 256) {
        int m = l[p];
        int jc = ginv[b * N_ + m];
        if (jc >= 0) {
            float coef = (m == n) ? 2.f : 1.f;
            srow[jc] = sr * d1[b * N_ + m] * ca[b * N_ + m] * coef;
        }
    }
    if (tid == 0 && !hasd[b * N_ + n]) {
        int jc = ginv[b * N_ + n];
        if (jc >= 0) srow[jc] = sr * d1[b * N_ + n] * ca[b * N_ + n];
    }
}

// ---------------- xc[ic,:] = sum_n S[n, idx[ic]] * x1[n,:] -------------------
__global__ void xupd_kernel(const int* __restrict__ lst, const int* __restrict__ deg,
                            const int* __restrict__ hasd, const float* __restrict__ d1,
                            const float* __restrict__ ca, const float* __restrict__ srec,
                            const int* __restrict__ idx, const int* __restrict__ cnt,
                            const float* __restrict__ x1, float* __restrict__ xc) {
    int b = blockIdx.y, ic = blockIdx.x, c = threadIdx.x;   // 128 threads
    int cn = cnt[b], cnp = (cn + 127) & ~127;
    if (ic >= cnp) return;
    float* orow = xc + ((size_t)(b * N_ + ic)) * H_;
    if (ic >= cn) { orow[c] = 0.f; return; }
    int m = idx[b * N_ + ic];
    float dmcam = d1[b * N_ + m] * ca[b * N_ + m];
    int dg = deg[b * N_ + m];
    const int* l = lst + ((size_t)(b * N_ + m)) * CAP;
    float acc = 0.f;
    for (int p = 0; p < dg; p++) {
        int n = l[p];
        float coef = (n == m) ? 2.f : 1.f;
        float sv = srec[b * N_ + n] * dmcam * coef;
        acc = fmaf(sv, x1[((size_t)(b * N_ + n)) * H_ + c], acc);
    }
    if (!hasd[b * N_ + m])
        acc = fmaf(srec[b * N_ + m] * dmcam, x1[((size_t)(b * N_ + m)) * H_ + c], acc);
    orow[c] = acc;
}

// ---------------- Tc[i,:] = sum_{j in list_i} Sc[j,:]  (adj binary) ----------
__global__ void adjS_kernel(const int* __restrict__ lst, const int* __restrict__ deg,
                            const int* __restrict__ cnt, const float* __restrict__ Sc,
                            float* __restrict__ Tc) {
    __shared__ float acc[N_];
    int b = blockIdx.y, i = blockIdx.x, tid = threadIdx.x;
    int cnp = (cnt[b] + 127) & ~127;
    for (int jc = tid; jc < cnp; jc += 256) acc[jc] = 0.f;
    __syncthreads();
    int dg = deg[b * N_ + i];
    const int* l = lst + ((size_t)(b * N_ + i)) * CAP;
    const float* Sb = Sc + (size_t)b * N_ * N_;
    for (int p = 0; p < dg; p++) {
        const float* srow = Sb + (size_t)l[p] * cnp;
        for (int jc = tid; jc < cnp; jc += 256) acc[jc] += srow[jc];
    }
    __syncthreads();
    float* trow = Tc + (size_t)b * N_ * N_ + (size_t)i * cnp;
    for (int jc = tid; jc < cnp; jc += 256) trow[jc] = acc[jc];
}

// ---------------- Ac[ic,:] = floorq(sum_n S[n,m] * Tc[n,:]) ------------------
__global__ void STT_kernel(const int* __restrict__ lst, const int* __restrict__ deg,
                           const int* __restrict__ hasd, const float* __restrict__ d1,
                           const float* __restrict__ ca, const float* __restrict__ srec,
                           const int* __restrict__ idx, const int* __restrict__ cnt,
                           const float* __restrict__ Tc, float* __restrict__ Ac) {
    __shared__ float acc[N_];
    int b = blockIdx.y, ic = blockIdx.x, tid = threadIdx.x;
    int cn = cnt[b], cnp = (cn + 127) & ~127;
    if (ic >= cnp) return;
    float* orow = Ac + ((size_t)(b * N_ + ic)) * N_;
    if (ic >= cn) { for (int jc = tid; jc < cnp; jc += 256) orow[jc] = 0.f; return; }
    int m = idx[b * N_ + ic];
    float dmcam = d1[b * N_ + m] * ca[b * N_ + m];
    for (int jc = tid; jc < cnp; jc += 256) acc[jc] = 0.f;
    __syncthreads();
    int dg = deg[b * N_ + m];
    const int* l = lst + ((size_t)(b * N_ + m)) * CAP;
    const float* Tb = Tc + (size_t)b * N_ * N_;
    for (int p = 0; p < dg; p++) {
        int n = l[p];
        float coef = (n == m) ? 2.f : 1.f;
        float sv = srec[b * N_ + n] * dmcam * coef;
        if (sv != 0.f) {
            const float* trow = Tb + (size_t)n * cnp;
            for (int jc = tid; jc < cnp; jc += 256) acc[jc] = fmaf(sv, trow[jc], acc[jc]);
        }
    }
    if (!hasd[b * N_ + m]) {
        float sv = srec[b * N_ + m] * dmcam;
        if (sv != 0.f) {
            const float* trow = Tb + (size_t)m * cnp;
            for (int jc = tid; jc < cnp; jc += 256) acc[jc] = fmaf(sv, trow[jc], acc[jc]);
        }
    }
    __syncthreads();
    for (int jc = tid; jc < cnp; jc += 256) orow[jc] = floorf(acc[jc] * 10000.f) / 10000.f;
}

// ---------------- width-restricted dense helpers (layer 2 / final) ----------
__global__ void rowstats_c_kernel(const float* __restrict__ A, const int* __restrict__ cnt,
                                  float* __restrict__ dout, float* __restrict__ rnz, int mode) {
    int b = blockIdx.y, i = blockIdx.x, tid = threadIdx.x;
    int cnp = (cnt[b] + 127) & ~127;
    if (i >= cnp) return;
    const float* row = A + ((size_t)(b * N_ + i)) * N_;
    float s = 0.f;
    for (int j = tid; j < cnp; j += 256) s += row[j];
    __shared__ float red[256];
    red[tid] = s; __syncthreads();
    for (int o = 128; o > 0; o >>= 1) { if (tid < o) red[tid] += red[tid + o]; __syncthreads(); }
    if (tid == 0) {
        float sum = red[0];
        if (mode == 0) {
            dout[b * N_ + i] = rsqrtf(fmaxf(sum - row[i] + 1.f, 1.f));
        } else {
            dout[b * N_ + i] = rsqrtf(fmaxf(sum + 1.f, 1.f));
            rnz[b * N_ + i] = (sum > 0.f) ? 1.f : 0.f;
        }
    }
}

__global__ void buildNA_c_kernel(const float* __restrict__ A, const float* __restrict__ d,
                                 const float* __restrict__ rnz, const int* __restrict__ cnt,
                                 float* __restrict__ NA, int mode) {
    int b = blockIdx.z, i = blockIdx.y;
    int j = blockIdx.x * 256 + threadIdx.x;
    int cnp = (cnt[b] + 127) & ~127;
    if (i >= cnp || j >= cnp) return;
    size_t idx = ((size_t)(b * N_ + i)) * N_ + j;
    float di = d[b * N_ + i], dj = d[b * N_ + j];
    float a = A[idx];
    float v;
    if (mode == 0) v = di * dj * ((i == j) ? 1.f : a);
    else           v = rnz[b * N_ + i] * di * dj * (a + ((i == j) ? 1.f : 0.f));
    NA[idx] = v;
}

__global__ void alpha2_kernel(const float* __restrict__ NA, const float* __restrict__ v,
                              const int* __restrict__ cnt, float* __restrict__ alp) {
    int b = blockIdx.y, n = blockIdx.x, tid = threadIdx.x;
    int cnp = (cnt[b] + 127) & ~127;
    if (n >= cnp) { if (tid == 0) alp[b * N_ + n] = 0.5f; return; }
    const float* row = NA + ((size_t)(b * N_ + n)) * N_;
    const float* vb  = v + b * N_;
    float s = 0.f;
    for (int m = tid; m < cnp; m += 256) s += row[m] * vb[m];
    __shared__ float red[256];
    red[tid] = s; __syncthreads();
    for (int o = 128; o > 0; o >>= 1) { if (tid < o) red[tid] += red[tid + o]; __syncthreads(); }
    if (tid == 0) {
        float r = red[0];
        float z = r * r;
        alp[b * N_ + n] = 1.f / (1.f + expf(-z));
    }
}

__global__ void buildS2_kernel(float* __restrict__ NA, const float* __restrict__ ca,
                               const int* __restrict__ cnt) {
    __shared__ float prod[N_];
    __shared__ float red[256];
    int b = blockIdx.y, n = blockIdx.x, tid = threadIdx.x;
    int cnp = (cnt[b] + 127) & ~127;
    if (n >= cnp) return;
    float* row = NA + ((size_t)(b * N_ + n)) * N_;
    const float* cab = ca + b * N_;
    float s = 0.f;
    for (int m = tid; m < cnp; m += 256) { float p = row[m] * cab[m]; prod[m] = p; s += p; }
    red[tid] = s; __syncthreads();
    for (int o = 128; o > 0; o >>= 1) { if (tid < o) red[tid] += red[tid + o]; __syncthreads(); }
    float denom = fmaxf(red[0], 1e-12f);
    for (int m = tid; m < cnp; m += 256) row[m] = prod[m] / denom;
}

// ---------------- bf16 split conversions --------------------------------------
__global__ void split_rm_kernel(const float* __restrict__ in, __nv_bfloat16* __restrict__ hi,
                                __nv_bfloat16* __restrict__ lo, const int* __restrict__ cnt) {
    int b = blockIdx.z, i = blockIdx.y;
    int j = blockIdx.x * 256 + threadIdx.x;
    int cnp = (cnt[b] + 127) & ~127;
    if (i >= cnp || j >= cnp) return;
    size_t idx = (size_t)b * N_ * N_ + (size_t)i * N_ + j;
    float v = in[idx];
    __nv_bfloat16 h = __float2bfloat16(v);
    hi[idx] = h;
    lo[idx] = __float2bfloat16(v - __bfloat162float(h));
}

// out[j][i] = in[i][j] (both stride N_), split to hi/lo
__global__ void split_tr_kernel(const float* __restrict__ in, __nv_bfloat16* __restrict__ hi,
                                __nv_bfloat16* __restrict__ lo, const int* __restrict__ cnt) {
    __shared__ float tile[32][33];
    int b = blockIdx.z;
    int cnp = (cnt[b] + 127) & ~127;
    int i0 = blockIdx.y * 32, j0 = blockIdx.x * 32;
    if (i0 >= cnp || j0 >= cnp) return;
    size_t boff = (size_t)b * N_ * N_;
    int tx = threadIdx.x, ty = threadIdx.y;   // (32, 8)
    #pragma unroll
    for (int r = 0; r < 4; r++) {
        int i = ty + r * 8;
        tile[i][tx] = in[boff + (size_t)(i0 + i) * N_ + j0 + tx];
    }
    __syncthreads();
    #pragma unroll
    for (int r = 0; r < 4; r++) {
        int j = ty + r * 8;
        float v = tile[tx][j];
        __nv_bfloat16 h = __float2bfloat16(v);
        size_t o = boff + (size_t)(j0 + j) * N_ + i0 + tx;
        hi[o] = h;
        lo[o] = __float2bfloat16(v - __bfloat162float(h));
    }
}

// ---------------- bf16-split tensor GEMM (mma.sync m16n8k16) -----------------
// C[m][n] = sum over 3 passes: Ahi*Bhi + Ahi*Blo + Alo*Bhi
// A operands row-major [m][k] stride N_; B operands TRANSPOSED [n][k] stride N_.
// EPI: 0 none, 3 floor-quant. M = N = K = cnp (dynamic per batch).
template<int EPI>
__global__ void __launch_bounds__(256, 2) gemm_bf16_kernel(
    const __nv_bfloat16* __restrict__ Ahi, const __nv_bfloat16* __restrict__ Alo,
    const __nv_bfloat16* __restrict__ BThi, const __nv_bfloat16* __restrict__ BTlo,
    float* __restrict__ C, const int* __restrict__ cnt) {
    __shared__ __nv_bfloat16 As[2][128 * 40];
    __shared__ __nv_bfloat16 Bs[2][128 * 40];
    const int b = blockIdx.z;
    const int cnp = (cnt[b] + 127) & ~127;
    const int m0 = blockIdx.y * 128, n0 = blockIdx.x * 128;
    if (m0 >= cnp || n0 >= cnp) return;
    const size_t boff = (size_t)b * N_ * N_;
    const int tid = threadIdx.x;
    const int wid = tid >> 5, lane = tid & 31;
    const int wm = wid >> 1, wn = wid & 1;     // warps 4 x 2 -> warp tile 32 x 64
    const int g = lane >> 2, t4 = lane & 3;
    const int KT = cnp >> 5, TT = 3 * KT;

    float acc[2][8][4];
    #pragma unroll
    for (int fm = 0; fm < 2; fm++)
        #pragma unroll
        for (int fn = 0; fn < 8; fn++)
            #pragma unroll
            for (int r = 0; r < 4; r++) acc[fm][fn][r] = 0.f;

    auto stage = [&](int t, int buf) {
        const __nv_bfloat16 *Ag, *Bg; int kt;
        if (t < KT)            { Ag = Ahi; Bg = BThi; kt = t; }
        else if (t < 2 * KT)   { Ag = Ahi; Bg = BTlo; kt = t - KT; }
        else                   { Ag = Alo; Bg = BThi; kt = t - 2 * KT; }
        Ag += boff + (size_t)m0 * N_ + kt * 32;
        Bg += boff + (size_t)n0 * N_ + kt * 32;
        #pragma unroll
        for (int q = 0; q < 4; q++) {
            int c = q * 256 + tid;
            int row = c >> 3, cc = (c & 7) * 4;
            CP8(&As[buf][row * 40 + cc], Ag + (size_t)row * N_ + cc);
            CP8(&Bs[buf][row * 40 + cc], Bg + (size_t)row * N_ + cc);
        }
    };

    stage(0, 0);
    CP_COMMIT();

    for (int t = 0; t < TT; t++) {
        CP_WAIT0();
        __syncthreads();
        if (t + 1 < TT) { stage(t + 1, (t + 1) & 1); CP_COMMIT(); }
        const int buf = t & 1;
        #pragma unroll
        for (int kh = 0; kh < 32; kh += 16) {
            uint32_t af[2][4];
            #pragma unroll
            for (int fm = 0; fm < 2; fm++) {
                const __nv_bfloat16* p = &As[buf][(wm * 32 + fm * 16 + g) * 40 + kh + t4 * 2];
                af[fm][0] = *(const uint32_t*)p;
                af[fm][1] = *(const uint32_t*)(p + 8 * 40);
                af[fm][2] = *(const uint32_t*)(p + 8);
                af[fm][3] = *(const uint32_t*)(p + 8 * 40 + 8);
            }
            #pragma unroll
            for (int fn = 0; fn < 8; fn++) {
                const __nv_bfloat16* p = &Bs[buf][(wn * 64 + fn * 8 + g) * 40 + kh + t4 * 2];
                uint32_t b0 = *(const uint32_t*)p;
                uint32_t b1 = *(const uint32_t*)(p + 8);
                mma_bf16(acc[0][fn], af[0], b0, b1);
                mma_bf16(acc[1][fn], af[1], b0, b1);
            }
        }
        __syncthreads();
    }

    #pragma unroll
    for (int fm = 0; fm < 2; fm++) {
        int mr = m0 + wm * 32 + fm * 16 + g;
        #pragma unroll
        for (int fn = 0; fn < 8; fn++) {
            int n = n0 + wn * 64 + fn * 8 + t4 * 2;
            float v0 = acc[fm][fn][0], v1 = acc[fm][fn][1];
            float v2 = acc[fm][fn][2], v3 = acc[fm][fn][3];
            if (EPI == 3) {
                v0 = floorf(v0 * 10000.f) / 10000.f;
                v1 = floorf(v1 * 10000.f) / 10000.f;
                v2 = floorf(v2 * 10000.f) / 10000.f;
                v3 = floorf(v3 * 10000.f) / 10000.f;
            }
            float* p0 = C + boff + (size_t)mr * N_ + n;
            p0[0] = v0; p0[1] = v1;
            float* p1 = p0 + 8 * N_;
            p1[0] = v2; p1[1] = v3;
        }
    }
}

// ---------------- double-buffered cp.async SIMT GEMM -------------------------
template<int TRANSA, int EPI>
__global__ void __launch_bounds__(256, 2) gemm2_kernel(
    const float* __restrict__ A, const float* __restrict__ Bm, float* __restrict__ C,
    int M, int Kd, int Nc, int lda, int ldb, int ldc,
    long sA, long sB, long sC,
    const float* __restrict__ bias, const float* __restrict__ mask,
    const int* __restrict__ cnt, int dynM, int dynK, int dynN) {
    __shared__ float As[2][128 * 16];
    __shared__ float Bs[2][16 * 128];
    const int b = blockIdx.z;
    int Mp = M, Kp = Kd, Np = Nc;
    if (cnt) {
        int p = (cnt[b] + 127) & ~127;
        if (dynM) Mp = p; if (dynK) Kp = p; if (dynN) Np = p;
    }
    const int n0 = blockIdx.x * 128, m0 = blockIdx.y * 128;
    if (m0 >= Mp || n0 >= Np) return;
    A  += (size_t)b * sA;
    Bm += (size_t)b * sB;
    C  += (size_t)b * sC;
    const int tid = threadIdx.x, tx = tid & 15, ty = tid >> 4;
    float acc[8][8];
    #pragma unroll
    for (int i = 0; i < 8; i++)
        #pragma unroll
        for (int j = 0; j < 8; j++) acc[i][j] = 0.f;

    const int Kt = Kp >> 4;

    auto load_tiles = [&](int k0, int buf) {
        if (!TRANSA) {
            #pragma unroll
            for (int q = 0; q < 2; q++) {
                int c = tid + q * 256;
                int row = c >> 2, col4 = (c & 3) * 4;
                const float* src = A + (size_t)(m0 + row) * lda + k0 + col4;
                CP16(&As[buf][row * 16 + col4], src);
            }
        } else {
            #pragma unroll
            for (int q = 0; q < 2; q++) {
                int c = tid + q * 256;
                int row = c >> 5, col4 = (c & 31) * 4;
                const float* src = A + (size_t)(k0 + row) * lda + m0 + col4;
                CP16(&As[buf][row * 128 + col4], src);
            }
        }
        #pragma unroll
        for (int q = 0; q < 2; q++) {
            int c = tid + q * 256;
            int row = c >> 5, col4 = (c & 31) * 4;
            const float* src = Bm + (size_t)(k0 + row) * ldb + n0 + col4;
            CP16(&Bs[buf][row * 128 + col4], src);
        }
    };

    load_tiles(0, 0);
    CP_COMMIT();

    for (int t = 0; t < Kt; t++) {
        CP_WAIT0();
        __syncthreads();
        if (t + 1 < Kt) { load_tiles((t + 1) << 4, (t + 1) & 1); CP_COMMIT(); }
        const int buf = t & 1;
        #pragma unroll
        for (int k = 0; k < 16; k++) {
            float a[8], bv[8];
            if (!TRANSA) {
                #pragma unroll
                for (int i = 0; i < 8; i++) a[i] = As[buf][(ty * 8 + i) * 16 + k];
            } else {
                *(float4*)(a)     = *(const float4*)&As[buf][k * 128 + ty * 8];
                *(float4*)(a + 4) = *(const float4*)&As[buf][k * 128 + ty * 8 + 4];
            }
            *(float4*)(bv)     = *(const float4*)&Bs[buf][k * 128 + tx * 8];
            *(float4*)(bv + 4) = *(const float4*)&Bs[buf][k * 128 + tx * 8 + 4];
            #pragma unroll
            for (int i = 0; i < 8; i++)
                #pragma unroll
                for (int j = 0; j < 8; j++) acc[i][j] = fmaf(a[i], bv[j], acc[i][j]);
        }
        __syncthreads();
    }
    #pragma unroll
    for (int i = 0; i < 8; i++) {
        int m = m0 + ty * 8 + i;
        float mk = (EPI == 2) ? mask[(size_t)b * N_ + m] : 1.f;
        #pragma unroll
        for (int j = 0; j < 8; j++) {
            int n = n0 + tx * 8 + j;
            float v = acc[i][j];
            if (EPI == 2)      { v = (v + bias[n]) * mk; }
            else if (EPI == 3) { v = floorf(v * 10000.f) / 10000.f; }
            C[(size_t)m * ldc + n] = v;
        }
    }
}

// ---------------- output means (two-stage, deterministic) --------------------
__global__ void mean1_part_kernel(const float* __restrict__ x1, float* __restrict__ p1) {
    int b = blockIdx.y, q = blockIdx.x, c = threadIdx.x;   // 128 threads
    float s = 0.f;
    for (int n = q * 512; n < (q + 1) * 512; n++) s += x1[((size_t)(b * N_ + n)) * H_ + c];
    p1[(b * 4 + q) * H_ + c] = s;
}

__global__ void mean2_part_kernel(const float* __restrict__ x2f, const int* __restrict__ cnt,
                                  float* __restrict__ p2) {
    int b = blockIdx.y, q = blockIdx.x, c = threadIdx.x;   // 256 threads
    int cn = cnt[b];
    int lo = q * 512, hi = (q + 1) * 512; if (hi > cn) hi = cn;
    float s = 0.f;
    for (int n = lo; n < hi; n++) s += x2f[((size_t)(b * N_ + n)) * F_ + c];
    p2[(b * 4 + q) * F_ + c] = s;
}

__global__ void mean_combine_kernel(const float* __restrict__ p1, const float* __restrict__ p2,
                                    const float* __restrict__ b2, const float* __restrict__ mrest,
                                    float* __restrict__ out) {
    int b = blockIdx.x, c = threadIdx.x;   // 384 threads
    if (c < H_) {
        float s = 0.f;
        for (int q = 0; q < 4; q++) s += p1[(b * 4 + q) * H_ + c];
        out[b * OUTC + c] = s / (float)N_;
    } else {
        int cc = c - H_;
        float s = b2[cc] * mrest[b];
        for (int q = 0; q < 4; q++) s += p2[(b * 4 + q) * F_ + cc];
        out[b * OUTC + c] = s / (float)N_;
    }
}

extern "C" void kernel_launch(void* const* d_in, const int* in_sizes, int n_in,
                              void* d_out, int out_size) {
    const float* x    = (const float*)d_in[0];
    const float* adj  = (const float*)d_in[1];
    const float* mask = (const float*)d_in[2];
    const float* W1   = (const float*)d_in[3];
    const float* b1   = (const float*)d_in[4];
    const float* Watt = (const float*)d_in[5];
    const float* batt = (const float*)d_in[6];
    const float* W2   = (const float*)d_in[7];
    const float* b2   = (const float*)d_in[8];
    float* out = (float*)d_out;

    float *pNA,*pT,*pAc,*pA3,*pSc,*pxW,*px1,*pxc,*px3,*px2f;
    float *pv,*palp,*pca,*psrec,*pd0,*pd1,*prnz,*pd2,*prz2,*pcut,*pmaskc,*pmrest,*pp1,*pp2;
    __nv_bfloat16 *pAhi,*pAlo,*pSThi,*pSTlo,*pTThi,*pTTlo;
    int *plst,*pdeg,*phasd,*pidx,*pginv,*pcnt;
    cudaGetSymbolAddress((void**)&pNA,  g_NA);
    cudaGetSymbolAddress((void**)&pT,   g_T);
    cudaGetSymbolAddress((void**)&pAc,  g_Ac);
    cudaGetSymbolAddress((void**)&pA3,  g_A3);
    cudaGetSymbolAddress((void**)&pSc,  g_Sc);
    cudaGetSymbolAddress((void**)&pAhi, g_Ahi);
    cudaGetSymbolAddress((void**)&pAlo, g_Alo);
    cudaGetSymbolAddress((void**)&pSThi,g_SThi);
    cudaGetSymbolAddress((void**)&pSTlo,g_STlo);
    cudaGetSymbolAddress((void**)&pTThi,g_TThi);
    cudaGetSymbolAddress((void**)&pTTlo,g_TTlo);
    cudaGetSymbolAddress((void**)&pxW,  g_xW);
    cudaGetSymbolAddress((void**)&px1,  g_x1);
    cudaGetSymbolAddress((void**)&pxc,  g_xc);
    cudaGetSymbolAddress((void**)&px3,  g_x3);
    cudaGetSymbolAddress((void**)&px2f, g_x2f);
    cudaGetSymbolAddress((void**)&pv,   g_v);
    cudaGetSymbolAddress((void**)&palp, g_alp);
    cudaGetSymbolAddress((void**)&pca,  g_ca);
    cudaGetSymbolAddress((void**)&psrec,g_srec);
    cudaGetSymbolAddress((void**)&pd0,  g_d0);
    cudaGetSymbolAddress((void**)&pd1,  g_d1);
    cudaGetSymbolAddress((void**)&prnz, g_rnz);
    cudaGetSymbolAddress((void**)&pd2,  g_d2);
    cudaGetSymbolAddress((void**)&prz2, g_rz2);
    cudaGetSymbolAddress((void**)&pcut, g_cut);
    cudaGetSymbolAddress((void**)&pmaskc, g_maskc);
    cudaGetSymbolAddress((void**)&pmrest, g_mrest);
    cudaGetSymbolAddress((void**)&pp1,  g_p1);
    cudaGetSymbolAddress((void**)&pp2,  g_p2);
    cudaGetSymbolAddress((void**)&plst, g_lst);
    cudaGetSymbolAddress((void**)&pdeg, g_deg);
    cudaGetSymbolAddress((void**)&phasd,g_hasd);
    cudaGetSymbolAddress((void**)&pidx, g_idx);
    cudaGetSymbolAddress((void**)&pginv,g_ginv);
    cudaGetSymbolAddress((void**)&pcnt, g_cnt);

    // ---- CSR + degree stats (single adj scan) ----
    csr_build_kernel<<<dim3(N_, B_), 256>>>(adj, plst, pdeg, phasd, pd0, pd1, prnz);

    // ---- GCN layer 1 (sparse aggregation) ----
    gemm2_kernel<0,0><<<dim3(1,16,B_),256>>>(x, W1, pxW, N_, F_, H_, F_, H_, H_,
        (long)N_*F_, 0, (long)N_*H_, nullptr, nullptr, nullptr, 0,0,0);
    gcn1_kernel<<<dim3(N_, B_), 128>>>(plst, pdeg, pd0, pxW, b1, mask, px1);

    // ---- coarsen layer 1 (sparse, no dense NA/S) ----
    gemv_watt_kernel<<<(B_*N_)/8, 256>>>(px1, Watt, batt, pv);
    alpha1_kernel<<<dim3(N_/8, B_), 256>>>(plst, pdeg, pd1, prnz, pv, palp);
    topk_cut_kernel<<<B_, 1024>>>(palp, pcut);
    ca_kernel<<<(B_*N_)/256, 256>>>(palp, pcut, pca);
    compact_kernel<<<B_, 1024>>>(pca, pidx, pginv, pcnt);
    compact_mask_kernel<<<B_, 256>>>(mask, pidx, pcnt, pmaskc, pmrest);
    srec_kernel<<<dim3(N_/8, B_), 256>>>(plst, pdeg, pd1, prnz, pca, psrec);
    buildSc_kernel<<<dim3(N_, B_), 256>>>(plst, pdeg, phasd, pd1, pca, psrec, pginv, pcnt, pSc);
    xupd_kernel<<<dim3(N_, B_), 128>>>(plst, pdeg, phasd, pd1, pca, psrec, pidx, pcnt, px1, pxc);
    adjS_kernel<<<dim3(N_, B_), 256>>>(plst, pdeg, pcnt, pSc, pT);
    STT_kernel<<<dim3(N_, B_), 256>>>(plst, pdeg, phasd, pd1, pca, psrec, pidx, pcnt, pT, pAc);

    // ---- coarsen layer 2 (compacted; big GEMMs on tensor pipe) ----
    rowstats_c_kernel<<<dim3(N_, B_), 256>>>(pAc, pcnt, pd2, prz2, 1);
    buildNA_c_kernel<<<dim3(8, N_, B_), 256>>>(pAc, pd2, prz2, pcnt, pNA, 1);
    gemv_watt_kernel<<<(B_*N_)/8, 256>>>(pxc, Watt, batt, pv);
    alpha2_kernel<<<dim3(N_, B_), 256>>>(pNA, pv, pcnt, palp);
    topk_cut_kernel<<<B_, 1024>>>(palp, pcut);
    ca_kernel<<<(B_*N_)/256, 256>>>(palp, pcut, pca);
    buildS2_kernel<<<dim3(N_, B_), 256>>>(pNA, pca, pcnt);          // NA -> S2c in place
    // x3 = S2c^T @ xc (SIMT, small)
    gemm2_kernel<1,0><<<dim3(1,16,B_),256>>>(pNA, pxc, px3, N_, N_, H_, N_, H_, H_,
        (long)N_*N_, (long)N_*H_, (long)N_*H_, nullptr, nullptr, pcnt, 1,1,0);
    // bf16 splits: Ac row-major; S2c transposed
    split_rm_kernel<<<dim3(8, N_, B_), 256>>>(pAc, pAhi, pAlo, pcnt);
    split_tr_kernel<<<dim3(64, 64, B_), dim3(32, 8)>>>(pNA, pSThi, pSTlo, pcnt);
    // T2 = Ac @ S2c   (tensor, fp32-grade via 3-pass split)
    gemm_bf16_kernel<0><<<dim3(16,16,B_),256>>>(pAhi, pAlo, pSThi, pSTlo, pT, pcnt);
    // T2 transposed split
    split_tr_kernel<<<dim3(64, 64, B_), dim3(32, 8)>>>(pT, pTThi, pTTlo, pcnt);
    // A3 = S2c^T @ T2 (A operand = ST buffers), floor-quant
    gemm_bf16_kernel<3><<<dim3(16,16,B_),256>>>(pSThi, pSTlo, pTThi, pTTlo, pA3, pcnt);

    // ---- final GCN (compacted): x2f = (NA3 @ (x3 @ W2) + b2) * maskc ----
    rowstats_c_kernel<<<dim3(N_, B_), 256>>>(pA3, pcnt, pd2, nullptr, 0);
    buildNA_c_kernel<<<dim3(8, N_, B_), 256>>>(pA3, pd2, nullptr, pcnt, pNA, 0);
    gemm2_kernel<0,0><<<dim3(2,16,B_),256>>>(px3, W2, pxW, N_, H_, F_, H_, F_, F_,
        (long)N_*H_, 0, (long)N_*F_, nullptr, nullptr, pcnt, 1,0,0);
    gemm2_kernel<0,2><<<dim3(2,16,B_),256>>>(pNA, pxW, px2f, N_, N_, F_, N_, F_, F_,
        (long)N_*N_, (long)N_*F_, (long)N_*F_, b2, pmaskc, pcnt, 1,1,0);

    // ---- concat means ----
    mean1_part_kernel<<<dim3(4, B_), 128>>>(px1, pp1);
    mean2_part_kernel<<<dim3(4, B_), 256>>>(px2f, pcnt, pp2);
    mean_combine_kernel<<<B_, 384>>>(pp1, pp2, b2, pmrest, out);
}

// round 5
// speedup vs baseline: 4.7615x; 1.1117x over previous
#include <cuda_runtime.h>
#include <cuda_bf16.h>
#include <math.h>
#include <stdint.h>

#define B_ 8
#define N_ 2048
#define F_ 256
#define H_ 128
#define K_ 1025
#define OUTC 384
#define CAP 256

// ---------------- scratch (device globals; no allocation allowed) ----------
__device__ float g_NA[(size_t)B_*N_*N_];   // layer2 S2c (stride N_)
__device__ float g_T [(size_t)B_*N_*N_];   // Tc (layer1, stride cnp) then T2 (stride N_)
__device__ float g_Ac[(size_t)B_*N_*N_];   // compacted A2 (stride N_)
__device__ float g_A3[(size_t)B_*N_*N_];   // compacted A3 (stride N_)
__device__ float g_Sc[(size_t)B_*N_*N_];   // compacted S (stride cnp)
__device__ __nv_bfloat16 g_Ahi[(size_t)B_*N_*N_], g_Alo[(size_t)B_*N_*N_];
__device__ __nv_bfloat16 g_SThi[(size_t)B_*N_*N_], g_STlo[(size_t)B_*N_*N_];
__device__ __nv_bfloat16 g_TThi[(size_t)B_*N_*N_], g_TTlo[(size_t)B_*N_*N_];
__device__ float g_xW [B_*N_*F_];
__device__ float g_x1 [B_*N_*H_];
__device__ float g_xc [B_*N_*H_];
__device__ float g_x3 [B_*N_*H_];
__device__ float g_x2f[B_*N_*F_];
__device__ int   g_lst[(size_t)B_*N_*CAP];
__device__ int   g_deg[B_*N_];
__device__ int   g_hasd[B_*N_];
__device__ float g_d0[B_*N_], g_d1[B_*N_], g_rnz[B_*N_];
__device__ float g_d2[B_*N_], g_rz2[B_*N_];
__device__ float g_v[B_*N_], g_alp[B_*N_], g_ca[B_*N_], g_srec[B_*N_];
__device__ float g_cut[B_];
__device__ float g_maskc[B_*N_], g_mrest[B_];
__device__ int   g_idx[B_*N_], g_ginv[B_*N_], g_cnt[B_];
__device__ float g_p1[B_*4*H_], g_p2[B_*4*F_];

// ---------------- async-copy / mma helpers -----------------------------------
#define CP16(dst, src) { \
    unsigned _a = (unsigned)__cvta_generic_to_shared(dst); \
    asm volatile("cp.async.cg.shared.global [%0], [%1], 16;\n" :: "r"(_a), "l"(src)); }
#define CP8(dst, src) { \
    unsigned _a = (unsigned)__cvta_generic_to_shared(dst); \
    asm volatile("cp.async.ca.shared.global [%0], [%1], 8;\n" :: "r"(_a), "l"(src)); }
#define CP_COMMIT() asm volatile("cp.async.commit_group;\n")
#define CP_WAIT0()  asm volatile("cp.async.wait_group 0;\n")

__device__ __forceinline__ void mma_bf16(float* c, const uint32_t* a, uint32_t b0, uint32_t b1) {
    asm volatile("mma.sync.aligned.m16n8k16.row.col.f32.bf16.bf16.f32 "
        "{%0,%1,%2,%3}, {%4,%5,%6,%7}, {%8,%9}, {%0,%1,%2,%3};"
        : "+f"(c[0]), "+f"(c[1]), "+f"(c[2]), "+f"(c[3])
        : "r"(a[0]), "r"(a[1]), "r"(a[2]), "r"(a[3]), "r"(b0), "r"(b1));
}
__device__ __forceinline__ void ldsm4(uint32_t* r, const void* p) {
    uint32_t a = (uint32_t)__cvta_generic_to_shared(p);
    asm volatile("ldmatrix.sync.aligned.m8n8.x4.shared.b16 {%0,%1,%2,%3}, [%4];"
        : "=r"(r[0]), "=r"(r[1]), "=r"(r[2]), "=r"(r[3]) : "r"(a));
}

// ---------------- CSR build + degree stats (one adj scan) -------------------
__global__ void csr_build_kernel(const float* __restrict__ adj, int* __restrict__ lst,
                                 int* __restrict__ deg, int* __restrict__ hasd,
                                 float* __restrict__ d0, float* __restrict__ d1,
                                 float* __restrict__ rnz) {
    __shared__ int sc[256];
    __shared__ int hd;
    int b = blockIdx.y, i = blockIdx.x, tid = threadIdx.x;
    const float* arow = adj + ((size_t)(b * N_ + i)) * N_;
    if (tid == 0) hd = 0;
    __syncthreads();
    int flags[8];
    int c = 0;
    #pragma unroll
    for (int q = 0; q < 8; q++) {
        int j = tid + q * 256;
        int f = (arow[j] != 0.f) ? 1 : 0;
        flags[q] = f; c += f;
        if (f && j == i) hd = 1;
    }
    sc[tid] = c; __syncthreads();
    for (int o = 1; o < 256; o <<= 1) {
        int v = (tid >= o) ? sc[tid - o] : 0; __syncthreads();
        sc[tid] += v; __syncthreads();
    }
    int base = sc[tid] - c;
    int* l = lst + ((size_t)(b * N_ + i)) * CAP;
    #pragma unroll
    for (int q = 0; q < 8; q++) {
        int j = tid + q * 256;
        if (flags[q]) { if (base < CAP) l[base] = j; base++; }
    }
    __syncthreads();
    if (tid == 0) {
        int total = sc[255];
        deg[b * N_ + i] = (total > CAP) ? CAP : total;
        hasd[b * N_ + i] = hd;
        d0[b * N_ + i] = rsqrtf(fmaxf((float)(total - hd) + 1.f, 1.f));
        d1[b * N_ + i] = rsqrtf((float)total + 1.f);
        rnz[b * N_ + i] = (total > 0) ? 1.f : 0.f;
    }
}

// ---------------- GCN layer 1 sparse aggregation -----------------------------
__global__ void gcn1_kernel(const int* __restrict__ lst, const int* __restrict__ deg,
                            const float* __restrict__ d0, const float* __restrict__ xW,
                            const float* __restrict__ b1, const float* __restrict__ mask,
                            float* __restrict__ x1) {
    int b = blockIdx.y, i = blockIdx.x, c = threadIdx.x;   // 128 threads
    int dg = deg[b * N_ + i];
    const int* l = lst + ((size_t)(b * N_ + i)) * CAP;
    float di = d0[b * N_ + i];
    float acc = di * di * xW[((size_t)(b * N_ + i)) * H_ + c];
    for (int p = 0; p < dg; p++) {
        int j = l[p];
        if (j != i) acc = fmaf(di * d0[b * N_ + j], xW[((size_t)(b * N_ + j)) * H_ + c], acc);
    }
    float vv = (acc + b1[c]) * mask[b * N_ + i];
    x1[((size_t)(b * N_ + i)) * H_ + c] = fmaxf(vv, 0.f);
}

// ---------------- v = x @ Watt + batt ----------------------------------------
__global__ void gemv_watt_kernel(const float* __restrict__ x, const float* __restrict__ Watt,
                                 const float* __restrict__ batt, float* __restrict__ v) {
    int w = blockIdx.x * 8 + (threadIdx.x >> 5);
    int lane = threadIdx.x & 31;
    if (w >= B_ * N_) return;
    const float* xr = x + (size_t)w * H_;
    float s = 0.f;
    #pragma unroll
    for (int c = lane; c < H_; c += 32) s += xr[c] * Watt[c];
    #pragma unroll
    for (int o = 16; o > 0; o >>= 1) s += __shfl_down_sync(0xffffffffu, s, o);
    if (lane == 0) v[w] = s + batt[0];
}

// ---------------- layer-1 alpha (sparse) --------------------------------------
__global__ void alpha1_kernel(const int* __restrict__ lst, const int* __restrict__ deg,
                              const float* __restrict__ d1, const float* __restrict__ rnz,
                              const float* __restrict__ v, float* __restrict__ alp) {
    int b = blockIdx.y;
    int i = blockIdx.x * 8 + (threadIdx.x >> 5);
    int lane = threadIdx.x & 31;
    const int* l = lst + ((size_t)(b * N_ + i)) * CAP;
    int dg = deg[b * N_ + i];
    float s = 0.f;
    for (int p = lane; p < dg; p += 32) { int j = l[p]; s += d1[b * N_ + j] * v[b * N_ + j]; }
    #pragma unroll
    for (int o = 16; o > 0; o >>= 1) s += __shfl_down_sync(0xffffffffu, s, o);
    if (lane == 0) {
        float di = d1[b * N_ + i];
        float r = rnz[b * N_ + i] * di * (s + di * v[b * N_ + i]);
        float z = r * r;
        alp[b * N_ + i] = 1.f / (1.f + expf(-z));
    }
}

// ---------------- exact K-th largest via bitonic sort ------------------------
__global__ void topk_cut_kernel(const float* __restrict__ alp, float* __restrict__ cut) {
    __shared__ float s[N_];
    int b = blockIdx.x, t = threadIdx.x;   // 1024 threads
    s[t] = alp[b * N_ + t];
    s[t + 1024] = alp[b * N_ + t + 1024];
    __syncthreads();
    for (int k = 2; k <= N_; k <<= 1) {
        for (int j = k >> 1; j > 0; j >>= 1) {
            for (int i = t; i < N_; i += 1024) {
                int ixj = i ^ j;
                if (ixj > i) {
                    float a = s[i], c = s[ixj];
                    if (((i & k) == 0) ? (a > c) : (a < c)) { s[i] = c; s[ixj] = a; }
                }
            }
            __syncthreads();
        }
    }
    if (t == 0) cut[b] = s[N_ - K_];
}

__global__ void ca_kernel(const float* __restrict__ alp, const float* __restrict__ cut,
                          float* __restrict__ ca) {
    int idx = blockIdx.x * 256 + threadIdx.x;
    int b = idx / N_;
    ca[idx] = fmaxf(alp[idx] + 1e-7f - cut[b], 0.f);
}

// ---------------- deterministic kept-set compaction (prefix scan) -----------
__global__ void compact_kernel(const float* __restrict__ ca, int* __restrict__ idx,
                               int* __restrict__ ginv, int* __restrict__ cnt) {
    __shared__ int sc[1024];
    int b = blockIdx.x, t = threadIdx.x;   // 1024 threads
    int f0 = (ca[b * N_ + 2 * t]     > 0.f) ? 1 : 0;
    int f1 = (ca[b * N_ + 2 * t + 1] > 0.f) ? 1 : 0;
    ginv[b * N_ + 2 * t] = -1;
    ginv[b * N_ + 2 * t + 1] = -1;
    int c = f0 + f1;
    sc[t] = c; __syncthreads();
    for (int o = 1; o < 1024; o <<= 1) {
        int v = (t >= o) ? sc[t - o] : 0; __syncthreads();
        sc[t] += v; __syncthreads();
    }
    int base = sc[t] - c;
    if (f0) { idx[b * N_ + base] = 2 * t;     ginv[b * N_ + 2 * t]     = base; base++; }
    if (f1) { idx[b * N_ + base] = 2 * t + 1; ginv[b * N_ + 2 * t + 1] = base; }
    if (t == 1023) cnt[b] = sc[1023];
}

__global__ void compact_mask_kernel(const float* __restrict__ mask, const int* __restrict__ idx,
                                    const int* __restrict__ cnt, float* __restrict__ maskc,
                                    float* __restrict__ mrest) {
    __shared__ float red[256];
    int b = blockIdx.x, t = threadIdx.x;
    int c = cnt[b];
    float local = 0.f;
    for (int i = t; i < N_; i += 256) {
        float mv = 0.f;
        if (i < c) mv = mask[b * N_ + idx[b * N_ + i]];
        maskc[b * N_ + i] = mv;
        local += mask[b * N_ + i] - mv;
    }
    red[t] = local; __syncthreads();
    for (int o = 128; o > 0; o >>= 1) { if (t < o) red[t] += red[t + o]; __syncthreads(); }
    if (t == 0) mrest[b] = red[0];
}

// ---------------- layer-1 S row normalizer -----------------------------------
__global__ void srec_kernel(const int* __restrict__ lst, const int* __restrict__ deg,
                            const float* __restrict__ d1, const float* __restrict__ rnz,
                            const float* __restrict__ ca, float* __restrict__ srec) {
    int b = blockIdx.y;
    int i = blockIdx.x * 8 + (threadIdx.x >> 5);
    int lane = threadIdx.x & 31;
    const int* l = lst + ((size_t)(b * N_ + i)) * CAP;
    int dg = deg[b * N_ + i];
    float s = 0.f;
    for (int p = lane; p < dg; p += 32) { int j = l[p]; s += d1[b * N_ + j] * ca[b * N_ + j]; }
    #pragma unroll
    for (int o = 16; o > 0; o >>= 1) s += __shfl_down_sync(0xffffffffu, s, o);
    if (lane == 0) {
        float di = d1[b * N_ + i];
        float raw = rnz[b * N_ + i] * di * (s + di * ca[b * N_ + i]);
        srec[b * N_ + i] = rnz[b * N_ + i] * di / fmaxf(raw, 1e-12f);
    }
}

// ---------------- column-compacted S (stride cnp) ----------------------------
__global__ void buildSc_kernel(const int* __restrict__ lst, const int* __restrict__ deg,
                               const int* __restrict__ hasd, const float* __restrict__ d1,
                               const float* __restrict__ ca, const float* __restrict__ srec,
                               const int* __restrict__ ginv, const int* __restrict__ cnt,
                               float* __restrict__ Sc) {
    int b = blockIdx.y, n = blockIdx.x, tid = threadIdx.x;
    int cnp = (cnt[b] + 127) & ~127;
    float* srow = Sc + (size_t)b * N_ * N_ + (size_t)n * cnp;
    float4* srow4 = (float4*)srow;
    float4 z4 = make_float4(0.f, 0.f, 0.f, 0.f);
    for (int jc = tid; jc < (cnp >> 2); jc += 256) srow4[jc] = z4;
    __syncthreads();
    int dg = deg[b * N_ + n];
    const int* l = lst + ((size_t)(b * N_ + n)) * CAP;
    float sr = srec[b * N_ + n];
    for (int p = tid; p < dg; p += 256) {
        int m = l[p];
        int jc = ginv[b * N_ + m];
        if (jc >= 0) {
            float coef = (m == n) ? 2.f : 1.f;
            srow[jc] = sr * d1[b * N_ + m] * ca[b * N_ + m] * coef;
        }
    }
    if (tid == 0 && !hasd[b * N_ + n]) {
        int jc = ginv[b * N_ + n];
        if (jc >= 0) srow[jc] = sr * d1[b * N_ + n] * ca[b * N_ + n];
    }
}

// ---------------- xc[ic,:] = sum_n S[n, idx[ic]] * x1[n,:] -------------------
__global__ void xupd_kernel(const int* __restrict__ lst, const int* __restrict__ deg,
                            const int* __restrict__ hasd, const float* __restrict__ d1,
                            const float* __restrict__ ca, const float* __restrict__ srec,
                            const int* __restrict__ idx, const int* __restrict__ cnt,
                            const float* __restrict__ x1, float* __restrict__ xc) {
    int b = blockIdx.y, ic = blockIdx.x, c = threadIdx.x;   // 128 threads
    int cn = cnt[b], cnp = (cn + 127) & ~127;
    if (ic >= cnp) return;
    float* orow = xc + ((size_t)(b * N_ + ic)) * H_;
    if (ic >= cn) { orow[c] = 0.f; return; }
    int m = idx[b * N_ + ic];
    float dmcam = d1[b * N_ + m] * ca[b * N_ + m];
    int dg = deg[b * N_ + m];
    const int* l = lst + ((size_t)(b * N_ + m)) * CAP;
    float acc = 0.f;
    for (int p = 0; p < dg; p++) {
        int n = l[p];
        float coef = (n == m) ? 2.f : 1.f;
        float sv = srec[b * N_ + n] * dmcam * coef;
        acc = fmaf(sv, x1[((size_t)(b * N_ + n)) * H_ + c], acc);
    }
    if (!hasd[b * N_ + m])
        acc = fmaf(srec[b * N_ + m] * dmcam, x1[((size_t)(b * N_ + m)) * H_ + c], acc);
    orow[c] = acc;
}

// ---------------- Tc[i,:] = sum_{j in list_i} Sc[j,:]  (float4) --------------
__global__ void adjS_kernel(const int* __restrict__ lst, const int* __restrict__ deg,
                            const int* __restrict__ cnt, const float* __restrict__ Sc,
                            float* __restrict__ Tc) {
    __shared__ float4 acc4[N_ / 4];
    int b = blockIdx.y, i = blockIdx.x, tid = threadIdx.x;
    int cnp4 = ((cnt[b] + 127) & ~127) >> 2;
    float4 z4 = make_float4(0.f, 0.f, 0.f, 0.f);
    for (int jc = tid; jc < cnp4; jc += 256) acc4[jc] = z4;
    __syncthreads();
    int dg = deg[b * N_ + i];
    const int* l = lst + ((size_t)(b * N_ + i)) * CAP;
    const float* Sb = Sc + (size_t)b * N_ * N_;
    for (int p = 0; p < dg; p++) {
        const float4* srow = (const float4*)(Sb + (size_t)l[p] * (cnp4 << 2));
        for (int jc = tid; jc < cnp4; jc += 256) {
            float4 s = srow[jc], a = acc4[jc];
            a.x += s.x; a.y += s.y; a.z += s.z; a.w += s.w;
            acc4[jc] = a;
        }
    }
    __syncthreads();
    float4* trow = (float4*)(Tc + (size_t)b * N_ * N_ + (size_t)i * (cnp4 << 2));
    for (int jc = tid; jc < cnp4; jc += 256) trow[jc] = acc4[jc];
}

// ---------------- Ac[ic,:] = floorq(sum_n S[n,m] * Tc[n,:])  (float4) --------
__global__ void STT_kernel(const int* __restrict__ lst, const int* __restrict__ deg,
                           const int* __restrict__ hasd, const float* __restrict__ d1,
                           const float* __restrict__ ca, const float* __restrict__ srec,
                           const int* __restrict__ idx, const int* __restrict__ cnt,
                           const float* __restrict__ Tc, float* __restrict__ Ac) {
    __shared__ float4 acc4[N_ / 4];
    int b = blockIdx.y, ic = blockIdx.x, tid = threadIdx.x;
    int cn = cnt[b], cnp = (cn + 127) & ~127, cnp4 = cnp >> 2;
    if (ic >= cnp) return;
    float4* orow4 = (float4*)(Ac + ((size_t)(b * N_ + ic)) * N_);
    float4 z4 = make_float4(0.f, 0.f, 0.f, 0.f);
    if (ic >= cn) { for (int jc = tid; jc < cnp4; jc += 256) orow4[jc] = z4; return; }
    int m = idx[b * N_ + ic];
    float dmcam = d1[b * N_ + m] * ca[b * N_ + m];
    for (int jc = tid; jc < cnp4; jc += 256) acc4[jc] = z4;
    __syncthreads();
    int dg = deg[b * N_ + m];
    const int* l = lst + ((size_t)(b * N_ + m)) * CAP;
    const float* Tb = Tc + (size_t)b * N_ * N_;
    for (int p = 0; p < dg; p++) {
        int n = l[p];
        float coef = (n == m) ? 2.f : 1.f;
        float sv = srec[b * N_ + n] * dmcam * coef;
        if (sv != 0.f) {
            const float4* trow = (const float4*)(Tb + (size_t)n * cnp);
            for (int jc = tid; jc < cnp4; jc += 256) {
                float4 t = trow[jc], a = acc4[jc];
                a.x = fmaf(sv, t.x, a.x); a.y = fmaf(sv, t.y, a.y);
                a.z = fmaf(sv, t.z, a.z); a.w = fmaf(sv, t.w, a.w);
                acc4[jc] = a;
            }
        }
    }
    if (!hasd[b * N_ + m]) {
        float sv = srec[b * N_ + m] * dmcam;
        if (sv != 0.f) {
            const float4* trow = (const float4*)(Tb + (size_t)m * cnp);
            for (int jc = tid; jc < cnp4; jc += 256) {
                float4 t = trow[jc], a = acc4[jc];
                a.x = fmaf(sv, t.x, a.x); a.y = fmaf(sv, t.y, a.y);
                a.z = fmaf(sv, t.z, a.z); a.w = fmaf(sv, t.w, a.w);
                acc4[jc] = a;
            }
        }
    }
    __syncthreads();
    for (int jc = tid; jc < cnp4; jc += 256) {
        float4 a = acc4[jc];
        a.x = floorf(a.x * 10000.f) / 10000.f;
        a.y = floorf(a.y * 10000.f) / 10000.f;
        a.z = floorf(a.z * 10000.f) / 10000.f;
        a.w = floorf(a.w * 10000.f) / 10000.f;
        orow4[jc] = a;
    }
}

// ---------------- layer-2 / final helpers (fused, read Ac/A3 directly) -------
__global__ void rowstats_c_kernel(const float* __restrict__ A, const int* __restrict__ cnt,
                                  float* __restrict__ dout, float* __restrict__ rnz, int mode) {
    int b = blockIdx.y, i = blockIdx.x, tid = threadIdx.x;
    int cnp = (cnt[b] + 127) & ~127;
    if (i >= cnp) return;
    const float* row = A + ((size_t)(b * N_ + i)) * N_;
    const float4* row4 = (const float4*)row;
    float s = 0.f;
    for (int j = tid; j < (cnp >> 2); j += 256) {
        float4 a = row4[j]; s += (a.x + a.y) + (a.z + a.w);
    }
    __shared__ float red[256];
    red[tid] = s; __syncthreads();
    for (int o = 128; o > 0; o >>= 1) { if (tid < o) red[tid] += red[tid + o]; __syncthreads(); }
    if (tid == 0) {
        float sum = red[0];
        if (mode == 0) {
            dout[b * N_ + i] = rsqrtf(fmaxf(sum - row[i] + 1.f, 1.f));
        } else {
            dout[b * N_ + i] = rsqrtf(fmaxf(sum + 1.f, 1.f));
            rnz[b * N_ + i] = (sum > 0.f) ? 1.f : 0.f;
        }
    }
}

// alpha_n = sigmoid((rnz_n d_n sum_m (Ac_nm + delta) d_m v_m)^2) straight from Ac
__global__ void alpha2d_kernel(const float* __restrict__ Ac, const float* __restrict__ d2,
                               const float* __restrict__ rz2, const float* __restrict__ v,
                               const int* __restrict__ cnt, float* __restrict__ alp) {
    __shared__ float dv[N_];
    __shared__ float red[256];
    int b = blockIdx.y, n = blockIdx.x, tid = threadIdx.x;
    int cnp = (cnt[b] + 127) & ~127;
    if (n >= cnp) { if (tid == 0) alp[b * N_ + n] = 0.5f; return; }
    for (int m = tid; m < cnp; m += 256) dv[m] = d2[b * N_ + m] * v[b * N_ + m];
    __syncthreads();
    const float4* row4 = (const float4*)(Ac + ((size_t)(b * N_ + n)) * N_);
    const float4* dv4 = (const float4*)dv;
    float s = 0.f;
    for (int m = tid; m < (cnp >> 2); m += 256) {
        float4 a = row4[m], w = dv4[m];
        s += a.x * w.x + a.y * w.y + a.z * w.z + a.w * w.w;
    }
    red[tid] = s; __syncthreads();
    for (int o = 128; o > 0; o >>= 1) { if (tid < o) red[tid] += red[tid + o]; __syncthreads(); }
    if (tid == 0) {
        float r = rz2[b * N_ + n] * d2[b * N_ + n] * (red[0] + dv[n]);
        alp[b * N_ + n] = 1.f / (1.f + expf(-r * r));
    }
}

// S2c row n from Ac directly: p_m = (Ac+delta)*d_m*ca_m; S = f*p / max(f*sum(p),1e-12)
__global__ void buildS2d_kernel(const float* __restrict__ Ac, const float* __restrict__ d2,
                                const float* __restrict__ rz2, const float* __restrict__ ca,
                                const int* __restrict__ cnt, float* __restrict__ S2) {
    __shared__ float dca[N_];
    __shared__ float p[N_];
    __shared__ float red[256];
    int b = blockIdx.y, n = blockIdx.x, tid = threadIdx.x;
    int cnp = (cnt[b] + 127) & ~127;
    if (n >= cnp) return;
    for (int m = tid; m < cnp; m += 256) dca[m] = d2[b * N_ + m] * ca[b * N_ + m];
    __syncthreads();
    const float4* row4 = (const float4*)(Ac + ((size_t)(b * N_ + n)) * N_);
    const float4* dca4 = (const float4*)dca;
    float4* p4 = (float4*)p;
    for (int m = tid; m < (cnp >> 2); m += 256) {
        float4 a = row4[m], w = dca4[m];
        p4[m] = make_float4(a.x * w.x, a.y * w.y, a.z * w.z, a.w * w.w);
    }
    __syncthreads();
    if (tid == 0) p[n] += dca[n];
    __syncthreads();
    float s = 0.f;
    for (int m = tid; m < cnp; m += 256) s += p[m];
    red[tid] = s; __syncthreads();
    for (int o = 128; o > 0; o >>= 1) { if (tid < o) red[tid] += red[tid + o]; __syncthreads(); }
    float f = rz2[b * N_ + n] * d2[b * N_ + n];
    float inv = f / fmaxf(f * red[0], 1e-12f);
    float* orow = S2 + ((size_t)(b * N_ + n)) * N_;
    for (int m = tid; m < cnp; m += 256) orow[m] = p[m] * inv;
}

// ---------------- bf16 split conversions --------------------------------------
__global__ void split_rm_kernel(const float* __restrict__ in, __nv_bfloat16* __restrict__ hi,
                                __nv_bfloat16* __restrict__ lo, const int* __restrict__ cnt) {
    int b = blockIdx.z, i = blockIdx.y;
    int j = blockIdx.x * 256 + threadIdx.x;
    int cnp = (cnt[b] + 127) & ~127;
    if (i >= cnp || j >= cnp) return;
    size_t idx = (size_t)b * N_ * N_ + (size_t)i * N_ + j;
    float v = in[idx];
    __nv_bfloat16 h = __float2bfloat16(v);
    hi[idx] = h;
    lo[idx] = __float2bfloat16(v - __bfloat162float(h));
}

// NA3 split on the fly: v = d_i d_j (i==j ? 1 : A3_ij)
__global__ void split_na3_kernel(const float* __restrict__ A3, const float* __restrict__ d,
                                 const int* __restrict__ cnt, __nv_bfloat16* __restrict__ hi,
                                 __nv_bfloat16* __restrict__ lo) {
    int b = blockIdx.z, i = blockIdx.y;
    int j = blockIdx.x * 256 + threadIdx.x;
    int cnp = (cnt[b] + 127) & ~127;
    if (i >= cnp || j >= cnp) return;
    size_t idx = (size_t)b * N_ * N_ + (size_t)i * N_ + j;
    float v = d[b * N_ + i] * d[b * N_ + j] * ((i == j) ? 1.f : A3[idx]);
    __nv_bfloat16 h = __float2bfloat16(v);
    hi[idx] = h;
    lo[idx] = __float2bfloat16(v - __bfloat162float(h));
}

// generic transposed split: out[j][i] = in[i][j]; in R x C (ld), out stride N_
__global__ void split_tr_kernel(const float* __restrict__ in, __nv_bfloat16* __restrict__ hi,
                                __nv_bfloat16* __restrict__ lo, const int* __restrict__ cnt,
                                int Rfixed, int Cfixed, int ld, long sIn) {
    __shared__ float tile[32][33];
    int b = blockIdx.z;
    int cnp = (cnt[b] + 127) & ~127;
    int R = Rfixed ? Rfixed : cnp;
    int C = Cfixed ? Cfixed : cnp;
    int i0 = blockIdx.y * 32, j0 = blockIdx.x * 32;
    if (i0 >= R || j0 >= C) return;
    const float* inb = in + (size_t)b * sIn;
    size_t boff = (size_t)b * N_ * N_;
    int tx = threadIdx.x, ty = threadIdx.y;   // (32, 8)
    #pragma unroll
    for (int r = 0; r < 4; r++) {
        int i = ty + r * 8;
        tile[i][tx] = inb[(size_t)(i0 + i) * ld + j0 + tx];
    }
    __syncthreads();
    #pragma unroll
    for (int r = 0; r < 4; r++) {
        int j = ty + r * 8;
        float v = tile[tx][j];
        __nv_bfloat16 h = __float2bfloat16(v);
        size_t o = boff + (size_t)(j0 + j) * N_ + i0 + tx;
        hi[o] = h;
        lo[o] = __float2bfloat16(v - __bfloat162float(h));
    }
}

// ---------------- bf16-split tensor GEMM (mma.sync + ldmatrix) ---------------
// C = A @ B via 3-pass split. A row-major [m][k] stride N_; BT [n][k] stride N_.
// M = K = cnp; N = NpFixed or cnp. EPI: 0 none, 2 (+bias)*mask, 3 floor-quant.
template<int EPI>
__global__ void __launch_bounds__(256, 2) gemm_bf16_kernel(
    const __nv_bfloat16* __restrict__ Ahi, const __nv_bfloat16* __restrict__ Alo,
    const __nv_bfloat16* __restrict__ BThi, const __nv_bfloat16* __restrict__ BTlo,
    float* __restrict__ C, const int* __restrict__ cnt,
    int NpFixed, int ldc, long sC,
    const float* __restrict__ bias, const float* __restrict__ mask) {
    __shared__ __nv_bfloat16 As[2][128 * 40];
    __shared__ __nv_bfloat16 Bs[2][128 * 40];
    const int b = blockIdx.z;
    const int cnp = (cnt[b] + 127) & ~127;
    const int Np = NpFixed ? NpFixed : cnp;
    const int m0 = blockIdx.y * 128, n0 = blockIdx.x * 128;
    if (m0 >= cnp || n0 >= Np) return;
    const size_t boff = (size_t)b * N_ * N_;
    const int tid = threadIdx.x;
    const int wid = tid >> 5, lane = tid & 31;
    const int wm = wid >> 1, wn = wid & 1;     // warps 4 x 2 -> warp tile 32 x 64
    const int g = lane >> 2, t4 = lane & 3;
    // ldmatrix lane addressing
    const int a_row = lane & 15;
    const int a_k   = (lane & 16) ? 8 : 0;
    const int b_row = (lane & 7) + ((lane & 16) ? 8 : 0);
    const int b_k   = (lane & 8) ? 8 : 0;
    const int KT = cnp >> 5, TT = 3 * KT;

    float acc[2][8][4];
    #pragma unroll
    for (int fm = 0; fm < 2; fm++)
        #pragma unroll
        for (int fn = 0; fn < 8; fn++)
            #pragma unroll
            for (int r = 0; r < 4; r++) acc[fm][fn][r] = 0.f;

    auto stage = [&](int t, int buf) {
        const __nv_bfloat16 *Ag, *Bg; int kt;
        if (t < KT)            { Ag = Ahi; Bg = BThi; kt = t; }
        else if (t < 2 * KT)   { Ag = Ahi; Bg = BTlo; kt = t - KT; }
        else                   { Ag = Alo; Bg = BThi; kt = t - 2 * KT; }
        Ag += boff + (size_t)m0 * N_ + kt * 32;
        Bg += boff + (size_t)n0 * N_ + kt * 32;
        #pragma unroll
        for (int q = 0; q < 4; q++) {
            int c = q * 256 + tid;
            int row = c >> 3, cc = (c & 7) * 4;
            CP8(&As[buf][row * 40 + cc], Ag + (size_t)row * N_ + cc);
            CP8(&Bs[buf][row * 40 + cc], Bg + (size_t)row * N_ + cc);
        }
    };

    stage(0, 0);
    CP_COMMIT();

    for (int t = 0; t < TT; t++) {
        CP_WAIT0();
        __syncthreads();
        if (t + 1 < TT) { stage(t + 1, (t + 1) & 1); CP_COMMIT(); }
        const int buf = t & 1;
        #pragma unroll
        for (int kh = 0; kh < 32; kh += 16) {
            uint32_t af[2][4];
            #pragma unroll
            for (int fm = 0; fm < 2; fm++)
                ldsm4(af[fm], &As[buf][(wm * 32 + fm * 16 + a_row) * 40 + kh + a_k]);
            #pragma unroll
            for (int fn2 = 0; fn2 < 4; fn2++) {
                uint32_t bb[4];
                ldsm4(bb, &Bs[buf][(wn * 64 + fn2 * 16 + b_row) * 40 + kh + b_k]);
                mma_bf16(acc[0][2 * fn2],     af[0], bb[0], bb[1]);
                mma_bf16(acc[1][2 * fn2],     af[1], bb[0], bb[1]);
                mma_bf16(acc[0][2 * fn2 + 1], af[0], bb[2], bb[3]);
                mma_bf16(acc[1][2 * fn2 + 1], af[1], bb[2], bb[3]);
            }
        }
        __syncthreads();
    }

    #pragma unroll
    for (int fm = 0; fm < 2; fm++) {
        int mr = m0 + wm * 32 + fm * 16 + g;
        float mk = (EPI == 2) ? mask[(size_t)b * N_ + mr] : 1.f;
        #pragma unroll
        for (int fn = 0; fn < 8; fn++) {
            int n = n0 + wn * 64 + fn * 8 + t4 * 2;
            float v0 = acc[fm][fn][0], v1 = acc[fm][fn][1];
            float v2 = acc[fm][fn][2], v3 = acc[fm][fn][3];
            if (EPI == 2) {
                v0 = (v0 + bias[n]) * mk;     v1 = (v1 + bias[n + 1]) * mk;
                v2 = (v2 + bias[n]) * mk;     v3 = (v3 + bias[n + 1]) * mk;
            } else if (EPI == 3) {
                v0 = floorf(v0 * 10000.f) / 10000.f;
                v1 = floorf(v1 * 10000.f) / 10000.f;
                v2 = floorf(v2 * 10000.f) / 10000.f;
                v3 = floorf(v3 * 10000.f) / 10000.f;
            }
            float* p0 = C + (size_t)b * sC + (size_t)mr * ldc + n;
            p0[0] = v0; p0[1] = v1;
            float* p1 = p0 + 8 * (size_t)ldc;
            p1[0] = v2; p1[1] = v3;
        }
    }
}

// ---------------- double-buffered cp.async SIMT GEMM (small GEMMs) -----------
template<int TRANSA, int EPI>
__global__ void __launch_bounds__(256, 2) gemm2_kernel(
    const float* __restrict__ A, const float* __restrict__ Bm, float* __restrict__ C,
    int M, int Kd, int Nc, int lda, int ldb, int ldc,
    long sA, long sB, long sC,
    const float* __restrict__ bias, const float* __restrict__ mask,
    const int* __restrict__ cnt, int dynM, int dynK, int dynN) {
    __shared__ float As[2][128 * 16];
    __shared__ float Bs[2][16 * 128];
    const int b = blockIdx.z;
    int Mp = M, Kp = Kd, Np = Nc;
    if (cnt) {
        int p = (cnt[b] + 127) & ~127;
        if (dynM) Mp = p; if (dynK) Kp = p; if (dynN) Np = p;
    }
    const int n0 = blockIdx.x * 128, m0 = blockIdx.y * 128;
    if (m0 >= Mp || n0 >= Np) return;
    A  += (size_t)b * sA;
    Bm += (size_t)b * sB;
    C  += (size_t)b * sC;
    const int tid = threadIdx.x, tx = tid & 15, ty = tid >> 4;
    float acc[8][8];
    #pragma unroll
    for (int i = 0; i < 8; i++)
        #pragma unroll
        for (int j = 0; j < 8; j++) acc[i][j] = 0.f;

    const int Kt = Kp >> 4;

    auto load_tiles = [&](int k0, int buf) {
        if (!TRANSA) {
            #pragma unroll
            for (int q = 0; q < 2; q++) {
                int c = tid + q * 256;
                int row = c >> 2, col4 = (c & 3) * 4;
                const float* src = A + (size_t)(m0 + row) * lda + k0 + col4;
                CP16(&As[buf][row * 16 + col4], src);
            }
        } else {
            #pragma unroll
            for (int q = 0; q < 2; q++) {
                int c = tid + q * 256;
                int row = c >> 5, col4 = (c & 31) * 4;
                const float* src = A + (size_t)(k0 + row) * lda + m0 + col4;
                CP16(&As[buf][row * 128 + col4], src);
            }
        }
        #pragma unroll
        for (int q = 0; q < 2; q++) {
            int c = tid + q * 256;
            int row = c >> 5, col4 = (c & 31) * 4;
            const float* src = Bm + (size_t)(k0 + row) * ldb + n0 + col4;
            CP16(&Bs[buf][row * 128 + col4], src);
        }
    };

    load_tiles(0, 0);
    CP_COMMIT();

    for (int t = 0; t < Kt; t++) {
        CP_WAIT0();
        __syncthreads();
        if (t + 1 < Kt) { load_tiles((t + 1) << 4, (t + 1) & 1); CP_COMMIT(); }
        const int buf = t & 1;
        #pragma unroll
        for (int k = 0; k < 16; k++) {
            float a[8], bv[8];
            if (!TRANSA) {
                #pragma unroll
                for (int i = 0; i < 8; i++) a[i] = As[buf][(ty * 8 + i) * 16 + k];
            } else {
                *(float4*)(a)     = *(const float4*)&As[buf][k * 128 + ty * 8];
                *(float4*)(a + 4) = *(const float4*)&As[buf][k * 128 + ty * 8 + 4];
            }
            *(float4*)(bv)     = *(const float4*)&Bs[buf][k * 128 + tx * 8];
            *(float4*)(bv + 4) = *(const float4*)&Bs[buf][k * 128 + tx * 8 + 4];
            #pragma unroll
            for (int i = 0; i < 8; i++)
                #pragma unroll
                for (int j = 0; j < 8; j++) acc[i][j] = fmaf(a[i], bv[j], acc[i][j]);
        }
        __syncthreads();
    }
    #pragma unroll
    for (int i = 0; i < 8; i++) {
        int m = m0 + ty * 8 + i;
        float mk = (EPI == 2) ? mask[(size_t)b * N_ + m] : 1.f;
        #pragma unroll
        for (int j = 0; j < 8; j++) {
            int n = n0 + tx * 8 + j;
            float v = acc[i][j];
            if (EPI == 2)      { v = (v + bias[n]) * mk; }
            else if (EPI == 3) { v = floorf(v * 10000.f) / 10000.f; }
            C[(size_t)m * ldc + n] = v;
        }
    }
}

// ---------------- output means (two-stage, deterministic) --------------------
__global__ void mean1_part_kernel(const float* __restrict__ x1, float* __restrict__ p1) {
    int b = blockIdx.y, q = blockIdx.x, c = threadIdx.x;   // 128 threads
    float s = 0.f;
    for (int n = q * 512; n < (q + 1) * 512; n++) s += x1[((size_t)(b * N_ + n)) * H_ + c];
    p1[(b * 4 + q) * H_ + c] = s;
}

__global__ void mean2_part_kernel(const float* __restrict__ x2f, const int* __restrict__ cnt,
                                  float* __restrict__ p2) {
    int b = blockIdx.y, q = blockIdx.x, c = threadIdx.x;   // 256 threads
    int cn = cnt[b];
    int lo = q * 512, hi = (q + 1) * 512; if (hi > cn) hi = cn;
    float s = 0.f;
    for (int n = lo; n < hi; n++) s += x2f[((size_t)(b * N_ + n)) * F_ + c];
    p2[(b * 4 + q) * F_ + c] = s;
}

__global__ void mean_combine_kernel(const float* __restrict__ p1, const float* __restrict__ p2,
                                    const float* __restrict__ b2, const float* __restrict__ mrest,
                                    float* __restrict__ out) {
    int b = blockIdx.x, c = threadIdx.x;   // 384 threads
    if (c < H_) {
        float s = 0.f;
        for (int q = 0; q < 4; q++) s += p1[(b * 4 + q) * H_ + c];
        out[b * OUTC + c] = s / (float)N_;
    } else {
        int cc = c - H_;
        float s = b2[cc] * mrest[b];
        for (int q = 0; q < 4; q++) s += p2[(b * 4 + q) * F_ + cc];
        out[b * OUTC + c] = s / (float)N_;
    }
}

extern "C" void kernel_launch(void* const* d_in, const int* in_sizes, int n_in,
                              void* d_out, int out_size) {
    const float* x    = (const float*)d_in[0];
    const float* adj  = (const float*)d_in[1];
    const float* mask = (const float*)d_in[2];
    const float* W1   = (const float*)d_in[3];
    const float* b1   = (const float*)d_in[4];
    const float* Watt = (const float*)d_in[5];
    const float* batt = (const float*)d_in[6];
    const float* W2   = (const float*)d_in[7];
    const float* b2   = (const float*)d_in[8];
    float* out = (float*)d_out;

    float *pNA,*pT,*pAc,*pA3,*pSc,*pxW,*px1,*pxc,*px3,*px2f;
    float *pv,*palp,*pca,*psrec,*pd0,*pd1,*prnz,*pd2,*prz2,*pcut,*pmaskc,*pmrest,*pp1,*pp2;
    __nv_bfloat16 *pAhi,*pAlo,*pSThi,*pSTlo,*pTThi,*pTTlo;
    int *plst,*pdeg,*phasd,*pidx,*pginv,*pcnt;
    cudaGetSymbolAddress((void**)&pNA,  g_NA);
    cudaGetSymbolAddress((void**)&pT,   g_T);
    cudaGetSymbolAddress((void**)&pAc,  g_Ac);
    cudaGetSymbolAddress((void**)&pA3,  g_A3);
    cudaGetSymbolAddress((void**)&pSc,  g_Sc);
    cudaGetSymbolAddress((void**)&pAhi, g_Ahi);
    cudaGetSymbolAddress((void**)&pAlo, g_Alo);
    cudaGetSymbolAddress((void**)&pSThi,g_SThi);
    cudaGetSymbolAddress((void**)&pSTlo,g_STlo);
    cudaGetSymbolAddress((void**)&pTThi,g_TThi);
    cudaGetSymbolAddress((void**)&pTTlo,g_TTlo);
    cudaGetSymbolAddress((void**)&pxW,  g_xW);
    cudaGetSymbolAddress((void**)&px1,  g_x1);
    cudaGetSymbolAddress((void**)&pxc,  g_xc);
    cudaGetSymbolAddress((void**)&px3,  g_x3);
    cudaGetSymbolAddress((void**)&px2f, g_x2f);
    cudaGetSymbolAddress((void**)&pv,   g_v);
    cudaGetSymbolAddress((void**)&palp, g_alp);
    cudaGetSymbolAddress((void**)&pca,  g_ca);
    cudaGetSymbolAddress((void**)&psrec,g_srec);
    cudaGetSymbolAddress((void**)&pd0,  g_d0);
    cudaGetSymbolAddress((void**)&pd1,  g_d1);
    cudaGetSymbolAddress((void**)&prnz, g_rnz);
    cudaGetSymbolAddress((void**)&pd2,  g_d2);
    cudaGetSymbolAddress((void**)&prz2, g_rz2);
    cudaGetSymbolAddress((void**)&pcut, g_cut);
    cudaGetSymbolAddress((void**)&pmaskc, g_maskc);
    cudaGetSymbolAddress((void**)&pmrest, g_mrest);
    cudaGetSymbolAddress((void**)&pp1,  g_p1);
    cudaGetSymbolAddress((void**)&pp2,  g_p2);
    cudaGetSymbolAddress((void**)&plst, g_lst);
    cudaGetSymbolAddress((void**)&pdeg, g_deg);
    cudaGetSymbolAddress((void**)&phasd,g_hasd);
    cudaGetSymbolAddress((void**)&pidx, g_idx);
    cudaGetSymbolAddress((void**)&pginv,g_ginv);
    cudaGetSymbolAddress((void**)&pcnt, g_cnt);

    // ---- CSR + degree stats (single adj scan) ----
    csr_build_kernel<<<dim3(N_, B_), 256>>>(adj, plst, pdeg, phasd, pd0, pd1, prnz);

    // ---- GCN layer 1 (sparse aggregation) ----
    gemm2_kernel<0,0><<<dim3(1,16,B_),256>>>(x, W1, pxW, N_, F_, H_, F_, H_, H_,
        (long)N_*F_, 0, (long)N_*H_, nullptr, nullptr, nullptr, 0,0,0);
    gcn1_kernel<<<dim3(N_, B_), 128>>>(plst, pdeg, pd0, pxW, b1, mask, px1);

    // ---- coarsen layer 1 (sparse) ----
    gemv_watt_kernel<<<(B_*N_)/8, 256>>>(px1, Watt, batt, pv);
    alpha1_kernel<<<dim3(N_/8, B_), 256>>>(plst, pdeg, pd1, prnz, pv, palp);
    topk_cut_kernel<<<B_, 1024>>>(palp, pcut);
    ca_kernel<<<(B_*N_)/256, 256>>>(palp, pcut, pca);
    compact_kernel<<<B_, 1024>>>(pca, pidx, pginv, pcnt);
    compact_mask_kernel<<<B_, 256>>>(mask, pidx, pcnt, pmaskc, pmrest);
    srec_kernel<<<dim3(N_/8, B_), 256>>>(plst, pdeg, pd1, prnz, pca, psrec);
    buildSc_kernel<<<dim3(N_, B_), 256>>>(plst, pdeg, phasd, pd1, pca, psrec, pginv, pcnt, pSc);
    xupd_kernel<<<dim3(N_, B_), 128>>>(plst, pdeg, phasd, pd1, pca, psrec, pidx, pcnt, px1, pxc);
    adjS_kernel<<<dim3(N_, B_), 256>>>(plst, pdeg, pcnt, pSc, pT);
    STT_kernel<<<dim3(N_, B_), 256>>>(plst, pdeg, phasd, pd1, pca, psrec, pidx, pcnt, pT, pAc);

    // ---- coarsen layer 2 (fused elementwise + tensor GEMMs) ----
    rowstats_c_kernel<<<dim3(N_, B_), 256>>>(pAc, pcnt, pd2, prz2, 1);
    gemv_watt_kernel<<<(B_*N_)/8, 256>>>(pxc, Watt, batt, pv);
    alpha2d_kernel<<<dim3(N_, B_), 256>>>(pAc, pd2, prz2, pv, pcnt, palp);
    topk_cut_kernel<<<B_, 1024>>>(palp, pcut);
    ca_kernel<<<(B_*N_)/256, 256>>>(palp, pcut, pca);
    buildS2d_kernel<<<dim3(N_, B_), 256>>>(pAc, pd2, prz2, pca, pcnt, pNA);   // -> S2c
    // splits: S2c^T, xc^T
    split_tr_kernel<<<dim3(64, 64, B_), dim3(32, 8)>>>(pNA, pSThi, pSTlo, pcnt,
        0, 0, N_, (long)N_*N_);
    split_tr_kernel<<<dim3(4, 64, B_), dim3(32, 8)>>>(pxc, pTThi, pTTlo, pcnt,
        0, H_, H_, (long)N_*H_);
    // x3 = S2c^T @ xc (tensor)
    gemm_bf16_kernel<0><<<dim3(1,16,B_),256>>>(pSThi, pSTlo, pTThi, pTTlo, px3, pcnt,
        H_, H_, (long)N_*H_, nullptr, nullptr);
    // T2 = Ac @ S2c (tensor)
    split_rm_kernel<<<dim3(8, N_, B_), 256>>>(pAc, pAhi, pAlo, pcnt);
    gemm_bf16_kernel<0><<<dim3(16,16,B_),256>>>(pAhi, pAlo, pSThi, pSTlo, pT, pcnt,
        0, N_, (long)N_*N_, nullptr, nullptr);
    // A3 = S2c^T @ T2 (tensor, floor-quant)
    split_tr_kernel<<<dim3(64, 64, B_), dim3(32, 8)>>>(pT, pTThi, pTTlo, pcnt,
        0, 0, N_, (long)N_*N_);
    gemm_bf16_kernel<3><<<dim3(16,16,B_),256>>>(pSThi, pSTlo, pTThi, pTTlo, pA3, pcnt,
        0, N_, (long)N_*N_, nullptr, nullptr);

    // ---- final GCN (compacted, tensor): x2f = (NA3 @ (x3 @ W2) + b2) * maskc
    rowstats_c_kernel<<<dim3(N_, B_), 256>>>(pA3, pcnt, pd2, nullptr, 0);
    split_na3_kernel<<<dim3(8, N_, B_), 256>>>(pA3, pd2, pcnt, pAhi, pAlo);
    gemm2_kernel<0,0><<<dim3(2,16,B_),256>>>(px3, W2, pxW, N_, H_, F_, H_, F_, F_,
        (long)N_*H_, 0, (long)N_*F_, nullptr, nullptr, pcnt, 1,0,0);
    split_tr_kernel<<<dim3(8, 64, B_), dim3(32, 8)>>>(pxW, pTThi, pTTlo, pcnt,
        0, F_, F_, (long)N_*F_);
    gemm_bf16_kernel<2><<<dim3(2,16,B_),256>>>(pAhi, pAlo, pTThi, pTTlo, px2f, pcnt,
        F_, F_, (long)N_*F_, b2, pmaskc);

    // ---- concat means ----
    mean1_part_kernel<<<dim3(4, B_), 128>>>(px1, pp1);
    mean2_part_kernel<<<dim3(4, B_), 256>>>(px2f, pcnt, pp2);
    mean_combine_kernel<<<B_, 384>>>(pp1, pp2, b2, pmrest, out);
}

// round 6
// speedup vs baseline: 5.5586x; 1.1674x over previous
#include <cuda_runtime.h>
#include <cuda_bf16.h>
#include <math.h>
#include <stdint.h>

#define B_ 8
#define N_ 2048
#define F_ 256
#define H_ 128
#define K_ 1025
#define OUTC 384
#define CAP 256

// ---------------- scratch (device globals; no allocation allowed) ----------
__device__ float g_NA[(size_t)B_*N_*N_];   // layer2 S2c (stride N_)
__device__ float g_T [(size_t)B_*N_*N_];   // Tc (layer1, stride cnp)
__device__ float g_Ac[(size_t)B_*N_*N_];   // compacted A2 (stride N_)
__device__ float g_A3[(size_t)B_*N_*N_];   // compacted A3 (stride N_)
__device__ float g_Sc[(size_t)B_*N_*N_];   // compacted S (stride cnp)
__device__ __nv_bfloat16 g_Ahi[(size_t)B_*N_*N_], g_Alo[(size_t)B_*N_*N_];
__device__ __nv_bfloat16 g_SThi[(size_t)B_*N_*N_], g_STlo[(size_t)B_*N_*N_];
__device__ __nv_bfloat16 g_TThi[(size_t)B_*N_*N_], g_TTlo[(size_t)B_*N_*N_];
__device__ float g_xW [B_*N_*F_];
__device__ float g_x1 [B_*N_*H_];
__device__ float g_xc [B_*N_*H_];
__device__ float g_x3 [B_*N_*H_];
__device__ float g_x2f[B_*N_*F_];
__device__ int   g_lst[(size_t)B_*N_*CAP];
__device__ int   g_deg[B_*N_];
__device__ int   g_hasd[B_*N_];
__device__ float g_d0[B_*N_], g_d1[B_*N_], g_rnz[B_*N_];
__device__ float g_d2[B_*N_], g_rz2[B_*N_];
__device__ float g_v[B_*N_], g_alp[B_*N_], g_ca[B_*N_], g_srec[B_*N_];
__device__ float g_cut[B_];
__device__ float g_maskc[B_*N_], g_mrest[B_];
__device__ int   g_idx[B_*N_], g_ginv[B_*N_], g_cnt[B_];
__device__ float g_p1[B_*4*H_], g_p2[B_*4*F_];

// ---------------- async-copy / mma helpers -----------------------------------
#define CP16(dst, src) { \
    unsigned _a = (unsigned)__cvta_generic_to_shared(dst); \
    asm volatile("cp.async.cg.shared.global [%0], [%1], 16;\n" :: "r"(_a), "l"(src)); }
#define CP_COMMIT() asm volatile("cp.async.commit_group;\n")
#define CP_WAIT0()  asm volatile("cp.async.wait_group 0;\n")

__device__ __forceinline__ void mma_bf16(float* c, const uint32_t* a, uint32_t b0, uint32_t b1) {
    asm volatile("mma.sync.aligned.m16n8k16.row.col.f32.bf16.bf16.f32 "
        "{%0,%1,%2,%3}, {%4,%5,%6,%7}, {%8,%9}, {%0,%1,%2,%3};"
        : "+f"(c[0]), "+f"(c[1]), "+f"(c[2]), "+f"(c[3])
        : "r"(a[0]), "r"(a[1]), "r"(a[2]), "r"(a[3]), "r"(b0), "r"(b1));
}
__device__ __forceinline__ void ldsm4(uint32_t* r, const void* p) {
    uint32_t a = (uint32_t)__cvta_generic_to_shared(p);
    asm volatile("ldmatrix.sync.aligned.m8n8.x4.shared.b16 {%0,%1,%2,%3}, [%4];"
        : "=r"(r[0]), "=r"(r[1]), "=r"(r[2]), "=r"(r[3]) : "r"(a));
}
__device__ __forceinline__ __nv_bfloat162 split_hi2(float v0, float v1) {
    __nv_bfloat162 h; h.x = __float2bfloat16(v0); h.y = __float2bfloat16(v1); return h;
}
__device__ __forceinline__ __nv_bfloat162 split_lo2(float v0, float v1, __nv_bfloat162 h) {
    __nv_bfloat162 l;
    l.x = __float2bfloat16(v0 - __bfloat162float(h.x));
    l.y = __float2bfloat16(v1 - __bfloat162float(h.y));
    return l;
}

// ---------------- CSR build + degree stats (one adj scan) -------------------
__global__ void csr_build_kernel(const float* __restrict__ adj, int* __restrict__ lst,
                                 int* __restrict__ deg, int* __restrict__ hasd,
                                 float* __restrict__ d0, float* __restrict__ d1,
                                 float* __restrict__ rnz) {
    __shared__ int sc[256];
    __shared__ int hd;
    int b = blockIdx.y, i = blockIdx.x, tid = threadIdx.x;
    const float* arow = adj + ((size_t)(b * N_ + i)) * N_;
    if (tid == 0) hd = 0;
    __syncthreads();
    int flags[8];
    int c = 0;
    #pragma unroll
    for (int q = 0; q < 8; q++) {
        int j = tid + q * 256;
        int f = (arow[j] != 0.f) ? 1 : 0;
        flags[q] = f; c += f;
        if (f && j == i) hd = 1;
    }
    sc[tid] = c; __syncthreads();
    for (int o = 1; o < 256; o <<= 1) {
        int v = (tid >= o) ? sc[tid - o] : 0; __syncthreads();
        sc[tid] += v; __syncthreads();
    }
    int base = sc[tid] - c;
    int* l = lst + ((size_t)(b * N_ + i)) * CAP;
    #pragma unroll
    for (int q = 0; q < 8; q++) {
        int j = tid + q * 256;
        if (flags[q]) { if (base < CAP) l[base] = j; base++; }
    }
    __syncthreads();
    if (tid == 0) {
        int total = sc[255];
        deg[b * N_ + i] = (total > CAP) ? CAP : total;
        hasd[b * N_ + i] = hd;
        d0[b * N_ + i] = rsqrtf(fmaxf((float)(total - hd) + 1.f, 1.f));
        d1[b * N_ + i] = rsqrtf((float)total + 1.f);
        rnz[b * N_ + i] = (total > 0) ? 1.f : 0.f;
    }
}

// ---------------- GCN layer 1 sparse aggregation -----------------------------
__global__ void gcn1_kernel(const int* __restrict__ lst, const int* __restrict__ deg,
                            const float* __restrict__ d0, const float* __restrict__ xW,
                            const float* __restrict__ b1, const float* __restrict__ mask,
                            float* __restrict__ x1) {
    int b = blockIdx.y, i = blockIdx.x, c = threadIdx.x;   // 128 threads
    int dg = deg[b * N_ + i];
    const int* l = lst + ((size_t)(b * N_ + i)) * CAP;
    float di = d0[b * N_ + i];
    float acc = di * di * xW[((size_t)(b * N_ + i)) * H_ + c];
    for (int p = 0; p < dg; p++) {
        int j = l[p];
        if (j != i) acc = fmaf(di * d0[b * N_ + j], xW[((size_t)(b * N_ + j)) * H_ + c], acc);
    }
    float vv = (acc + b1[c]) * mask[b * N_ + i];
    x1[((size_t)(b * N_ + i)) * H_ + c] = fmaxf(vv, 0.f);
}

// ---------------- v = x @ Watt + batt ----------------------------------------
__global__ void gemv_watt_kernel(const float* __restrict__ x, const float* __restrict__ Watt,
                                 const float* __restrict__ batt, float* __restrict__ v) {
    int w = blockIdx.x * 8 + (threadIdx.x >> 5);
    int lane = threadIdx.x & 31;
    if (w >= B_ * N_) return;
    const float* xr = x + (size_t)w * H_;
    float s = 0.f;
    #pragma unroll
    for (int c = lane; c < H_; c += 32) s += xr[c] * Watt[c];
    #pragma unroll
    for (int o = 16; o > 0; o >>= 1) s += __shfl_down_sync(0xffffffffu, s, o);
    if (lane == 0) v[w] = s + batt[0];
}

// ---------------- layer-1 alpha (sparse) --------------------------------------
__global__ void alpha1_kernel(const int* __restrict__ lst, const int* __restrict__ deg,
                              const float* __restrict__ d1, const float* __restrict__ rnz,
                              const float* __restrict__ v, float* __restrict__ alp) {
    int b = blockIdx.y;
    int i = blockIdx.x * 8 + (threadIdx.x >> 5);
    int lane = threadIdx.x & 31;
    const int* l = lst + ((size_t)(b * N_ + i)) * CAP;
    int dg = deg[b * N_ + i];
    float s = 0.f;
    for (int p = lane; p < dg; p += 32) { int j = l[p]; s += d1[b * N_ + j] * v[b * N_ + j]; }
    #pragma unroll
    for (int o = 16; o > 0; o >>= 1) s += __shfl_down_sync(0xffffffffu, s, o);
    if (lane == 0) {
        float di = d1[b * N_ + i];
        float r = rnz[b * N_ + i] * di * (s + di * v[b * N_ + i]);
        float z = r * r;
        alp[b * N_ + i] = 1.f / (1.f + expf(-z));
    }
}

// ---------------- exact K-th largest via bitonic sort ------------------------
__global__ void topk_cut_kernel(const float* __restrict__ alp, float* __restrict__ cut) {
    __shared__ float s[N_];
    int b = blockIdx.x, t = threadIdx.x;   // 1024 threads
    s[t] = alp[b * N_ + t];
    s[t + 1024] = alp[b * N_ + t + 1024];
    __syncthreads();
    for (int k = 2; k <= N_; k <<= 1) {
        for (int j = k >> 1; j > 0; j >>= 1) {
            for (int i = t; i < N_; i += 1024) {
                int ixj = i ^ j;
                if (ixj > i) {
                    float a = s[i], c = s[ixj];
                    if (((i & k) == 0) ? (a > c) : (a < c)) { s[i] = c; s[ixj] = a; }
                }
            }
            __syncthreads();
        }
    }
    if (t == 0) cut[b] = s[N_ - K_];
}

__global__ void ca_kernel(const float* __restrict__ alp, const float* __restrict__ cut,
                          float* __restrict__ ca) {
    int idx = blockIdx.x * 256 + threadIdx.x;
    int b = idx / N_;
    ca[idx] = fmaxf(alp[idx] + 1e-7f - cut[b], 0.f);
}

// ---------------- deterministic kept-set compaction (prefix scan) -----------
__global__ void compact_kernel(const float* __restrict__ ca, int* __restrict__ idx,
                               int* __restrict__ ginv, int* __restrict__ cnt) {
    __shared__ int sc[1024];
    int b = blockIdx.x, t = threadIdx.x;   // 1024 threads
    int f0 = (ca[b * N_ + 2 * t]     > 0.f) ? 1 : 0;
    int f1 = (ca[b * N_ + 2 * t + 1] > 0.f) ? 1 : 0;
    ginv[b * N_ + 2 * t] = -1;
    ginv[b * N_ + 2 * t + 1] = -1;
    int c = f0 + f1;
    sc[t] = c; __syncthreads();
    for (int o = 1; o < 1024; o <<= 1) {
        int v = (t >= o) ? sc[t - o] : 0; __syncthreads();
        sc[t] += v; __syncthreads();
    }
    int base = sc[t] - c;
    if (f0) { idx[b * N_ + base] = 2 * t;     ginv[b * N_ + 2 * t]     = base; base++; }
    if (f1) { idx[b * N_ + base] = 2 * t + 1; ginv[b * N_ + 2 * t + 1] = base; }
    if (t == 1023) cnt[b] = sc[1023];
}

__global__ void compact_mask_kernel(const float* __restrict__ mask, const int* __restrict__ idx,
                                    const int* __restrict__ cnt, float* __restrict__ maskc,
                                    float* __restrict__ mrest) {
    __shared__ float red[256];
    int b = blockIdx.x, t = threadIdx.x;
    int c = cnt[b];
    float local = 0.f;
    for (int i = t; i < N_; i += 256) {
        float mv = 0.f;
        if (i < c) mv = mask[b * N_ + idx[b * N_ + i]];
        maskc[b * N_ + i] = mv;
        local += mask[b * N_ + i] - mv;
    }
    red[t] = local; __syncthreads();
    for (int o = 128; o > 0; o >>= 1) { if (t < o) red[t] += red[t + o]; __syncthreads(); }
    if (t == 0) mrest[b] = red[0];
}

// ---------------- layer-1 S row normalizer -----------------------------------
__global__ void srec_kernel(const int* __restrict__ lst, const int* __restrict__ deg,
                            const float* __restrict__ d1, const float* __restrict__ rnz,
                            const float* __restrict__ ca, float* __restrict__ srec) {
    int b = blockIdx.y;
    int i = blockIdx.x * 8 + (threadIdx.x >> 5);
    int lane = threadIdx.x & 31;
    const int* l = lst + ((size_t)(b * N_ + i)) * CAP;
    int dg = deg[b * N_ + i];
    float s = 0.f;
    for (int p = lane; p < dg; p += 32) { int j = l[p]; s += d1[b * N_ + j] * ca[b * N_ + j]; }
    #pragma unroll
    for (int o = 16; o > 0; o >>= 1) s += __shfl_down_sync(0xffffffffu, s, o);
    if (lane == 0) {
        float di = d1[b * N_ + i];
        float raw = rnz[b * N_ + i] * di * (s + di * ca[b * N_ + i]);
        srec[b * N_ + i] = rnz[b * N_ + i] * di / fmaxf(raw, 1e-12f);
    }
}

// ---------------- column-compacted S (stride cnp) ----------------------------
__global__ void buildSc_kernel(const int* __restrict__ lst, const int* __restrict__ deg,
                               const int* __restrict__ hasd, const float* __restrict__ d1,
                               const float* __restrict__ ca, const float* __restrict__ srec,
                               const int* __restrict__ ginv, const int* __restrict__ cnt,
                               float* __restrict__ Sc) {
    int b = blockIdx.y, n = blockIdx.x, tid = threadIdx.x;
    int cnp = (cnt[b] + 127) & ~127;
    float* srow = Sc + (size_t)b * N_ * N_ + (size_t)n * cnp;
    float4* srow4 = (float4*)srow;
    float4 z4 = make_float4(0.f, 0.f, 0.f, 0.f);
    for (int jc = tid; jc < (cnp >> 2); jc += 256) srow4[jc] = z4;
    __syncthreads();
    int dg = deg[b * N_ + n];
    const int* l = lst + ((size_t)(b * N_ + n)) * CAP;
    float sr = srec[b * N_ + n];
    for (int p = tid; p < dg; p += 256) {
        int m = l[p];
        int jc = ginv[b * N_ + m];
        if (jc >= 0) {
            float coef = (m == n) ? 2.f : 1.f;
            srow[jc] = sr * d1[b * N_ + m] * ca[b * N_ + m] * coef;
        }
    }
    if (tid == 0 && !hasd[b * N_ + n]) {
        int jc = ginv[b * N_ + n];
        if (jc >= 0) srow[jc] = sr * d1[b * N_ + n] * ca[b * N_ + n];
    }
}

// ---------------- xc[ic,:] = sum_n S[n, idx[ic]] * x1[n,:] -------------------
__global__ void xupd_kernel(const int* __restrict__ lst, const int* __restrict__ deg,
                            const int* __restrict__ hasd, const float* __restrict__ d1,
                            const float* __restrict__ ca, const float* __restrict__ srec,
                            const int* __restrict__ idx, const int* __restrict__ cnt,
                            const float* __restrict__ x1, float* __restrict__ xc) {
    int b = blockIdx.y, ic = blockIdx.x, c = threadIdx.x;   // 128 threads
    int cn = cnt[b], cnp = (cn + 127) & ~127;
    if (ic >= cnp) return;
    float* orow = xc + ((size_t)(b * N_ + ic)) * H_;
    if (ic >= cn) { orow[c] = 0.f; return; }
    int m = idx[b * N_ + ic];
    float dmcam = d1[b * N_ + m] * ca[b * N_ + m];
    int dg = deg[b * N_ + m];
    const int* l = lst + ((size_t)(b * N_ + m)) * CAP;
    float acc = 0.f;
    for (int p = 0; p < dg; p++) {
        int n = l[p];
        float coef = (n == m) ? 2.f : 1.f;
        float sv = srec[b * N_ + n] * dmcam * coef;
        acc = fmaf(sv, x1[((size_t)(b * N_ + n)) * H_ + c], acc);
    }
    if (!hasd[b * N_ + m])
        acc = fmaf(srec[b * N_ + m] * dmcam, x1[((size_t)(b * N_ + m)) * H_ + c], acc);
    orow[c] = acc;
}

// ---------------- Tc[i,:] = sum_{j in list_i} Sc[j,:]  (float4) --------------
__global__ void adjS_kernel(const int* __restrict__ lst, const int* __restrict__ deg,
                            const int* __restrict__ cnt, const float* __restrict__ Sc,
                            float* __restrict__ Tc) {
    __shared__ float4 acc4[N_ / 4];
    int b = blockIdx.y, i = blockIdx.x, tid = threadIdx.x;
    int cnp4 = ((cnt[b] + 127) & ~127) >> 2;
    float4 z4 = make_float4(0.f, 0.f, 0.f, 0.f);
    for (int jc = tid; jc < cnp4; jc += 256) acc4[jc] = z4;
    __syncthreads();
    int dg = deg[b * N_ + i];
    const int* l = lst + ((size_t)(b * N_ + i)) * CAP;
    const float* Sb = Sc + (size_t)b * N_ * N_;
    for (int p = 0; p < dg; p++) {
        const float4* srow = (const float4*)(Sb + (size_t)l[p] * (cnp4 << 2));
        for (int jc = tid; jc < cnp4; jc += 256) {
            float4 s = srow[jc], a = acc4[jc];
            a.x += s.x; a.y += s.y; a.z += s.z; a.w += s.w;
            acc4[jc] = a;
        }
    }
    __syncthreads();
    float4* trow = (float4*)(Tc + (size_t)b * N_ * N_ + (size_t)i * (cnp4 << 2));
    for (int jc = tid; jc < cnp4; jc += 256) trow[jc] = acc4[jc];
}

// -------- Ac[ic,:] = floorq(sum_n S[n,m] * Tc[n,:]); fused bf16 split --------
__global__ void STT_kernel(const int* __restrict__ lst, const int* __restrict__ deg,
                           const int* __restrict__ hasd, const float* __restrict__ d1,
                           const float* __restrict__ ca, const float* __restrict__ srec,
                           const int* __restrict__ idx, const int* __restrict__ cnt,
                           const float* __restrict__ Tc, float* __restrict__ Ac,
                           __nv_bfloat16* __restrict__ Achi, __nv_bfloat16* __restrict__ Aclo) {
    __shared__ float4 acc4[N_ / 4];
    int b = blockIdx.y, ic = blockIdx.x, tid = threadIdx.x;
    int cn = cnt[b], cnp = (cn + 127) & ~127, cnp4 = cnp >> 2;
    if (ic >= cnp) return;
    size_t rowoff = ((size_t)(b * N_ + ic)) * N_;
    float4* orow4 = (float4*)(Ac + rowoff);
    __nv_bfloat162* ohi = (__nv_bfloat162*)(Achi + rowoff);
    __nv_bfloat162* olo = (__nv_bfloat162*)(Aclo + rowoff);
    float4 z4 = make_float4(0.f, 0.f, 0.f, 0.f);
    if (ic >= cn) {
        __nv_bfloat162 zb; zb.x = __float2bfloat16(0.f); zb.y = zb.x;
        for (int jc = tid; jc < cnp4; jc += 256) {
            orow4[jc] = z4;
            ohi[jc * 2] = zb; ohi[jc * 2 + 1] = zb;
            olo[jc * 2] = zb; olo[jc * 2 + 1] = zb;
        }
        return;
    }
    int m = idx[b * N_ + ic];
    float dmcam = d1[b * N_ + m] * ca[b * N_ + m];
    for (int jc = tid; jc < cnp4; jc += 256) acc4[jc] = z4;
    __syncthreads();
    int dg = deg[b * N_ + m];
    const int* l = lst + ((size_t)(b * N_ + m)) * CAP;
    const float* Tb = Tc + (size_t)b * N_ * N_;
    for (int p = 0; p < dg; p++) {
        int n = l[p];
        float coef = (n == m) ? 2.f : 1.f;
        float sv = srec[b * N_ + n] * dmcam * coef;
        if (sv != 0.f) {
            const float4* trow = (const float4*)(Tb + (size_t)n * cnp);
            for (int jc = tid; jc < cnp4; jc += 256) {
                float4 t = trow[jc], a = acc4[jc];
                a.x = fmaf(sv, t.x, a.x); a.y = fmaf(sv, t.y, a.y);
                a.z = fmaf(sv, t.z, a.z); a.w = fmaf(sv, t.w, a.w);
                acc4[jc] = a;
            }
        }
    }
    if (!hasd[b * N_ + m]) {
        float sv = srec[b * N_ + m] * dmcam;
        if (sv != 0.f) {
            const float4* trow = (const float4*)(Tb + (size_t)m * cnp);
            for (int jc = tid; jc < cnp4; jc += 256) {
                float4 t = trow[jc], a = acc4[jc];
                a.x = fmaf(sv, t.x, a.x); a.y = fmaf(sv, t.y, a.y);
                a.z = fmaf(sv, t.z, a.z); a.w = fmaf(sv, t.w, a.w);
                acc4[jc] = a;
            }
        }
    }
    __syncthreads();
    for (int jc = tid; jc < cnp4; jc += 256) {
        float4 a = acc4[jc];
        a.x = floorf(a.x * 10000.f) / 10000.f;
        a.y = floorf(a.y * 10000.f) / 10000.f;
        a.z = floorf(a.z * 10000.f) / 10000.f;
        a.w = floorf(a.w * 10000.f) / 10000.f;
        orow4[jc] = a;
        __nv_bfloat162 h01 = split_hi2(a.x, a.y), h23 = split_hi2(a.z, a.w);
        ohi[jc * 2] = h01; ohi[jc * 2 + 1] = h23;
        olo[jc * 2] = split_lo2(a.x, a.y, h01); olo[jc * 2 + 1] = split_lo2(a.z, a.w, h23);
    }
}

// ---------------- layer-2 / final helpers (fused, read Ac/A3 directly) -------
__global__ void rowstats_c_kernel(const float* __restrict__ A, const int* __restrict__ cnt,
                                  float* __restrict__ dout, float* __restrict__ rnz, int mode) {
    int b = blockIdx.y, i = blockIdx.x, tid = threadIdx.x;
    int cnp = (cnt[b] + 127) & ~127;
    if (i >= cnp) return;
    const float* row = A + ((size_t)(b * N_ + i)) * N_;
    const float4* row4 = (const float4*)row;
    float s = 0.f;
    for (int j = tid; j < (cnp >> 2); j += 256) {
        float4 a = row4[j]; s += (a.x + a.y) + (a.z + a.w);
    }
    __shared__ float red[256];
    red[tid] = s; __syncthreads();
    for (int o = 128; o > 0; o >>= 1) { if (tid < o) red[tid] += red[tid + o]; __syncthreads(); }
    if (tid == 0) {
        float sum = red[0];
        if (mode == 0) {
            dout[b * N_ + i] = rsqrtf(fmaxf(sum - row[i] + 1.f, 1.f));
        } else {
            dout[b * N_ + i] = rsqrtf(fmaxf(sum + 1.f, 1.f));
            rnz[b * N_ + i] = (sum > 0.f) ? 1.f : 0.f;
        }
    }
}

__global__ void alpha2d_kernel(const float* __restrict__ Ac, const float* __restrict__ d2,
                               const float* __restrict__ rz2, const float* __restrict__ v,
                               const int* __restrict__ cnt, float* __restrict__ alp) {
    __shared__ float dv[N_];
    __shared__ float red[256];
    int b = blockIdx.y, n = blockIdx.x, tid = threadIdx.x;
    int cnp = (cnt[b] + 127) & ~127;
    if (n >= cnp) { if (tid == 0) alp[b * N_ + n] = 0.5f; return; }
    for (int m = tid; m < cnp; m += 256) dv[m] = d2[b * N_ + m] * v[b * N_ + m];
    __syncthreads();
    const float4* row4 = (const float4*)(Ac + ((size_t)(b * N_ + n)) * N_);
    const float4* dv4 = (const float4*)dv;
    float s = 0.f;
    for (int m = tid; m < (cnp >> 2); m += 256) {
        float4 a = row4[m], w = dv4[m];
        s += a.x * w.x + a.y * w.y + a.z * w.z + a.w * w.w;
    }
    red[tid] = s; __syncthreads();
    for (int o = 128; o > 0; o >>= 1) { if (tid < o) red[tid] += red[tid + o]; __syncthreads(); }
    if (tid == 0) {
        float r = rz2[b * N_ + n] * d2[b * N_ + n] * (red[0] + dv[n]);
        alp[b * N_ + n] = 1.f / (1.f + expf(-r * r));
    }
}

__global__ void buildS2d_kernel(const float* __restrict__ Ac, const float* __restrict__ d2,
                                const float* __restrict__ rz2, const float* __restrict__ ca,
                                const int* __restrict__ cnt, float* __restrict__ S2) {
    __shared__ float dca[N_];
    __shared__ float p[N_];
    __shared__ float red[256];
    int b = blockIdx.y, n = blockIdx.x, tid = threadIdx.x;
    int cnp = (cnt[b] + 127) & ~127;
    if (n >= cnp) return;
    for (int m = tid; m < cnp; m += 256) dca[m] = d2[b * N_ + m] * ca[b * N_ + m];
    __syncthreads();
    const float4* row4 = (const float4*)(Ac + ((size_t)(b * N_ + n)) * N_);
    const float4* dca4 = (const float4*)dca;
    float4* p4 = (float4*)p;
    for (int m = tid; m < (cnp >> 2); m += 256) {
        float4 a = row4[m], w = dca4[m];
        p4[m] = make_float4(a.x * w.x, a.y * w.y, a.z * w.z, a.w * w.w);
    }
    __syncthreads();
    if (tid == 0) p[n] += dca[n];
    __syncthreads();
    float s = 0.f;
    for (int m = tid; m < cnp; m += 256) s += p[m];
    red[tid] = s; __syncthreads();
    for (int o = 128; o > 0; o >>= 1) { if (tid < o) red[tid] += red[tid + o]; __syncthreads(); }
    float f = rz2[b * N_ + n] * d2[b * N_ + n];
    float inv = f / fmaxf(f * red[0], 1e-12f);
    float* orow = S2 + ((size_t)(b * N_ + n)) * N_;
    for (int m = tid; m < cnp; m += 256) orow[m] = p[m] * inv;
}

// ---------------- bf16 split conversions --------------------------------------
// NA3 split on the fly: v = d_i d_j (i==j ? 1 : A3_ij)
__global__ void split_na3_kernel(const float* __restrict__ A3, const float* __restrict__ d,
                                 const int* __restrict__ cnt, __nv_bfloat16* __restrict__ hi,
                                 __nv_bfloat16* __restrict__ lo) {
    int b = blockIdx.z, i = blockIdx.y;
    int j = blockIdx.x * 256 + threadIdx.x;
    int cnp = (cnt[b] + 127) & ~127;
    if (i >= cnp || j >= cnp) return;
    size_t idx = (size_t)b * N_ * N_ + (size_t)i * N_ + j;
    float v = d[b * N_ + i] * d[b * N_ + j] * ((i == j) ? 1.f : A3[idx]);
    __nv_bfloat16 h = __float2bfloat16(v);
    hi[idx] = h;
    lo[idx] = __float2bfloat16(v - __bfloat162float(h));
}

// generic transposed split: out[j][i] = in[i][j]; in R x C (ld), out stride N_
__global__ void split_tr_kernel(const float* __restrict__ in, __nv_bfloat16* __restrict__ hi,
                                __nv_bfloat16* __restrict__ lo, const int* __restrict__ cnt,
                                int Rfixed, int Cfixed, int ld, long sIn) {
    __shared__ float tile[32][33];
    int b = blockIdx.z;
    int cnp = (cnt[b] + 127) & ~127;
    int R = Rfixed ? Rfixed : cnp;
    int C = Cfixed ? Cfixed : cnp;
    int i0 = blockIdx.y * 32, j0 = blockIdx.x * 32;
    if (i0 >= R || j0 >= C) return;
    const float* inb = in + (size_t)b * sIn;
    size_t boff = (size_t)b * N_ * N_;
    int tx = threadIdx.x, ty = threadIdx.y;   // (32, 8)
    #pragma unroll
    for (int r = 0; r < 4; r++) {
        int i = ty + r * 8;
        tile[i][tx] = inb[(size_t)(i0 + i) * ld + j0 + tx];
    }
    __syncthreads();
    #pragma unroll
    for (int r = 0; r < 4; r++) {
        int j = ty + r * 8;
        float v = tile[tx][j];
        __nv_bfloat16 h = __float2bfloat16(v);
        size_t o = boff + (size_t)(j0 + j) * N_ + i0 + tx;
        hi[o] = h;
        lo[o] = __float2bfloat16(v - __bfloat162float(h));
    }
}

// ---------------- bf16-split tensor GEMM, single-K-pass ----------------------
// C = A @ B: hi*hi + hi*lo + lo*hi accumulated per k-tile (fp32 accum).
// A row-major [m][k] stride N_; BT [n][k] stride N_.
// M = K = cnp; N = NpFixed or cnp.
// EPI: 0 none, 2 (+bias)*mask, 3 floor-quant, 4 row-major bf16 hi/lo split out.
#define TSZ (128 * 40)
template<int EPI>
__global__ void __launch_bounds__(256, 2) gemm_bf16_kernel(
    const __nv_bfloat16* __restrict__ Ahi, const __nv_bfloat16* __restrict__ Alo,
    const __nv_bfloat16* __restrict__ BThi, const __nv_bfloat16* __restrict__ BTlo,
    float* __restrict__ C, const int* __restrict__ cnt,
    int NpFixed, int ldc, long sC,
    const float* __restrict__ bias, const float* __restrict__ mask,
    __nv_bfloat16* __restrict__ Chi, __nv_bfloat16* __restrict__ Clo) {
    extern __shared__ __nv_bfloat16 sm[];   // [2 stages][4 tiles][128*40]
    const int b = blockIdx.z;
    const int cnp = (cnt[b] + 127) & ~127;
    const int Np = NpFixed ? NpFixed : cnp;
    const int m0 = blockIdx.y * 128, n0 = blockIdx.x * 128;
    if (m0 >= cnp || n0 >= Np) return;
    const size_t boff = (size_t)b * N_ * N_;
    const int tid = threadIdx.x;
    const int wid = tid >> 5, lane = tid & 31;
    const int wm = wid >> 1, wn = wid & 1;     // warps 4 x 2 -> warp tile 32 x 64
    const int g = lane >> 2, t4 = lane & 3;
    const int a_row = lane & 15;
    const int a_k   = (lane & 16) ? 8 : 0;
    const int b_row = (lane & 7) + ((lane & 16) ? 8 : 0);
    const int b_k   = (lane & 8) ? 8 : 0;
    const int KT = cnp >> 5;

    float acc[2][8][4];
    #pragma unroll
    for (int fm = 0; fm < 2; fm++)
        #pragma unroll
        for (int fn = 0; fn < 8; fn++)
            #pragma unroll
            for (int r = 0; r < 4; r++) acc[fm][fn][r] = 0.f;

    const __nv_bfloat16* gsrc[4];
    auto stage = [&](int kt, int buf) {
        gsrc[0] = Ahi  + boff + (size_t)m0 * N_ + kt * 32;
        gsrc[1] = Alo  + boff + (size_t)m0 * N_ + kt * 32;
        gsrc[2] = BThi + boff + (size_t)n0 * N_ + kt * 32;
        gsrc[3] = BTlo + boff + (size_t)n0 * N_ + kt * 32;
        int row = tid >> 2, cc = (tid & 3) * 8;
        #pragma unroll
        for (int w = 0; w < 4; w++) {
            __nv_bfloat16* dst = sm + (size_t)(buf * 4 + w) * TSZ;
            CP16(dst + row * 40 + cc,        gsrc[w] + (size_t)row * N_ + cc);
            CP16(dst + (row + 64) * 40 + cc, gsrc[w] + (size_t)(row + 64) * N_ + cc);
        }
    };

    stage(0, 0);
    CP_COMMIT();

    for (int t = 0; t < KT; t++) {
        CP_WAIT0();
        __syncthreads();
        if (t + 1 < KT) { stage(t + 1, (t + 1) & 1); CP_COMMIT(); }
        const __nv_bfloat16* Ah = sm + (size_t)((t & 1) * 4 + 0) * TSZ;
        const __nv_bfloat16* Al = sm + (size_t)((t & 1) * 4 + 1) * TSZ;
        const __nv_bfloat16* Bh = sm + (size_t)((t & 1) * 4 + 2) * TSZ;
        const __nv_bfloat16* Bl = sm + (size_t)((t & 1) * 4 + 3) * TSZ;
        #pragma unroll
        for (int kh = 0; kh < 32; kh += 16) {
            uint32_t ah[2][4], al[2][4];
            #pragma unroll
            for (int fm = 0; fm < 2; fm++) {
                int ao = (wm * 32 + fm * 16 + a_row) * 40 + kh + a_k;
                ldsm4(ah[fm], Ah + ao);
                ldsm4(al[fm], Al + ao);
            }
            #pragma unroll
            for (int fn2 = 0; fn2 < 4; fn2++) {
                int bo = (wn * 64 + fn2 * 16 + b_row) * 40 + kh + b_k;
                uint32_t bh[4], bl[4];
                ldsm4(bh, Bh + bo);
                ldsm4(bl, Bl + bo);
                #pragma unroll
                for (int fm = 0; fm < 2; fm++) {
                    mma_bf16(acc[fm][2 * fn2],     ah[fm], bh[0], bh[1]);
                    mma_bf16(acc[fm][2 * fn2],     ah[fm], bl[0], bl[1]);
                    mma_bf16(acc[fm][2 * fn2],     al[fm], bh[0], bh[1]);
                    mma_bf16(acc[fm][2 * fn2 + 1], ah[fm], bh[2], bh[3]);
                    mma_bf16(acc[fm][2 * fn2 + 1], ah[fm], bl[2], bl[3]);
                    mma_bf16(acc[fm][2 * fn2 + 1], al[fm], bh[2], bh[3]);
                }
            }
        }
        __syncthreads();
    }

    #pragma unroll
    for (int fm = 0; fm < 2; fm++) {
        int mr = m0 + wm * 32 + fm * 16 + g;
        float mk = (EPI == 2) ? mask[(size_t)b * N_ + mr] : 1.f;
        #pragma unroll
        for (int fn = 0; fn < 8; fn++) {
            int n = n0 + wn * 64 + fn * 8 + t4 * 2;
            float v0 = acc[fm][fn][0], v1 = acc[fm][fn][1];
            float v2 = acc[fm][fn][2], v3 = acc[fm][fn][3];
            if (EPI == 2) {
                v0 = (v0 + bias[n]) * mk;     v1 = (v1 + bias[n + 1]) * mk;
                v2 = (v2 + bias[n]) * mk;     v3 = (v3 + bias[n + 1]) * mk;
            } else if (EPI == 3) {
                v0 = floorf(v0 * 10000.f) / 10000.f;
                v1 = floorf(v1 * 10000.f) / 10000.f;
                v2 = floorf(v2 * 10000.f) / 10000.f;
                v3 = floorf(v3 * 10000.f) / 10000.f;
            }
            if (EPI == 4) {
                size_t o0 = (size_t)b * sC + (size_t)mr * ldc + n;
                size_t o1 = o0 + 8 * (size_t)ldc;
                __nv_bfloat162 h0 = split_hi2(v0, v1), h1 = split_hi2(v2, v3);
                *(__nv_bfloat162*)(Chi + o0) = h0;
                *(__nv_bfloat162*)(Chi + o1) = h1;
                *(__nv_bfloat162*)(Clo + o0) = split_lo2(v0, v1, h0);
                *(__nv_bfloat162*)(Clo + o1) = split_lo2(v2, v3, h1);
            } else {
                float* p0 = C + (size_t)b * sC + (size_t)mr * ldc + n;
                p0[0] = v0; p0[1] = v1;
                float* p1 = p0 + 8 * (size_t)ldc;
                p1[0] = v2; p1[1] = v3;
            }
        }
    }
}

// ---------------- double-buffered cp.async SIMT GEMM (small GEMMs) -----------
template<int TRANSA, int EPI>
__global__ void __launch_bounds__(256, 2) gemm2_kernel(
    const float* __restrict__ A, const float* __restrict__ Bm, float* __restrict__ C,
    int M, int Kd, int Nc, int lda, int ldb, int ldc,
    long sA, long sB, long sC,
    const float* __restrict__ bias, const float* __restrict__ mask,
    const int* __restrict__ cnt, int dynM, int dynK, int dynN) {
    __shared__ float As[2][128 * 16];
    __shared__ float Bs[2][16 * 128];
    const int b = blockIdx.z;
    int Mp = M, Kp = Kd, Np = Nc;
    if (cnt) {
        int p = (cnt[b] + 127) & ~127;
        if (dynM) Mp = p; if (dynK) Kp = p; if (dynN) Np = p;
    }
    const int n0 = blockIdx.x * 128, m0 = blockIdx.y * 128;
    if (m0 >= Mp || n0 >= Np) return;
    A  += (size_t)b * sA;
    Bm += (size_t)b * sB;
    C  += (size_t)b * sC;
    const int tid = threadIdx.x, tx = tid & 15, ty = tid >> 4;
    float acc[8][8];
    #pragma unroll
    for (int i = 0; i < 8; i++)
        #pragma unroll
        for (int j = 0; j < 8; j++) acc[i][j] = 0.f;

    const int Kt = Kp >> 4;

    auto load_tiles = [&](int k0, int buf) {
        if (!TRANSA) {
            #pragma unroll
            for (int q = 0; q < 2; q++) {
                int c = tid + q * 256;
                int row = c >> 2, col4 = (c & 3) * 4;
                const float* src = A + (size_t)(m0 + row) * lda + k0 + col4;
                CP16(&As[buf][row * 16 + col4], src);
            }
        } else {
            #pragma unroll
            for (int q = 0; q < 2; q++) {
                int c = tid + q * 256;
                int row = c >> 5, col4 = (c & 31) * 4;
                const float* src = A + (size_t)(k0 + row) * lda + m0 + col4;
                CP16(&As[buf][row * 128 + col4], src);
            }
        }
        #pragma unroll
        for (int q = 0; q < 2; q++) {
            int c = tid + q * 256;
            int row = c >> 5, col4 = (c & 31) * 4;
            const float* src = Bm + (size_t)(k0 + row) * ldb + n0 + col4;
            CP16(&Bs[buf][row * 128 + col4], src);
        }
    };

    load_tiles(0, 0);
    CP_COMMIT();

    for (int t = 0; t < Kt; t++) {
        CP_WAIT0();
        __syncthreads();
        if (t + 1 < Kt) { load_tiles((t + 1) << 4, (t + 1) & 1); CP_COMMIT(); }
        const int buf = t & 1;
        #pragma unroll
        for (int k = 0; k < 16; k++) {
            float a[8], bv[8];
            if (!TRANSA) {
                #pragma unroll
                for (int i = 0; i < 8; i++) a[i] = As[buf][(ty * 8 + i) * 16 + k];
            } else {
                *(float4*)(a)     = *(const float4*)&As[buf][k * 128 + ty * 8];
                *(float4*)(a + 4) = *(const float4*)&As[buf][k * 128 + ty * 8 + 4];
            }
            *(float4*)(bv)     = *(const float4*)&Bs[buf][k * 128 + tx * 8];
            *(float4*)(bv + 4) = *(const float4*)&Bs[buf][k * 128 + tx * 8 + 4];
            #pragma unroll
            for (int i = 0; i < 8; i++)
                #pragma unroll
                for (int j = 0; j < 8; j++) acc[i][j] = fmaf(a[i], bv[j], acc[i][j]);
        }
        __syncthreads();
    }
    #pragma unroll
    for (int i = 0; i < 8; i++) {
        int m = m0 + ty * 8 + i;
        float mk = (EPI == 2) ? mask[(size_t)b * N_ + m] : 1.f;
        #pragma unroll
        for (int j = 0; j < 8; j++) {
            int n = n0 + tx * 8 + j;
            float v = acc[i][j];
            if (EPI == 2)      { v = (v + bias[n]) * mk; }
            else if (EPI == 3) { v = floorf(v * 10000.f) / 10000.f; }
            C[(size_t)m * ldc + n] = v;
        }
    }
}

// ---------------- output means (two-stage, deterministic) --------------------
__global__ void mean1_part_kernel(const float* __restrict__ x1, float* __restrict__ p1) {
    int b = blockIdx.y, q = blockIdx.x, c = threadIdx.x;   // 128 threads
    float s = 0.f;
    for (int n = q * 512; n < (q + 1) * 512; n++) s += x1[((size_t)(b * N_ + n)) * H_ + c];
    p1[(b * 4 + q) * H_ + c] = s;
}

__global__ void mean2_part_kernel(const float* __restrict__ x2f, const int* __restrict__ cnt,
                                  float* __restrict__ p2) {
    int b = blockIdx.y, q = blockIdx.x, c = threadIdx.x;   // 256 threads
    int cn = cnt[b];
    int lo = q * 512, hi = (q + 1) * 512; if (hi > cn) hi = cn;
    float s = 0.f;
    for (int n = lo; n < hi; n++) s += x2f[((size_t)(b * N_ + n)) * F_ + c];
    p2[(b * 4 + q) * F_ + c] = s;
}

__global__ void mean_combine_kernel(const float* __restrict__ p1, const float* __restrict__ p2,
                                    const float* __restrict__ b2, const float* __restrict__ mrest,
                                    float* __restrict__ out) {
    int b = blockIdx.x, c = threadIdx.x;   // 384 threads
    if (c < H_) {
        float s = 0.f;
        for (int q = 0; q < 4; q++) s += p1[(b * 4 + q) * H_ + c];
        out[b * OUTC + c] = s / (float)N_;
    } else {
        int cc = c - H_;
        float s = b2[cc] * mrest[b];
        for (int q = 0; q < 4; q++) s += p2[(b * 4 + q) * F_ + cc];
        out[b * OUTC + c] = s / (float)N_;
    }
}

extern "C" void kernel_launch(void* const* d_in, const int* in_sizes, int n_in,
                              void* d_out, int out_size) {
    const float* x    = (const float*)d_in[0];
    const float* adj  = (const float*)d_in[1];
    const float* mask = (const float*)d_in[2];
    const float* W1   = (const float*)d_in[3];
    const float* b1   = (const float*)d_in[4];
    const float* Watt = (const float*)d_in[5];
    const float* batt = (const float*)d_in[6];
    const float* W2   = (const float*)d_in[7];
    const float* b2   = (const float*)d_in[8];
    float* out = (float*)d_out;

    float *pNA,*pT,*pAc,*pA3,*pSc,*pxW,*px1,*pxc,*px3,*px2f;
    float *pv,*palp,*pca,*psrec,*pd0,*pd1,*prnz,*pd2,*prz2,*pcut,*pmaskc,*pmrest,*pp1,*pp2;
    __nv_bfloat16 *pAhi,*pAlo,*pSThi,*pSTlo,*pTThi,*pTTlo;
    int *plst,*pdeg,*phasd,*pidx,*pginv,*pcnt;
    cudaGetSymbolAddress((void**)&pNA,  g_NA);
    cudaGetSymbolAddress((void**)&pT,   g_T);
    cudaGetSymbolAddress((void**)&pAc,  g_Ac);
    cudaGetSymbolAddress((void**)&pA3,  g_A3);
    cudaGetSymbolAddress((void**)&pSc,  g_Sc);
    cudaGetSymbolAddress((void**)&pAhi, g_Ahi);
    cudaGetSymbolAddress((void**)&pAlo, g_Alo);
    cudaGetSymbolAddress((void**)&pSThi,g_SThi);
    cudaGetSymbolAddress((void**)&pSTlo,g_STlo);
    cudaGetSymbolAddress((void**)&pTThi,g_TThi);
    cudaGetSymbolAddress((void**)&pTTlo,g_TTlo);
    cudaGetSymbolAddress((void**)&pxW,  g_xW);
    cudaGetSymbolAddress((void**)&px1,  g_x1);
    cudaGetSymbolAddress((void**)&pxc,  g_xc);
    cudaGetSymbolAddress((void**)&px3,  g_x3);
    cudaGetSymbolAddress((void**)&px2f, g_x2f);
    cudaGetSymbolAddress((void**)&pv,   g_v);
    cudaGetSymbolAddress((void**)&palp, g_alp);
    cudaGetSymbolAddress((void**)&pca,  g_ca);
    cudaGetSymbolAddress((void**)&psrec,g_srec);
    cudaGetSymbolAddress((void**)&pd0,  g_d0);
    cudaGetSymbolAddress((void**)&pd1,  g_d1);
    cudaGetSymbolAddress((void**)&prnz, g_rnz);
    cudaGetSymbolAddress((void**)&pd2,  g_d2);
    cudaGetSymbolAddress((void**)&prz2, g_rz2);
    cudaGetSymbolAddress((void**)&pcut, g_cut);
    cudaGetSymbolAddress((void**)&pmaskc, g_maskc);
    cudaGetSymbolAddress((void**)&pmrest, g_mrest);
    cudaGetSymbolAddress((void**)&pp1,  g_p1);
    cudaGetSymbolAddress((void**)&pp2,  g_p2);
    cudaGetSymbolAddress((void**)&plst, g_lst);
    cudaGetSymbolAddress((void**)&pdeg, g_deg);
    cudaGetSymbolAddress((void**)&phasd,g_hasd);
    cudaGetSymbolAddress((void**)&pidx, g_idx);
    cudaGetSymbolAddress((void**)&pginv,g_ginv);
    cudaGetSymbolAddress((void**)&pcnt, g_cnt);

    const int BF16_SMEM = 2 * 4 * TSZ * 2;   // 81920 bytes
    cudaFuncSetAttribute(gemm_bf16_kernel<0>, cudaFuncAttributeMaxDynamicSharedMemorySize, BF16_SMEM);
    cudaFuncSetAttribute(gemm_bf16_kernel<2>, cudaFuncAttributeMaxDynamicSharedMemorySize, BF16_SMEM);
    cudaFuncSetAttribute(gemm_bf16_kernel<3>, cudaFuncAttributeMaxDynamicSharedMemorySize, BF16_SMEM);
    cudaFuncSetAttribute(gemm_bf16_kernel<4>, cudaFuncAttributeMaxDynamicSharedMemorySize, BF16_SMEM);

    // ---- CSR + degree stats (single adj scan) ----
    csr_build_kernel<<<dim3(N_, B_), 256>>>(adj, plst, pdeg, phasd, pd0, pd1, prnz);

    // ---- GCN layer 1 (sparse aggregation) ----
    gemm2_kernel<0,0><<<dim3(1,16,B_),256>>>(x, W1, pxW, N_, F_, H_, F_, H_, H_,
        (long)N_*F_, 0, (long)N_*H_, nullptr, nullptr, nullptr, 0,0,0);
    gcn1_kernel<<<dim3(N_, B_), 128>>>(plst, pdeg, pd0, pxW, b1, mask, px1);

    // ---- coarsen layer 1 (sparse) ----
    gemv_watt_kernel<<<(B_*N_)/8, 256>>>(px1, Watt, batt, pv);
    alpha1_kernel<<<dim3(N_/8, B_), 256>>>(plst, pdeg, pd1, prnz, pv, palp);
    topk_cut_kernel<<<B_, 1024>>>(palp, pcut);
    ca_kernel<<<(B_*N_)/256, 256>>>(palp, pcut, pca);
    compact_kernel<<<B_, 1024>>>(pca, pidx, pginv, pcnt);
    compact_mask_kernel<<<B_, 256>>>(mask, pidx, pcnt, pmaskc, pmrest);
    srec_kernel<<<dim3(N_/8, B_), 256>>>(plst, pdeg, pd1, prnz, pca, psrec);
    buildSc_kernel<<<dim3(N_, B_), 256>>>(plst, pdeg, phasd, pd1, pca, psrec, pginv, pcnt, pSc);
    xupd_kernel<<<dim3(N_, B_), 128>>>(plst, pdeg, phasd, pd1, pca, psrec, pidx, pcnt, px1, pxc);
    adjS_kernel<<<dim3(N_, B_), 256>>>(plst, pdeg, pcnt, pSc, pT);
    // Ac + fused row-major bf16 split of Ac
    STT_kernel<<<dim3(N_, B_), 256>>>(plst, pdeg, phasd, pd1, pca, psrec, pidx, pcnt,
                                      pT, pAc, pAhi, pAlo);

    // ---- coarsen layer 2 (fused elementwise + single-pass tensor GEMMs) ----
    rowstats_c_kernel<<<dim3(N_, B_), 256>>>(pAc, pcnt, pd2, prz2, 1);
    gemv_watt_kernel<<<(B_*N_)/8, 256>>>(pxc, Watt, batt, pv);
    alpha2d_kernel<<<dim3(N_, B_), 256>>>(pAc, pd2, prz2, pv, pcnt, palp);
    topk_cut_kernel<<<B_, 1024>>>(palp, pcut);
    ca_kernel<<<(B_*N_)/256, 256>>>(palp, pcut, pca);
    buildS2d_kernel<<<dim3(N_, B_), 256>>>(pAc, pd2, prz2, pca, pcnt, pNA);   // -> S2c
    // S2c^T split (A operand for all layer-2 tensor GEMMs)
    split_tr_kernel<<<dim3(64, 64, B_), dim3(32, 8)>>>(pNA, pSThi, pSTlo, pcnt,
        0, 0, N_, (long)N_*N_);
    // xc^T split into TT (consumed by x3 GEMM before TT is overwritten)
    split_tr_kernel<<<dim3(4, 64, B_), dim3(32, 8)>>>(pxc, pTThi, pTTlo, pcnt,
        0, H_, H_, (long)N_*H_);
    // x3 = S2c^T @ xc (tensor)
    gemm_bf16_kernel<0><<<dim3(1,16,B_),256,BF16_SMEM>>>(pSThi, pSTlo, pTThi, pTTlo,
        px3, pcnt, H_, H_, (long)N_*H_, nullptr, nullptr, nullptr, nullptr);
    // T2^T = S2c^T @ Ac^T: A=ST, BT=Ac row-major; epilogue writes bf16 split -> TT
    gemm_bf16_kernel<4><<<dim3(16,16,B_),256,BF16_SMEM>>>(pSThi, pSTlo, pAhi, pAlo,
        nullptr, pcnt, 0, N_, (long)N_*N_, nullptr, nullptr, pTThi, pTTlo);
    // A3 = S2c^T @ T2: A=ST, BT=T2^T (=TT), floor-quant
    gemm_bf16_kernel<3><<<dim3(16,16,B_),256,BF16_SMEM>>>(pSThi, pSTlo, pTThi, pTTlo,
        pA3, pcnt, 0, N_, (long)N_*N_, nullptr, nullptr, nullptr, nullptr);

    // ---- final GCN (compacted, tensor): x2f = (NA3 @ (x3 @ W2) + b2) * maskc
    rowstats_c_kernel<<<dim3(N_, B_), 256>>>(pA3, pcnt, pd2, nullptr, 0);
    split_na3_kernel<<<dim3(8, N_, B_), 256>>>(pA3, pd2, pcnt, pAhi, pAlo);
    gemm2_kernel<0,0><<<dim3(2,16,B_),256>>>(px3, W2, pxW, N_, H_, F_, H_, F_, F_,
        (long)N_*H_, 0, (long)N_*F_, nullptr, nullptr, pcnt, 1,0,0);
    split_tr_kernel<<<dim3(8, 64, B_), dim3(32, 8)>>>(pxW, pTThi, pTTlo, pcnt,
        0, F_, F_, (long)N_*F_);
    gemm_bf16_kernel<2><<<dim3(2,16,B_),256,BF16_SMEM>>>(pAhi, pAlo, pTThi, pTTlo,
        px2f, pcnt, F_, F_, (long)N_*F_, b2, pmaskc, nullptr, nullptr);

    // ---- concat means ----
    mean1_part_kernel<<<dim3(4, B_), 128>>>(px1, pp1);
    mean2_part_kernel<<<dim3(4, B_), 256>>>(px2f, pcnt, pp2);
    mean_combine_kernel<<<B_, 384>>>(pp1, pp2, b2, pmrest, out);
}

// round 7
// speedup vs baseline: 5.9375x; 1.0682x over previous
#include <cuda_runtime.h>
#include <cuda_bf16.h>
#include <math.h>
#include <stdint.h>

#define B_ 8
#define N_ 2048
#define F_ 256
#define H_ 128
#define K_ 1025
#define OUTC 384
#define CAP 256

// ---------------- scratch (device globals; no allocation allowed) ----------
__device__ float g_NA[(size_t)B_*N_*N_];   // layer2 S2c (stride N_)
__device__ float g_T [(size_t)B_*N_*N_];   // Tc (layer1, stride cnp)
__device__ float g_Ac[(size_t)B_*N_*N_];   // compacted A2 (stride N_)
__device__ float g_A3[(size_t)B_*N_*N_];   // compacted A3 (stride N_)
__device__ __nv_bfloat16 g_Ahi[(size_t)B_*N_*N_], g_Alo[(size_t)B_*N_*N_];
__device__ __nv_bfloat16 g_SThi[(size_t)B_*N_*N_], g_STlo[(size_t)B_*N_*N_];
__device__ __nv_bfloat16 g_TThi[(size_t)B_*N_*N_], g_TTlo[(size_t)B_*N_*N_];
__device__ float g_xW [B_*N_*F_];
__device__ float g_x1 [B_*N_*H_];
__device__ float g_xc [B_*N_*H_];
__device__ float g_x3 [B_*N_*H_];
__device__ float g_x2f[B_*N_*F_];
__device__ int   g_lst[(size_t)B_*N_*CAP];
__device__ int   g_deg[B_*N_];
__device__ int   g_hasd[B_*N_];
__device__ float g_d0[B_*N_], g_d1[B_*N_], g_rnz[B_*N_];
__device__ float g_d2[B_*N_], g_rz2[B_*N_];
__device__ float g_v[B_*N_], g_alp[B_*N_], g_ca[B_*N_], g_srec[B_*N_];
__device__ float g_cut[B_];
__device__ float g_maskc[B_*N_], g_mrest[B_];
__device__ int   g_idx[B_*N_], g_ginv[B_*N_], g_cnt[B_];
__device__ float g_p1[B_*4*H_], g_p2[B_*4*F_];

// ---------------- async-copy / mma helpers -----------------------------------
#define CP16(dst, src) { \
    unsigned _a = (unsigned)__cvta_generic_to_shared(dst); \
    asm volatile("cp.async.cg.shared.global [%0], [%1], 16;\n" :: "r"(_a), "l"(src)); }
#define CP_COMMIT() asm volatile("cp.async.commit_group;\n")
#define CP_WAIT0()  asm volatile("cp.async.wait_group 0;\n")

__device__ __forceinline__ void mma_bf16(float* c, const uint32_t* a, uint32_t b0, uint32_t b1) {
    asm volatile("mma.sync.aligned.m16n8k16.row.col.f32.bf16.bf16.f32 "
        "{%0,%1,%2,%3}, {%4,%5,%6,%7}, {%8,%9}, {%0,%1,%2,%3};"
        : "+f"(c[0]), "+f"(c[1]), "+f"(c[2]), "+f"(c[3])
        : "r"(a[0]), "r"(a[1]), "r"(a[2]), "r"(a[3]), "r"(b0), "r"(b1));
}
__device__ __forceinline__ void ldsm4(uint32_t* r, const void* p) {
    uint32_t a = (uint32_t)__cvta_generic_to_shared(p);
    asm volatile("ldmatrix.sync.aligned.m8n8.x4.shared.b16 {%0,%1,%2,%3}, [%4];"
        : "=r"(r[0]), "=r"(r[1]), "=r"(r[2]), "=r"(r[3]) : "r"(a));
}
__device__ __forceinline__ __nv_bfloat162 split_hi2(float v0, float v1) {
    __nv_bfloat162 h; h.x = __float2bfloat16(v0); h.y = __float2bfloat16(v1); return h;
}
__device__ __forceinline__ __nv_bfloat162 split_lo2(float v0, float v1, __nv_bfloat162 h) {
    __nv_bfloat162 l;
    l.x = __float2bfloat16(v0 - __bfloat162float(h.x));
    l.y = __float2bfloat16(v1 - __bfloat162float(h.y));
    return l;
}

// ---------------- CSR build + degree stats (one adj scan) -------------------
__global__ void csr_build_kernel(const float* __restrict__ adj, int* __restrict__ lst,
                                 int* __restrict__ deg, int* __restrict__ hasd,
                                 float* __restrict__ d0, float* __restrict__ d1,
                                 float* __restrict__ rnz) {
    __shared__ int sc[256];
    __shared__ int hd;
    int b = blockIdx.y, i = blockIdx.x, tid = threadIdx.x;
    const float* arow = adj + ((size_t)(b * N_ + i)) * N_;
    if (tid == 0) hd = 0;
    __syncthreads();
    int flags[8];
    int c = 0;
    #pragma unroll
    for (int q = 0; q < 8; q++) {
        int j = tid + q * 256;
        int f = (arow[j] != 0.f) ? 1 : 0;
        flags[q] = f; c += f;
        if (f && j == i) hd = 1;
    }
    sc[tid] = c; __syncthreads();
    for (int o = 1; o < 256; o <<= 1) {
        int v = (tid >= o) ? sc[tid - o] : 0; __syncthreads();
        sc[tid] += v; __syncthreads();
    }
    int base = sc[tid] - c;
    int* l = lst + ((size_t)(b * N_ + i)) * CAP;
    #pragma unroll
    for (int q = 0; q < 8; q++) {
        int j = tid + q * 256;
        if (flags[q]) { if (base < CAP) l[base] = j; base++; }
    }
    __syncthreads();
    if (tid == 0) {
        int total = sc[255];
        deg[b * N_ + i] = (total > CAP) ? CAP : total;
        hasd[b * N_ + i] = hd;
        d0[b * N_ + i] = rsqrtf(fmaxf((float)(total - hd) + 1.f, 1.f));
        d1[b * N_ + i] = rsqrtf((float)total + 1.f);
        rnz[b * N_ + i] = (total > 0) ? 1.f : 0.f;
    }
}

// ---------------- GCN layer 1 sparse aggregation -----------------------------
__global__ void gcn1_kernel(const int* __restrict__ lst, const int* __restrict__ deg,
                            const float* __restrict__ d0, const float* __restrict__ xW,
                            const float* __restrict__ b1, const float* __restrict__ mask,
                            float* __restrict__ x1) {
    int b = blockIdx.y, i = blockIdx.x, c = threadIdx.x;   // 128 threads
    int dg = deg[b * N_ + i];
    const int* l = lst + ((size_t)(b * N_ + i)) * CAP;
    float di = d0[b * N_ + i];
    float acc = di * di * xW[((size_t)(b * N_ + i)) * H_ + c];
    for (int p = 0; p < dg; p++) {
        int j = l[p];
        if (j != i) acc = fmaf(di * d0[b * N_ + j], xW[((size_t)(b * N_ + j)) * H_ + c], acc);
    }
    float vv = (acc + b1[c]) * mask[b * N_ + i];
    x1[((size_t)(b * N_ + i)) * H_ + c] = fmaxf(vv, 0.f);
}

// ---------------- v = x @ Watt + batt ----------------------------------------
__global__ void gemv_watt_kernel(const float* __restrict__ x, const float* __restrict__ Watt,
                                 const float* __restrict__ batt, float* __restrict__ v) {
    int w = blockIdx.x * 8 + (threadIdx.x >> 5);
    int lane = threadIdx.x & 31;
    if (w >= B_ * N_) return;
    const float* xr = x + (size_t)w * H_;
    float s = 0.f;
    #pragma unroll
    for (int c = lane; c < H_; c += 32) s += xr[c] * Watt[c];
    #pragma unroll
    for (int o = 16; o > 0; o >>= 1) s += __shfl_down_sync(0xffffffffu, s, o);
    if (lane == 0) v[w] = s + batt[0];
}

// ---------------- layer-1 alpha (sparse) --------------------------------------
__global__ void alpha1_kernel(const int* __restrict__ lst, const int* __restrict__ deg,
                              const float* __restrict__ d1, const float* __restrict__ rnz,
                              const float* __restrict__ v, float* __restrict__ alp) {
    int b = blockIdx.y;
    int i = blockIdx.x * 8 + (threadIdx.x >> 5);
    int lane = threadIdx.x & 31;
    const int* l = lst + ((size_t)(b * N_ + i)) * CAP;
    int dg = deg[b * N_ + i];
    float s = 0.f;
    for (int p = lane; p < dg; p += 32) { int j = l[p]; s += d1[b * N_ + j] * v[b * N_ + j]; }
    #pragma unroll
    for (int o = 16; o > 0; o >>= 1) s += __shfl_down_sync(0xffffffffu, s, o);
    if (lane == 0) {
        float di = d1[b * N_ + i];
        float r = rnz[b * N_ + i] * di * (s + di * v[b * N_ + i]);
        float z = r * r;
        alp[b * N_ + i] = 1.f / (1.f + expf(-z));
    }
}

// ---------------- exact K-th largest via bitonic sort ------------------------
__global__ void topk_cut_kernel(const float* __restrict__ alp, float* __restrict__ cut) {
    __shared__ float s[N_];
    int b = blockIdx.x, t = threadIdx.x;   // 1024 threads
    s[t] = alp[b * N_ + t];
    s[t + 1024] = alp[b * N_ + t + 1024];
    __syncthreads();
    for (int k = 2; k <= N_; k <<= 1) {
        for (int j = k >> 1; j > 0; j >>= 1) {
            for (int i = t; i < N_; i += 1024) {
                int ixj = i ^ j;
                if (ixj > i) {
                    float a = s[i], c = s[ixj];
                    if (((i & k) == 0) ? (a > c) : (a < c)) { s[i] = c; s[ixj] = a; }
                }
            }
            __syncthreads();
        }
    }
    if (t == 0) cut[b] = s[N_ - K_];
}

__global__ void ca_kernel(const float* __restrict__ alp, const float* __restrict__ cut,
                          float* __restrict__ ca) {
    int idx = blockIdx.x * 256 + threadIdx.x;
    int b = idx / N_;
    ca[idx] = fmaxf(alp[idx] + 1e-7f - cut[b], 0.f);
}

// ---------------- deterministic kept-set compaction (prefix scan) -----------
__global__ void compact_kernel(const float* __restrict__ ca, int* __restrict__ idx,
                               int* __restrict__ ginv, int* __restrict__ cnt) {
    __shared__ int sc[1024];
    int b = blockIdx.x, t = threadIdx.x;   // 1024 threads
    int f0 = (ca[b * N_ + 2 * t]     > 0.f) ? 1 : 0;
    int f1 = (ca[b * N_ + 2 * t + 1] > 0.f) ? 1 : 0;
    ginv[b * N_ + 2 * t] = -1;
    ginv[b * N_ + 2 * t + 1] = -1;
    int c = f0 + f1;
    sc[t] = c; __syncthreads();
    for (int o = 1; o < 1024; o <<= 1) {
        int v = (t >= o) ? sc[t - o] : 0; __syncthreads();
        sc[t] += v; __syncthreads();
    }
    int base = sc[t] - c;
    if (f0) { idx[b * N_ + base] = 2 * t;     ginv[b * N_ + 2 * t]     = base; base++; }
    if (f1) { idx[b * N_ + base] = 2 * t + 1; ginv[b * N_ + 2 * t + 1] = base; }
    if (t == 1023) cnt[b] = sc[1023];
}

__global__ void compact_mask_kernel(const float* __restrict__ mask, const int* __restrict__ idx,
                                    const int* __restrict__ cnt, float* __restrict__ maskc,
                                    float* __restrict__ mrest) {
    __shared__ float red[256];
    int b = blockIdx.x, t = threadIdx.x;
    int c = cnt[b];
    float local = 0.f;
    for (int i = t; i < N_; i += 256) {
        float mv = 0.f;
        if (i < c) mv = mask[b * N_ + idx[b * N_ + i]];
        maskc[b * N_ + i] = mv;
        local += mask[b * N_ + i] - mv;
    }
    red[t] = local; __syncthreads();
    for (int o = 128; o > 0; o >>= 1) { if (t < o) red[t] += red[t + o]; __syncthreads(); }
    if (t == 0) mrest[b] = red[0];
}

// ---------------- layer-1 S row normalizer -----------------------------------
__global__ void srec_kernel(const int* __restrict__ lst, const int* __restrict__ deg,
                            const float* __restrict__ d1, const float* __restrict__ rnz,
                            const float* __restrict__ ca, float* __restrict__ srec) {
    int b = blockIdx.y;
    int i = blockIdx.x * 8 + (threadIdx.x >> 5);
    int lane = threadIdx.x & 31;
    const int* l = lst + ((size_t)(b * N_ + i)) * CAP;
    int dg = deg[b * N_ + i];
    float s = 0.f;
    for (int p = lane; p < dg; p += 32) { int j = l[p]; s += d1[b * N_ + j] * ca[b * N_ + j]; }
    #pragma unroll
    for (int o = 16; o > 0; o >>= 1) s += __shfl_down_sync(0xffffffffu, s, o);
    if (lane == 0) {
        float di = d1[b * N_ + i];
        float raw = rnz[b * N_ + i] * di * (s + di * ca[b * N_ + i]);
        srec[b * N_ + i] = rnz[b * N_ + i] * di / fmaxf(raw, 1e-12f);
    }
}

// ---------------- xc[ic,:] = sum_n S[n, idx[ic]] * x1[n,:] -------------------
__global__ void xupd_kernel(const int* __restrict__ lst, const int* __restrict__ deg,
                            const int* __restrict__ hasd, const float* __restrict__ d1,
                            const float* __restrict__ ca, const float* __restrict__ srec,
                            const int* __restrict__ idx, const int* __restrict__ cnt,
                            const float* __restrict__ x1, float* __restrict__ xc) {
    int b = blockIdx.y, ic = blockIdx.x, c = threadIdx.x;   // 128 threads
    int cn = cnt[b], cnp = (cn + 127) & ~127;
    if (ic >= cnp) return;
    float* orow = xc + ((size_t)(b * N_ + ic)) * H_;
    if (ic >= cn) { orow[c] = 0.f; return; }
    int m = idx[b * N_ + ic];
    float dmcam = d1[b * N_ + m] * ca[b * N_ + m];
    int dg = deg[b * N_ + m];
    const int* l = lst + ((size_t)(b * N_ + m)) * CAP;
    float acc = 0.f;
    for (int p = 0; p < dg; p++) {
        int n = l[p];
        float coef = (n == m) ? 2.f : 1.f;
        float sv = srec[b * N_ + n] * dmcam * coef;
        acc = fmaf(sv, x1[((size_t)(b * N_ + n)) * H_ + c], acc);
    }
    if (!hasd[b * N_ + m])
        acc = fmaf(srec[b * N_ + m] * dmcam, x1[((size_t)(b * N_ + m)) * H_ + c], acc);
    orow[c] = acc;
}

// ---- Tc[i,:] = sum_{j in list_i} S_row_j, S rows expanded on the fly --------
// One warp per output row; warp-private shared accumulator; sequential over j
// (columns within one j are distinct -> race-free, deterministic).
__global__ void adjS_sparse_kernel(const int* __restrict__ lst, const int* __restrict__ deg,
                                   const int* __restrict__ hasd, const float* __restrict__ d1,
                                   const float* __restrict__ ca, const float* __restrict__ srec,
                                   const int* __restrict__ ginv, const int* __restrict__ cnt,
                                   float* __restrict__ Tc) {
    __shared__ float acc[4][N_];
    int b = blockIdx.y, tid = threadIdx.x;   // 128 threads = 4 warps
    int w = tid >> 5, lane = tid & 31;
    int i = blockIdx.x * 4 + w;
    int cnp = (cnt[b] + 127) & ~127;
    float* a = acc[w];
    float4* a4 = (float4*)a;
    float4 z4 = make_float4(0.f, 0.f, 0.f, 0.f);
    for (int jc = lane; jc < (cnp >> 2); jc += 32) a4[jc] = z4;
    __syncwarp();
    int dgi = deg[b * N_ + i];
    const int* li = lst + ((size_t)(b * N_ + i)) * CAP;
    const int* gv = ginv + b * N_;
    for (int p = 0; p < dgi; p++) {
        int j = li[p];
        int dgj = deg[b * N_ + j];
        const int* lj = lst + ((size_t)(b * N_ + j)) * CAP;
        float sr = srec[b * N_ + j];
        for (int q = lane; q < dgj; q += 32) {
            int m = lj[q];
            int jc = gv[m];
            if (jc >= 0) {
                float coef = (m == j) ? 2.f : 1.f;
                a[jc] += sr * d1[b * N_ + m] * ca[b * N_ + m] * coef;
            }
        }
        __syncwarp();
        if (lane == 0 && !hasd[b * N_ + j]) {
            int jc = gv[j];
            if (jc >= 0) a[jc] += sr * d1[b * N_ + j] * ca[b * N_ + j];
        }
        __syncwarp();
    }
    float4* trow4 = (float4*)(Tc + (size_t)b * N_ * N_ + (size_t)i * cnp);
    for (int jc = lane; jc < (cnp >> 2); jc += 32) trow4[jc] = a4[jc];
}

// -------- Ac[ic,:] = floorq(sum_n S[n,m] * Tc[n,:]); fused bf16 split --------
__global__ void STT_kernel(const int* __restrict__ lst, const int* __restrict__ deg,
                           const int* __restrict__ hasd, const float* __restrict__ d1,
                           const float* __restrict__ ca, const float* __restrict__ srec,
                           const int* __restrict__ idx, const int* __restrict__ cnt,
                           const float* __restrict__ Tc, float* __restrict__ Ac,
                           __nv_bfloat16* __restrict__ Achi, __nv_bfloat16* __restrict__ Aclo) {
    __shared__ float4 acc4[N_ / 4];
    int b = blockIdx.y, ic = blockIdx.x, tid = threadIdx.x;
    int cn = cnt[b], cnp = (cn + 127) & ~127, cnp4 = cnp >> 2;
    if (ic >= cnp) return;
    size_t rowoff = ((size_t)(b * N_ + ic)) * N_;
    float4* orow4 = (float4*)(Ac + rowoff);
    __nv_bfloat162* ohi = (__nv_bfloat162*)(Achi + rowoff);
    __nv_bfloat162* olo = (__nv_bfloat162*)(Aclo + rowoff);
    float4 z4 = make_float4(0.f, 0.f, 0.f, 0.f);
    if (ic >= cn) {
        __nv_bfloat162 zb; zb.x = __float2bfloat16(0.f); zb.y = zb.x;
        for (int jc = tid; jc < cnp4; jc += 256) {
            orow4[jc] = z4;
            ohi[jc * 2] = zb; ohi[jc * 2 + 1] = zb;
            olo[jc * 2] = zb; olo[jc * 2 + 1] = zb;
        }
        return;
    }
    int m = idx[b * N_ + ic];
    float dmcam = d1[b * N_ + m] * ca[b * N_ + m];
    for (int jc = tid; jc < cnp4; jc += 256) acc4[jc] = z4;
    __syncthreads();
    int dg = deg[b * N_ + m];
    const int* l = lst + ((size_t)(b * N_ + m)) * CAP;
    const float* Tb = Tc + (size_t)b * N_ * N_;
    for (int p = 0; p < dg; p++) {
        int n = l[p];
        float coef = (n == m) ? 2.f : 1.f;
        float sv = srec[b * N_ + n] * dmcam * coef;
        if (sv != 0.f) {
            const float4* trow = (const float4*)(Tb + (size_t)n * cnp);
            for (int jc = tid; jc < cnp4; jc += 256) {
                float4 t = trow[jc], a = acc4[jc];
                a.x = fmaf(sv, t.x, a.x); a.y = fmaf(sv, t.y, a.y);
                a.z = fmaf(sv, t.z, a.z); a.w = fmaf(sv, t.w, a.w);
                acc4[jc] = a;
            }
        }
    }
    if (!hasd[b * N_ + m]) {
        float sv = srec[b * N_ + m] * dmcam;
        if (sv != 0.f) {
            const float4* trow = (const float4*)(Tb + (size_t)m * cnp);
            for (int jc = tid; jc < cnp4; jc += 256) {
                float4 t = trow[jc], a = acc4[jc];
                a.x = fmaf(sv, t.x, a.x); a.y = fmaf(sv, t.y, a.y);
                a.z = fmaf(sv, t.z, a.z); a.w = fmaf(sv, t.w, a.w);
                acc4[jc] = a;
            }
        }
    }
    __syncthreads();
    for (int jc = tid; jc < cnp4; jc += 256) {
        float4 a = acc4[jc];
        a.x = floorf(a.x * 10000.f) / 10000.f;
        a.y = floorf(a.y * 10000.f) / 10000.f;
        a.z = floorf(a.z * 10000.f) / 10000.f;
        a.w = floorf(a.w * 10000.f) / 10000.f;
        orow4[jc] = a;
        __nv_bfloat162 h01 = split_hi2(a.x, a.y), h23 = split_hi2(a.z, a.w);
        ohi[jc * 2] = h01; ohi[jc * 2 + 1] = h23;
        olo[jc * 2] = split_lo2(a.x, a.y, h01); olo[jc * 2 + 1] = split_lo2(a.z, a.w, h23);
    }
}

// ---------------- layer-2 / final helpers (fused, read Ac/A3 directly) -------
__global__ void rowstats_c_kernel(const float* __restrict__ A, const int* __restrict__ cnt,
                                  float* __restrict__ dout, float* __restrict__ rnz, int mode) {
    int b = blockIdx.y, i = blockIdx.x, tid = threadIdx.x;
    int cnp = (cnt[b] + 127) & ~127;
    if (i >= cnp) return;
    const float* row = A + ((size_t)(b * N_ + i)) * N_;
    const float4* row4 = (const float4*)row;
    float s = 0.f;
    for (int j = tid; j < (cnp >> 2); j += 256) {
        float4 a = row4[j]; s += (a.x + a.y) + (a.z + a.w);
    }
    __shared__ float red[256];
    red[tid] = s; __syncthreads();
    for (int o = 128; o > 0; o >>= 1) { if (tid < o) red[tid] += red[tid + o]; __syncthreads(); }
    if (tid == 0) {
        float sum = red[0];
        if (mode == 0) {
            dout[b * N_ + i] = rsqrtf(fmaxf(sum - row[i] + 1.f, 1.f));
        } else {
            dout[b * N_ + i] = rsqrtf(fmaxf(sum + 1.f, 1.f));
            rnz[b * N_ + i] = (sum > 0.f) ? 1.f : 0.f;
        }
    }
}

__global__ void alpha2d_kernel(const float* __restrict__ Ac, const float* __restrict__ d2,
                               const float* __restrict__ rz2, const float* __restrict__ v,
                               const int* __restrict__ cnt, float* __restrict__ alp) {
    __shared__ float dv[N_];
    __shared__ float red[256];
    int b = blockIdx.y, n = blockIdx.x, tid = threadIdx.x;
    int cnp = (cnt[b] + 127) & ~127;
    if (n >= cnp) { if (tid == 0) alp[b * N_ + n] = 0.5f; return; }
    for (int m = tid; m < cnp; m += 256) dv[m] = d2[b * N_ + m] * v[b * N_ + m];
    __syncthreads();
    const float4* row4 = (const float4*)(Ac + ((size_t)(b * N_ + n)) * N_);
    const float4* dv4 = (const float4*)dv;
    float s = 0.f;
    for (int m = tid; m < (cnp >> 2); m += 256) {
        float4 a = row4[m], w = dv4[m];
        s += a.x * w.x + a.y * w.y + a.z * w.z + a.w * w.w;
    }
    red[tid] = s; __syncthreads();
    for (int o = 128; o > 0; o >>= 1) { if (tid < o) red[tid] += red[tid + o]; __syncthreads(); }
    if (tid == 0) {
        float r = rz2[b * N_ + n] * d2[b * N_ + n] * (red[0] + dv[n]);
        alp[b * N_ + n] = 1.f / (1.f + expf(-r * r));
    }
}

__global__ void buildS2d_kernel(const float* __restrict__ Ac, const float* __restrict__ d2,
                                const float* __restrict__ rz2, const float* __restrict__ ca,
                                const int* __restrict__ cnt, float* __restrict__ S2) {
    __shared__ float dca[N_];
    __shared__ float p[N_];
    __shared__ float red[256];
    int b = blockIdx.y, n = blockIdx.x, tid = threadIdx.x;
    int cnp = (cnt[b] + 127) & ~127;
    if (n >= cnp) return;
    for (int m = tid; m < cnp; m += 256) dca[m] = d2[b * N_ + m] * ca[b * N_ + m];
    __syncthreads();
    const float4* row4 = (const float4*)(Ac + ((size_t)(b * N_ + n)) * N_);
    const float4* dca4 = (const float4*)dca;
    float4* p4 = (float4*)p;
    for (int m = tid; m < (cnp >> 2); m += 256) {
        float4 a = row4[m], w = dca4[m];
        p4[m] = make_float4(a.x * w.x, a.y * w.y, a.z * w.z, a.w * w.w);
    }
    __syncthreads();
    if (tid == 0) p[n] += dca[n];
    __syncthreads();
    float s = 0.f;
    for (int m = tid; m < cnp; m += 256) s += p[m];
    red[tid] = s; __syncthreads();
    for (int o = 128; o > 0; o >>= 1) { if (tid < o) red[tid] += red[tid + o]; __syncthreads(); }
    float f = rz2[b * N_ + n] * d2[b * N_ + n];
    float inv = f / fmaxf(f * red[0], 1e-12f);
    float* orow = S2 + ((size_t)(b * N_ + n)) * N_;
    for (int m = tid; m < cnp; m += 256) orow[m] = p[m] * inv;
}

// ---------------- bf16 split conversions --------------------------------------
// NA3 split on the fly: v = d_i d_j (i==j ? 1 : A3_ij)
__global__ void split_na3_kernel(const float* __restrict__ A3, const float* __restrict__ d,
                                 const int* __restrict__ cnt, __nv_bfloat16* __restrict__ hi,
                                 __nv_bfloat16* __restrict__ lo) {
    int b = blockIdx.z, i = blockIdx.y;
    int j = blockIdx.x * 256 + threadIdx.x;
    int cnp = (cnt[b] + 127) & ~127;
    if (i >= cnp || j >= cnp) return;
    size_t idx = (size_t)b * N_ * N_ + (size_t)i * N_ + j;
    float v = d[b * N_ + i] * d[b * N_ + j] * ((i == j) ? 1.f : A3[idx]);
    __nv_bfloat16 h = __float2bfloat16(v);
    hi[idx] = h;
    lo[idx] = __float2bfloat16(v - __bfloat162float(h));
}

// generic transposed split: out[j][i] = in[i][j]; in R x C (ld), out stride N_
__global__ void split_tr_kernel(const float* __restrict__ in, __nv_bfloat16* __restrict__ hi,
                                __nv_bfloat16* __restrict__ lo, const int* __restrict__ cnt,
                                int Rfixed, int Cfixed, int ld, long sIn) {
    __shared__ float tile[32][33];
    int b = blockIdx.z;
    int cnp = (cnt[b] + 127) & ~127;
    int R = Rfixed ? Rfixed : cnp;
    int C = Cfixed ? Cfixed : cnp;
    int i0 = blockIdx.y * 32, j0 = blockIdx.x * 32;
    if (i0 >= R || j0 >= C) return;
    const float* inb = in + (size_t)b * sIn;
    size_t boff = (size_t)b * N_ * N_;
    int tx = threadIdx.x, ty = threadIdx.y;   // (32, 8)
    #pragma unroll
    for (int r = 0; r < 4; r++) {
        int i = ty + r * 8;
        tile[i][tx] = inb[(size_t)(i0 + i) * ld + j0 + tx];
    }
    __syncthreads();
    #pragma unroll
    for (int r = 0; r < 4; r++) {
        int j = ty + r * 8;
        float v = tile[tx][j];
        __nv_bfloat16 h = __float2bfloat16(v);
        size_t o = boff + (size_t)(j0 + j) * N_ + i0 + tx;
        hi[o] = h;
        lo[o] = __float2bfloat16(v - __bfloat162float(h));
    }
}

// ---------------- bf16-split tensor GEMM, single-K-pass ----------------------
// C = A @ B: hi*hi + hi*lo + lo*hi accumulated per k-tile (fp32 accum).
// A row-major [m][k] stride N_; BT [n][k] stride N_.
// M = K = cnp; N = NpFixed or cnp.
// EPI: 0 none, 2 (+bias)*mask, 3 floor-quant, 4 row-major bf16 hi/lo split out.
#define TSZ (128 * 40)
template<int EPI>
__global__ void __launch_bounds__(256, 2) gemm_bf16_kernel(
    const __nv_bfloat16* __restrict__ Ahi, const __nv_bfloat16* __restrict__ Alo,
    const __nv_bfloat16* __restrict__ BThi, const __nv_bfloat16* __restrict__ BTlo,
    float* __restrict__ C, const int* __restrict__ cnt,
    int NpFixed, int ldc, long sC,
    const float* __restrict__ bias, const float* __restrict__ mask,
    __nv_bfloat16* __restrict__ Chi, __nv_bfloat16* __restrict__ Clo) {
    extern __shared__ __nv_bfloat16 sm[];   // [2 stages][4 tiles][128*40]
    const int b = blockIdx.z;
    const int cnp = (cnt[b] + 127) & ~127;
    const int Np = NpFixed ? NpFixed : cnp;
    const int m0 = blockIdx.y * 128, n0 = blockIdx.x * 128;
    if (m0 >= cnp || n0 >= Np) return;
    const size_t boff = (size_t)b * N_ * N_;
    const int tid = threadIdx.x;
    const int wid = tid >> 5, lane = tid & 31;
    const int wm = wid >> 1, wn = wid & 1;     // warps 4 x 2 -> warp tile 32 x 64
    const int g = lane >> 2, t4 = lane & 3;
    const int a_row = lane & 15;
    const int a_k   = (lane & 16) ? 8 : 0;
    const int b_row = (lane & 7) + ((lane & 16) ? 8 : 0);
    const int b_k   = (lane & 8) ? 8 : 0;
    const int KT = cnp >> 5;

    float acc[2][8][4];
    #pragma unroll
    for (int fm = 0; fm < 2; fm++)
        #pragma unroll
        for (int fn = 0; fn < 8; fn++)
            #pragma unroll
            for (int r = 0; r < 4; r++) acc[fm][fn][r] = 0.f;

    const __nv_bfloat16* gsrc[4];
    auto stage = [&](int kt, int buf) {
        gsrc[0] = Ahi  + boff + (size_t)m0 * N_ + kt * 32;
        gsrc[1] = Alo  + boff + (size_t)m0 * N_ + kt * 32;
        gsrc[2] = BThi + boff + (size_t)n0 * N_ + kt * 32;
        gsrc[3] = BTlo + boff + (size_t)n0 * N_ + kt * 32;
        int row = tid >> 2, cc = (tid & 3) * 8;
        #pragma unroll
        for (int w = 0; w < 4; w++) {
            __nv_bfloat16* dst = sm + (size_t)(buf * 4 + w) * TSZ;
            CP16(dst + row * 40 + cc,        gsrc[w] + (size_t)row * N_ + cc);
            CP16(dst + (row + 64) * 40 + cc, gsrc[w] + (size_t)(row + 64) * N_ + cc);
        }
    };

    stage(0, 0);
    CP_COMMIT();

    for (int t = 0; t < KT; t++) {
        CP_WAIT0();
        __syncthreads();
        if (t + 1 < KT) { stage(t + 1, (t + 1) & 1); CP_COMMIT(); }
        const __nv_bfloat16* Ah = sm + (size_t)((t & 1) * 4 + 0) * TSZ;
        const __nv_bfloat16* Al = sm + (size_t)((t & 1) * 4 + 1) * TSZ;
        const __nv_bfloat16* Bh = sm + (size_t)((t & 1) * 4 + 2) * TSZ;
        const __nv_bfloat16* Bl = sm + (size_t)((t & 1) * 4 + 3) * TSZ;
        #pragma unroll
        for (int kh = 0; kh < 32; kh += 16) {
            uint32_t ah[2][4], al[2][4];
            #pragma unroll
            for (int fm = 0; fm < 2; fm++) {
                int ao = (wm * 32 + fm * 16 + a_row) * 40 + kh + a_k;
                ldsm4(ah[fm], Ah + ao);
                ldsm4(al[fm], Al + ao);
            }
            #pragma unroll
            for (int fn2 = 0; fn2 < 4; fn2++) {
                int bo = (wn * 64 + fn2 * 16 + b_row) * 40 + kh + b_k;
                uint32_t bh[4], bl[4];
                ldsm4(bh, Bh + bo);
                ldsm4(bl, Bl + bo);
                #pragma unroll
                for (int fm = 0; fm < 2; fm++) {
                    mma_bf16(acc[fm][2 * fn2],     ah[fm], bh[0], bh[1]);
                    mma_bf16(acc[fm][2 * fn2],     ah[fm], bl[0], bl[1]);
                    mma_bf16(acc[fm][2 * fn2],     al[fm], bh[0], bh[1]);
                    mma_bf16(acc[fm][2 * fn2 + 1], ah[fm], bh[2], bh[3]);
                    mma_bf16(acc[fm][2 * fn2 + 1], ah[fm], bl[2], bl[3]);
                    mma_bf16(acc[fm][2 * fn2 + 1], al[fm], bh[2], bh[3]);
                }
            }
        }
        __syncthreads();
    }

    #pragma unroll
    for (int fm = 0; fm < 2; fm++) {
        int mr = m0 + wm * 32 + fm * 16 + g;
        float mk = (EPI == 2) ? mask[(size_t)b * N_ + mr] : 1.f;
        #pragma unroll
        for (int fn = 0; fn < 8; fn++) {
            int n = n0 + wn * 64 + fn * 8 + t4 * 2;
            float v0 = acc[fm][fn][0], v1 = acc[fm][fn][1];
            float v2 = acc[fm][fn][2], v3 = acc[fm][fn][3];
            if (EPI == 2) {
                v0 = (v0 + bias[n]) * mk;     v1 = (v1 + bias[n + 1]) * mk;
                v2 = (v2 + bias[n]) * mk;     v3 = (v3 + bias[n + 1]) * mk;
            } else if (EPI == 3) {
                v0 = floorf(v0 * 10000.f) / 10000.f;
                v1 = floorf(v1 * 10000.f) / 10000.f;
                v2 = floorf(v2 * 10000.f) / 10000.f;
                v3 = floorf(v3 * 10000.f) / 10000.f;
            }
            if (EPI == 4) {
                size_t o0 = (size_t)b * sC + (size_t)mr * ldc + n;
                size_t o1 = o0 + 8 * (size_t)ldc;
                __nv_bfloat162 h0 = split_hi2(v0, v1), h1 = split_hi2(v2, v3);
                *(__nv_bfloat162*)(Chi + o0) = h0;
                *(__nv_bfloat162*)(Chi + o1) = h1;
                *(__nv_bfloat162*)(Clo + o0) = split_lo2(v0, v1, h0);
                *(__nv_bfloat162*)(Clo + o1) = split_lo2(v2, v3, h1);
            } else {
                float* p0 = C + (size_t)b * sC + (size_t)mr * ldc + n;
                p0[0] = v0; p0[1] = v1;
                float* p1 = p0 + 8 * (size_t)ldc;
                p1[0] = v2; p1[1] = v3;
            }
        }
    }
}

// ---------------- double-buffered cp.async SIMT GEMM (small GEMMs) -----------
template<int TRANSA, int EPI>
__global__ void __launch_bounds__(256, 2) gemm2_kernel(
    const float* __restrict__ A, const float* __restrict__ Bm, float* __restrict__ C,
    int M, int Kd, int Nc, int lda, int ldb, int ldc,
    long sA, long sB, long sC,
    const float* __restrict__ bias, const float* __restrict__ mask,
    const int* __restrict__ cnt, int dynM, int dynK, int dynN) {
    __shared__ float As[2][128 * 16];
    __shared__ float Bs[2][16 * 128];
    const int b = blockIdx.z;
    int Mp = M, Kp = Kd, Np = Nc;
    if (cnt) {
        int p = (cnt[b] + 127) & ~127;
        if (dynM) Mp = p; if (dynK) Kp = p; if (dynN) Np = p;
    }
    const int n0 = blockIdx.x * 128, m0 = blockIdx.y * 128;
    if (m0 >= Mp || n0 >= Np) return;
    A  += (size_t)b * sA;
    Bm += (size_t)b * sB;
    C  += (size_t)b * sC;
    const int tid = threadIdx.x, tx = tid & 15, ty = tid >> 4;
    float acc[8][8];
    #pragma unroll
    for (int i = 0; i < 8; i++)
        #pragma unroll
        for (int j = 0; j < 8; j++) acc[i][j] = 0.f;

    const int Kt = Kp >> 4;

    auto load_tiles = [&](int k0, int buf) {
        if (!TRANSA) {
            #pragma unroll
            for (int q = 0; q < 2; q++) {
                int c = tid + q * 256;
                int row = c >> 2, col4 = (c & 3) * 4;
                const float* src = A + (size_t)(m0 + row) * lda + k0 + col4;
                CP16(&As[buf][row * 16 + col4], src);
            }
        } else {
            #pragma unroll
            for (int q = 0; q < 2; q++) {
                int c = tid + q * 256;
                int row = c >> 5, col4 = (c & 31) * 4;
                const float* src = A + (size_t)(k0 + row) * lda + m0 + col4;
                CP16(&As[buf][row * 128 + col4], src);
            }
        }
        #pragma unroll
        for (int q = 0; q < 2; q++) {
            int c = tid + q * 256;
            int row = c >> 5, col4 = (c & 31) * 4;
            const float* src = Bm + (size_t)(k0 + row) * ldb + n0 + col4;
            CP16(&Bs[buf][row * 128 + col4], src);
        }
    };

    load_tiles(0, 0);
    CP_COMMIT();

    for (int t = 0; t < Kt; t++) {
        CP_WAIT0();
        __syncthreads();
        if (t + 1 < Kt) { load_tiles((t + 1) << 4, (t + 1) & 1); CP_COMMIT(); }
        const int buf = t & 1;
        #pragma unroll
        for (int k = 0; k < 16; k++) {
            float a[8], bv[8];
            if (!TRANSA) {
                #pragma unroll
                for (int i = 0; i < 8; i++) a[i] = As[buf][(ty * 8 + i) * 16 + k];
            } else {
                *(float4*)(a)     = *(const float4*)&As[buf][k * 128 + ty * 8];
                *(float4*)(a + 4) = *(const float4*)&As[buf][k * 128 + ty * 8 + 4];
            }
            *(float4*)(bv)     = *(const float4*)&Bs[buf][k * 128 + tx * 8];
            *(float4*)(bv + 4) = *(const float4*)&Bs[buf][k * 128 + tx * 8 + 4];
            #pragma unroll
            for (int i = 0; i < 8; i++)
                #pragma unroll
                for (int j = 0; j < 8; j++) acc[i][j] = fmaf(a[i], bv[j], acc[i][j]);
        }
        __syncthreads();
    }
    #pragma unroll
    for (int i = 0; i < 8; i++) {
        int m = m0 + ty * 8 + i;
        float mk = (EPI == 2) ? mask[(size_t)b * N_ + m] : 1.f;
        #pragma unroll
        for (int j = 0; j < 8; j++) {
            int n = n0 + tx * 8 + j;
            float v = acc[i][j];
            if (EPI == 2)      { v = (v + bias[n]) * mk; }
            else if (EPI == 3) { v = floorf(v * 10000.f) / 10000.f; }
            C[(size_t)m * ldc + n] = v;
        }
    }
}

// ---------------- output means (two-stage, deterministic) --------------------
__global__ void mean1_part_kernel(const float* __restrict__ x1, float* __restrict__ p1) {
    int b = blockIdx.y, q = blockIdx.x, c = threadIdx.x;   // 128 threads
    float s = 0.f;
    for (int n = q * 512; n < (q + 1) * 512; n++) s += x1[((size_t)(b * N_ + n)) * H_ + c];
    p1[(b * 4 + q) * H_ + c] = s;
}

__global__ void mean2_part_kernel(const float* __restrict__ x2f, const int* __restrict__ cnt,
                                  float* __restrict__ p2) {
    int b = blockIdx.y, q = blockIdx.x, c = threadIdx.x;   // 256 threads
    int cn = cnt[b];
    int lo = q * 512, hi = (q + 1) * 512; if (hi > cn) hi = cn;
    float s = 0.f;
    for (int n = lo; n < hi; n++) s += x2f[((size_t)(b * N_ + n)) * F_ + c];
    p2[(b * 4 + q) * F_ + c] = s;
}

__global__ void mean_combine_kernel(const float* __restrict__ p1, const float* __restrict__ p2,
                                    const float* __restrict__ b2, const float* __restrict__ mrest,
                                    float* __restrict__ out) {
    int b = blockIdx.x, c = threadIdx.x;   // 384 threads
    if (c < H_) {
        float s = 0.f;
        for (int q = 0; q < 4; q++) s += p1[(b * 4 + q) * H_ + c];
        out[b * OUTC + c] = s / (float)N_;
    } else {
        int cc = c - H_;
        float s = b2[cc] * mrest[b];
        for (int q = 0; q < 4; q++) s += p2[(b * 4 + q) * F_ + cc];
        out[b * OUTC + c] = s / (float)N_;
    }
}

extern "C" void kernel_launch(void* const* d_in, const int* in_sizes, int n_in,
                              void* d_out, int out_size) {
    const float* x    = (const float*)d_in[0];
    const float* adj  = (const float*)d_in[1];
    const float* mask = (const float*)d_in[2];
    const float* W1   = (const float*)d_in[3];
    const float* b1   = (const float*)d_in[4];
    const float* Watt = (const float*)d_in[5];
    const float* batt = (const float*)d_in[6];
    const float* W2   = (const float*)d_in[7];
    const float* b2   = (const float*)d_in[8];
    float* out = (float*)d_out;

    float *pNA,*pT,*pAc,*pA3,*pxW,*px1,*pxc,*px3,*px2f;
    float *pv,*palp,*pca,*psrec,*pd0,*pd1,*prnz,*pd2,*prz2,*pcut,*pmaskc,*pmrest,*pp1,*pp2;
    __nv_bfloat16 *pAhi,*pAlo,*pSThi,*pSTlo,*pTThi,*pTTlo;
    int *plst,*pdeg,*phasd,*pidx,*pginv,*pcnt;
    cudaGetSymbolAddress((void**)&pNA,  g_NA);
    cudaGetSymbolAddress((void**)&pT,   g_T);
    cudaGetSymbolAddress((void**)&pAc,  g_Ac);
    cudaGetSymbolAddress((void**)&pA3,  g_A3);
    cudaGetSymbolAddress((void**)&pAhi, g_Ahi);
    cudaGetSymbolAddress((void**)&pAlo, g_Alo);
    cudaGetSymbolAddress((void**)&pSThi,g_SThi);
    cudaGetSymbolAddress((void**)&pSTlo,g_STlo);
    cudaGetSymbolAddress((void**)&pTThi,g_TThi);
    cudaGetSymbolAddress((void**)&pTTlo,g_TTlo);
    cudaGetSymbolAddress((void**)&pxW,  g_xW);
    cudaGetSymbolAddress((void**)&px1,  g_x1);
    cudaGetSymbolAddress((void**)&pxc,  g_xc);
    cudaGetSymbolAddress((void**)&px3,  g_x3);
    cudaGetSymbolAddress((void**)&px2f, g_x2f);
    cudaGetSymbolAddress((void**)&pv,   g_v);
    cudaGetSymbolAddress((void**)&palp, g_alp);
    cudaGetSymbolAddress((void**)&pca,  g_ca);
    cudaGetSymbolAddress((void**)&psrec,g_srec);
    cudaGetSymbolAddress((void**)&pd0,  g_d0);
    cudaGetSymbolAddress((void**)&pd1,  g_d1);
    cudaGetSymbolAddress((void**)&prnz, g_rnz);
    cudaGetSymbolAddress((void**)&pd2,  g_d2);
    cudaGetSymbolAddress((void**)&prz2, g_rz2);
    cudaGetSymbolAddress((void**)&pcut, g_cut);
    cudaGetSymbolAddress((void**)&pmaskc, g_maskc);
    cudaGetSymbolAddress((void**)&pmrest, g_mrest);
    cudaGetSymbolAddress((void**)&pp1,  g_p1);
    cudaGetSymbolAddress((void**)&pp2,  g_p2);
    cudaGetSymbolAddress((void**)&plst, g_lst);
    cudaGetSymbolAddress((void**)&pdeg, g_deg);
    cudaGetSymbolAddress((void**)&phasd,g_hasd);
    cudaGetSymbolAddress((void**)&pidx, g_idx);
    cudaGetSymbolAddress((void**)&pginv,g_ginv);
    cudaGetSymbolAddress((void**)&pcnt, g_cnt);

    const int BF16_SMEM = 2 * 4 * TSZ * 2;   // 81920 bytes
    cudaFuncSetAttribute(gemm_bf16_kernel<0>, cudaFuncAttributeMaxDynamicSharedMemorySize, BF16_SMEM);
    cudaFuncSetAttribute(gemm_bf16_kernel<2>, cudaFuncAttributeMaxDynamicSharedMemorySize, BF16_SMEM);
    cudaFuncSetAttribute(gemm_bf16_kernel<3>, cudaFuncAttributeMaxDynamicSharedMemorySize, BF16_SMEM);
    cudaFuncSetAttribute(gemm_bf16_kernel<4>, cudaFuncAttributeMaxDynamicSharedMemorySize, BF16_SMEM);

    // ---- CSR + degree stats (single adj scan) ----
    csr_build_kernel<<<dim3(N_, B_), 256>>>(adj, plst, pdeg, phasd, pd0, pd1, prnz);

    // ---- GCN layer 1 (sparse aggregation) ----
    gemm2_kernel<0,0><<<dim3(1,16,B_),256>>>(x, W1, pxW, N_, F_, H_, F_, H_, H_,
        (long)N_*F_, 0, (long)N_*H_, nullptr, nullptr, nullptr, 0,0,0);
    gcn1_kernel<<<dim3(N_, B_), 128>>>(plst, pdeg, pd0, pxW, b1, mask, px1);

    // ---- coarsen layer 1 (sparse, no dense S anywhere) ----
    gemv_watt_kernel<<<(B_*N_)/8, 256>>>(px1, Watt, batt, pv);
    alpha1_kernel<<<dim3(N_/8, B_), 256>>>(plst, pdeg, pd1, prnz, pv, palp);
    topk_cut_kernel<<<B_, 1024>>>(palp, pcut);
    ca_kernel<<<(B_*N_)/256, 256>>>(palp, pcut, pca);
    compact_kernel<<<B_, 1024>>>(pca, pidx, pginv, pcnt);
    compact_mask_kernel<<<B_, 256>>>(mask, pidx, pcnt, pmaskc, pmrest);
    srec_kernel<<<dim3(N_/8, B_), 256>>>(plst, pdeg, pd1, prnz, pca, psrec);
    xupd_kernel<<<dim3(N_, B_), 128>>>(plst, pdeg, phasd, pd1, pca, psrec, pidx, pcnt, px1, pxc);
    // Tc = adj @ S expanded sparsely on the fly (S never materialized)
    adjS_sparse_kernel<<<dim3(N_/4, B_), 128>>>(plst, pdeg, phasd, pd1, pca, psrec,
                                                pginv, pcnt, pT);
    // Ac + fused row-major bf16 split of Ac
    STT_kernel<<<dim3(N_, B_), 256>>>(plst, pdeg, phasd, pd1, pca, psrec, pidx, pcnt,
                                      pT, pAc, pAhi, pAlo);

    // ---- coarsen layer 2 (fused elementwise + single-pass tensor GEMMs) ----
    rowstats_c_kernel<<<dim3(N_, B_), 256>>>(pAc, pcnt, pd2, prz2, 1);
    gemv_watt_kernel<<<(B_*N_)/8, 256>>>(pxc, Watt, batt, pv);
    alpha2d_kernel<<<dim3(N_, B_), 256>>>(pAc, pd2, prz2, pv, pcnt, palp);
    topk_cut_kernel<<<B_, 1024>>>(palp, pcut);
    ca_kernel<<<(B_*N_)/256, 256>>>(palp, pcut, pca);
    buildS2d_kernel<<<dim3(N_, B_), 256>>>(pAc, pd2, prz2, pca, pcnt, pNA);   // -> S2c
    // S2c^T split (A operand for all layer-2 tensor GEMMs)
    split_tr_kernel<<<dim3(64, 64, B_), dim3(32, 8)>>>(pNA, pSThi, pSTlo, pcnt,
        0, 0, N_, (long)N_*N_);
    // xc^T split into TT (consumed by x3 GEMM before TT is overwritten)
    split_tr_kernel<<<dim3(4, 64, B_), dim3(32, 8)>>>(pxc, pTThi, pTTlo, pcnt,
        0, H_, H_, (long)N_*H_);
    // x3 = S2c^T @ xc (tensor)
    gemm_bf16_kernel<0><<<dim3(1,16,B_),256,BF16_SMEM>>>(pSThi, pSTlo, pTThi, pTTlo,
        px3, pcnt, H_, H_, (long)N_*H_, nullptr, nullptr, nullptr, nullptr);
    // T2^T = S2c^T @ Ac^T: A=ST, BT=Ac row-major; epilogue writes bf16 split -> TT
    gemm_bf16_kernel<4><<<dim3(16,16,B_),256,BF16_SMEM>>>(pSThi, pSTlo, pAhi, pAlo,
        nullptr, pcnt, 0, N_, (long)N_*N_, nullptr, nullptr, pTThi, pTTlo);
    // A3 = S2c^T @ T2: A=ST, BT=T2^T (=TT), floor-quant
    gemm_bf16_kernel<3><<<dim3(16,16,B_),256,BF16_SMEM>>>(pSThi, pSTlo, pTThi, pTTlo,
        pA3, pcnt, 0, N_, (long)N_*N_, nullptr, nullptr, nullptr, nullptr);

    // ---- final GCN (compacted, tensor): x2f = (NA3 @ (x3 @ W2) + b2) * maskc
    rowstats_c_kernel<<<dim3(N_, B_), 256>>>(pA3, pcnt, pd2, nullptr, 0);
    split_na3_kernel<<<dim3(8, N_, B_), 256>>>(pA3, pd2, pcnt, pAhi, pAlo);
    gemm2_kernel<0,0><<<dim3(2,16,B_),256>>>(px3, W2, pxW, N_, H_, F_, H_, F_, F_,
        (long)N_*H_, 0, (long)N_*F_, nullptr, nullptr, pcnt, 1,0,0);
    split_tr_kernel<<<dim3(8, 64, B_), dim3(32, 8)>>>(pxW, pTThi, pTTlo, pcnt,
        0, F_, F_, (long)N_*F_);
    gemm_bf16_kernel<2><<<dim3(2,16,B_),256,BF16_SMEM>>>(pAhi, pAlo, pTThi, pTTlo,
        px2f, pcnt, F_, F_, (long)N_*F_, b2, pmaskc, nullptr, nullptr);

    // ---- concat means ----
    mean1_part_kernel<<<dim3(4, B_), 128>>>(px1, pp1);
    mean2_part_kernel<<<dim3(4, B_), 256>>>(px2f, pcnt, pp2);
    mean_combine_kernel<<<B_, 384>>>(pp1, pp2, b2, pmrest, out);
}

// round 8
// speedup vs baseline: 6.6109x; 1.1134x over previous
#include <cuda_runtime.h>
#include <cuda_bf16.h>
#include <math.h>
#include <stdint.h>

#define B_ 8
#define N_ 2048
#define F_ 256
#define H_ 128
#define K_ 1025
#define OUTC 384
#define CAP 256

// ---------------- scratch (device globals; no allocation allowed) ----------
__device__ float g_T [(size_t)B_*N_*N_];   // Tc (layer1, stride cnp)
__device__ float g_Ac[(size_t)B_*N_*N_];   // compacted A2 (stride N_)
__device__ float g_A3[(size_t)B_*N_*N_];   // compacted A3 (stride N_)
__device__ __nv_bfloat16 g_Ahi[(size_t)B_*N_*N_], g_Alo[(size_t)B_*N_*N_];
__device__ __nv_bfloat16 g_SThi[(size_t)B_*N_*N_], g_STlo[(size_t)B_*N_*N_];
__device__ __nv_bfloat16 g_TThi[(size_t)B_*N_*N_], g_TTlo[(size_t)B_*N_*N_];
__device__ float g_xW [B_*N_*F_];
__device__ float g_x1 [B_*N_*H_];
__device__ float g_xc [B_*N_*H_];
__device__ float g_x3 [B_*N_*H_];
__device__ int   g_lst[(size_t)B_*N_*CAP];
__device__ int   g_deg[B_*N_];
__device__ int   g_hasd[B_*N_];
__device__ float g_d0[B_*N_], g_d1[B_*N_], g_rnz[B_*N_];
__device__ float g_d2[B_*N_], g_rz2[B_*N_];
__device__ float g_v[B_*N_], g_alp[B_*N_], g_ca[B_*N_], g_srec[B_*N_];
__device__ float g_cut[B_];
__device__ float g_maskc[B_*N_], g_mrest[B_];
__device__ int   g_idx[B_*N_], g_ginv[B_*N_], g_cnt[B_];
__device__ float g_p1[B_*4*H_], g_p2[B_*4*F_];

// ---------------- async-copy / mma helpers -----------------------------------
#define CP16(dst, src) { \
    unsigned _a = (unsigned)__cvta_generic_to_shared(dst); \
    asm volatile("cp.async.cg.shared.global [%0], [%1], 16;\n" :: "r"(_a), "l"(src)); }
#define CP_COMMIT() asm volatile("cp.async.commit_group;\n")
#define CP_WAIT0()  asm volatile("cp.async.wait_group 0;\n")

__device__ __forceinline__ void mma_bf16(float* c, const uint32_t* a, uint32_t b0, uint32_t b1) {
    asm volatile("mma.sync.aligned.m16n8k16.row.col.f32.bf16.bf16.f32 "
        "{%0,%1,%2,%3}, {%4,%5,%6,%7}, {%8,%9}, {%0,%1,%2,%3};"
        : "+f"(c[0]), "+f"(c[1]), "+f"(c[2]), "+f"(c[3])
        : "r"(a[0]), "r"(a[1]), "r"(a[2]), "r"(a[3]), "r"(b0), "r"(b1));
}
__device__ __forceinline__ void ldsm4(uint32_t* r, const void* p) {
    uint32_t a = (uint32_t)__cvta_generic_to_shared(p);
    asm volatile("ldmatrix.sync.aligned.m8n8.x4.shared.b16 {%0,%1,%2,%3}, [%4];"
        : "=r"(r[0]), "=r"(r[1]), "=r"(r[2]), "=r"(r[3]) : "r"(a));
}
__device__ __forceinline__ __nv_bfloat162 split_hi2(float v0, float v1) {
    __nv_bfloat162 h; h.x = __float2bfloat16(v0); h.y = __float2bfloat16(v1); return h;
}
__device__ __forceinline__ __nv_bfloat162 split_lo2(float v0, float v1, __nv_bfloat162 h) {
    __nv_bfloat162 l;
    l.x = __float2bfloat16(v0 - __bfloat162float(h.x));
    l.y = __float2bfloat16(v1 - __bfloat162float(h.y));
    return l;
}

// ---------------- CSR build + degree stats (one adj scan) -------------------
__global__ void csr_build_kernel(const float* __restrict__ adj, int* __restrict__ lst,
                                 int* __restrict__ deg, int* __restrict__ hasd,
                                 float* __restrict__ d0, float* __restrict__ d1,
                                 float* __restrict__ rnz) {
    __shared__ int sc[256];
    __shared__ int hd;
    int b = blockIdx.y, i = blockIdx.x, tid = threadIdx.x;
    const float* arow = adj + ((size_t)(b * N_ + i)) * N_;
    if (tid == 0) hd = 0;
    __syncthreads();
    int flags[8];
    int c = 0;
    #pragma unroll
    for (int q = 0; q < 8; q++) {
        int j = tid + q * 256;
        int f = (arow[j] != 0.f) ? 1 : 0;
        flags[q] = f; c += f;
        if (f && j == i) hd = 1;
    }
    sc[tid] = c; __syncthreads();
    for (int o = 1; o < 256; o <<= 1) {
        int v = (tid >= o) ? sc[tid - o] : 0; __syncthreads();
        sc[tid] += v; __syncthreads();
    }
    int base = sc[tid] - c;
    int* l = lst + ((size_t)(b * N_ + i)) * CAP;
    #pragma unroll
    for (int q = 0; q < 8; q++) {
        int j = tid + q * 256;
        if (flags[q]) { if (base < CAP) l[base] = j; base++; }
    }
    __syncthreads();
    if (tid == 0) {
        int total = sc[255];
        deg[b * N_ + i] = (total > CAP) ? CAP : total;
        hasd[b * N_ + i] = hd;
        d0[b * N_ + i] = rsqrtf(fmaxf((float)(total - hd) + 1.f, 1.f));
        d1[b * N_ + i] = rsqrtf((float)total + 1.f);
        rnz[b * N_ + i] = (total > 0) ? 1.f : 0.f;
    }
}

// ---------------- GCN layer 1 sparse aggregation -----------------------------
__global__ void gcn1_kernel(const int* __restrict__ lst, const int* __restrict__ deg,
                            const float* __restrict__ d0, const float* __restrict__ xW,
                            const float* __restrict__ b1, const float* __restrict__ mask,
                            float* __restrict__ x1) {
    int b = blockIdx.y, i = blockIdx.x, c = threadIdx.x;   // 128 threads
    int dg = deg[b * N_ + i];
    const int* l = lst + ((size_t)(b * N_ + i)) * CAP;
    float di = d0[b * N_ + i];
    float acc = di * di * xW[((size_t)(b * N_ + i)) * H_ + c];
    for (int p = 0; p < dg; p++) {
        int j = l[p];
        if (j != i) acc = fmaf(di * d0[b * N_ + j], xW[((size_t)(b * N_ + j)) * H_ + c], acc);
    }
    float vv = (acc + b1[c]) * mask[b * N_ + i];
    x1[((size_t)(b * N_ + i)) * H_ + c] = fmaxf(vv, 0.f);
}

// ---------------- v = x @ Watt + batt ----------------------------------------
__global__ void gemv_watt_kernel(const float* __restrict__ x, const float* __restrict__ Watt,
                                 const float* __restrict__ batt, float* __restrict__ v) {
    int w = blockIdx.x * 8 + (threadIdx.x >> 5);
    int lane = threadIdx.x & 31;
    if (w >= B_ * N_) return;
    const float* xr = x + (size_t)w * H_;
    float s = 0.f;
    #pragma unroll
    for (int c = lane; c < H_; c += 32) s += xr[c] * Watt[c];
    #pragma unroll
    for (int o = 16; o > 0; o >>= 1) s += __shfl_down_sync(0xffffffffu, s, o);
    if (lane == 0) v[w] = s + batt[0];
}

// ---------------- layer-1 alpha (sparse) --------------------------------------
__global__ void alpha1_kernel(const int* __restrict__ lst, const int* __restrict__ deg,
                              const float* __restrict__ d1, const float* __restrict__ rnz,
                              const float* __restrict__ v, float* __restrict__ alp) {
    int b = blockIdx.y;
    int i = blockIdx.x * 8 + (threadIdx.x >> 5);
    int lane = threadIdx.x & 31;
    const int* l = lst + ((size_t)(b * N_ + i)) * CAP;
    int dg = deg[b * N_ + i];
    float s = 0.f;
    for (int p = lane; p < dg; p += 32) { int j = l[p]; s += d1[b * N_ + j] * v[b * N_ + j]; }
    #pragma unroll
    for (int o = 16; o > 0; o >>= 1) s += __shfl_down_sync(0xffffffffu, s, o);
    if (lane == 0) {
        float di = d1[b * N_ + i];
        float r = rnz[b * N_ + i] * di * (s + di * v[b * N_ + i]);
        float z = r * r;
        alp[b * N_ + i] = 1.f / (1.f + expf(-z));
    }
}

// ---------------- exact K-th largest via bitonic sort ------------------------
__global__ void topk_cut_kernel(const float* __restrict__ alp, float* __restrict__ cut) {
    __shared__ float s[N_];
    int b = blockIdx.x, t = threadIdx.x;   // 1024 threads
    s[t] = alp[b * N_ + t];
    s[t + 1024] = alp[b * N_ + t + 1024];
    __syncthreads();
    for (int k = 2; k <= N_; k <<= 1) {
        for (int j = k >> 1; j > 0; j >>= 1) {
            for (int i = t; i < N_; i += 1024) {
                int ixj = i ^ j;
                if (ixj > i) {
                    float a = s[i], c = s[ixj];
                    if (((i & k) == 0) ? (a > c) : (a < c)) { s[i] = c; s[ixj] = a; }
                }
            }
            __syncthreads();
        }
    }
    if (t == 0) cut[b] = s[N_ - K_];
}

__global__ void ca_kernel(const float* __restrict__ alp, const float* __restrict__ cut,
                          float* __restrict__ ca) {
    int idx = blockIdx.x * 256 + threadIdx.x;
    int b = idx / N_;
    ca[idx] = fmaxf(alp[idx] + 1e-7f - cut[b], 0.f);
}

// ---------------- deterministic kept-set compaction (prefix scan) -----------
__global__ void compact_kernel(const float* __restrict__ ca, int* __restrict__ idx,
                               int* __restrict__ ginv, int* __restrict__ cnt) {
    __shared__ int sc[1024];
    int b = blockIdx.x, t = threadIdx.x;   // 1024 threads
    int f0 = (ca[b * N_ + 2 * t]     > 0.f) ? 1 : 0;
    int f1 = (ca[b * N_ + 2 * t + 1] > 0.f) ? 1 : 0;
    ginv[b * N_ + 2 * t] = -1;
    ginv[b * N_ + 2 * t + 1] = -1;
    int c = f0 + f1;
    sc[t] = c; __syncthreads();
    for (int o = 1; o < 1024; o <<= 1) {
        int v = (t >= o) ? sc[t - o] : 0; __syncthreads();
        sc[t] += v; __syncthreads();
    }
    int base = sc[t] - c;
    if (f0) { idx[b * N_ + base] = 2 * t;     ginv[b * N_ + 2 * t]     = base; base++; }
    if (f1) { idx[b * N_ + base] = 2 * t + 1; ginv[b * N_ + 2 * t + 1] = base; }
    if (t == 1023) cnt[b] = sc[1023];
}

// maskc = compacted mask; mrest = TOTAL mask sum (for final-layer bias fold)
__global__ void compact_mask_kernel(const float* __restrict__ mask, const int* __restrict__ idx,
                                    const int* __restrict__ cnt, float* __restrict__ maskc,
                                    float* __restrict__ mrest) {
    __shared__ float red[256];
    int b = blockIdx.x, t = threadIdx.x;
    int c = cnt[b];
    float local = 0.f;
    for (int i = t; i < N_; i += 256) {
        float mv = 0.f;
        if (i < c) mv = mask[b * N_ + idx[b * N_ + i]];
        maskc[b * N_ + i] = mv;
        local += mask[b * N_ + i];
    }
    red[t] = local; __syncthreads();
    for (int o = 128; o > 0; o >>= 1) { if (t < o) red[t] += red[t + o]; __syncthreads(); }
    if (t == 0) mrest[b] = red[0];
}

// ---------------- layer-1 S row normalizer -----------------------------------
__global__ void srec_kernel(const int* __restrict__ lst, const int* __restrict__ deg,
                            const float* __restrict__ d1, const float* __restrict__ rnz,
                            const float* __restrict__ ca, float* __restrict__ srec) {
    int b = blockIdx.y;
    int i = blockIdx.x * 8 + (threadIdx.x >> 5);
    int lane = threadIdx.x & 31;
    const int* l = lst + ((size_t)(b * N_ + i)) * CAP;
    int dg = deg[b * N_ + i];
    float s = 0.f;
    for (int p = lane; p < dg; p += 32) { int j = l[p]; s += d1[b * N_ + j] * ca[b * N_ + j]; }
    #pragma unroll
    for (int o = 16; o > 0; o >>= 1) s += __shfl_down_sync(0xffffffffu, s, o);
    if (lane == 0) {
        float di = d1[b * N_ + i];
        float raw = rnz[b * N_ + i] * di * (s + di * ca[b * N_ + i]);
        srec[b * N_ + i] = rnz[b * N_ + i] * di / fmaxf(raw, 1e-12f);
    }
}

// ---------------- xc[ic,:] = sum_n S[n, idx[ic]] * x1[n,:] -------------------
__global__ void xupd_kernel(const int* __restrict__ lst, const int* __restrict__ deg,
                            const int* __restrict__ hasd, const float* __restrict__ d1,
                            const float* __restrict__ ca, const float* __restrict__ srec,
                            const int* __restrict__ idx, const int* __restrict__ cnt,
                            const float* __restrict__ x1, float* __restrict__ xc) {
    int b = blockIdx.y, ic = blockIdx.x, c = threadIdx.x;   // 128 threads
    int cn = cnt[b], cnp = (cn + 127) & ~127;
    if (ic >= cnp) return;
    float* orow = xc + ((size_t)(b * N_ + ic)) * H_;
    if (ic >= cn) { orow[c] = 0.f; return; }
    int m = idx[b * N_ + ic];
    float dmcam = d1[b * N_ + m] * ca[b * N_ + m];
    int dg = deg[b * N_ + m];
    const int* l = lst + ((size_t)(b * N_ + m)) * CAP;
    float acc = 0.f;
    for (int p = 0; p < dg; p++) {
        int n = l[p];
        float coef = (n == m) ? 2.f : 1.f;
        float sv = srec[b * N_ + n] * dmcam * coef;
        acc = fmaf(sv, x1[((size_t)(b * N_ + n)) * H_ + c], acc);
    }
    if (!hasd[b * N_ + m])
        acc = fmaf(srec[b * N_ + m] * dmcam, x1[((size_t)(b * N_ + m)) * H_ + c], acc);
    orow[c] = acc;
}

// ---- Tc[i,:] = sum_{j in list_i} S_row_j, S rows expanded on the fly --------
__global__ void adjS_sparse_kernel(const int* __restrict__ lst, const int* __restrict__ deg,
                                   const int* __restrict__ hasd, const float* __restrict__ d1,
                                   const float* __restrict__ ca, const float* __restrict__ srec,
                                   const int* __restrict__ ginv, const int* __restrict__ cnt,
                                   float* __restrict__ Tc) {
    __shared__ float acc[4][N_];
    int b = blockIdx.y, tid = threadIdx.x;   // 128 threads = 4 warps
    int w = tid >> 5, lane = tid & 31;
    int i = blockIdx.x * 4 + w;
    int cnp = (cnt[b] + 127) & ~127;
    float* a = acc[w];
    float4* a4 = (float4*)a;
    float4 z4 = make_float4(0.f, 0.f, 0.f, 0.f);
    for (int jc = lane; jc < (cnp >> 2); jc += 32) a4[jc] = z4;
    __syncwarp();
    int dgi = deg[b * N_ + i];
    const int* li = lst + ((size_t)(b * N_ + i)) * CAP;
    const int* gv = ginv + b * N_;
    for (int p = 0; p < dgi; p++) {
        int j = li[p];
        int dgj = deg[b * N_ + j];
        const int* lj = lst + ((size_t)(b * N_ + j)) * CAP;
        float sr = srec[b * N_ + j];
        for (int q = lane; q < dgj; q += 32) {
            int m = lj[q];
            int jc = gv[m];
            if (jc >= 0) {
                float coef = (m == j) ? 2.f : 1.f;
                a[jc] += sr * d1[b * N_ + m] * ca[b * N_ + m] * coef;
            }
        }
        __syncwarp();
        if (lane == 0 && !hasd[b * N_ + j]) {
            int jc = gv[j];
            if (jc >= 0) a[jc] += sr * d1[b * N_ + j] * ca[b * N_ + j];
        }
        __syncwarp();
    }
    float4* trow4 = (float4*)(Tc + (size_t)b * N_ * N_ + (size_t)i * cnp);
    for (int jc = lane; jc < (cnp >> 2); jc += 32) trow4[jc] = a4[jc];
}

// -------- Ac[ic,:] = floorq(sum_n S[n,m] * Tc[n,:]); fused bf16 split --------
__global__ void STT_kernel(const int* __restrict__ lst, const int* __restrict__ deg,
                           const int* __restrict__ hasd, const float* __restrict__ d1,
                           const float* __restrict__ ca, const float* __restrict__ srec,
                           const int* __restrict__ idx, const int* __restrict__ cnt,
                           const float* __restrict__ Tc, float* __restrict__ Ac,
                           __nv_bfloat16* __restrict__ Achi, __nv_bfloat16* __restrict__ Aclo) {
    __shared__ float4 acc4[N_ / 4];
    int b = blockIdx.y, ic = blockIdx.x, tid = threadIdx.x;
    int cn = cnt[b], cnp = (cn + 127) & ~127, cnp4 = cnp >> 2;
    if (ic >= cnp) return;
    size_t rowoff = ((size_t)(b * N_ + ic)) * N_;
    float4* orow4 = (float4*)(Ac + rowoff);
    __nv_bfloat162* ohi = (__nv_bfloat162*)(Achi + rowoff);
    __nv_bfloat162* olo = (__nv_bfloat162*)(Aclo + rowoff);
    float4 z4 = make_float4(0.f, 0.f, 0.f, 0.f);
    if (ic >= cn) {
        __nv_bfloat162 zb; zb.x = __float2bfloat16(0.f); zb.y = zb.x;
        for (int jc = tid; jc < cnp4; jc += 256) {
            orow4[jc] = z4;
            ohi[jc * 2] = zb; ohi[jc * 2 + 1] = zb;
            olo[jc * 2] = zb; olo[jc * 2 + 1] = zb;
        }
        return;
    }
    int m = idx[b * N_ + ic];
    float dmcam = d1[b * N_ + m] * ca[b * N_ + m];
    for (int jc = tid; jc < cnp4; jc += 256) acc4[jc] = z4;
    __syncthreads();
    int dg = deg[b * N_ + m];
    const int* l = lst + ((size_t)(b * N_ + m)) * CAP;
    const float* Tb = Tc + (size_t)b * N_ * N_;
    for (int p = 0; p < dg; p++) {
        int n = l[p];
        float coef = (n == m) ? 2.f : 1.f;
        float sv = srec[b * N_ + n] * dmcam * coef;
        if (sv != 0.f) {
            const float4* trow = (const float4*)(Tb + (size_t)n * cnp);
            for (int jc = tid; jc < cnp4; jc += 256) {
                float4 t = trow[jc], a = acc4[jc];
                a.x = fmaf(sv, t.x, a.x); a.y = fmaf(sv, t.y, a.y);
                a.z = fmaf(sv, t.z, a.z); a.w = fmaf(sv, t.w, a.w);
                acc4[jc] = a;
            }
        }
    }
    if (!hasd[b * N_ + m]) {
        float sv = srec[b * N_ + m] * dmcam;
        if (sv != 0.f) {
            const float4* trow = (const float4*)(Tb + (size_t)m * cnp);
            for (int jc = tid; jc < cnp4; jc += 256) {
                float4 t = trow[jc], a = acc4[jc];
                a.x = fmaf(sv, t.x, a.x); a.y = fmaf(sv, t.y, a.y);
                a.z = fmaf(sv, t.z, a.z); a.w = fmaf(sv, t.w, a.w);
                acc4[jc] = a;
            }
        }
    }
    __syncthreads();
    for (int jc = tid; jc < cnp4; jc += 256) {
        float4 a = acc4[jc];
        a.x = floorf(a.x * 10000.f) / 10000.f;
        a.y = floorf(a.y * 10000.f) / 10000.f;
        a.z = floorf(a.z * 10000.f) / 10000.f;
        a.w = floorf(a.w * 10000.f) / 10000.f;
        orow4[jc] = a;
        __nv_bfloat162 h01 = split_hi2(a.x, a.y), h23 = split_hi2(a.z, a.w);
        ohi[jc * 2] = h01; ohi[jc * 2 + 1] = h23;
        olo[jc * 2] = split_lo2(a.x, a.y, h01); olo[jc * 2 + 1] = split_lo2(a.z, a.w, h23);
    }
}

// ---------------- layer-2 / final helpers (fused, read Ac/A3 directly) -------
__global__ void rowstats_c_kernel(const float* __restrict__ A, const int* __restrict__ cnt,
                                  float* __restrict__ dout, float* __restrict__ rnz, int mode) {
    int b = blockIdx.y, i = blockIdx.x, tid = threadIdx.x;
    int cnp = (cnt[b] + 127) & ~127;
    if (i >= cnp) return;
    const float* row = A + ((size_t)(b * N_ + i)) * N_;
    const float4* row4 = (const float4*)row;
    float s = 0.f;
    for (int j = tid; j < (cnp >> 2); j += 256) {
        float4 a = row4[j]; s += (a.x + a.y) + (a.z + a.w);
    }
    __shared__ float red[256];
    red[tid] = s; __syncthreads();
    for (int o = 128; o > 0; o >>= 1) { if (tid < o) red[tid] += red[tid + o]; __syncthreads(); }
    if (tid == 0) {
        float sum = red[0];
        if (mode == 0) {
            dout[b * N_ + i] = rsqrtf(fmaxf(sum - row[i] + 1.f, 1.f));
        } else {
            dout[b * N_ + i] = rsqrtf(fmaxf(sum + 1.f, 1.f));
            rnz[b * N_ + i] = (sum > 0.f) ? 1.f : 0.f;
        }
    }
}

__global__ void alpha2d_kernel(const float* __restrict__ Ac, const float* __restrict__ d2,
                               const float* __restrict__ rz2, const float* __restrict__ v,
                               const int* __restrict__ cnt, float* __restrict__ alp) {
    __shared__ float dv[N_];
    __shared__ float red[256];
    int b = blockIdx.y, n = blockIdx.x, tid = threadIdx.x;
    int cnp = (cnt[b] + 127) & ~127;
    if (n >= cnp) { if (tid == 0) alp[b * N_ + n] = 0.5f; return; }
    for (int m = tid; m < cnp; m += 256) dv[m] = d2[b * N_ + m] * v[b * N_ + m];
    __syncthreads();
    const float4* row4 = (const float4*)(Ac + ((size_t)(b * N_ + n)) * N_);
    const float4* dv4 = (const float4*)dv;
    float s = 0.f;
    for (int m = tid; m < (cnp >> 2); m += 256) {
        float4 a = row4[m], w = dv4[m];
        s += a.x * w.x + a.y * w.y + a.z * w.z + a.w * w.w;
    }
    red[tid] = s; __syncthreads();
    for (int o = 128; o > 0; o >>= 1) { if (tid < o) red[tid] += red[tid + o]; __syncthreads(); }
    if (tid == 0) {
        float r = rz2[b * N_ + n] * d2[b * N_ + n] * (red[0] + dv[n]);
        alp[b * N_ + n] = 1.f / (1.f + expf(-r * r));
    }
}

// sinv[n] = f / max(f * sum_m (Ac[n][m]+delta)*dca[m], 1e-12), f = rz2*d2
__global__ void s2inv_kernel(const float* __restrict__ Ac, const float* __restrict__ d2,
                             const float* __restrict__ rz2, const float* __restrict__ ca,
                             const int* __restrict__ cnt, float* __restrict__ sinv) {
    __shared__ float dca[N_];
    __shared__ float red[256];
    int b = blockIdx.y, n = blockIdx.x, tid = threadIdx.x;
    int cnp = (cnt[b] + 127) & ~127;
    if (n >= cnp) return;
    for (int m = tid; m < cnp; m += 256) dca[m] = d2[b * N_ + m] * ca[b * N_ + m];
    __syncthreads();
    const float4* row4 = (const float4*)(Ac + ((size_t)(b * N_ + n)) * N_);
    const float4* dca4 = (const float4*)dca;
    float s = 0.f;
    for (int m = tid; m < (cnp >> 2); m += 256) {
        float4 a = row4[m], w = dca4[m];
        s += a.x * w.x + a.y * w.y + a.z * w.z + a.w * w.w;
    }
    red[tid] = s; __syncthreads();
    for (int o = 128; o > 0; o >>= 1) { if (tid < o) red[tid] += red[tid + o]; __syncthreads(); }
    if (tid == 0) {
        float sum = red[0] + dca[n];
        float f = rz2[b * N_ + n] * d2[b * N_ + n];
        sinv[b * N_ + n] = f / fmaxf(f * sum, 1e-12f);
    }
}

// ST[m][n] = S2[n][m] = (Ac[m][n] + (m==n)) * dca[m] * sinv[n]  (Ac symmetric)
// bf16 hi/lo split written row-major directly (no fp32 S2, no transpose).
__global__ void buildST_kernel(const float* __restrict__ Ac, const float* __restrict__ d2,
                               const float* __restrict__ ca, const float* __restrict__ sinv,
                               const int* __restrict__ cnt,
                               __nv_bfloat16* __restrict__ SThi, __nv_bfloat16* __restrict__ STlo) {
    __shared__ float siv[N_];
    int b = blockIdx.y, m = blockIdx.x, tid = threadIdx.x;
    int cnp = (cnt[b] + 127) & ~127;
    if (m >= cnp) return;
    for (int n = tid; n < cnp; n += 256) siv[n] = sinv[b * N_ + n];
    __syncthreads();
    float dcam = d2[b * N_ + m] * ca[b * N_ + m];
    size_t ro = ((size_t)(b * N_ + m)) * N_;
    const float4* row4 = (const float4*)(Ac + ro);
    __nv_bfloat162* ohi = (__nv_bfloat162*)(SThi + ro);
    __nv_bfloat162* olo = (__nv_bfloat162*)(STlo + ro);
    for (int q = tid; q < (cnp >> 2); q += 256) {
        float4 a = row4[q];
        int n = q << 2;
        float v0 = (a.x + ((n    ) == m ? 1.f : 0.f)) * dcam * siv[n];
        float v1 = (a.y + ((n + 1) == m ? 1.f : 0.f)) * dcam * siv[n + 1];
        float v2 = (a.z + ((n + 2) == m ? 1.f : 0.f)) * dcam * siv[n + 2];
        float v3 = (a.w + ((n + 3) == m ? 1.f : 0.f)) * dcam * siv[n + 3];
        __nv_bfloat162 h01 = split_hi2(v0, v1), h23 = split_hi2(v2, v3);
        ohi[q * 2] = h01; ohi[q * 2 + 1] = h23;
        olo[q * 2] = split_lo2(v0, v1, h01); olo[q * 2 + 1] = split_lo2(v2, v3, h23);
    }
}

// w[k] = d2[k] * (sum_m A3[k][m]*dv[m] - A3[k][k]*dv[k] + dv[k]), dv = d2*maskc
__global__ void wvec_kernel(const float* __restrict__ A3, const float* __restrict__ d2,
                            const float* __restrict__ maskc, const int* __restrict__ cnt,
                            float* __restrict__ wv) {
    __shared__ float dv[N_];
    __shared__ float red[256];
    int b = blockIdx.y, k = blockIdx.x, tid = threadIdx.x;
    int cnp = (cnt[b] + 127) & ~127;
    if (k >= cnp) return;
    for (int m = tid; m < cnp; m += 256) dv[m] = d2[b * N_ + m] * maskc[b * N_ + m];
    __syncthreads();
    const float* row = A3 + ((size_t)(b * N_ + k)) * N_;
    const float4* row4 = (const float4*)row;
    const float4* dv4 = (const float4*)dv;
    float s = 0.f;
    for (int m = tid; m < (cnp >> 2); m += 256) {
        float4 a = row4[m], w = dv4[m];
        s += a.x * w.x + a.y * w.y + a.z * w.z + a.w * w.w;
    }
    red[tid] = s; __syncthreads();
    for (int o = 128; o > 0; o >>= 1) { if (tid < o) red[tid] += red[tid + o]; __syncthreads(); }
    if (tid == 0)
        wv[b * N_ + k] = d2[b * N_ + k] * (red[0] - row[k] * dv[k] + dv[k]);
}

// p2 partial: sum_k wv[k]*xW[k,:] over k-chunk q
__global__ void out2_part_kernel(const float* __restrict__ xW, const float* __restrict__ wv,
                                 const int* __restrict__ cnt, float* __restrict__ p2) {
    int b = blockIdx.y, q = blockIdx.x, c = threadIdx.x;   // 256 threads
    int cnp = (cnt[b] + 127) & ~127;
    int lo = q * 512, hi = (q + 1) * 512; if (hi > cnp) hi = cnp;
    float s = 0.f;
    for (int k = lo; k < hi; k++)
        s = fmaf(wv[b * N_ + k], xW[((size_t)(b * N_ + k)) * F_ + c], s);
    p2[(b * 4 + q) * F_ + c] = s;
}

// generic transposed split: out[j][i] = in[i][j]; in R x C (ld), out stride N_
__global__ void split_tr_kernel(const float* __restrict__ in, __nv_bfloat16* __restrict__ hi,
                                __nv_bfloat16* __restrict__ lo, const int* __restrict__ cnt,
                                int Rfixed, int Cfixed, int ld, long sIn) {
    __shared__ float tile[32][33];
    int b = blockIdx.z;
    int cnp = (cnt[b] + 127) & ~127;
    int R = Rfixed ? Rfixed : cnp;
    int C = Cfixed ? Cfixed : cnp;
    int i0 = blockIdx.y * 32, j0 = blockIdx.x * 32;
    if (i0 >= R || j0 >= C) return;
    const float* inb = in + (size_t)b * sIn;
    size_t boff = (size_t)b * N_ * N_;
    int tx = threadIdx.x, ty = threadIdx.y;   // (32, 8)
    #pragma unroll
    for (int r = 0; r < 4; r++) {
        int i = ty + r * 8;
        tile[i][tx] = inb[(size_t)(i0 + i) * ld + j0 + tx];
    }
    __syncthreads();
    #pragma unroll
    for (int r = 0; r < 4; r++) {
        int j = ty + r * 8;
        float v = tile[tx][j];
        __nv_bfloat16 h = __float2bfloat16(v);
        size_t o = boff + (size_t)(j0 + j) * N_ + i0 + tx;
        hi[o] = h;
        lo[o] = __float2bfloat16(v - __bfloat162float(h));
    }
}

// ---------------- bf16-split tensor GEMM, single-K-pass ----------------------
// C = A @ B: hi*hi + hi*lo + lo*hi accumulated per k-tile (fp32 accum).
// A row-major [m][k] stride N_; BT [n][k] stride N_.
// M = K = cnp; N = NpFixed or cnp.
// EPI: 0 none, 3 floor-quant, 4 row-major bf16 hi/lo split out.
#define TSZ (128 * 40)
template<int EPI>
__global__ void __launch_bounds__(256, 2) gemm_bf16_kernel(
    const __nv_bfloat16* __restrict__ Ahi, const __nv_bfloat16* __restrict__ Alo,
    const __nv_bfloat16* __restrict__ BThi, const __nv_bfloat16* __restrict__ BTlo,
    float* __restrict__ C, const int* __restrict__ cnt,
    int NpFixed, int ldc, long sC,
    __nv_bfloat16* __restrict__ Chi, __nv_bfloat16* __restrict__ Clo) {
    extern __shared__ __nv_bfloat16 sm[];   // [2 stages][4 tiles][128*40]
    const int b = blockIdx.z;
    const int cnp = (cnt[b] + 127) & ~127;
    const int Np = NpFixed ? NpFixed : cnp;
    const int m0 = blockIdx.y * 128, n0 = blockIdx.x * 128;
    if (m0 >= cnp || n0 >= Np) return;
    const size_t boff = (size_t)b * N_ * N_;
    const int tid = threadIdx.x;
    const int wid = tid >> 5, lane = tid & 31;
    const int wm = wid >> 1, wn = wid & 1;     // warps 4 x 2 -> warp tile 32 x 64
    const int g = lane >> 2, t4 = lane & 3;
    const int a_row = lane & 15;
    const int a_k   = (lane & 16) ? 8 : 0;
    const int b_row = (lane & 7) + ((lane & 16) ? 8 : 0);
    const int b_k   = (lane & 8) ? 8 : 0;
    const int KT = cnp >> 5;

    float acc[2][8][4];
    #pragma unroll
    for (int fm = 0; fm < 2; fm++)
        #pragma unroll
        for (int fn = 0; fn < 8; fn++)
            #pragma unroll
            for (int r = 0; r < 4; r++) acc[fm][fn][r] = 0.f;

    const __nv_bfloat16* gsrc[4];
    auto stage = [&](int kt, int buf) {
        gsrc[0] = Ahi  + boff + (size_t)m0 * N_ + kt * 32;
        gsrc[1] = Alo  + boff + (size_t)m0 * N_ + kt * 32;
        gsrc[2] = BThi + boff + (size_t)n0 * N_ + kt * 32;
        gsrc[3] = BTlo + boff + (size_t)n0 * N_ + kt * 32;
        int row = tid >> 2, cc = (tid & 3) * 8;
        #pragma unroll
        for (int w = 0; w < 4; w++) {
            __nv_bfloat16* dst = sm + (size_t)(buf * 4 + w) * TSZ;
            CP16(dst + row * 40 + cc,        gsrc[w] + (size_t)row * N_ + cc);
            CP16(dst + (row + 64) * 40 + cc, gsrc[w] + (size_t)(row + 64) * N_ + cc);
        }
    };

    stage(0, 0);
    CP_COMMIT();

    for (int t = 0; t < KT; t++) {
        CP_WAIT0();
        __syncthreads();
        if (t + 1 < KT) { stage(t + 1, (t + 1) & 1); CP_COMMIT(); }
        const __nv_bfloat16* Ah = sm + (size_t)((t & 1) * 4 + 0) * TSZ;
        const __nv_bfloat16* Al = sm + (size_t)((t & 1) * 4 + 1) * TSZ;
        const __nv_bfloat16* Bh = sm + (size_t)((t & 1) * 4 + 2) * TSZ;
        const __nv_bfloat16* Bl = sm + (size_t)((t & 1) * 4 + 3) * TSZ;
        #pragma unroll
        for (int kh = 0; kh < 32; kh += 16) {
            uint32_t ah[2][4], al[2][4];
            #pragma unroll
            for (int fm = 0; fm < 2; fm++) {
                int ao = (wm * 32 + fm * 16 + a_row) * 40 + kh + a_k;
                ldsm4(ah[fm], Ah + ao);
                ldsm4(al[fm], Al + ao);
            }
            #pragma unroll
            for (int fn2 = 0; fn2 < 4; fn2++) {
                int bo = (wn * 64 + fn2 * 16 + b_row) * 40 + kh + b_k;
                uint32_t bh[4], bl[4];
                ldsm4(bh, Bh + bo);
                ldsm4(bl, Bl + bo);
                #pragma unroll
                for (int fm = 0; fm < 2; fm++) {
                    mma_bf16(acc[fm][2 * fn2],     ah[fm], bh[0], bh[1]);
                    mma_bf16(acc[fm][2 * fn2],     ah[fm], bl[0], bl[1]);
                    mma_bf16(acc[fm][2 * fn2],     al[fm], bh[0], bh[1]);
                    mma_bf16(acc[fm][2 * fn2 + 1], ah[fm], bh[2], bh[3]);
                    mma_bf16(acc[fm][2 * fn2 + 1], ah[fm], bl[2], bl[3]);
                    mma_bf16(acc[fm][2 * fn2 + 1], al[fm], bh[2], bh[3]);
                }
            }
        }
        __syncthreads();
    }

    #pragma unroll
    for (int fm = 0; fm < 2; fm++) {
        int mr = m0 + wm * 32 + fm * 16 + g;
        #pragma unroll
        for (int fn = 0; fn < 8; fn++) {
            int n = n0 + wn * 64 + fn * 8 + t4 * 2;
            float v0 = acc[fm][fn][0], v1 = acc[fm][fn][1];
            float v2 = acc[fm][fn][2], v3 = acc[fm][fn][3];
            if (EPI == 3) {
                v0 = floorf(v0 * 10000.f) / 10000.f;
                v1 = floorf(v1 * 10000.f) / 10000.f;
                v2 = floorf(v2 * 10000.f) / 10000.f;
                v3 = floorf(v3 * 10000.f) / 10000.f;
            }
            if (EPI == 4) {
                size_t o0 = (size_t)b * sC + (size_t)mr * ldc + n;
                size_t o1 = o0 + 8 * (size_t)ldc;
                __nv_bfloat162 h0 = split_hi2(v0, v1), h1 = split_hi2(v2, v3);
                *(__nv_bfloat162*)(Chi + o0) = h0;
                *(__nv_bfloat162*)(Chi + o1) = h1;
                *(__nv_bfloat162*)(Clo + o0) = split_lo2(v0, v1, h0);
                *(__nv_bfloat162*)(Clo + o1) = split_lo2(v2, v3, h1);
            } else {
                float* p0 = C + (size_t)b * sC + (size_t)mr * ldc + n;
                p0[0] = v0; p0[1] = v1;
                float* p1 = p0 + 8 * (size_t)ldc;
                p1[0] = v2; p1[1] = v3;
            }
        }
    }
}

// ---------------- double-buffered cp.async SIMT GEMM (small GEMMs) -----------
template<int TRANSA, int EPI>
__global__ void __launch_bounds__(256, 2) gemm2_kernel(
    const float* __restrict__ A, const float* __restrict__ Bm, float* __restrict__ C,
    int M, int Kd, int Nc, int lda, int ldb, int ldc,
    long sA, long sB, long sC,
    const float* __restrict__ bias, const float* __restrict__ mask,
    const int* __restrict__ cnt, int dynM, int dynK, int dynN) {
    __shared__ float As[2][128 * 16];
    __shared__ float Bs[2][16 * 128];
    const int b = blockIdx.z;
    int Mp = M, Kp = Kd, Np = Nc;
    if (cnt) {
        int p = (cnt[b] + 127) & ~127;
        if (dynM) Mp = p; if (dynK) Kp = p; if (dynN) Np = p;
    }
    const int n0 = blockIdx.x * 128, m0 = blockIdx.y * 128;
    if (m0 >= Mp || n0 >= Np) return;
    A  += (size_t)b * sA;
    Bm += (size_t)b * sB;
    C  += (size_t)b * sC;
    const int tid = threadIdx.x, tx = tid & 15, ty = tid >> 4;
    float acc[8][8];
    #pragma unroll
    for (int i = 0; i < 8; i++)
        #pragma unroll
        for (int j = 0; j < 8; j++) acc[i][j] = 0.f;

    const int Kt = Kp >> 4;

    auto load_tiles = [&](int k0, int buf) {
        if (!TRANSA) {
            #pragma unroll
            for (int q = 0; q < 2; q++) {
                int c = tid + q * 256;
                int row = c >> 2, col4 = (c & 3) * 4;
                const float* src = A + (size_t)(m0 + row) * lda + k0 + col4;
                CP16(&As[buf][row * 16 + col4], src);
            }
        } else {
            #pragma unroll
            for (int q = 0; q < 2; q++) {
                int c = tid + q * 256;
                int row = c >> 5, col4 = (c & 31) * 4;
                const float* src = A + (size_t)(k0 + row) * lda + m0 + col4;
                CP16(&As[buf][row * 128 + col4], src);
            }
        }
        #pragma unroll
        for (int q = 0; q < 2; q++) {
            int c = tid + q * 256;
            int row = c >> 5, col4 = (c & 31) * 4;
            const float* src = Bm + (size_t)(k0 + row) * ldb + n0 + col4;
            CP16(&Bs[buf][row * 128 + col4], src);
        }
    };

    load_tiles(0, 0);
    CP_COMMIT();

    for (int t = 0; t < Kt; t++) {
        CP_WAIT0();
        __syncthreads();
        if (t + 1 < Kt) { load_tiles((t + 1) << 4, (t + 1) & 1); CP_COMMIT(); }
        const int buf = t & 1;
        #pragma unroll
        for (int k = 0; k < 16; k++) {
            float a[8], bv[8];
            if (!TRANSA) {
                #pragma unroll
                for (int i = 0; i < 8; i++) a[i] = As[buf][(ty * 8 + i) * 16 + k];
            } else {
                *(float4*)(a)     = *(const float4*)&As[buf][k * 128 + ty * 8];
                *(float4*)(a + 4) = *(const float4*)&As[buf][k * 128 + ty * 8 + 4];
            }
            *(float4*)(bv)     = *(const float4*)&Bs[buf][k * 128 + tx * 8];
            *(float4*)(bv + 4) = *(const float4*)&Bs[buf][k * 128 + tx * 8 + 4];
            #pragma unroll
            for (int i = 0; i < 8; i++)
                #pragma unroll
                for (int j = 0; j < 8; j++) acc[i][j] = fmaf(a[i], bv[j], acc[i][j]);
        }
        __syncthreads();
    }
    #pragma unroll
    for (int i = 0; i < 8; i++) {
        int m = m0 + ty * 8 + i;
        float mk = (EPI == 2) ? mask[(size_t)b * N_ + m] : 1.f;
        #pragma unroll
        for (int j = 0; j < 8; j++) {
            int n = n0 + tx * 8 + j;
            float v = acc[i][j];
            if (EPI == 2)      { v = (v + bias[n]) * mk; }
            else if (EPI == 3) { v = floorf(v * 10000.f) / 10000.f; }
            C[(size_t)m * ldc + n] = v;
        }
    }
}

// ---------------- output means (two-stage, deterministic) --------------------
__global__ void mean1_part_kernel(const float* __restrict__ x1, float* __restrict__ p1) {
    int b = blockIdx.y, q = blockIdx.x, c = threadIdx.x;   // 128 threads
    float s = 0.f;
    for (int n = q * 512; n < (q + 1) * 512; n++) s += x1[((size_t)(b * N_ + n)) * H_ + c];
    p1[(b * 4 + q) * H_ + c] = s;
}

__global__ void mean_combine_kernel(const float* __restrict__ p1, const float* __restrict__ p2,
                                    const float* __restrict__ b2, const float* __restrict__ smask,
                                    float* __restrict__ out) {
    int b = blockIdx.x, c = threadIdx.x;   // 384 threads
    if (c < H_) {
        float s = 0.f;
        for (int q = 0; q < 4; q++) s += p1[(b * 4 + q) * H_ + c];
        out[b * OUTC + c] = s / (float)N_;
    } else {
        int cc = c - H_;
        float s = b2[cc] * smask[b];
        for (int q = 0; q < 4; q++) s += p2[(b * 4 + q) * F_ + cc];
        out[b * OUTC + c] = s / (float)N_;
    }
}

extern "C" void kernel_launch(void* const* d_in, const int* in_sizes, int n_in,
                              void* d_out, int out_size) {
    const float* x    = (const float*)d_in[0];
    const float* adj  = (const float*)d_in[1];
    const float* mask = (const float*)d_in[2];
    const float* W1   = (const float*)d_in[3];
    const float* b1   = (const float*)d_in[4];
    const float* Watt = (const float*)d_in[5];
    const float* batt = (const float*)d_in[6];
    const float* W2   = (const float*)d_in[7];
    const float* b2   = (const float*)d_in[8];
    float* out = (float*)d_out;

    float *pT,*pAc,*pA3,*pxW,*px1,*pxc,*px3;
    float *pv,*palp,*pca,*psrec,*pd0,*pd1,*prnz,*pd2,*prz2,*pcut,*pmaskc,*pmrest,*pp1,*pp2;
    __nv_bfloat16 *pAhi,*pAlo,*pSThi,*pSTlo,*pTThi,*pTTlo;
    int *plst,*pdeg,*phasd,*pidx,*pginv,*pcnt;
    cudaGetSymbolAddress((void**)&pT,   g_T);
    cudaGetSymbolAddress((void**)&pAc,  g_Ac);
    cudaGetSymbolAddress((void**)&pA3,  g_A3);
    cudaGetSymbolAddress((void**)&pAhi, g_Ahi);
    cudaGetSymbolAddress((void**)&pAlo, g_Alo);
    cudaGetSymbolAddress((void**)&pSThi,g_SThi);
    cudaGetSymbolAddress((void**)&pSTlo,g_STlo);
    cudaGetSymbolAddress((void**)&pTThi,g_TThi);
    cudaGetSymbolAddress((void**)&pTTlo,g_TTlo);
    cudaGetSymbolAddress((void**)&pxW,  g_xW);
    cudaGetSymbolAddress((void**)&px1,  g_x1);
    cudaGetSymbolAddress((void**)&pxc,  g_xc);
    cudaGetSymbolAddress((void**)&px3,  g_x3);
    cudaGetSymbolAddress((void**)&pv,   g_v);
    cudaGetSymbolAddress((void**)&palp, g_alp);
    cudaGetSymbolAddress((void**)&pca,  g_ca);
    cudaGetSymbolAddress((void**)&psrec,g_srec);
    cudaGetSymbolAddress((void**)&pd0,  g_d0);
    cudaGetSymbolAddress((void**)&pd1,  g_d1);
    cudaGetSymbolAddress((void**)&prnz, g_rnz);
    cudaGetSymbolAddress((void**)&pd2,  g_d2);
    cudaGetSymbolAddress((void**)&prz2, g_rz2);
    cudaGetSymbolAddress((void**)&pcut, g_cut);
    cudaGetSymbolAddress((void**)&pmaskc, g_maskc);
    cudaGetSymbolAddress((void**)&pmrest, g_mrest);
    cudaGetSymbolAddress((void**)&pp1,  g_p1);
    cudaGetSymbolAddress((void**)&pp2,  g_p2);
    cudaGetSymbolAddress((void**)&plst, g_lst);
    cudaGetSymbolAddress((void**)&pdeg, g_deg);
    cudaGetSymbolAddress((void**)&phasd,g_hasd);
    cudaGetSymbolAddress((void**)&pidx, g_idx);
    cudaGetSymbolAddress((void**)&pginv,g_ginv);
    cudaGetSymbolAddress((void**)&pcnt, g_cnt);

    const int BF16_SMEM = 2 * 4 * TSZ * 2;   // 81920 bytes
    cudaFuncSetAttribute(gemm_bf16_kernel<0>, cudaFuncAttributeMaxDynamicSharedMemorySize, BF16_SMEM);
    cudaFuncSetAttribute(gemm_bf16_kernel<3>, cudaFuncAttributeMaxDynamicSharedMemorySize, BF16_SMEM);
    cudaFuncSetAttribute(gemm_bf16_kernel<4>, cudaFuncAttributeMaxDynamicSharedMemorySize, BF16_SMEM);

    // ---- CSR + degree stats (single adj scan) ----
    csr_build_kernel<<<dim3(N_, B_), 256>>>(adj, plst, pdeg, phasd, pd0, pd1, prnz);

    // ---- GCN layer 1 (sparse aggregation) ----
    gemm2_kernel<0,0><<<dim3(1,16,B_),256>>>(x, W1, pxW, N_, F_, H_, F_, H_, H_,
        (long)N_*F_, 0, (long)N_*H_, nullptr, nullptr, nullptr, 0,0,0);
    gcn1_kernel<<<dim3(N_, B_), 128>>>(plst, pdeg, pd0, pxW, b1, mask, px1);

    // ---- coarsen layer 1 (sparse, no dense S anywhere) ----
    gemv_watt_kernel<<<(B_*N_)/8, 256>>>(px1, Watt, batt, pv);
    alpha1_kernel<<<dim3(N_/8, B_), 256>>>(plst, pdeg, pd1, prnz, pv, palp);
    topk_cut_kernel<<<B_, 1024>>>(palp, pcut);
    ca_kernel<<<(B_*N_)/256, 256>>>(palp, pcut, pca);
    compact_kernel<<<B_, 1024>>>(pca, pidx, pginv, pcnt);
    compact_mask_kernel<<<B_, 256>>>(mask, pidx, pcnt, pmaskc, pmrest);
    srec_kernel<<<dim3(N_/8, B_), 256>>>(plst, pdeg, pd1, prnz, pca, psrec);
    xupd_kernel<<<dim3(N_, B_), 128>>>(plst, pdeg, phasd, pd1, pca, psrec, pidx, pcnt, px1, pxc);
    adjS_sparse_kernel<<<dim3(N_/4, B_), 128>>>(plst, pdeg, phasd, pd1, pca, psrec,
                                                pginv, pcnt, pT);
    STT_kernel<<<dim3(N_, B_), 256>>>(plst, pdeg, phasd, pd1, pca, psrec, pidx, pcnt,
                                      pT, pAc, pAhi, pAlo);

    // ---- coarsen layer 2 (symmetric Ac: direct row-major ST build) ----
    rowstats_c_kernel<<<dim3(N_, B_), 256>>>(pAc, pcnt, pd2, prz2, 1);
    gemv_watt_kernel<<<(B_*N_)/8, 256>>>(pxc, Watt, batt, pv);
    alpha2d_kernel<<<dim3(N_, B_), 256>>>(pAc, pd2, prz2, pv, pcnt, palp);
    topk_cut_kernel<<<B_, 1024>>>(palp, pcut);
    ca_kernel<<<(B_*N_)/256, 256>>>(palp, pcut, pca);
    s2inv_kernel<<<dim3(N_, B_), 256>>>(pAc, pd2, prz2, pca, pcnt, psrec);
    buildST_kernel<<<dim3(N_, B_), 256>>>(pAc, pd2, pca, psrec, pcnt, pSThi, pSTlo);
    // xc^T split into TT (consumed by x3 GEMM before TT is overwritten)
    split_tr_kernel<<<dim3(4, 64, B_), dim3(32, 8)>>>(pxc, pTThi, pTTlo, pcnt,
        0, H_, H_, (long)N_*H_);
    // x3 = S2c^T @ xc (tensor)
    gemm_bf16_kernel<0><<<dim3(1,16,B_),256,BF16_SMEM>>>(pSThi, pSTlo, pTThi, pTTlo,
        px3, pcnt, H_, H_, (long)N_*H_, nullptr, nullptr);
    // T2^T = S2c^T @ Ac^T: A=ST, BT=Ac row-major; epilogue writes bf16 split -> TT
    gemm_bf16_kernel<4><<<dim3(16,16,B_),256,BF16_SMEM>>>(pSThi, pSTlo, pAhi, pAlo,
        nullptr, pcnt, 0, N_, (long)N_*N_, pTThi, pTTlo);
    // A3 = S2c^T @ T2: A=ST, BT=T2^T (=TT), floor-quant
    gemm_bf16_kernel<3><<<dim3(16,16,B_),256,BF16_SMEM>>>(pSThi, pSTlo, pTThi, pTTlo,
        pA3, pcnt, 0, N_, (long)N_*N_, nullptr, nullptr);

    // ---- final GCN: only the column mean is needed ----
    // mean(x2) = (w^T @ (x3 @ W2) + b2 * sum(mask)) / N,  w = NA3^T maskc (exact fp32)
    rowstats_c_kernel<<<dim3(N_, B_), 256>>>(pA3, pcnt, pd2, nullptr, 0);
    gemm2_kernel<0,0><<<dim3(2,16,B_),256>>>(px3, W2, pxW, N_, H_, F_, H_, F_, F_,
        (long)N_*H_, 0, (long)N_*F_, nullptr, nullptr, pcnt, 1,0,0);
    wvec_kernel<<<dim3(N_, B_), 256>>>(pA3, pd2, pmaskc, pcnt, pv);
    out2_part_kernel<<<dim3(4, B_), 256>>>(pxW, pv, pcnt, pp2);

    // ---- concat means ----
    mean1_part_kernel<<<dim3(4, B_), 128>>>(px1, pp1);
    mean_combine_kernel<<<B_, 384>>>(pp1, pp2, b2, pmrest, out);
}

// round 9
// speedup vs baseline: 7.0074x; 1.0600x over previous
#include <cuda_runtime.h>
#include <cuda_bf16.h>
#include <math.h>
#include <stdint.h>

#define B_ 8
#define N_ 2048
#define F_ 256
#define H_ 128
#define K_ 1025
#define OUTC 384
#define CAP 256

// ---------------- scratch (device globals; no allocation allowed) ----------
__device__ float g_T [(size_t)B_*N_*N_];   // Tc (layer1, stride cnp)
__device__ float g_Ac[(size_t)B_*N_*N_];   // compacted A2 (stride N_)
__device__ float g_A3[(size_t)B_*N_*N_];   // compacted A3 (stride N_)
__device__ __nv_bfloat16 g_Ahi[(size_t)B_*N_*N_], g_Alo[(size_t)B_*N_*N_];
__device__ __nv_bfloat16 g_SThi[(size_t)B_*N_*N_], g_STlo[(size_t)B_*N_*N_];
__device__ __nv_bfloat16 g_TThi[(size_t)B_*N_*N_], g_TTlo[(size_t)B_*N_*N_];
__device__ float g_xW [B_*N_*F_];
__device__ float g_x1 [B_*N_*H_];
__device__ float g_xc [B_*N_*H_];
__device__ float g_x3 [B_*N_*H_];
__device__ int   g_lst[(size_t)B_*N_*CAP];
__device__ int   g_deg[B_*N_];
__device__ int   g_hasd[B_*N_];
__device__ float g_d0[B_*N_], g_d1[B_*N_], g_rnz[B_*N_];
__device__ float g_d2[B_*N_], g_rz2[B_*N_];
__device__ float g_v[B_*N_], g_alp[B_*N_], g_ca[B_*N_], g_srec[B_*N_];
__device__ float g_cut[B_];
__device__ float g_maskc[B_*N_], g_mrest[B_];
__device__ int   g_idx[B_*N_], g_ginv[B_*N_], g_cnt[B_];
__device__ float g_p1[B_*4*H_], g_p2[B_*4*F_];

// ---------------- async-copy / mma helpers -----------------------------------
#define CP16(dst, src) { \
    unsigned _a = (unsigned)__cvta_generic_to_shared(dst); \
    asm volatile("cp.async.cg.shared.global [%0], [%1], 16;\n" :: "r"(_a), "l"(src)); }
#define CP_COMMIT() asm volatile("cp.async.commit_group;\n")
#define CP_WAIT0()  asm volatile("cp.async.wait_group 0;\n")

__device__ __forceinline__ void mma_bf16(float* c, const uint32_t* a, uint32_t b0, uint32_t b1) {
    asm volatile("mma.sync.aligned.m16n8k16.row.col.f32.bf16.bf16.f32 "
        "{%0,%1,%2,%3}, {%4,%5,%6,%7}, {%8,%9}, {%0,%1,%2,%3};"
        : "+f"(c[0]), "+f"(c[1]), "+f"(c[2]), "+f"(c[3])
        : "r"(a[0]), "r"(a[1]), "r"(a[2]), "r"(a[3]), "r"(b0), "r"(b1));
}
__device__ __forceinline__ void ldsm4(uint32_t* r, const void* p) {
    uint32_t a = (uint32_t)__cvta_generic_to_shared(p);
    asm volatile("ldmatrix.sync.aligned.m8n8.x4.shared.b16 {%0,%1,%2,%3}, [%4];"
        : "=r"(r[0]), "=r"(r[1]), "=r"(r[2]), "=r"(r[3]) : "r"(a));
}
__device__ __forceinline__ __nv_bfloat162 split_hi2(float v0, float v1) {
    __nv_bfloat162 h; h.x = __float2bfloat16(v0); h.y = __float2bfloat16(v1); return h;
}
__device__ __forceinline__ __nv_bfloat162 split_lo2(float v0, float v1, __nv_bfloat162 h) {
    __nv_bfloat162 l;
    l.x = __float2bfloat16(v0 - __bfloat162float(h.x));
    l.y = __float2bfloat16(v1 - __bfloat162float(h.y));
    return l;
}

// ---------------- CSR build + degree stats (one adj scan) -------------------
__global__ void csr_build_kernel(const float* __restrict__ adj, int* __restrict__ lst,
                                 int* __restrict__ deg, int* __restrict__ hasd,
                                 float* __restrict__ d0, float* __restrict__ d1,
                                 float* __restrict__ rnz) {
    __shared__ int sc[256];
    __shared__ int hd;
    int b = blockIdx.y, i = blockIdx.x, tid = threadIdx.x;
    const float* arow = adj + ((size_t)(b * N_ + i)) * N_;
    if (tid == 0) hd = 0;
    __syncthreads();
    int flags[8];
    int c = 0;
    #pragma unroll
    for (int q = 0; q < 8; q++) {
        int j = tid + q * 256;
        int f = (arow[j] != 0.f) ? 1 : 0;
        flags[q] = f; c += f;
        if (f && j == i) hd = 1;
    }
    sc[tid] = c; __syncthreads();
    for (int o = 1; o < 256; o <<= 1) {
        int v = (tid >= o) ? sc[tid - o] : 0; __syncthreads();
        sc[tid] += v; __syncthreads();
    }
    int base = sc[tid] - c;
    int* l = lst + ((size_t)(b * N_ + i)) * CAP;
    #pragma unroll
    for (int q = 0; q < 8; q++) {
        int j = tid + q * 256;
        if (flags[q]) { if (base < CAP) l[base] = j; base++; }
    }
    __syncthreads();
    if (tid == 0) {
        int total = sc[255];
        deg[b * N_ + i] = (total > CAP) ? CAP : total;
        hasd[b * N_ + i] = hd;
        d0[b * N_ + i] = rsqrtf(fmaxf((float)(total - hd) + 1.f, 1.f));
        d1[b * N_ + i] = rsqrtf((float)total + 1.f);
        rnz[b * N_ + i] = (total > 0) ? 1.f : 0.f;
    }
}

// ---------------- GCN layer 1 sparse aggregation -----------------------------
__global__ void gcn1_kernel(const int* __restrict__ lst, const int* __restrict__ deg,
                            const float* __restrict__ d0, const float* __restrict__ xW,
                            const float* __restrict__ b1, const float* __restrict__ mask,
                            float* __restrict__ x1) {
    int b = blockIdx.y, i = blockIdx.x, c = threadIdx.x;   // 128 threads
    int dg = deg[b * N_ + i];
    const int* l = lst + ((size_t)(b * N_ + i)) * CAP;
    float di = d0[b * N_ + i];
    float acc = di * di * xW[((size_t)(b * N_ + i)) * H_ + c];
    for (int p = 0; p < dg; p++) {
        int j = l[p];
        if (j != i) acc = fmaf(di * d0[b * N_ + j], xW[((size_t)(b * N_ + j)) * H_ + c], acc);
    }
    float vv = (acc + b1[c]) * mask[b * N_ + i];
    x1[((size_t)(b * N_ + i)) * H_ + c] = fmaxf(vv, 0.f);
}

// ---------------- v = x @ Watt + batt ----------------------------------------
__global__ void gemv_watt_kernel(const float* __restrict__ x, const float* __restrict__ Watt,
                                 const float* __restrict__ batt, float* __restrict__ v) {
    int w = blockIdx.x * 8 + (threadIdx.x >> 5);
    int lane = threadIdx.x & 31;
    if (w >= B_ * N_) return;
    const float* xr = x + (size_t)w * H_;
    float s = 0.f;
    #pragma unroll
    for (int c = lane; c < H_; c += 32) s += xr[c] * Watt[c];
    #pragma unroll
    for (int o = 16; o > 0; o >>= 1) s += __shfl_down_sync(0xffffffffu, s, o);
    if (lane == 0) v[w] = s + batt[0];
}

// ---------------- layer-1 alpha (sparse) --------------------------------------
__global__ void alpha1_kernel(const int* __restrict__ lst, const int* __restrict__ deg,
                              const float* __restrict__ d1, const float* __restrict__ rnz,
                              const float* __restrict__ v, float* __restrict__ alp) {
    int b = blockIdx.y;
    int i = blockIdx.x * 8 + (threadIdx.x >> 5);
    int lane = threadIdx.x & 31;
    const int* l = lst + ((size_t)(b * N_ + i)) * CAP;
    int dg = deg[b * N_ + i];
    float s = 0.f;
    for (int p = lane; p < dg; p += 32) { int j = l[p]; s += d1[b * N_ + j] * v[b * N_ + j]; }
    #pragma unroll
    for (int o = 16; o > 0; o >>= 1) s += __shfl_down_sync(0xffffffffu, s, o);
    if (lane == 0) {
        float di = d1[b * N_ + i];
        float r = rnz[b * N_ + i] * di * (s + di * v[b * N_ + i]);
        float z = r * r;
        alp[b * N_ + i] = 1.f / (1.f + expf(-z));
    }
}

// ---------------- exact K-th largest via bitonic sort ------------------------
__global__ void topk_cut_kernel(const float* __restrict__ alp, float* __restrict__ cut) {
    __shared__ float s[N_];
    int b = blockIdx.x, t = threadIdx.x;   // 1024 threads
    s[t] = alp[b * N_ + t];
    s[t + 1024] = alp[b * N_ + t + 1024];
    __syncthreads();
    for (int k = 2; k <= N_; k <<= 1) {
        for (int j = k >> 1; j > 0; j >>= 1) {
            for (int i = t; i < N_; i += 1024) {
                int ixj = i ^ j;
                if (ixj > i) {
                    float a = s[i], c = s[ixj];
                    if (((i & k) == 0) ? (a > c) : (a < c)) { s[i] = c; s[ixj] = a; }
                }
            }
            __syncthreads();
        }
    }
    if (t == 0) cut[b] = s[N_ - K_];
}

__global__ void ca_kernel(const float* __restrict__ alp, const float* __restrict__ cut,
                          float* __restrict__ ca) {
    int idx = blockIdx.x * 256 + threadIdx.x;
    int b = idx / N_;
    ca[idx] = fmaxf(alp[idx] + 1e-7f - cut[b], 0.f);
}

// ---------------- deterministic kept-set compaction (prefix scan) -----------
__global__ void compact_kernel(const float* __restrict__ ca, int* __restrict__ idx,
                               int* __restrict__ ginv, int* __restrict__ cnt) {
    __shared__ int sc[1024];
    int b = blockIdx.x, t = threadIdx.x;   // 1024 threads
    int f0 = (ca[b * N_ + 2 * t]     > 0.f) ? 1 : 0;
    int f1 = (ca[b * N_ + 2 * t + 1] > 0.f) ? 1 : 0;
    ginv[b * N_ + 2 * t] = -1;
    ginv[b * N_ + 2 * t + 1] = -1;
    int c = f0 + f1;
    sc[t] = c; __syncthreads();
    for (int o = 1; o < 1024; o <<= 1) {
        int v = (t >= o) ? sc[t - o] : 0; __syncthreads();
        sc[t] += v; __syncthreads();
    }
    int base = sc[t] - c;
    if (f0) { idx[b * N_ + base] = 2 * t;     ginv[b * N_ + 2 * t]     = base; base++; }
    if (f1) { idx[b * N_ + base] = 2 * t + 1; ginv[b * N_ + 2 * t + 1] = base; }
    if (t == 1023) cnt[b] = sc[1023];
}

// maskc = compacted mask; mrest = TOTAL mask sum (for final-layer bias fold)
__global__ void compact_mask_kernel(const float* __restrict__ mask, const int* __restrict__ idx,
                                    const int* __restrict__ cnt, float* __restrict__ maskc,
                                    float* __restrict__ mrest) {
    __shared__ float red[256];
    int b = blockIdx.x, t = threadIdx.x;
    int c = cnt[b];
    float local = 0.f;
    for (int i = t; i < N_; i += 256) {
        float mv = 0.f;
        if (i < c) mv = mask[b * N_ + idx[b * N_ + i]];
        maskc[b * N_ + i] = mv;
        local += mask[b * N_ + i];
    }
    red[t] = local; __syncthreads();
    for (int o = 128; o > 0; o >>= 1) { if (t < o) red[t] += red[t + o]; __syncthreads(); }
    if (t == 0) mrest[b] = red[0];
}

// ---------------- layer-1 S row normalizer -----------------------------------
__global__ void srec_kernel(const int* __restrict__ lst, const int* __restrict__ deg,
                            const float* __restrict__ d1, const float* __restrict__ rnz,
                            const float* __restrict__ ca, float* __restrict__ srec) {
    int b = blockIdx.y;
    int i = blockIdx.x * 8 + (threadIdx.x >> 5);
    int lane = threadIdx.x & 31;
    const int* l = lst + ((size_t)(b * N_ + i)) * CAP;
    int dg = deg[b * N_ + i];
    float s = 0.f;
    for (int p = lane; p < dg; p += 32) { int j = l[p]; s += d1[b * N_ + j] * ca[b * N_ + j]; }
    #pragma unroll
    for (int o = 16; o > 0; o >>= 1) s += __shfl_down_sync(0xffffffffu, s, o);
    if (lane == 0) {
        float di = d1[b * N_ + i];
        float raw = rnz[b * N_ + i] * di * (s + di * ca[b * N_ + i]);
        srec[b * N_ + i] = rnz[b * N_ + i] * di / fmaxf(raw, 1e-12f);
    }
}

// ---------------- xc[ic,:] = sum_n S[n, idx[ic]] * x1[n,:] -------------------
__global__ void xupd_kernel(const int* __restrict__ lst, const int* __restrict__ deg,
                            const int* __restrict__ hasd, const float* __restrict__ d1,
                            const float* __restrict__ ca, const float* __restrict__ srec,
                            const int* __restrict__ idx, const int* __restrict__ cnt,
                            const float* __restrict__ x1, float* __restrict__ xc) {
    int b = blockIdx.y, ic = blockIdx.x, c = threadIdx.x;   // 128 threads
    int cn = cnt[b], cnp = (cn + 127) & ~127;
    if (ic >= cnp) return;
    float* orow = xc + ((size_t)(b * N_ + ic)) * H_;
    if (ic >= cn) { orow[c] = 0.f; return; }
    int m = idx[b * N_ + ic];
    float dmcam = d1[b * N_ + m] * ca[b * N_ + m];
    int dg = deg[b * N_ + m];
    const int* l = lst + ((size_t)(b * N_ + m)) * CAP;
    float acc = 0.f;
    for (int p = 0; p < dg; p++) {
        int n = l[p];
        float coef = (n == m) ? 2.f : 1.f;
        float sv = srec[b * N_ + n] * dmcam * coef;
        acc = fmaf(sv, x1[((size_t)(b * N_ + n)) * H_ + c], acc);
    }
    if (!hasd[b * N_ + m])
        acc = fmaf(srec[b * N_ + m] * dmcam, x1[((size_t)(b * N_ + m)) * H_ + c], acc);
    orow[c] = acc;
}

// ---- Tc[i,:] = sum_{j in list_i} S_row_j, S rows expanded on the fly --------
__global__ void adjS_sparse_kernel(const int* __restrict__ lst, const int* __restrict__ deg,
                                   const int* __restrict__ hasd, const float* __restrict__ d1,
                                   const float* __restrict__ ca, const float* __restrict__ srec,
                                   const int* __restrict__ ginv, const int* __restrict__ cnt,
                                   float* __restrict__ Tc) {
    __shared__ float acc[4][N_];
    int b = blockIdx.y, tid = threadIdx.x;   // 128 threads = 4 warps
    int w = tid >> 5, lane = tid & 31;
    int i = blockIdx.x * 4 + w;
    int cnp = (cnt[b] + 127) & ~127;
    float* a = acc[w];
    float4* a4 = (float4*)a;
    float4 z4 = make_float4(0.f, 0.f, 0.f, 0.f);
    for (int jc = lane; jc < (cnp >> 2); jc += 32) a4[jc] = z4;
    __syncwarp();
    int dgi = deg[b * N_ + i];
    const int* li = lst + ((size_t)(b * N_ + i)) * CAP;
    const int* gv = ginv + b * N_;
    for (int p = 0; p < dgi; p++) {
        int j = li[p];
        int dgj = deg[b * N_ + j];
        const int* lj = lst + ((size_t)(b * N_ + j)) * CAP;
        float sr = srec[b * N_ + j];
        for (int q = lane; q < dgj; q += 32) {
            int m = lj[q];
            int jc = gv[m];
            if (jc >= 0) {
                float coef = (m == j) ? 2.f : 1.f;
                a[jc] += sr * d1[b * N_ + m] * ca[b * N_ + m] * coef;
            }
        }
        __syncwarp();
        if (lane == 0 && !hasd[b * N_ + j]) {
            int jc = gv[j];
            if (jc >= 0) a[jc] += sr * d1[b * N_ + j] * ca[b * N_ + j];
        }
        __syncwarp();
    }
    float4* trow4 = (float4*)(Tc + (size_t)b * N_ * N_ + (size_t)i * cnp);
    for (int jc = lane; jc < (cnp >> 2); jc += 32) trow4[jc] = a4[jc];
}

// -- Ac[ic,:] = floorq(sum_n S[n,m]*Tc[n,:]); fused bf16 split + d2/rz2 -------
__global__ void STT_kernel(const int* __restrict__ lst, const int* __restrict__ deg,
                           const int* __restrict__ hasd, const float* __restrict__ d1,
                           const float* __restrict__ ca, const float* __restrict__ srec,
                           const int* __restrict__ idx, const int* __restrict__ cnt,
                           const float* __restrict__ Tc, float* __restrict__ Ac,
                           __nv_bfloat16* __restrict__ Achi, __nv_bfloat16* __restrict__ Aclo,
                           float* __restrict__ d2out, float* __restrict__ rz2out) {
    __shared__ float4 acc4[N_ / 4];
    __shared__ float red[256];
    int b = blockIdx.y, ic = blockIdx.x, tid = threadIdx.x;
    int cn = cnt[b], cnp = (cn + 127) & ~127, cnp4 = cnp >> 2;
    if (ic >= cnp) return;
    size_t rowoff = ((size_t)(b * N_ + ic)) * N_;
    float4* orow4 = (float4*)(Ac + rowoff);
    __nv_bfloat162* ohi = (__nv_bfloat162*)(Achi + rowoff);
    __nv_bfloat162* olo = (__nv_bfloat162*)(Aclo + rowoff);
    float4 z4 = make_float4(0.f, 0.f, 0.f, 0.f);
    if (ic >= cn) {
        __nv_bfloat162 zb; zb.x = __float2bfloat16(0.f); zb.y = zb.x;
        for (int jc = tid; jc < cnp4; jc += 256) {
            orow4[jc] = z4;
            ohi[jc * 2] = zb; ohi[jc * 2 + 1] = zb;
            olo[jc * 2] = zb; olo[jc * 2 + 1] = zb;
        }
        if (tid == 0) { d2out[b * N_ + ic] = 1.f; rz2out[b * N_ + ic] = 0.f; }
        return;
    }
    int m = idx[b * N_ + ic];
    float dmcam = d1[b * N_ + m] * ca[b * N_ + m];
    for (int jc = tid; jc < cnp4; jc += 256) acc4[jc] = z4;
    __syncthreads();
    int dg = deg[b * N_ + m];
    const int* l = lst + ((size_t)(b * N_ + m)) * CAP;
    const float* Tb = Tc + (size_t)b * N_ * N_;
    for (int p = 0; p < dg; p++) {
        int n = l[p];
        float coef = (n == m) ? 2.f : 1.f;
        float sv = srec[b * N_ + n] * dmcam * coef;
        if (sv != 0.f) {
            const float4* trow = (const float4*)(Tb + (size_t)n * cnp);
            for (int jc = tid; jc < cnp4; jc += 256) {
                float4 t = trow[jc], a = acc4[jc];
                a.x = fmaf(sv, t.x, a.x); a.y = fmaf(sv, t.y, a.y);
                a.z = fmaf(sv, t.z, a.z); a.w = fmaf(sv, t.w, a.w);
                acc4[jc] = a;
            }
        }
    }
    if (!hasd[b * N_ + m]) {
        float sv = srec[b * N_ + m] * dmcam;
        if (sv != 0.f) {
            const float4* trow = (const float4*)(Tb + (size_t)m * cnp);
            for (int jc = tid; jc < cnp4; jc += 256) {
                float4 t = trow[jc], a = acc4[jc];
                a.x = fmaf(sv, t.x, a.x); a.y = fmaf(sv, t.y, a.y);
                a.z = fmaf(sv, t.z, a.z); a.w = fmaf(sv, t.w, a.w);
                acc4[jc] = a;
            }
        }
    }
    __syncthreads();
    float part = 0.f;
    for (int jc = tid; jc < cnp4; jc += 256) {
        float4 a = acc4[jc];
        a.x = floorf(a.x * 10000.f) / 10000.f;
        a.y = floorf(a.y * 10000.f) / 10000.f;
        a.z = floorf(a.z * 10000.f) / 10000.f;
        a.w = floorf(a.w * 10000.f) / 10000.f;
        orow4[jc] = a;
        part += (a.x + a.y) + (a.z + a.w);
        __nv_bfloat162 h01 = split_hi2(a.x, a.y), h23 = split_hi2(a.z, a.w);
        ohi[jc * 2] = h01; ohi[jc * 2 + 1] = h23;
        olo[jc * 2] = split_lo2(a.x, a.y, h01); olo[jc * 2 + 1] = split_lo2(a.z, a.w, h23);
    }
    red[tid] = part; __syncthreads();
    for (int o = 128; o > 0; o >>= 1) { if (tid < o) red[tid] += red[tid + o]; __syncthreads(); }
    if (tid == 0) {
        float sum = red[0];
        d2out[b * N_ + ic] = rsqrtf(fmaxf(sum + 1.f, 1.f));
        rz2out[b * N_ + ic] = (sum > 0.f) ? 1.f : 0.f;
    }
}

// ---------------- layer-2 / final helpers (read Ac/A3 directly) --------------
__global__ void rowstats_c_kernel(const float* __restrict__ A, const int* __restrict__ cnt,
                                  float* __restrict__ dout, float* __restrict__ rnz, int mode) {
    int b = blockIdx.y, i = blockIdx.x, tid = threadIdx.x;
    int cnp = (cnt[b] + 127) & ~127;
    if (i >= cnp) return;
    const float* row = A + ((size_t)(b * N_ + i)) * N_;
    const float4* row4 = (const float4*)row;
    float s = 0.f;
    for (int j = tid; j < (cnp >> 2); j += 256) {
        float4 a = row4[j]; s += (a.x + a.y) + (a.z + a.w);
    }
    __shared__ float red[256];
    red[tid] = s; __syncthreads();
    for (int o = 128; o > 0; o >>= 1) { if (tid < o) red[tid] += red[tid + o]; __syncthreads(); }
    if (tid == 0) {
        float sum = red[0];
        if (mode == 0) {
            dout[b * N_ + i] = rsqrtf(fmaxf(sum - row[i] + 1.f, 1.f));
        } else {
            dout[b * N_ + i] = rsqrtf(fmaxf(sum + 1.f, 1.f));
            rnz[b * N_ + i] = (sum > 0.f) ? 1.f : 0.f;
        }
    }
}

__global__ void alpha2d_kernel(const float* __restrict__ Ac, const float* __restrict__ d2,
                               const float* __restrict__ rz2, const float* __restrict__ v,
                               const int* __restrict__ cnt, float* __restrict__ alp) {
    __shared__ float dv[N_];
    __shared__ float red[256];
    int b = blockIdx.y, n = blockIdx.x, tid = threadIdx.x;
    int cnp = (cnt[b] + 127) & ~127;
    if (n >= cnp) { if (tid == 0) alp[b * N_ + n] = 0.5f; return; }
    for (int m = tid; m < cnp; m += 256) dv[m] = d2[b * N_ + m] * v[b * N_ + m];
    __syncthreads();
    const float4* row4 = (const float4*)(Ac + ((size_t)(b * N_ + n)) * N_);
    const float4* dv4 = (const float4*)dv;
    float s = 0.f;
    for (int m = tid; m < (cnp >> 2); m += 256) {
        float4 a = row4[m], w = dv4[m];
        s += a.x * w.x + a.y * w.y + a.z * w.z + a.w * w.w;
    }
    red[tid] = s; __syncthreads();
    for (int o = 128; o > 0; o >>= 1) { if (tid < o) red[tid] += red[tid + o]; __syncthreads(); }
    if (tid == 0) {
        float r = rz2[b * N_ + n] * d2[b * N_ + n] * (red[0] + dv[n]);
        alp[b * N_ + n] = 1.f / (1.f + expf(-r * r));
    }
}

// sinv[n] = f / max(f * sum_m (Ac[n][m]+delta)*dca[m], 1e-12), f = rz2*d2
__global__ void s2inv_kernel(const float* __restrict__ Ac, const float* __restrict__ d2,
                             const float* __restrict__ rz2, const float* __restrict__ ca,
                             const int* __restrict__ cnt, float* __restrict__ sinv) {
    __shared__ float dca[N_];
    __shared__ float red[256];
    int b = blockIdx.y, n = blockIdx.x, tid = threadIdx.x;
    int cnp = (cnt[b] + 127) & ~127;
    if (n >= cnp) return;
    for (int m = tid; m < cnp; m += 256) dca[m] = d2[b * N_ + m] * ca[b * N_ + m];
    __syncthreads();
    const float4* row4 = (const float4*)(Ac + ((size_t)(b * N_ + n)) * N_);
    const float4* dca4 = (const float4*)dca;
    float s = 0.f;
    for (int m = tid; m < (cnp >> 2); m += 256) {
        float4 a = row4[m], w = dca4[m];
        s += a.x * w.x + a.y * w.y + a.z * w.z + a.w * w.w;
    }
    red[tid] = s; __syncthreads();
    for (int o = 128; o > 0; o >>= 1) { if (tid < o) red[tid] += red[tid + o]; __syncthreads(); }
    if (tid == 0) {
        float sum = red[0] + dca[n];
        float f = rz2[b * N_ + n] * d2[b * N_ + n];
        sinv[b * N_ + n] = f / fmaxf(f * sum, 1e-12f);
    }
}

// ST[m][n] = S2[n][m] = (Ac[m][n] + (m==n)) * dca[m] * sinv[n]  (Ac symmetric)
__global__ void buildST_kernel(const float* __restrict__ Ac, const float* __restrict__ d2,
                               const float* __restrict__ ca, const float* __restrict__ sinv,
                               const int* __restrict__ cnt,
                               __nv_bfloat16* __restrict__ SThi, __nv_bfloat16* __restrict__ STlo) {
    __shared__ float siv[N_];
    int b = blockIdx.y, m = blockIdx.x, tid = threadIdx.x;
    int cnp = (cnt[b] + 127) & ~127;
    if (m >= cnp) return;
    for (int n = tid; n < cnp; n += 256) siv[n] = sinv[b * N_ + n];
    __syncthreads();
    float dcam = d2[b * N_ + m] * ca[b * N_ + m];
    size_t ro = ((size_t)(b * N_ + m)) * N_;
    const float4* row4 = (const float4*)(Ac + ro);
    __nv_bfloat162* ohi = (__nv_bfloat162*)(SThi + ro);
    __nv_bfloat162* olo = (__nv_bfloat162*)(STlo + ro);
    for (int q = tid; q < (cnp >> 2); q += 256) {
        float4 a = row4[q];
        int n = q << 2;
        float v0 = (a.x + ((n    ) == m ? 1.f : 0.f)) * dcam * siv[n];
        float v1 = (a.y + ((n + 1) == m ? 1.f : 0.f)) * dcam * siv[n + 1];
        float v2 = (a.z + ((n + 2) == m ? 1.f : 0.f)) * dcam * siv[n + 2];
        float v3 = (a.w + ((n + 3) == m ? 1.f : 0.f)) * dcam * siv[n + 3];
        __nv_bfloat162 h01 = split_hi2(v0, v1), h23 = split_hi2(v2, v3);
        ohi[q * 2] = h01; ohi[q * 2 + 1] = h23;
        olo[q * 2] = split_lo2(v0, v1, h01); olo[q * 2 + 1] = split_lo2(v2, v3, h23);
    }
}

// w[k] = d2[k] * (sum_m A3[k][m]*dv[m] - A3[k][k]*dv[k] + dv[k]), dv = d2*maskc
__global__ void wvec_kernel(const float* __restrict__ A3, const float* __restrict__ d2,
                            const float* __restrict__ maskc, const int* __restrict__ cnt,
                            float* __restrict__ wv) {
    __shared__ float dv[N_];
    __shared__ float red[256];
    int b = blockIdx.y, k = blockIdx.x, tid = threadIdx.x;
    int cnp = (cnt[b] + 127) & ~127;
    if (k >= cnp) return;
    for (int m = tid; m < cnp; m += 256) dv[m] = d2[b * N_ + m] * maskc[b * N_ + m];
    __syncthreads();
    const float* row = A3 + ((size_t)(b * N_ + k)) * N_;
    const float4* row4 = (const float4*)row;
    const float4* dv4 = (const float4*)dv;
    float s = 0.f;
    for (int m = tid; m < (cnp >> 2); m += 256) {
        float4 a = row4[m], w = dv4[m];
        s += a.x * w.x + a.y * w.y + a.z * w.z + a.w * w.w;
    }
    red[tid] = s; __syncthreads();
    for (int o = 128; o > 0; o >>= 1) { if (tid < o) red[tid] += red[tid + o]; __syncthreads(); }
    if (tid == 0)
        wv[b * N_ + k] = d2[b * N_ + k] * (red[0] - row[k] * dv[k] + dv[k]);
}

// p2 partial: sum_k wv[k]*xW[k,:] over k-chunk q
__global__ void out2_part_kernel(const float* __restrict__ xW, const float* __restrict__ wv,
                                 const int* __restrict__ cnt, float* __restrict__ p2) {
    int b = blockIdx.y, q = blockIdx.x, c = threadIdx.x;   // 256 threads
    int cnp = (cnt[b] + 127) & ~127;
    int lo = q * 512, hi = (q + 1) * 512; if (hi > cnp) hi = cnp;
    float s = 0.f;
    for (int k = lo; k < hi; k++)
        s = fmaf(wv[b * N_ + k], xW[((size_t)(b * N_ + k)) * F_ + c], s);
    p2[(b * 4 + q) * F_ + c] = s;
}

// generic transposed split: out[j][i] = in[i][j]; in R x C (ld), out stride N_
__global__ void split_tr_kernel(const float* __restrict__ in, __nv_bfloat16* __restrict__ hi,
                                __nv_bfloat16* __restrict__ lo, const int* __restrict__ cnt,
                                int Rfixed, int Cfixed, int ld, long sIn) {
    __shared__ float tile[32][33];
    int b = blockIdx.z;
    int cnp = (cnt[b] + 127) & ~127;
    int R = Rfixed ? Rfixed : cnp;
    int C = Cfixed ? Cfixed : cnp;
    int i0 = blockIdx.y * 32, j0 = blockIdx.x * 32;
    if (i0 >= R || j0 >= C) return;
    const float* inb = in + (size_t)b * sIn;
    size_t boff = (size_t)b * N_ * N_;
    int tx = threadIdx.x, ty = threadIdx.y;   // (32, 8)
    #pragma unroll
    for (int r = 0; r < 4; r++) {
        int i = ty + r * 8;
        tile[i][tx] = inb[(size_t)(i0 + i) * ld + j0 + tx];
    }
    __syncthreads();
    #pragma unroll
    for (int r = 0; r < 4; r++) {
        int j = ty + r * 8;
        float v = tile[tx][j];
        __nv_bfloat16 h = __float2bfloat16(v);
        size_t o = boff + (size_t)(j0 + j) * N_ + i0 + tx;
        hi[o] = h;
        lo[o] = __float2bfloat16(v - __bfloat162float(h));
    }
}

// ---------------- bf16-split tensor GEMM, single-K-pass ----------------------
// C = A @ B: hi*hi + hi*lo + lo*hi accumulated per k-tile (fp32 accum).
// A row-major [m][k] stride N_; BT [n][k] stride N_.
// M = K = cnp; N = NpFixed or cnp.
// EPI: 0 none, 4 row-major bf16 hi/lo split out,
//      5 floor-quant + SYMMETRIC output (upper blocks only, mirror write).
#define TSZ (128 * 40)
template<int EPI>
__global__ void __launch_bounds__(256, 2) gemm_bf16_kernel(
    const __nv_bfloat16* __restrict__ Ahi, const __nv_bfloat16* __restrict__ Alo,
    const __nv_bfloat16* __restrict__ BThi, const __nv_bfloat16* __restrict__ BTlo,
    float* __restrict__ C, const int* __restrict__ cnt,
    int NpFixed, int ldc, long sC,
    __nv_bfloat16* __restrict__ Chi, __nv_bfloat16* __restrict__ Clo) {
    extern __shared__ __nv_bfloat16 sm[];   // [2 stages][4 tiles][128*40]
    const int b = blockIdx.z;
    const int cnp = (cnt[b] + 127) & ~127;
    const int Np = NpFixed ? NpFixed : cnp;
    const int m0 = blockIdx.y * 128, n0 = blockIdx.x * 128;
    if (m0 >= cnp || n0 >= Np) return;
    if (EPI == 5 && m0 > n0) return;   // symmetric: upper-triangle blocks only
    const size_t boff = (size_t)b * N_ * N_;
    const int tid = threadIdx.x;
    const int wid = tid >> 5, lane = tid & 31;
    const int wm = wid >> 1, wn = wid & 1;     // warps 4 x 2 -> warp tile 32 x 64
    const int g = lane >> 2, t4 = lane & 3;
    const int a_row = lane & 15;
    const int a_k   = (lane & 16) ? 8 : 0;
    const int b_row = (lane & 7) + ((lane & 16) ? 8 : 0);
    const int b_k   = (lane & 8) ? 8 : 0;
    const int KT = cnp >> 5;

    float acc[2][8][4];
    #pragma unroll
    for (int fm = 0; fm < 2; fm++)
        #pragma unroll
        for (int fn = 0; fn < 8; fn++)
            #pragma unroll
            for (int r = 0; r < 4; r++) acc[fm][fn][r] = 0.f;

    const __nv_bfloat16* gsrc[4];
    auto stage = [&](int kt, int buf) {
        gsrc[0] = Ahi  + boff + (size_t)m0 * N_ + kt * 32;
        gsrc[1] = Alo  + boff + (size_t)m0 * N_ + kt * 32;
        gsrc[2] = BThi + boff + (size_t)n0 * N_ + kt * 32;
        gsrc[3] = BTlo + boff + (size_t)n0 * N_ + kt * 32;
        int row = tid >> 2, cc = (tid & 3) * 8;
        #pragma unroll
        for (int w = 0; w < 4; w++) {
            __nv_bfloat16* dst = sm + (size_t)(buf * 4 + w) * TSZ;
            CP16(dst + row * 40 + cc,        gsrc[w] + (size_t)row * N_ + cc);
            CP16(dst + (row + 64) * 40 + cc, gsrc[w] + (size_t)(row + 64) * N_ + cc);
        }
    };

    stage(0, 0);
    CP_COMMIT();

    for (int t = 0; t < KT; t++) {
        CP_WAIT0();
        __syncthreads();
        if (t + 1 < KT) { stage(t + 1, (t + 1) & 1); CP_COMMIT(); }
        const __nv_bfloat16* Ah = sm + (size_t)((t & 1) * 4 + 0) * TSZ;
        const __nv_bfloat16* Al = sm + (size_t)((t & 1) * 4 + 1) * TSZ;
        const __nv_bfloat16* Bh = sm + (size_t)((t & 1) * 4 + 2) * TSZ;
        const __nv_bfloat16* Bl = sm + (size_t)((t & 1) * 4 + 3) * TSZ;
        #pragma unroll
        for (int kh = 0; kh < 32; kh += 16) {
            uint32_t ah[2][4], al[2][4];
            #pragma unroll
            for (int fm = 0; fm < 2; fm++) {
                int ao = (wm * 32 + fm * 16 + a_row) * 40 + kh + a_k;
                ldsm4(ah[fm], Ah + ao);
                ldsm4(al[fm], Al + ao);
            }
            #pragma unroll
            for (int fn2 = 0; fn2 < 4; fn2++) {
                int bo = (wn * 64 + fn2 * 16 + b_row) * 40 + kh + b_k;
                uint32_t bh[4], bl[4];
                ldsm4(bh, Bh + bo);
                ldsm4(bl, Bl + bo);
                #pragma unroll
                for (int fm = 0; fm < 2; fm++) {
                    mma_bf16(acc[fm][2 * fn2],     ah[fm], bh[0], bh[1]);
                    mma_bf16(acc[fm][2 * fn2],     ah[fm], bl[0], bl[1]);
                    mma_bf16(acc[fm][2 * fn2],     al[fm], bh[0], bh[1]);
                    mma_bf16(acc[fm][2 * fn2 + 1], ah[fm], bh[2], bh[3]);
                    mma_bf16(acc[fm][2 * fn2 + 1], ah[fm], bl[2], bl[3]);
                    mma_bf16(acc[fm][2 * fn2 + 1], al[fm], bh[2], bh[3]);
                }
            }
        }
        __syncthreads();
    }

    float* smf = (float*)sm;   // EPI==5: 128x133 fp32 transpose staging (68KB <= 80KB)
    #pragma unroll
    for (int fm = 0; fm < 2; fm++) {
        int mr = m0 + wm * 32 + fm * 16 + g;
        #pragma unroll
        for (int fn = 0; fn < 8; fn++) {
            int n = n0 + wn * 64 + fn * 8 + t4 * 2;
            float v0 = acc[fm][fn][0], v1 = acc[fm][fn][1];
            float v2 = acc[fm][fn][2], v3 = acc[fm][fn][3];
            if (EPI == 5) {
                v0 = floorf(v0 * 10000.f) / 10000.f;
                v1 = floorf(v1 * 10000.f) / 10000.f;
                v2 = floorf(v2 * 10000.f) / 10000.f;
                v3 = floorf(v3 * 10000.f) / 10000.f;
                int r = wm * 32 + fm * 16 + g;       // local row
                int c = wn * 64 + fn * 8 + t4 * 2;   // local col
                smf[(c    ) * 133 + r]     = v0;
                smf[(c + 1) * 133 + r]     = v1;
                smf[(c    ) * 133 + r + 8] = v2;
                smf[(c + 1) * 133 + r + 8] = v3;
            }
            if (EPI == 4) {
                size_t o0 = (size_t)b * sC + (size_t)mr * ldc + n;
                size_t o1 = o0 + 8 * (size_t)ldc;
                __nv_bfloat162 h0 = split_hi2(v0, v1), h1 = split_hi2(v2, v3);
                *(__nv_bfloat162*)(Chi + o0) = h0;
                *(__nv_bfloat162*)(Chi + o1) = h1;
                *(__nv_bfloat162*)(Clo + o0) = split_lo2(v0, v1, h0);
                *(__nv_bfloat162*)(Clo + o1) = split_lo2(v2, v3, h1);
            } else {
                float* p0 = C + (size_t)b * sC + (size_t)mr * ldc + n;
                p0[0] = v0; p0[1] = v1;
                float* p1 = p0 + 8 * (size_t)ldc;
                p1[0] = v2; p1[1] = v3;
            }
        }
    }
    if (EPI == 5 && m0 != n0) {
        __syncthreads();
        float* Cb = C + (size_t)b * sC;
        for (int e = tid; e < 128 * 128; e += 256) {
            int r2 = e >> 7, c2 = e & 127;           // mirror row r2 = orig col
            Cb[(size_t)(n0 + r2) * ldc + m0 + c2] = smf[r2 * 133 + c2];
        }
    }
}

// ---------------- double-buffered cp.async SIMT GEMM (small GEMMs) -----------
template<int TRANSA, int EPI>
__global__ void __launch_bounds__(256, 2) gemm2_kernel(
    const float* __restrict__ A, const float* __restrict__ Bm, float* __restrict__ C,
    int M, int Kd, int Nc, int lda, int ldb, int ldc,
    long sA, long sB, long sC,
    const float* __restrict__ bias, const float* __restrict__ mask,
    const int* __restrict__ cnt, int dynM, int dynK, int dynN) {
    __shared__ float As[2][128 * 16];
    __shared__ float Bs[2][16 * 128];
    const int b = blockIdx.z;
    int Mp = M, Kp = Kd, Np = Nc;
    if (cnt) {
        int p = (cnt[b] + 127) & ~127;
        if (dynM) Mp = p; if (dynK) Kp = p; if (dynN) Np = p;
    }
    const int n0 = blockIdx.x * 128, m0 = blockIdx.y * 128;
    if (m0 >= Mp || n0 >= Np) return;
    A  += (size_t)b * sA;
    Bm += (size_t)b * sB;
    C  += (size_t)b * sC;
    const int tid = threadIdx.x, tx = tid & 15, ty = tid >> 4;
    float acc[8][8];
    #pragma unroll
    for (int i = 0; i < 8; i++)
        #pragma unroll
        for (int j = 0; j < 8; j++) acc[i][j] = 0.f;

    const int Kt = Kp >> 4;

    auto load_tiles = [&](int k0, int buf) {
        if (!TRANSA) {
            #pragma unroll
            for (int q = 0; q < 2; q++) {
                int c = tid + q * 256;
                int row = c >> 2, col4 = (c & 3) * 4;
                const float* src = A + (size_t)(m0 + row) * lda + k0 + col4;
                CP16(&As[buf][row * 16 + col4], src);
            }
        } else {
            #pragma unroll
            for (int q = 0; q < 2; q++) {
                int c = tid + q * 256;
                int row = c >> 5, col4 = (c & 31) * 4;
                const float* src = A + (size_t)(k0 + row) * lda + m0 + col4;
                CP16(&As[buf][row * 128 + col4], src);
            }
        }
        #pragma unroll
        for (int q = 0; q < 2; q++) {
            int c = tid + q * 256;
            int row = c >> 5, col4 = (c & 31) * 4;
            const float* src = Bm + (size_t)(k0 + row) * ldb + n0 + col4;
            CP16(&Bs[buf][row * 128 + col4], src);
        }
    };

    load_tiles(0, 0);
    CP_COMMIT();

    for (int t = 0; t < Kt; t++) {
        CP_WAIT0();
        __syncthreads();
        if (t + 1 < Kt) { load_tiles((t + 1) << 4, (t + 1) & 1); CP_COMMIT(); }
        const int buf = t & 1;
        #pragma unroll
        for (int k = 0; k < 16; k++) {
            float a[8], bv[8];
            if (!TRANSA) {
                #pragma unroll
                for (int i = 0; i < 8; i++) a[i] = As[buf][(ty * 8 + i) * 16 + k];
            } else {
                *(float4*)(a)     = *(const float4*)&As[buf][k * 128 + ty * 8];
                *(float4*)(a + 4) = *(const float4*)&As[buf][k * 128 + ty * 8 + 4];
            }
            *(float4*)(bv)     = *(const float4*)&Bs[buf][k * 128 + tx * 8];
            *(float4*)(bv + 4) = *(const float4*)&Bs[buf][k * 128 + tx * 8 + 4];
            #pragma unroll
            for (int i = 0; i < 8; i++)
                #pragma unroll
                for (int j = 0; j < 8; j++) acc[i][j] = fmaf(a[i], bv[j], acc[i][j]);
        }
        __syncthreads();
    }
    #pragma unroll
    for (int i = 0; i < 8; i++) {
        int m = m0 + ty * 8 + i;
        float mk = (EPI == 2) ? mask[(size_t)b * N_ + m] : 1.f;
        #pragma unroll
        for (int j = 0; j < 8; j++) {
            int n = n0 + tx * 8 + j;
            float v = acc[i][j];
            if (EPI == 2)      { v = (v + bias[n]) * mk; }
            else if (EPI == 3) { v = floorf(v * 10000.f) / 10000.f; }
            C[(size_t)m * ldc + n] = v;
        }
    }
}

// ---------------- output means (two-stage, deterministic) --------------------
__global__ void mean1_part_kernel(const float* __restrict__ x1, float* __restrict__ p1) {
    int b = blockIdx.y, q = blockIdx.x, c = threadIdx.x;   // 128 threads
    float s = 0.f;
    for (int n = q * 512; n < (q + 1) * 512; n++) s += x1[((size_t)(b * N_ + n)) * H_ + c];
    p1[(b * 4 + q) * H_ + c] = s;
}

__global__ void mean_combine_kernel(const float* __restrict__ p1, const float* __restrict__ p2,
                                    const float* __restrict__ b2, const float* __restrict__ smask,
                                    float* __restrict__ out) {
    int b = blockIdx.x, c = threadIdx.x;   // 384 threads
    if (c < H_) {
        float s = 0.f;
        for (int q = 0; q < 4; q++) s += p1[(b * 4 + q) * H_ + c];
        out[b * OUTC + c] = s / (float)N_;
    } else {
        int cc = c - H_;
        float s = b2[cc] * smask[b];
        for (int q = 0; q < 4; q++) s += p2[(b * 4 + q) * F_ + cc];
        out[b * OUTC + c] = s / (float)N_;
    }
}

extern "C" void kernel_launch(void* const* d_in, const int* in_sizes, int n_in,
                              void* d_out, int out_size) {
    const float* x    = (const float*)d_in[0];
    const float* adj  = (const float*)d_in[1];
    const float* mask = (const float*)d_in[2];
    const float* W1   = (const float*)d_in[3];
    const float* b1   = (const float*)d_in[4];
    const float* Watt = (const float*)d_in[5];
    const float* batt = (const float*)d_in[6];
    const float* W2   = (const float*)d_in[7];
    const float* b2   = (const float*)d_in[8];
    float* out = (float*)d_out;

    float *pT,*pAc,*pA3,*pxW,*px1,*pxc,*px3;
    float *pv,*palp,*pca,*psrec,*pd0,*pd1,*prnz,*pd2,*prz2,*pcut,*pmaskc,*pmrest,*pp1,*pp2;
    __nv_bfloat16 *pAhi,*pAlo,*pSThi,*pSTlo,*pTThi,*pTTlo;
    int *plst,*pdeg,*phasd,*pidx,*pginv,*pcnt;
    cudaGetSymbolAddress((void**)&pT,   g_T);
    cudaGetSymbolAddress((void**)&pAc,  g_Ac);
    cudaGetSymbolAddress((void**)&pA3,  g_A3);
    cudaGetSymbolAddress((void**)&pAhi, g_Ahi);
    cudaGetSymbolAddress((void**)&pAlo, g_Alo);
    cudaGetSymbolAddress((void**)&pSThi,g_SThi);
    cudaGetSymbolAddress((void**)&pSTlo,g_STlo);
    cudaGetSymbolAddress((void**)&pTThi,g_TThi);
    cudaGetSymbolAddress((void**)&pTTlo,g_TTlo);
    cudaGetSymbolAddress((void**)&pxW,  g_xW);
    cudaGetSymbolAddress((void**)&px1,  g_x1);
    cudaGetSymbolAddress((void**)&pxc,  g_xc);
    cudaGetSymbolAddress((void**)&px3,  g_x3);
    cudaGetSymbolAddress((void**)&pv,   g_v);
    cudaGetSymbolAddress((void**)&palp, g_alp);
    cudaGetSymbolAddress((void**)&pca,  g_ca);
    cudaGetSymbolAddress((void**)&psrec,g_srec);
    cudaGetSymbolAddress((void**)&pd0,  g_d0);
    cudaGetSymbolAddress((void**)&pd1,  g_d1);
    cudaGetSymbolAddress((void**)&prnz, g_rnz);
    cudaGetSymbolAddress((void**)&pd2,  g_d2);
    cudaGetSymbolAddress((void**)&prz2, g_rz2);
    cudaGetSymbolAddress((void**)&pcut, g_cut);
    cudaGetSymbolAddress((void**)&pmaskc, g_maskc);
    cudaGetSymbolAddress((void**)&pmrest, g_mrest);
    cudaGetSymbolAddress((void**)&pp1,  g_p1);
    cudaGetSymbolAddress((void**)&pp2,  g_p2);
    cudaGetSymbolAddress((void**)&plst, g_lst);
    cudaGetSymbolAddress((void**)&pdeg, g_deg);
    cudaGetSymbolAddress((void**)&phasd,g_hasd);
    cudaGetSymbolAddress((void**)&pidx, g_idx);
    cudaGetSymbolAddress((void**)&pginv,g_ginv);
    cudaGetSymbolAddress((void**)&pcnt, g_cnt);

    const int BF16_SMEM = 2 * 4 * TSZ * 2;   // 81920 bytes
    cudaFuncSetAttribute(gemm_bf16_kernel<0>, cudaFuncAttributeMaxDynamicSharedMemorySize, BF16_SMEM);
    cudaFuncSetAttribute(gemm_bf16_kernel<4>, cudaFuncAttributeMaxDynamicSharedMemorySize, BF16_SMEM);
    cudaFuncSetAttribute(gemm_bf16_kernel<5>, cudaFuncAttributeMaxDynamicSharedMemorySize, BF16_SMEM);

    // ---- CSR + degree stats (single adj scan) ----
    csr_build_kernel<<<dim3(N_, B_), 256>>>(adj, plst, pdeg, phasd, pd0, pd1, prnz);

    // ---- GCN layer 1 (sparse aggregation) ----
    gemm2_kernel<0,0><<<dim3(1,16,B_),256>>>(x, W1, pxW, N_, F_, H_, F_, H_, H_,
        (long)N_*F_, 0, (long)N_*H_, nullptr, nullptr, nullptr, 0,0,0);
    gcn1_kernel<<<dim3(N_, B_), 128>>>(plst, pdeg, pd0, pxW, b1, mask, px1);

    // ---- coarsen layer 1 (sparse, no dense S anywhere) ----
    gemv_watt_kernel<<<(B_*N_)/8, 256>>>(px1, Watt, batt, pv);
    alpha1_kernel<<<dim3(N_/8, B_), 256>>>(plst, pdeg, pd1, prnz, pv, palp);
    topk_cut_kernel<<<B_, 1024>>>(palp, pcut);
    ca_kernel<<<(B_*N_)/256, 256>>>(palp, pcut, pca);
    compact_kernel<<<B_, 1024>>>(pca, pidx, pginv, pcnt);
    compact_mask_kernel<<<B_, 256>>>(mask, pidx, pcnt, pmaskc, pmrest);
    srec_kernel<<<dim3(N_/8, B_), 256>>>(plst, pdeg, pd1, prnz, pca, psrec);
    xupd_kernel<<<dim3(N_, B_), 128>>>(plst, pdeg, phasd, pd1, pca, psrec, pidx, pcnt, px1, pxc);
    adjS_sparse_kernel<<<dim3(N_/4, B_), 128>>>(plst, pdeg, phasd, pd1, pca, psrec,
                                                pginv, pcnt, pT);
    // Ac + fused bf16 split + fused d2/rz2 row stats
    STT_kernel<<<dim3(N_, B_), 256>>>(plst, pdeg, phasd, pd1, pca, psrec, pidx, pcnt,
                                      pT, pAc, pAhi, pAlo, pd2, prz2);

    // ---- coarsen layer 2 (symmetric Ac: direct row-major ST build) ----
    gemv_watt_kernel<<<(B_*N_)/8, 256>>>(pxc, Watt, batt, pv);
    alpha2d_kernel<<<dim3(N_, B_), 256>>>(pAc, pd2, prz2, pv, pcnt, palp);
    topk_cut_kernel<<<B_, 1024>>>(palp, pcut);
    ca_kernel<<<(B_*N_)/256, 256>>>(palp, pcut, pca);
    s2inv_kernel<<<dim3(N_, B_), 256>>>(pAc, pd2, prz2, pca, pcnt, psrec);
    buildST_kernel<<<dim3(N_, B_), 256>>>(pAc, pd2, pca, psrec, pcnt, pSThi, pSTlo);
    // xc^T split into TT (consumed by x3 GEMM before TT is overwritten)
    split_tr_kernel<<<dim3(4, 64, B_), dim3(32, 8)>>>(pxc, pTThi, pTTlo, pcnt,
        0, H_, H_, (long)N_*H_);
    // x3 = S2c^T @ xc (tensor)
    gemm_bf16_kernel<0><<<dim3(1,16,B_),256,BF16_SMEM>>>(pSThi, pSTlo, pTThi, pTTlo,
        px3, pcnt, H_, H_, (long)N_*H_, nullptr, nullptr);
    // T2^T = S2c^T @ Ac^T: A=ST, BT=Ac row-major; epilogue writes bf16 split -> TT
    gemm_bf16_kernel<4><<<dim3(16,16,B_),256,BF16_SMEM>>>(pSThi, pSTlo, pAhi, pAlo,
        nullptr, pcnt, 0, N_, (long)N_*N_, pTThi, pTTlo);
    // A3 = S2c^T @ T2 (symmetric): upper blocks only, floor-quant, mirror write
    gemm_bf16_kernel<5><<<dim3(16,16,B_),256,BF16_SMEM>>>(pSThi, pSTlo, pTThi, pTTlo,
        pA3, pcnt, 0, N_, (long)N_*N_, nullptr, nullptr);

    // ---- final GCN: only the column mean is needed ----
    // mean(x2) = (w^T @ (x3 @ W2) + b2 * sum(mask)) / N,  w = NA3^T maskc (exact fp32)
    rowstats_c_kernel<<<dim3(N_, B_), 256>>>(pA3, pcnt, pd2, nullptr, 0);
    gemm2_kernel<0,0><<<dim3(2,16,B_),256>>>(px3, W2, pxW, N_, H_, F_, H_, F_, F_,
        (long)N_*H_, 0, (long)N_*F_, nullptr, nullptr, pcnt, 1,0,0);
    wvec_kernel<<<dim3(N_, B_), 256>>>(pA3, pd2, pmaskc, pcnt, pv);
    out2_part_kernel<<<dim3(4, B_), 256>>>(pxW, pv, pcnt, pp2);

    // ---- concat means ----
    mean1_part_kernel<<<dim3(4, B_), 128>>>(px1, pp1);
    mean_combine_kernel<<<B_, 384>>>(pp1, pp2, b2, pmrest, out);
}

// round 10
// speedup vs baseline: 7.5462x; 1.0769x over previous
#include <cuda_runtime.h>
#include <cuda_bf16.h>
#include <math.h>
#include <stdint.h>

#define B_ 8
#define N_ 2048
#define F_ 256
#define H_ 128
#define K_ 1025
#define OUTC 384
#define CAP 256

// ---------------- scratch (device globals; no allocation allowed) ----------
__device__ float g_T [(size_t)B_*N_*N_];   // Tc (layer1, stride cnp)
__device__ float g_Ac[(size_t)B_*N_*N_];   // compacted A2 (stride N_)
__device__ float g_A3[(size_t)B_*N_*N_];   // compacted A3 (stride N_)
__device__ __nv_bfloat16 g_Ahi[(size_t)B_*N_*N_], g_Alo[(size_t)B_*N_*N_];
__device__ __nv_bfloat16 g_SThi[(size_t)B_*N_*N_], g_STlo[(size_t)B_*N_*N_];
__device__ __nv_bfloat16 g_TThi[(size_t)B_*N_*N_], g_TTlo[(size_t)B_*N_*N_];
__device__ __nv_bfloat16 g_xTh[B_*H_*N_], g_xTl[B_*H_*N_];   // xc^T split
__device__ float g_xW [B_*N_*F_];
__device__ float g_x1 [B_*N_*H_];
__device__ float g_xc [B_*N_*H_];
__device__ float g_x3 [B_*N_*H_];
__device__ int   g_lst[(size_t)B_*N_*CAP];
__device__ int   g_deg[B_*N_];
__device__ int   g_hasd[B_*N_];
__device__ float g_d0[B_*N_], g_d1[B_*N_], g_rnz[B_*N_];
__device__ float g_d2[B_*N_], g_rz2[B_*N_];
__device__ float g_v[B_*N_], g_alp[B_*N_], g_ca[B_*N_], g_srec[B_*N_];
__device__ float g_cut[B_];
__device__ float g_maskc[B_*N_], g_mrest[B_];
__device__ int   g_idx[B_*N_], g_ginv[B_*N_], g_cnt[B_];
__device__ float g_p1[B_*4*H_], g_p2[B_*4*F_];

// ---------------- async-copy / mma helpers -----------------------------------
#define CP16(dst, src) { \
    unsigned _a = (unsigned)__cvta_generic_to_shared(dst); \
    asm volatile("cp.async.cg.shared.global [%0], [%1], 16;\n" :: "r"(_a), "l"(src)); }
#define CP_COMMIT() asm volatile("cp.async.commit_group;\n")
#define CP_WAIT0()  asm volatile("cp.async.wait_group 0;\n")

__device__ __forceinline__ void mma_bf16(float* c, const uint32_t* a, uint32_t b0, uint32_t b1) {
    asm volatile("mma.sync.aligned.m16n8k16.row.col.f32.bf16.bf16.f32 "
        "{%0,%1,%2,%3}, {%4,%5,%6,%7}, {%8,%9}, {%0,%1,%2,%3};"
        : "+f"(c[0]), "+f"(c[1]), "+f"(c[2]), "+f"(c[3])
        : "r"(a[0]), "r"(a[1]), "r"(a[2]), "r"(a[3]), "r"(b0), "r"(b1));
}
__device__ __forceinline__ void ldsm4(uint32_t* r, const void* p) {
    uint32_t a = (uint32_t)__cvta_generic_to_shared(p);
    asm volatile("ldmatrix.sync.aligned.m8n8.x4.shared.b16 {%0,%1,%2,%3}, [%4];"
        : "=r"(r[0]), "=r"(r[1]), "=r"(r[2]), "=r"(r[3]) : "r"(a));
}
__device__ __forceinline__ __nv_bfloat162 split_hi2(float v0, float v1) {
    __nv_bfloat162 h; h.x = __float2bfloat16(v0); h.y = __float2bfloat16(v1); return h;
}
__device__ __forceinline__ __nv_bfloat162 split_lo2(float v0, float v1, __nv_bfloat162 h) {
    __nv_bfloat162 l;
    l.x = __float2bfloat16(v0 - __bfloat162float(h.x));
    l.y = __float2bfloat16(v1 - __bfloat162float(h.y));
    return l;
}

// ---------------- CSR build + degree stats (one adj scan, float4) -----------
__global__ void csr_build_kernel(const float* __restrict__ adj, int* __restrict__ lst,
                                 int* __restrict__ deg, int* __restrict__ hasd,
                                 float* __restrict__ d0, float* __restrict__ d1,
                                 float* __restrict__ rnz) {
    __shared__ int sc[256];
    __shared__ int hd;
    int b = blockIdx.y, i = blockIdx.x, tid = threadIdx.x;
    const float4* arow4 = (const float4*)(adj + ((size_t)(b * N_ + i)) * N_);
    if (tid == 0) hd = 0;
    __syncthreads();
    float vals[8];
    *(float4*)(vals)     = arow4[tid * 2];
    *(float4*)(vals + 4) = arow4[tid * 2 + 1];
    int f[8];
    int c = 0, hloc = 0;
    #pragma unroll
    for (int e = 0; e < 8; e++) {
        int j = tid * 8 + e;
        f[e] = (vals[e] != 0.f) ? 1 : 0;
        c += f[e];
        if (f[e] && j == i) hloc = 1;
    }
    if (hloc) hd = 1;
    sc[tid] = c; __syncthreads();
    for (int o = 1; o < 256; o <<= 1) {
        int v = (tid >= o) ? sc[tid - o] : 0; __syncthreads();
        sc[tid] += v; __syncthreads();
    }
    int base = sc[tid] - c;
    int* l = lst + ((size_t)(b * N_ + i)) * CAP;
    #pragma unroll
    for (int e = 0; e < 8; e++) {
        if (f[e]) { if (base < CAP) l[base] = tid * 8 + e; base++; }
    }
    __syncthreads();
    if (tid == 0) {
        int total = sc[255];
        deg[b * N_ + i] = (total > CAP) ? CAP : total;
        hasd[b * N_ + i] = hd;
        d0[b * N_ + i] = rsqrtf(fmaxf((float)(total - hd) + 1.f, 1.f));
        d1[b * N_ + i] = rsqrtf((float)total + 1.f);
        rnz[b * N_ + i] = (total > 0) ? 1.f : 0.f;
    }
}

// ---------------- GCN layer 1 sparse aggregation -----------------------------
__global__ void gcn1_kernel(const int* __restrict__ lst, const int* __restrict__ deg,
                            const float* __restrict__ d0, const float* __restrict__ xW,
                            const float* __restrict__ b1, const float* __restrict__ mask,
                            float* __restrict__ x1) {
    int b = blockIdx.y, i = blockIdx.x, c = threadIdx.x;   // 128 threads
    int dg = deg[b * N_ + i];
    const int* l = lst + ((size_t)(b * N_ + i)) * CAP;
    float di = d0[b * N_ + i];
    float acc = di * di * xW[((size_t)(b * N_ + i)) * H_ + c];
    for (int p = 0; p < dg; p++) {
        int j = l[p];
        if (j != i) acc = fmaf(di * d0[b * N_ + j], xW[((size_t)(b * N_ + j)) * H_ + c], acc);
    }
    float vv = (acc + b1[c]) * mask[b * N_ + i];
    x1[((size_t)(b * N_ + i)) * H_ + c] = fmaxf(vv, 0.f);
}

// ---------------- v = x @ Watt + batt ----------------------------------------
__global__ void gemv_watt_kernel(const float* __restrict__ x, const float* __restrict__ Watt,
                                 const float* __restrict__ batt, float* __restrict__ v) {
    int w = blockIdx.x * 8 + (threadIdx.x >> 5);
    int lane = threadIdx.x & 31;
    if (w >= B_ * N_) return;
    const float* xr = x + (size_t)w * H_;
    float s = 0.f;
    #pragma unroll
    for (int c = lane; c < H_; c += 32) s += xr[c] * Watt[c];
    #pragma unroll
    for (int o = 16; o > 0; o >>= 1) s += __shfl_down_sync(0xffffffffu, s, o);
    if (lane == 0) v[w] = s + batt[0];
}

// ---------------- layer-1 alpha (sparse) --------------------------------------
__global__ void alpha1_kernel(const int* __restrict__ lst, const int* __restrict__ deg,
                              const float* __restrict__ d1, const float* __restrict__ rnz,
                              const float* __restrict__ v, float* __restrict__ alp) {
    int b = blockIdx.y;
    int i = blockIdx.x * 8 + (threadIdx.x >> 5);
    int lane = threadIdx.x & 31;
    const int* l = lst + ((size_t)(b * N_ + i)) * CAP;
    int dg = deg[b * N_ + i];
    float s = 0.f;
    for (int p = lane; p < dg; p += 32) { int j = l[p]; s += d1[b * N_ + j] * v[b * N_ + j]; }
    #pragma unroll
    for (int o = 16; o > 0; o >>= 1) s += __shfl_down_sync(0xffffffffu, s, o);
    if (lane == 0) {
        float di = d1[b * N_ + i];
        float r = rnz[b * N_ + i] * di * (s + di * v[b * N_ + i]);
        float z = r * r;
        alp[b * N_ + i] = 1.f / (1.f + expf(-z));
    }
}

// ---------------- exact K-th largest via bitonic sort ------------------------
__global__ void topk_cut_kernel(const float* __restrict__ alp, float* __restrict__ cut) {
    __shared__ float s[N_];
    int b = blockIdx.x, t = threadIdx.x;   // 1024 threads
    s[t] = alp[b * N_ + t];
    s[t + 1024] = alp[b * N_ + t + 1024];
    __syncthreads();
    for (int k = 2; k <= N_; k <<= 1) {
        for (int j = k >> 1; j > 0; j >>= 1) {
            for (int i = t; i < N_; i += 1024) {
                int ixj = i ^ j;
                if (ixj > i) {
                    float a = s[i], c = s[ixj];
                    if (((i & k) == 0) ? (a > c) : (a < c)) { s[i] = c; s[ixj] = a; }
                }
            }
            __syncthreads();
        }
    }
    if (t == 0) cut[b] = s[N_ - K_];
}

__global__ void ca_kernel(const float* __restrict__ alp, const float* __restrict__ cut,
                          float* __restrict__ ca) {
    int idx = blockIdx.x * 256 + threadIdx.x;
    int b = idx / N_;
    ca[idx] = fmaxf(alp[idx] + 1e-7f - cut[b], 0.f);
}

// ---------------- deterministic kept-set compaction (prefix scan) -----------
__global__ void compact_kernel(const float* __restrict__ ca, int* __restrict__ idx,
                               int* __restrict__ ginv, int* __restrict__ cnt) {
    __shared__ int sc[1024];
    int b = blockIdx.x, t = threadIdx.x;   // 1024 threads
    int f0 = (ca[b * N_ + 2 * t]     > 0.f) ? 1 : 0;
    int f1 = (ca[b * N_ + 2 * t + 1] > 0.f) ? 1 : 0;
    ginv[b * N_ + 2 * t] = -1;
    ginv[b * N_ + 2 * t + 1] = -1;
    int c = f0 + f1;
    sc[t] = c; __syncthreads();
    for (int o = 1; o < 1024; o <<= 1) {
        int v = (t >= o) ? sc[t - o] : 0; __syncthreads();
        sc[t] += v; __syncthreads();
    }
    int base = sc[t] - c;
    if (f0) { idx[b * N_ + base] = 2 * t;     ginv[b * N_ + 2 * t]     = base; base++; }
    if (f1) { idx[b * N_ + base] = 2 * t + 1; ginv[b * N_ + 2 * t + 1] = base; }
    if (t == 1023) cnt[b] = sc[1023];
}

// maskc = compacted mask; mrest = TOTAL mask sum (for final-layer bias fold)
__global__ void compact_mask_kernel(const float* __restrict__ mask, const int* __restrict__ idx,
                                    const int* __restrict__ cnt, float* __restrict__ maskc,
                                    float* __restrict__ mrest) {
    __shared__ float red[256];
    int b = blockIdx.x, t = threadIdx.x;
    int c = cnt[b];
    float local = 0.f;
    for (int i = t; i < N_; i += 256) {
        float mv = 0.f;
        if (i < c) mv = mask[b * N_ + idx[b * N_ + i]];
        maskc[b * N_ + i] = mv;
        local += mask[b * N_ + i];
    }
    red[t] = local; __syncthreads();
    for (int o = 128; o > 0; o >>= 1) { if (t < o) red[t] += red[t + o]; __syncthreads(); }
    if (t == 0) mrest[b] = red[0];
}

// ---------------- layer-1 S row normalizer -----------------------------------
__global__ void srec_kernel(const int* __restrict__ lst, const int* __restrict__ deg,
                            const float* __restrict__ d1, const float* __restrict__ rnz,
                            const float* __restrict__ ca, float* __restrict__ srec) {
    int b = blockIdx.y;
    int i = blockIdx.x * 8 + (threadIdx.x >> 5);
    int lane = threadIdx.x & 31;
    const int* l = lst + ((size_t)(b * N_ + i)) * CAP;
    int dg = deg[b * N_ + i];
    float s = 0.f;
    for (int p = lane; p < dg; p += 32) { int j = l[p]; s += d1[b * N_ + j] * ca[b * N_ + j]; }
    #pragma unroll
    for (int o = 16; o > 0; o >>= 1) s += __shfl_down_sync(0xffffffffu, s, o);
    if (lane == 0) {
        float di = d1[b * N_ + i];
        float raw = rnz[b * N_ + i] * di * (s + di * ca[b * N_ + i]);
        srec[b * N_ + i] = rnz[b * N_ + i] * di / fmaxf(raw, 1e-12f);
    }
}

// ---------------- xc[ic,:] = sum_n S[n, idx[ic]] * x1[n,:] -------------------
__global__ void xupd_kernel(const int* __restrict__ lst, const int* __restrict__ deg,
                            const int* __restrict__ hasd, const float* __restrict__ d1,
                            const float* __restrict__ ca, const float* __restrict__ srec,
                            const int* __restrict__ idx, const int* __restrict__ cnt,
                            const float* __restrict__ x1, float* __restrict__ xc) {
    int b = blockIdx.y, ic = blockIdx.x, c = threadIdx.x;   // 128 threads
    int cn = cnt[b], cnp = (cn + 127) & ~127;
    if (ic >= cnp) return;
    float* orow = xc + ((size_t)(b * N_ + ic)) * H_;
    if (ic >= cn) { orow[c] = 0.f; return; }
    int m = idx[b * N_ + ic];
    float dmcam = d1[b * N_ + m] * ca[b * N_ + m];
    int dg = deg[b * N_ + m];
    const int* l = lst + ((size_t)(b * N_ + m)) * CAP;
    float acc = 0.f;
    for (int p = 0; p < dg; p++) {
        int n = l[p];
        float coef = (n == m) ? 2.f : 1.f;
        float sv = srec[b * N_ + n] * dmcam * coef;
        acc = fmaf(sv, x1[((size_t)(b * N_ + n)) * H_ + c], acc);
    }
    if (!hasd[b * N_ + m])
        acc = fmaf(srec[b * N_ + m] * dmcam, x1[((size_t)(b * N_ + m)) * H_ + c], acc);
    orow[c] = acc;
}

// ---- Tc[i,:] = sum_{j in list_i} S_row_j, S rows expanded on the fly --------
__global__ void adjS_sparse_kernel(const int* __restrict__ lst, const int* __restrict__ deg,
                                   const int* __restrict__ hasd, const float* __restrict__ d1,
                                   const float* __restrict__ ca, const float* __restrict__ srec,
                                   const int* __restrict__ ginv, const int* __restrict__ cnt,
                                   float* __restrict__ Tc) {
    __shared__ float acc[4][N_];
    int b = blockIdx.y, tid = threadIdx.x;   // 128 threads = 4 warps
    int w = tid >> 5, lane = tid & 31;
    int i = blockIdx.x * 4 + w;
    int cnp = (cnt[b] + 127) & ~127;
    float* a = acc[w];
    float4* a4 = (float4*)a;
    float4 z4 = make_float4(0.f, 0.f, 0.f, 0.f);
    for (int jc = lane; jc < (cnp >> 2); jc += 32) a4[jc] = z4;
    __syncwarp();
    int dgi = deg[b * N_ + i];
    const int* li = lst + ((size_t)(b * N_ + i)) * CAP;
    const int* gv = ginv + b * N_;
    for (int p = 0; p < dgi; p++) {
        int j = li[p];
        int dgj = deg[b * N_ + j];
        const int* lj = lst + ((size_t)(b * N_ + j)) * CAP;
        float sr = srec[b * N_ + j];
        for (int q = lane; q < dgj; q += 32) {
            int m = lj[q];
            int jc = gv[m];
            if (jc >= 0) {
                float coef = (m == j) ? 2.f : 1.f;
                a[jc] += sr * d1[b * N_ + m] * ca[b * N_ + m] * coef;
            }
        }
        __syncwarp();
        if (lane == 0 && !hasd[b * N_ + j]) {
            int jc = gv[j];
            if (jc >= 0) a[jc] += sr * d1[b * N_ + j] * ca[b * N_ + j];
        }
        __syncwarp();
    }
    float4* trow4 = (float4*)(Tc + (size_t)b * N_ * N_ + (size_t)i * cnp);
    for (int jc = lane; jc < (cnp >> 2); jc += 32) trow4[jc] = a4[jc];
}

// -- Ac[ic,:] = floorq(sum_n S[n,m]*Tc[n,:]); fused bf16 split + d2/rz2 -------
__global__ void STT_kernel(const int* __restrict__ lst, const int* __restrict__ deg,
                           const int* __restrict__ hasd, const float* __restrict__ d1,
                           const float* __restrict__ ca, const float* __restrict__ srec,
                           const int* __restrict__ idx, const int* __restrict__ cnt,
                           const float* __restrict__ Tc, float* __restrict__ Ac,
                           __nv_bfloat16* __restrict__ Achi, __nv_bfloat16* __restrict__ Aclo,
                           float* __restrict__ d2out, float* __restrict__ rz2out) {
    __shared__ float4 acc4[N_ / 4];
    __shared__ float red[256];
    int b = blockIdx.y, ic = blockIdx.x, tid = threadIdx.x;
    int cn = cnt[b], cnp = (cn + 127) & ~127, cnp4 = cnp >> 2;
    if (ic >= cnp) return;
    size_t rowoff = ((size_t)(b * N_ + ic)) * N_;
    float4* orow4 = (float4*)(Ac + rowoff);
    __nv_bfloat162* ohi = (__nv_bfloat162*)(Achi + rowoff);
    __nv_bfloat162* olo = (__nv_bfloat162*)(Aclo + rowoff);
    float4 z4 = make_float4(0.f, 0.f, 0.f, 0.f);
    if (ic >= cn) {
        __nv_bfloat162 zb; zb.x = __float2bfloat16(0.f); zb.y = zb.x;
        for (int jc = tid; jc < cnp4; jc += 256) {
            orow4[jc] = z4;
            ohi[jc * 2] = zb; ohi[jc * 2 + 1] = zb;
            olo[jc * 2] = zb; olo[jc * 2 + 1] = zb;
        }
        if (tid == 0) { d2out[b * N_ + ic] = 1.f; rz2out[b * N_ + ic] = 0.f; }
        return;
    }
    int m = idx[b * N_ + ic];
    float dmcam = d1[b * N_ + m] * ca[b * N_ + m];
    for (int jc = tid; jc < cnp4; jc += 256) acc4[jc] = z4;
    __syncthreads();
    int dg = deg[b * N_ + m];
    const int* l = lst + ((size_t)(b * N_ + m)) * CAP;
    const float* Tb = Tc + (size_t)b * N_ * N_;
    for (int p = 0; p < dg; p++) {
        int n = l[p];
        float coef = (n == m) ? 2.f : 1.f;
        float sv = srec[b * N_ + n] * dmcam * coef;
        if (sv != 0.f) {
            const float4* trow = (const float4*)(Tb + (size_t)n * cnp);
            for (int jc = tid; jc < cnp4; jc += 256) {
                float4 t = trow[jc], a = acc4[jc];
                a.x = fmaf(sv, t.x, a.x); a.y = fmaf(sv, t.y, a.y);
                a.z = fmaf(sv, t.z, a.z); a.w = fmaf(sv, t.w, a.w);
                acc4[jc] = a;
            }
        }
    }
    if (!hasd[b * N_ + m]) {
        float sv = srec[b * N_ + m] * dmcam;
        if (sv != 0.f) {
            const float4* trow = (const float4*)(Tb + (size_t)m * cnp);
            for (int jc = tid; jc < cnp4; jc += 256) {
                float4 t = trow[jc], a = acc4[jc];
                a.x = fmaf(sv, t.x, a.x); a.y = fmaf(sv, t.y, a.y);
                a.z = fmaf(sv, t.z, a.z); a.w = fmaf(sv, t.w, a.w);
                acc4[jc] = a;
            }
        }
    }
    __syncthreads();
    float part = 0.f;
    for (int jc = tid; jc < cnp4; jc += 256) {
        float4 a = acc4[jc];
        a.x = floorf(a.x * 10000.f) / 10000.f;
        a.y = floorf(a.y * 10000.f) / 10000.f;
        a.z = floorf(a.z * 10000.f) / 10000.f;
        a.w = floorf(a.w * 10000.f) / 10000.f;
        orow4[jc] = a;
        part += (a.x + a.y) + (a.z + a.w);
        __nv_bfloat162 h01 = split_hi2(a.x, a.y), h23 = split_hi2(a.z, a.w);
        ohi[jc * 2] = h01; ohi[jc * 2 + 1] = h23;
        olo[jc * 2] = split_lo2(a.x, a.y, h01); olo[jc * 2 + 1] = split_lo2(a.z, a.w, h23);
    }
    red[tid] = part; __syncthreads();
    for (int o = 128; o > 0; o >>= 1) { if (tid < o) red[tid] += red[tid + o]; __syncthreads(); }
    if (tid == 0) {
        float sum = red[0];
        d2out[b * N_ + ic] = rsqrtf(fmaxf(sum + 1.f, 1.f));
        rz2out[b * N_ + ic] = (sum > 0.f) ? 1.f : 0.f;
    }
}

// ---------------- layer-2 / final helpers (read Ac/A3 directly) --------------
__global__ void rowstats_c_kernel(const float* __restrict__ A, const int* __restrict__ cnt,
                                  float* __restrict__ dout, float* __restrict__ rnz, int mode) {
    int b = blockIdx.y, i = blockIdx.x, tid = threadIdx.x;
    int cnp = (cnt[b] + 127) & ~127;
    if (i >= cnp) return;
    const float* row = A + ((size_t)(b * N_ + i)) * N_;
    const float4* row4 = (const float4*)row;
    float s = 0.f;
    for (int j = tid; j < (cnp >> 2); j += 256) {
        float4 a = row4[j]; s += (a.x + a.y) + (a.z + a.w);
    }
    __shared__ float red[256];
    red[tid] = s; __syncthreads();
    for (int o = 128; o > 0; o >>= 1) { if (tid < o) red[tid] += red[tid + o]; __syncthreads(); }
    if (tid == 0) {
        float sum = red[0];
        if (mode == 0) {
            dout[b * N_ + i] = rsqrtf(fmaxf(sum - row[i] + 1.f, 1.f));
        } else {
            dout[b * N_ + i] = rsqrtf(fmaxf(sum + 1.f, 1.f));
            rnz[b * N_ + i] = (sum > 0.f) ? 1.f : 0.f;
        }
    }
}

__global__ void alpha2d_kernel(const float* __restrict__ Ac, const float* __restrict__ d2,
                               const float* __restrict__ rz2, const float* __restrict__ v,
                               const int* __restrict__ cnt, float* __restrict__ alp) {
    __shared__ float dv[N_];
    __shared__ float red[256];
    int b = blockIdx.y, n = blockIdx.x, tid = threadIdx.x;
    int cnp = (cnt[b] + 127) & ~127;
    if (n >= cnp) { if (tid == 0) alp[b * N_ + n] = 0.5f; return; }
    for (int m = tid; m < cnp; m += 256) dv[m] = d2[b * N_ + m] * v[b * N_ + m];
    __syncthreads();
    const float4* row4 = (const float4*)(Ac + ((size_t)(b * N_ + n)) * N_);
    const float4* dv4 = (const float4*)dv;
    float s = 0.f;
    for (int m = tid; m < (cnp >> 2); m += 256) {
        float4 a = row4[m], w = dv4[m];
        s += a.x * w.x + a.y * w.y + a.z * w.z + a.w * w.w;
    }
    red[tid] = s; __syncthreads();
    for (int o = 128; o > 0; o >>= 1) { if (tid < o) red[tid] += red[tid + o]; __syncthreads(); }
    if (tid == 0) {
        float r = rz2[b * N_ + n] * d2[b * N_ + n] * (red[0] + dv[n]);
        alp[b * N_ + n] = 1.f / (1.f + expf(-r * r));
    }
}

// sinv[n] = f / max(f * sum_m (Ac[n][m]+delta)*dca[m], 1e-12), f = rz2*d2
__global__ void s2inv_kernel(const float* __restrict__ Ac, const float* __restrict__ d2,
                             const float* __restrict__ rz2, const float* __restrict__ ca,
                             const int* __restrict__ cnt, float* __restrict__ sinv) {
    __shared__ float dca[N_];
    __shared__ float red[256];
    int b = blockIdx.y, n = blockIdx.x, tid = threadIdx.x;
    int cnp = (cnt[b] + 127) & ~127;
    if (n >= cnp) return;
    for (int m = tid; m < cnp; m += 256) dca[m] = d2[b * N_ + m] * ca[b * N_ + m];
    __syncthreads();
    const float4* row4 = (const float4*)(Ac + ((size_t)(b * N_ + n)) * N_);
    const float4* dca4 = (const float4*)dca;
    float s = 0.f;
    for (int m = tid; m < (cnp >> 2); m += 256) {
        float4 a = row4[m], w = dca4[m];
        s += a.x * w.x + a.y * w.y + a.z * w.z + a.w * w.w;
    }
    red[tid] = s; __syncthreads();
    for (int o = 128; o > 0; o >>= 1) { if (tid < o) red[tid] += red[tid + o]; __syncthreads(); }
    if (tid == 0) {
        float sum = red[0] + dca[n];
        float f = rz2[b * N_ + n] * d2[b * N_ + n];
        sinv[b * N_ + n] = f / fmaxf(f * sum, 1e-12f);
    }
}

// ST[m][n] = S2[n][m] = (Ac[m][n] + (m==n)) * dca[m] * sinv[n]  (Ac symmetric)
__global__ void buildST_kernel(const float* __restrict__ Ac, const float* __restrict__ d2,
                               const float* __restrict__ ca, const float* __restrict__ sinv,
                               const int* __restrict__ cnt,
                               __nv_bfloat16* __restrict__ SThi, __nv_bfloat16* __restrict__ STlo) {
    __shared__ float siv[N_];
    int b = blockIdx.y, m = blockIdx.x, tid = threadIdx.x;
    int cnp = (cnt[b] + 127) & ~127;
    if (m >= cnp) return;
    for (int n = tid; n < cnp; n += 256) siv[n] = sinv[b * N_ + n];
    __syncthreads();
    float dcam = d2[b * N_ + m] * ca[b * N_ + m];
    size_t ro = ((size_t)(b * N_ + m)) * N_;
    const float4* row4 = (const float4*)(Ac + ro);
    __nv_bfloat162* ohi = (__nv_bfloat162*)(SThi + ro);
    __nv_bfloat162* olo = (__nv_bfloat162*)(STlo + ro);
    for (int q = tid; q < (cnp >> 2); q += 256) {
        float4 a = row4[q];
        int n = q << 2;
        float v0 = (a.x + ((n    ) == m ? 1.f : 0.f)) * dcam * siv[n];
        float v1 = (a.y + ((n + 1) == m ? 1.f : 0.f)) * dcam * siv[n + 1];
        float v2 = (a.z + ((n + 2) == m ? 1.f : 0.f)) * dcam * siv[n + 2];
        float v3 = (a.w + ((n + 3) == m ? 1.f : 0.f)) * dcam * siv[n + 3];
        __nv_bfloat162 h01 = split_hi2(v0, v1), h23 = split_hi2(v2, v3);
        ohi[q * 2] = h01; ohi[q * 2 + 1] = h23;
        olo[q * 2] = split_lo2(v0, v1, h01); olo[q * 2 + 1] = split_lo2(v2, v3, h23);
    }
}

// w[k] = d2[k] * (sum_m A3[k][m]*dv[m] - A3[k][k]*dv[k] + dv[k]), dv = d2*maskc
__global__ void wvec_kernel(const float* __restrict__ A3, const float* __restrict__ d2,
                            const float* __restrict__ maskc, const int* __restrict__ cnt,
                            float* __restrict__ wv) {
    __shared__ float dv[N_];
    __shared__ float red[256];
    int b = blockIdx.y, k = blockIdx.x, tid = threadIdx.x;
    int cnp = (cnt[b] + 127) & ~127;
    if (k >= cnp) return;
    for (int m = tid; m < cnp; m += 256) dv[m] = d2[b * N_ + m] * maskc[b * N_ + m];
    __syncthreads();
    const float* row = A3 + ((size_t)(b * N_ + k)) * N_;
    const float4* row4 = (const float4*)row;
    const float4* dv4 = (const float4*)dv;
    float s = 0.f;
    for (int m = tid; m < (cnp >> 2); m += 256) {
        float4 a = row4[m], w = dv4[m];
        s += a.x * w.x + a.y * w.y + a.z * w.z + a.w * w.w;
    }
    red[tid] = s; __syncthreads();
    for (int o = 128; o > 0; o >>= 1) { if (tid < o) red[tid] += red[tid + o]; __syncthreads(); }
    if (tid == 0)
        wv[b * N_ + k] = d2[b * N_ + k] * (red[0] - row[k] * dv[k] + dv[k]);
}

// p2 partial: sum_k wv[k]*xW[k,:] over k-chunk q
__global__ void out2_part_kernel(const float* __restrict__ xW, const float* __restrict__ wv,
                                 const int* __restrict__ cnt, float* __restrict__ p2) {
    int b = blockIdx.y, q = blockIdx.x, c = threadIdx.x;   // 256 threads
    int cnp = (cnt[b] + 127) & ~127;
    int lo = q * 512, hi = (q + 1) * 512; if (hi > cnp) hi = cnp;
    float s = 0.f;
    for (int k = lo; k < hi; k++)
        s = fmaf(wv[b * N_ + k], xW[((size_t)(b * N_ + k)) * F_ + c], s);
    p2[(b * 4 + q) * F_ + c] = s;
}

// generic transposed split: out[j][i] = in[i][j]; in R x C (ld), out stride N_
__global__ void split_tr_kernel(const float* __restrict__ in, __nv_bfloat16* __restrict__ hi,
                                __nv_bfloat16* __restrict__ lo, const int* __restrict__ cnt,
                                int Rfixed, int Cfixed, int ld, long sIn, long sOut) {
    __shared__ float tile[32][33];
    int b = blockIdx.z;
    int cnp = (cnt[b] + 127) & ~127;
    int R = Rfixed ? Rfixed : cnp;
    int C = Cfixed ? Cfixed : cnp;
    int i0 = blockIdx.y * 32, j0 = blockIdx.x * 32;
    if (i0 >= R || j0 >= C) return;
    const float* inb = in + (size_t)b * sIn;
    size_t boff = (size_t)b * sOut;
    int tx = threadIdx.x, ty = threadIdx.y;   // (32, 8)
    #pragma unroll
    for (int r = 0; r < 4; r++) {
        int i = ty + r * 8;
        tile[i][tx] = inb[(size_t)(i0 + i) * ld + j0 + tx];
    }
    __syncthreads();
    #pragma unroll
    for (int r = 0; r < 4; r++) {
        int j = ty + r * 8;
        float v = tile[tx][j];
        __nv_bfloat16 h = __float2bfloat16(v);
        size_t o = boff + (size_t)(j0 + j) * N_ + i0 + tx;
        hi[o] = h;
        lo[o] = __float2bfloat16(v - __bfloat162float(h));
    }
}

// ---------------- bf16-split tensor GEMM, single-K-pass ----------------------
// C = A @ B: hi*hi + hi*lo + lo*hi accumulated per k-tile (fp32 accum).
// A row-major [m][k] stride N_; BT [n][k] stride N_.  M = K = cnp.
// EPI 4: row-major bf16 hi/lo split out; PLUS merged second region:
//        the LAST grid column reads B2 (H_ rows, stride N_) and writes fp32 C2.
// EPI 5: floor-quant + SYMMETRIC output (upper blocks only, mirror write).
#define TSZ (128 * 40)
template<int EPI>
__global__ void __launch_bounds__(256, 2) gemm_bf16_kernel(
    const __nv_bfloat16* __restrict__ Ahi, const __nv_bfloat16* __restrict__ Alo,
    const __nv_bfloat16* __restrict__ BThi, const __nv_bfloat16* __restrict__ BTlo,
    float* __restrict__ C, const int* __restrict__ cnt,
    int ldc, long sC,
    __nv_bfloat16* __restrict__ Chi, __nv_bfloat16* __restrict__ Clo,
    const __nv_bfloat16* __restrict__ B2hi, const __nv_bfloat16* __restrict__ B2lo,
    float* __restrict__ C2, int ldc2, long sC2) {
    extern __shared__ __nv_bfloat16 sm[];   // [2 stages][4 tiles][128*40]
    const int b = blockIdx.z;
    const int cnp = (cnt[b] + 127) & ~127;
    const int m0 = blockIdx.y * 128;
    const int n0 = blockIdx.x * 128;
    const bool reg2 = (EPI == 4) && (blockIdx.x == gridDim.x - 1);
    if (m0 >= cnp) return;
    if (!reg2) {
        if (n0 >= cnp) return;
        if (EPI == 5 && m0 > n0) return;   // symmetric: upper-triangle blocks only
    }
    const size_t boff = (size_t)b * N_ * N_;
    const int tid = threadIdx.x;
    const int wid = tid >> 5, lane = tid & 31;
    const int wm = wid >> 1, wn = wid & 1;     // warps 4 x 2 -> warp tile 32 x 64
    const int g = lane >> 2, t4 = lane & 3;
    const int a_row = lane & 15;
    const int a_k   = (lane & 16) ? 8 : 0;
    const int b_row = (lane & 7) + ((lane & 16) ? 8 : 0);
    const int b_k   = (lane & 8) ? 8 : 0;
    const int KT = cnp >> 5;

    float acc[2][8][4];
    #pragma unroll
    for (int fm = 0; fm < 2; fm++)
        #pragma unroll
        for (int fn = 0; fn < 8; fn++)
            #pragma unroll
            for (int r = 0; r < 4; r++) acc[fm][fn][r] = 0.f;

    const __nv_bfloat16* gsrc[4];
    auto stage = [&](int kt, int buf) {
        gsrc[0] = Ahi + boff + (size_t)m0 * N_ + kt * 32;
        gsrc[1] = Alo + boff + (size_t)m0 * N_ + kt * 32;
        if (reg2) {
            gsrc[2] = B2hi + (size_t)b * H_ * N_ + kt * 32;
            gsrc[3] = B2lo + (size_t)b * H_ * N_ + kt * 32;
        } else {
            gsrc[2] = BThi + boff + (size_t)n0 * N_ + kt * 32;
            gsrc[3] = BTlo + boff + (size_t)n0 * N_ + kt * 32;
        }
        int row = tid >> 2, cc = (tid & 3) * 8;
        #pragma unroll
        for (int w = 0; w < 4; w++) {
            __nv_bfloat16* dst = sm + (size_t)(buf * 4 + w) * TSZ;
            CP16(dst + row * 40 + cc,        gsrc[w] + (size_t)row * N_ + cc);
            CP16(dst + (row + 64) * 40 + cc, gsrc[w] + (size_t)(row + 64) * N_ + cc);
        }
    };

    stage(0, 0);
    CP_COMMIT();

    for (int t = 0; t < KT; t++) {
        CP_WAIT0();
        __syncthreads();
        if (t + 1 < KT) { stage(t + 1, (t + 1) & 1); CP_COMMIT(); }
        const __nv_bfloat16* Ah = sm + (size_t)((t & 1) * 4 + 0) * TSZ;
        const __nv_bfloat16* Al = sm + (size_t)((t & 1) * 4 + 1) * TSZ;
        const __nv_bfloat16* Bh = sm + (size_t)((t & 1) * 4 + 2) * TSZ;
        const __nv_bfloat16* Bl = sm + (size_t)((t & 1) * 4 + 3) * TSZ;
        #pragma unroll
        for (int kh = 0; kh < 32; kh += 16) {
            uint32_t ah[2][4], al[2][4];
            #pragma unroll
            for (int fm = 0; fm < 2; fm++) {
                int ao = (wm * 32 + fm * 16 + a_row) * 40 + kh + a_k;
                ldsm4(ah[fm], Ah + ao);
                ldsm4(al[fm], Al + ao);
            }
            #pragma unroll
            for (int fn2 = 0; fn2 < 4; fn2++) {
                int bo = (wn * 64 + fn2 * 16 + b_row) * 40 + kh + b_k;
                uint32_t bh[4], bl[4];
                ldsm4(bh, Bh + bo);
                ldsm4(bl, Bl + bo);
                #pragma unroll
                for (int fm = 0; fm < 2; fm++) {
                    mma_bf16(acc[fm][2 * fn2],     ah[fm], bh[0], bh[1]);
                    mma_bf16(acc[fm][2 * fn2],     ah[fm], bl[0], bl[1]);
                    mma_bf16(acc[fm][2 * fn2],     al[fm], bh[0], bh[1]);
                    mma_bf16(acc[fm][2 * fn2 + 1], ah[fm], bh[2], bh[3]);
                    mma_bf16(acc[fm][2 * fn2 + 1], ah[fm], bl[2], bl[3]);
                    mma_bf16(acc[fm][2 * fn2 + 1], al[fm], bh[2], bh[3]);
                }
            }
        }
        __syncthreads();
    }

    float* smf = (float*)sm;   // EPI==5: 128x133 fp32 transpose staging (68KB <= 80KB)
    #pragma unroll
    for (int fm = 0; fm < 2; fm++) {
        int mr = m0 + wm * 32 + fm * 16 + g;
        #pragma unroll
        for (int fn = 0; fn < 8; fn++) {
            int lc = wn * 64 + fn * 8 + t4 * 2;   // local col
            float v0 = acc[fm][fn][0], v1 = acc[fm][fn][1];
            float v2 = acc[fm][fn][2], v3 = acc[fm][fn][3];
            if (reg2) {
                float* p0 = C2 + (size_t)b * sC2 + (size_t)mr * ldc2 + lc;
                p0[0] = v0; p0[1] = v1;
                float* p1 = p0 + 8 * (size_t)ldc2;
                p1[0] = v2; p1[1] = v3;
            } else if (EPI == 5) {
                v0 = floorf(v0 * 10000.f) / 10000.f;
                v1 = floorf(v1 * 10000.f) / 10000.f;
                v2 = floorf(v2 * 10000.f) / 10000.f;
                v3 = floorf(v3 * 10000.f) / 10000.f;
                int r = wm * 32 + fm * 16 + g;
                smf[(lc    ) * 133 + r]     = v0;
                smf[(lc + 1) * 133 + r]     = v1;
                smf[(lc    ) * 133 + r + 8] = v2;
                smf[(lc + 1) * 133 + r + 8] = v3;
                int n = n0 + lc;
                float* p0 = C + (size_t)b * sC + (size_t)mr * ldc + n;
                p0[0] = v0; p0[1] = v1;
                float* p1 = p0 + 8 * (size_t)ldc;
                p1[0] = v2; p1[1] = v3;
            } else {   // EPI 4 region 1: bf16 split out
                int n = n0 + lc;
                size_t o0 = (size_t)b * sC + (size_t)mr * ldc + n;
                size_t o1 = o0 + 8 * (size_t)ldc;
                __nv_bfloat162 h0 = split_hi2(v0, v1), h1 = split_hi2(v2, v3);
                *(__nv_bfloat162*)(Chi + o0) = h0;
                *(__nv_bfloat162*)(Chi + o1) = h1;
                *(__nv_bfloat162*)(Clo + o0) = split_lo2(v0, v1, h0);
                *(__nv_bfloat162*)(Clo + o1) = split_lo2(v2, v3, h1);
            }
        }
    }
    if (EPI == 5 && m0 != n0) {
        __syncthreads();
        float* Cb = C + (size_t)b * sC;
        for (int e = tid; e < 128 * 128; e += 256) {
            int r2 = e >> 7, c2 = e & 127;
            Cb[(size_t)(n0 + r2) * ldc + m0 + c2] = smf[r2 * 133 + c2];
        }
    }
}

// ---------------- double-buffered cp.async SIMT GEMM (small GEMMs) -----------
template<int TRANSA, int EPI>
__global__ void __launch_bounds__(256, 2) gemm2_kernel(
    const float* __restrict__ A, const float* __restrict__ Bm, float* __restrict__ C,
    int M, int Kd, int Nc, int lda, int ldb, int ldc,
    long sA, long sB, long sC,
    const float* __restrict__ bias, const float* __restrict__ mask,
    const int* __restrict__ cnt, int dynM, int dynK, int dynN) {
    __shared__ float As[2][128 * 16];
    __shared__ float Bs[2][16 * 128];
    const int b = blockIdx.z;
    int Mp = M, Kp = Kd, Np = Nc;
    if (cnt) {
        int p = (cnt[b] + 127) & ~127;
        if (dynM) Mp = p; if (dynK) Kp = p; if (dynN) Np = p;
    }
    const int n0 = blockIdx.x * 128, m0 = blockIdx.y * 128;
    if (m0 >= Mp || n0 >= Np) return;
    A  += (size_t)b * sA;
    Bm += (size_t)b * sB;
    C  += (size_t)b * sC;
    const int tid = threadIdx.x, tx = tid & 15, ty = tid >> 4;
    float acc[8][8];
    #pragma unroll
    for (int i = 0; i < 8; i++)
        #pragma unroll
        for (int j = 0; j < 8; j++) acc[i][j] = 0.f;

    const int Kt = Kp >> 4;

    auto load_tiles = [&](int k0, int buf) {
        if (!TRANSA) {
            #pragma unroll
            for (int q = 0; q < 2; q++) {
                int c = tid + q * 256;
                int row = c >> 2, col4 = (c & 3) * 4;
                const float* src = A + (size_t)(m0 + row) * lda + k0 + col4;
                CP16(&As[buf][row * 16 + col4], src);
            }
        } else {
            #pragma unroll
            for (int q = 0; q < 2; q++) {
                int c = tid + q * 256;
                int row = c >> 5, col4 = (c & 31) * 4;
                const float* src = A + (size_t)(k0 + row) * lda + m0 + col4;
                CP16(&As[buf][row * 128 + col4], src);
            }
        }
        #pragma unroll
        for (int q = 0; q < 2; q++) {
            int c = tid + q * 256;
            int row = c >> 5, col4 = (c & 31) * 4;
            const float* src = Bm + (size_t)(k0 + row) * ldb + n0 + col4;
            CP16(&Bs[buf][row * 128 + col4], src);
        }
    };

    load_tiles(0, 0);
    CP_COMMIT();

    for (int t = 0; t < Kt; t++) {
        CP_WAIT0();
        __syncthreads();
        if (t + 1 < Kt) { load_tiles((t + 1) << 4, (t + 1) & 1); CP_COMMIT(); }
        const int buf = t & 1;
        #pragma unroll
        for (int k = 0; k < 16; k++) {
            float a[8], bv[8];
            if (!TRANSA) {
                #pragma unroll
                for (int i = 0; i < 8; i++) a[i] = As[buf][(ty * 8 + i) * 16 + k];
            } else {
                *(float4*)(a)     = *(const float4*)&As[buf][k * 128 + ty * 8];
                *(float4*)(a + 4) = *(const float4*)&As[buf][k * 128 + ty * 8 + 4];
            }
            *(float4*)(bv)     = *(const float4*)&Bs[buf][k * 128 + tx * 8];
            *(float4*)(bv + 4) = *(const float4*)&Bs[buf][k * 128 + tx * 8 + 4];
            #pragma unroll
            for (int i = 0; i < 8; i++)
                #pragma unroll
                for (int j = 0; j < 8; j++) acc[i][j] = fmaf(a[i], bv[j], acc[i][j]);
        }
        __syncthreads();
    }
    #pragma unroll
    for (int i = 0; i < 8; i++) {
        int m = m0 + ty * 8 + i;
        float mk = (EPI == 2) ? mask[(size_t)b * N_ + m] : 1.f;
        #pragma unroll
        for (int j = 0; j < 8; j++) {
            int n = n0 + tx * 8 + j;
            float v = acc[i][j];
            if (EPI == 2)      { v = (v + bias[n]) * mk; }
            else if (EPI == 3) { v = floorf(v * 10000.f) / 10000.f; }
            C[(size_t)m * ldc + n] = v;
        }
    }
}

// ---------------- output means (two-stage, deterministic) --------------------
__global__ void mean1_part_kernel(const float* __restrict__ x1, float* __restrict__ p1) {
    int b = blockIdx.y, q = blockIdx.x, c = threadIdx.x;   // 128 threads
    float s = 0.f;
    for (int n = q * 512; n < (q + 1) * 512; n++) s += x1[((size_t)(b * N_ + n)) * H_ + c];
    p1[(b * 4 + q) * H_ + c] = s;
}

__global__ void mean_combine_kernel(const float* __restrict__ p1, const float* __restrict__ p2,
                                    const float* __restrict__ b2, const float* __restrict__ smask,
                                    float* __restrict__ out) {
    int b = blockIdx.x, c = threadIdx.x;   // 384 threads
    if (c < H_) {
        float s = 0.f;
        for (int q = 0; q < 4; q++) s += p1[(b * 4 + q) * H_ + c];
        out[b * OUTC + c] = s / (float)N_;
    } else {
        int cc = c - H_;
        float s = b2[cc] * smask[b];
        for (int q = 0; q < 4; q++) s += p2[(b * 4 + q) * F_ + cc];
        out[b * OUTC + c] = s / (float)N_;
    }
}

extern "C" void kernel_launch(void* const* d_in, const int* in_sizes, int n_in,
                              void* d_out, int out_size) {
    const float* x    = (const float*)d_in[0];
    const float* adj  = (const float*)d_in[1];
    const float* mask = (const float*)d_in[2];
    const float* W1   = (const float*)d_in[3];
    const float* b1   = (const float*)d_in[4];
    const float* Watt = (const float*)d_in[5];
    const float* batt = (const float*)d_in[6];
    const float* W2   = (const float*)d_in[7];
    const float* b2   = (const float*)d_in[8];
    float* out = (float*)d_out;

    float *pT,*pAc,*pA3,*pxW,*px1,*pxc,*px3;
    float *pv,*palp,*pca,*psrec,*pd0,*pd1,*prnz,*pd2,*prz2,*pcut,*pmaskc,*pmrest,*pp1,*pp2;
    __nv_bfloat16 *pAhi,*pAlo,*pSThi,*pSTlo,*pTThi,*pTTlo,*pxTh,*pxTl;
    int *plst,*pdeg,*phasd,*pidx,*pginv,*pcnt;
    cudaGetSymbolAddress((void**)&pT,   g_T);
    cudaGetSymbolAddress((void**)&pAc,  g_Ac);
    cudaGetSymbolAddress((void**)&pA3,  g_A3);
    cudaGetSymbolAddress((void**)&pAhi, g_Ahi);
    cudaGetSymbolAddress((void**)&pAlo, g_Alo);
    cudaGetSymbolAddress((void**)&pSThi,g_SThi);
    cudaGetSymbolAddress((void**)&pSTlo,g_STlo);
    cudaGetSymbolAddress((void**)&pTThi,g_TThi);
    cudaGetSymbolAddress((void**)&pTTlo,g_TTlo);
    cudaGetSymbolAddress((void**)&pxTh, g_xTh);
    cudaGetSymbolAddress((void**)&pxTl, g_xTl);
    cudaGetSymbolAddress((void**)&pxW,  g_xW);
    cudaGetSymbolAddress((void**)&px1,  g_x1);
    cudaGetSymbolAddress((void**)&pxc,  g_xc);
    cudaGetSymbolAddress((void**)&px3,  g_x3);
    cudaGetSymbolAddress((void**)&pv,   g_v);
    cudaGetSymbolAddress((void**)&palp, g_alp);
    cudaGetSymbolAddress((void**)&pca,  g_ca);
    cudaGetSymbolAddress((void**)&psrec,g_srec);
    cudaGetSymbolAddress((void**)&pd0,  g_d0);
    cudaGetSymbolAddress((void**)&pd1,  g_d1);
    cudaGetSymbolAddress((void**)&prnz, g_rnz);
    cudaGetSymbolAddress((void**)&pd2,  g_d2);
    cudaGetSymbolAddress((void**)&prz2, g_rz2);
    cudaGetSymbolAddress((void**)&pcut, g_cut);
    cudaGetSymbolAddress((void**)&pmaskc, g_maskc);
    cudaGetSymbolAddress((void**)&pmrest, g_mrest);
    cudaGetSymbolAddress((void**)&pp1,  g_p1);
    cudaGetSymbolAddress((void**)&pp2,  g_p2);
    cudaGetSymbolAddress((void**)&plst, g_lst);
    cudaGetSymbolAddress((void**)&pdeg, g_deg);
    cudaGetSymbolAddress((void**)&phasd,g_hasd);
    cudaGetSymbolAddress((void**)&pidx, g_idx);
    cudaGetSymbolAddress((void**)&pginv,g_ginv);
    cudaGetSymbolAddress((void**)&pcnt, g_cnt);

    const int BF16_SMEM = 2 * 4 * TSZ * 2;   // 81920 bytes
    cudaFuncSetAttribute(gemm_bf16_kernel<4>, cudaFuncAttributeMaxDynamicSharedMemorySize, BF16_SMEM);
    cudaFuncSetAttribute(gemm_bf16_kernel<5>, cudaFuncAttributeMaxDynamicSharedMemorySize, BF16_SMEM);

    // ---- CSR + degree stats (single adj scan) ----
    csr_build_kernel<<<dim3(N_, B_), 256>>>(adj, plst, pdeg, phasd, pd0, pd1, prnz);

    // ---- GCN layer 1 (sparse aggregation) ----
    gemm2_kernel<0,0><<<dim3(1,16,B_),256>>>(x, W1, pxW, N_, F_, H_, F_, H_, H_,
        (long)N_*F_, 0, (long)N_*H_, nullptr, nullptr, nullptr, 0,0,0);
    gcn1_kernel<<<dim3(N_, B_), 128>>>(plst, pdeg, pd0, pxW, b1, mask, px1);

    // ---- coarsen layer 1 (sparse, no dense S anywhere) ----
    gemv_watt_kernel<<<(B_*N_)/8, 256>>>(px1, Watt, batt, pv);
    alpha1_kernel<<<dim3(N_/8, B_), 256>>>(plst, pdeg, pd1, prnz, pv, palp);
    topk_cut_kernel<<<B_, 1024>>>(palp, pcut);
    ca_kernel<<<(B_*N_)/256, 256>>>(palp, pcut, pca);
    compact_kernel<<<B_, 1024>>>(pca, pidx, pginv, pcnt);
    compact_mask_kernel<<<B_, 256>>>(mask, pidx, pcnt, pmaskc, pmrest);
    srec_kernel<<<dim3(N_/8, B_), 256>>>(plst, pdeg, pd1, prnz, pca, psrec);
    xupd_kernel<<<dim3(N_, B_), 128>>>(plst, pdeg, phasd, pd1, pca, psrec, pidx, pcnt, px1, pxc);
    adjS_sparse_kernel<<<dim3(N_/4, B_), 128>>>(plst, pdeg, phasd, pd1, pca, psrec,
                                                pginv, pcnt, pT);
    // Ac + fused bf16 split + fused d2/rz2 row stats
    STT_kernel<<<dim3(N_, B_), 256>>>(plst, pdeg, phasd, pd1, pca, psrec, pidx, pcnt,
                                      pT, pAc, pAhi, pAlo, pd2, prz2);

    // ---- coarsen layer 2 (symmetric Ac: direct row-major ST build) ----
    gemv_watt_kernel<<<(B_*N_)/8, 256>>>(pxc, Watt, batt, pv);
    alpha2d_kernel<<<dim3(N_, B_), 256>>>(pAc, pd2, prz2, pv, pcnt, palp);
    topk_cut_kernel<<<B_, 1024>>>(palp, pcut);
    ca_kernel<<<(B_*N_)/256, 256>>>(palp, pcut, pca);
    s2inv_kernel<<<dim3(N_, B_), 256>>>(pAc, pd2, prz2, pca, pcnt, psrec);
    buildST_kernel<<<dim3(N_, B_), 256>>>(pAc, pd2, pca, psrec, pcnt, pSThi, pSTlo);
    // xc^T split (B2 operand for the merged GEMM)
    split_tr_kernel<<<dim3(4, 64, B_), dim3(32, 8)>>>(pxc, pxTh, pxTl, pcnt,
        0, H_, H_, (long)N_*H_, (long)H_*N_);
    // MERGED: T2^T = ST @ Ac^T (bf16 split -> TT)  AND  x3 = ST @ xc (fp32)
    gemm_bf16_kernel<4><<<dim3(17,16,B_),256,BF16_SMEM>>>(pSThi, pSTlo, pAhi, pAlo,
        nullptr, pcnt, N_, (long)N_*N_, pTThi, pTTlo,
        pxTh, pxTl, px3, H_, (long)N_*H_);
    // A3 = ST @ T2 (symmetric): upper blocks only, floor-quant, mirror write
    gemm_bf16_kernel<5><<<dim3(16,16,B_),256,BF16_SMEM>>>(pSThi, pSTlo, pTThi, pTTlo,
        pA3, pcnt, N_, (long)N_*N_, nullptr, nullptr,
        nullptr, nullptr, nullptr, 0, 0);

    // ---- final GCN: only the column mean is needed ----
    rowstats_c_kernel<<<dim3(N_, B_), 256>>>(pA3, pcnt, pd2, nullptr, 0);
    gemm2_kernel<0,0><<<dim3(2,16,B_),256>>>(px3, W2, pxW, N_, H_, F_, H_, F_, F_,
        (long)N_*H_, 0, (long)N_*F_, nullptr, nullptr, pcnt, 1,0,0);
    wvec_kernel<<<dim3(N_, B_), 256>>>(pA3, pd2, pmaskc, pcnt, pv);
    out2_part_kernel<<<dim3(4, B_), 256>>>(pxW, pv, pcnt, pp2);

    // ---- concat means ----
    mean1_part_kernel<<<dim3(4, B_), 128>>>(px1, pp1);
    mean_combine_kernel<<<B_, 384>>>(pp1, pp2, b2, pmrest, out);
}

// round 11
// speedup vs baseline: 7.5595x; 1.0018x over previous
#include <cuda_runtime.h>
#include <cuda_bf16.h>
#include <math.h>
#include <stdint.h>

#define B_ 8
#define N_ 2048
#define F_ 256
#define H_ 128
#define K_ 1025
#define OUTC 384
#define CAP 256

// ---------------- scratch (device globals; no allocation allowed) ----------
__device__ float g_T [(size_t)B_*N_*N_];   // Tc (layer1, stride cnp)
__device__ float g_Ac[(size_t)B_*N_*N_];   // compacted A2 (stride N_)
__device__ float g_A3[(size_t)B_*N_*N_];   // compacted A3 (stride N_)
__device__ __nv_bfloat16 g_Ahi[(size_t)B_*N_*N_], g_Alo[(size_t)B_*N_*N_];
__device__ __nv_bfloat16 g_SThi[(size_t)B_*N_*N_], g_STlo[(size_t)B_*N_*N_];
__device__ __nv_bfloat16 g_TThi[(size_t)B_*N_*N_], g_TTlo[(size_t)B_*N_*N_];
__device__ __nv_bfloat16 g_xTh[B_*H_*N_], g_xTl[B_*H_*N_];   // xc^T split
__device__ float g_xW [B_*N_*F_];
__device__ float g_x1 [B_*N_*H_];
__device__ float g_xc [B_*N_*H_];
__device__ float g_x3 [B_*N_*H_];
__device__ int   g_lst[(size_t)B_*N_*CAP];
__device__ int   g_deg[B_*N_];
__device__ int   g_hasd[B_*N_];
__device__ float g_d0[B_*N_], g_d1[B_*N_], g_rnz[B_*N_];
__device__ float g_d2[B_*N_], g_rz2[B_*N_];
__device__ float g_v[B_*N_], g_alp[B_*N_], g_ca[B_*N_], g_srec[B_*N_];
__device__ float g_cut[B_];
__device__ float g_maskc[B_*N_], g_mrest[B_];
__device__ int   g_idx[B_*N_], g_ginv[B_*N_], g_cnt[B_];
__device__ float g_p1[B_*4*H_], g_p2[B_*4*F_];

// ---------------- async-copy / mma helpers -----------------------------------
#define CP16(dst, src) { \
    unsigned _a = (unsigned)__cvta_generic_to_shared(dst); \
    asm volatile("cp.async.cg.shared.global [%0], [%1], 16;\n" :: "r"(_a), "l"(src)); }
#define CP_COMMIT() asm volatile("cp.async.commit_group;\n")
#define CP_WAIT0()  asm volatile("cp.async.wait_group 0;\n")

__device__ __forceinline__ void mma_bf16(float* c, const uint32_t* a, uint32_t b0, uint32_t b1) {
    asm volatile("mma.sync.aligned.m16n8k16.row.col.f32.bf16.bf16.f32 "
        "{%0,%1,%2,%3}, {%4,%5,%6,%7}, {%8,%9}, {%0,%1,%2,%3};"
        : "+f"(c[0]), "+f"(c[1]), "+f"(c[2]), "+f"(c[3])
        : "r"(a[0]), "r"(a[1]), "r"(a[2]), "r"(a[3]), "r"(b0), "r"(b1));
}
__device__ __forceinline__ void ldsm4(uint32_t* r, const void* p) {
    uint32_t a = (uint32_t)__cvta_generic_to_shared(p);
    asm volatile("ldmatrix.sync.aligned.m8n8.x4.shared.b16 {%0,%1,%2,%3}, [%4];"
        : "=r"(r[0]), "=r"(r[1]), "=r"(r[2]), "=r"(r[3]) : "r"(a));
}
__device__ __forceinline__ __nv_bfloat162 split_hi2(float v0, float v1) {
    __nv_bfloat162 h; h.x = __float2bfloat16(v0); h.y = __float2bfloat16(v1); return h;
}
__device__ __forceinline__ __nv_bfloat162 split_lo2(float v0, float v1, __nv_bfloat162 h) {
    __nv_bfloat162 l;
    l.x = __float2bfloat16(v0 - __bfloat162float(h.x));
    l.y = __float2bfloat16(v1 - __bfloat162float(h.y));
    return l;
}

// ---------------- CSR build + degree stats (one adj scan, float4) -----------
__global__ void csr_build_kernel(const float* __restrict__ adj, int* __restrict__ lst,
                                 int* __restrict__ deg, int* __restrict__ hasd,
                                 float* __restrict__ d0, float* __restrict__ d1,
                                 float* __restrict__ rnz) {
    __shared__ int sc[256];
    __shared__ int hd;
    int b = blockIdx.y, i = blockIdx.x, tid = threadIdx.x;
    const float4* arow4 = (const float4*)(adj + ((size_t)(b * N_ + i)) * N_);
    if (tid == 0) hd = 0;
    __syncthreads();
    float vals[8];
    *(float4*)(vals)     = arow4[tid * 2];
    *(float4*)(vals + 4) = arow4[tid * 2 + 1];
    int f[8];
    int c = 0, hloc = 0;
    #pragma unroll
    for (int e = 0; e < 8; e++) {
        int j = tid * 8 + e;
        f[e] = (vals[e] != 0.f) ? 1 : 0;
        c += f[e];
        if (f[e] && j == i) hloc = 1;
    }
    if (hloc) hd = 1;
    sc[tid] = c; __syncthreads();
    for (int o = 1; o < 256; o <<= 1) {
        int v = (tid >= o) ? sc[tid - o] : 0; __syncthreads();
        sc[tid] += v; __syncthreads();
    }
    int base = sc[tid] - c;
    int* l = lst + ((size_t)(b * N_ + i)) * CAP;
    #pragma unroll
    for (int e = 0; e < 8; e++) {
        if (f[e]) { if (base < CAP) l[base] = tid * 8 + e; base++; }
    }
    __syncthreads();
    if (tid == 0) {
        int total = sc[255];
        deg[b * N_ + i] = (total > CAP) ? CAP : total;
        hasd[b * N_ + i] = hd;
        d0[b * N_ + i] = rsqrtf(fmaxf((float)(total - hd) + 1.f, 1.f));
        d1[b * N_ + i] = rsqrtf((float)total + 1.f);
        rnz[b * N_ + i] = (total > 0) ? 1.f : 0.f;
    }
}

// ---------------- GCN layer 1 sparse aggregation -----------------------------
__global__ void gcn1_kernel(const int* __restrict__ lst, const int* __restrict__ deg,
                            const float* __restrict__ d0, const float* __restrict__ xW,
                            const float* __restrict__ b1, const float* __restrict__ mask,
                            float* __restrict__ x1) {
    int b = blockIdx.y, i = blockIdx.x, c = threadIdx.x;   // 128 threads
    int dg = deg[b * N_ + i];
    const int* l = lst + ((size_t)(b * N_ + i)) * CAP;
    float di = d0[b * N_ + i];
    float acc = di * di * xW[((size_t)(b * N_ + i)) * H_ + c];
    for (int p = 0; p < dg; p++) {
        int j = l[p];
        if (j != i) acc = fmaf(di * d0[b * N_ + j], xW[((size_t)(b * N_ + j)) * H_ + c], acc);
    }
    float vv = (acc + b1[c]) * mask[b * N_ + i];
    x1[((size_t)(b * N_ + i)) * H_ + c] = fmaxf(vv, 0.f);
}

// ---------------- v = x @ Watt + batt ----------------------------------------
__global__ void gemv_watt_kernel(const float* __restrict__ x, const float* __restrict__ Watt,
                                 const float* __restrict__ batt, float* __restrict__ v) {
    int w = blockIdx.x * 8 + (threadIdx.x >> 5);
    int lane = threadIdx.x & 31;
    if (w >= B_ * N_) return;
    const float* xr = x + (size_t)w * H_;
    float s = 0.f;
    #pragma unroll
    for (int c = lane; c < H_; c += 32) s += xr[c] * Watt[c];
    #pragma unroll
    for (int o = 16; o > 0; o >>= 1) s += __shfl_down_sync(0xffffffffu, s, o);
    if (lane == 0) v[w] = s + batt[0];
}

// ---------------- layer-1 alpha (sparse) --------------------------------------
__global__ void alpha1_kernel(const int* __restrict__ lst, const int* __restrict__ deg,
                              const float* __restrict__ d1, const float* __restrict__ rnz,
                              const float* __restrict__ v, float* __restrict__ alp) {
    int b = blockIdx.y;
    int i = blockIdx.x * 8 + (threadIdx.x >> 5);
    int lane = threadIdx.x & 31;
    const int* l = lst + ((size_t)(b * N_ + i)) * CAP;
    int dg = deg[b * N_ + i];
    float s = 0.f;
    for (int p = lane; p < dg; p += 32) { int j = l[p]; s += d1[b * N_ + j] * v[b * N_ + j]; }
    #pragma unroll
    for (int o = 16; o > 0; o >>= 1) s += __shfl_down_sync(0xffffffffu, s, o);
    if (lane == 0) {
        float di = d1[b * N_ + i];
        float r = rnz[b * N_ + i] * di * (s + di * v[b * N_ + i]);
        float z = r * r;
        alp[b * N_ + i] = 1.f / (1.f + expf(-z));
    }
}

// ---------------- exact K-th largest via bitonic sort ------------------------
__global__ void topk_cut_kernel(const float* __restrict__ alp, float* __restrict__ cut) {
    __shared__ float s[N_];
    int b = blockIdx.x, t = threadIdx.x;   // 1024 threads
    s[t] = alp[b * N_ + t];
    s[t + 1024] = alp[b * N_ + t + 1024];
    __syncthreads();
    for (int k = 2; k <= N_; k <<= 1) {
        for (int j = k >> 1; j > 0; j >>= 1) {
            for (int i = t; i < N_; i += 1024) {
                int ixj = i ^ j;
                if (ixj > i) {
                    float a = s[i], c = s[ixj];
                    if (((i & k) == 0) ? (a > c) : (a < c)) { s[i] = c; s[ixj] = a; }
                }
            }
            __syncthreads();
        }
    }
    if (t == 0) cut[b] = s[N_ - K_];
}

__global__ void ca_kernel(const float* __restrict__ alp, const float* __restrict__ cut,
                          float* __restrict__ ca) {
    int idx = blockIdx.x * 256 + threadIdx.x;
    int b = idx / N_;
    ca[idx] = fmaxf(alp[idx] + 1e-7f - cut[b], 0.f);
}

// ---------------- deterministic kept-set compaction (prefix scan) -----------
__global__ void compact_kernel(const float* __restrict__ ca, int* __restrict__ idx,
                               int* __restrict__ ginv, int* __restrict__ cnt) {
    __shared__ int sc[1024];
    int b = blockIdx.x, t = threadIdx.x;   // 1024 threads
    int f0 = (ca[b * N_ + 2 * t]     > 0.f) ? 1 : 0;
    int f1 = (ca[b * N_ + 2 * t + 1] > 0.f) ? 1 : 0;
    ginv[b * N_ + 2 * t] = -1;
    ginv[b * N_ + 2 * t + 1] = -1;
    int c = f0 + f1;
    sc[t] = c; __syncthreads();
    for (int o = 1; o < 1024; o <<= 1) {
        int v = (t >= o) ? sc[t - o] : 0; __syncthreads();
        sc[t] += v; __syncthreads();
    }
    int base = sc[t] - c;
    if (f0) { idx[b * N_ + base] = 2 * t;     ginv[b * N_ + 2 * t]     = base; base++; }
    if (f1) { idx[b * N_ + base] = 2 * t + 1; ginv[b * N_ + 2 * t + 1] = base; }
    if (t == 1023) cnt[b] = sc[1023];
}

// maskc = compacted mask; mrest = TOTAL mask sum (for final-layer bias fold)
__global__ void compact_mask_kernel(const float* __restrict__ mask, const int* __restrict__ idx,
                                    const int* __restrict__ cnt, float* __restrict__ maskc,
                                    float* __restrict__ mrest) {
    __shared__ float red[256];
    int b = blockIdx.x, t = threadIdx.x;
    int c = cnt[b];
    float local = 0.f;
    for (int i = t; i < N_; i += 256) {
        float mv = 0.f;
        if (i < c) mv = mask[b * N_ + idx[b * N_ + i]];
        maskc[b * N_ + i] = mv;
        local += mask[b * N_ + i];
    }
    red[t] = local; __syncthreads();
    for (int o = 128; o > 0; o >>= 1) { if (t < o) red[t] += red[t + o]; __syncthreads(); }
    if (t == 0) mrest[b] = red[0];
}

// ---------------- layer-1 S row normalizer -----------------------------------
__global__ void srec_kernel(const int* __restrict__ lst, const int* __restrict__ deg,
                            const float* __restrict__ d1, const float* __restrict__ rnz,
                            const float* __restrict__ ca, float* __restrict__ srec) {
    int b = blockIdx.y;
    int i = blockIdx.x * 8 + (threadIdx.x >> 5);
    int lane = threadIdx.x & 31;
    const int* l = lst + ((size_t)(b * N_ + i)) * CAP;
    int dg = deg[b * N_ + i];
    float s = 0.f;
    for (int p = lane; p < dg; p += 32) { int j = l[p]; s += d1[b * N_ + j] * ca[b * N_ + j]; }
    #pragma unroll
    for (int o = 16; o > 0; o >>= 1) s += __shfl_down_sync(0xffffffffu, s, o);
    if (lane == 0) {
        float di = d1[b * N_ + i];
        float raw = rnz[b * N_ + i] * di * (s + di * ca[b * N_ + i]);
        srec[b * N_ + i] = rnz[b * N_ + i] * di / fmaxf(raw, 1e-12f);
    }
}

// ---------------- xc[ic,:] = sum_n S[n, idx[ic]] * x1[n,:] -------------------
__global__ void xupd_kernel(const int* __restrict__ lst, const int* __restrict__ deg,
                            const int* __restrict__ hasd, const float* __restrict__ d1,
                            const float* __restrict__ ca, const float* __restrict__ srec,
                            const int* __restrict__ idx, const int* __restrict__ cnt,
                            const float* __restrict__ x1, float* __restrict__ xc) {
    int b = blockIdx.y, ic = blockIdx.x, c = threadIdx.x;   // 128 threads
    int cn = cnt[b], cnp = (cn + 127) & ~127;
    if (ic >= cnp) return;
    float* orow = xc + ((size_t)(b * N_ + ic)) * H_;
    if (ic >= cn) { orow[c] = 0.f; return; }
    int m = idx[b * N_ + ic];
    float dmcam = d1[b * N_ + m] * ca[b * N_ + m];
    int dg = deg[b * N_ + m];
    const int* l = lst + ((size_t)(b * N_ + m)) * CAP;
    float acc = 0.f;
    for (int p = 0; p < dg; p++) {
        int n = l[p];
        float coef = (n == m) ? 2.f : 1.f;
        float sv = srec[b * N_ + n] * dmcam * coef;
        acc = fmaf(sv, x1[((size_t)(b * N_ + n)) * H_ + c], acc);
    }
    if (!hasd[b * N_ + m])
        acc = fmaf(srec[b * N_ + m] * dmcam, x1[((size_t)(b * N_ + m)) * H_ + c], acc);
    orow[c] = acc;
}

// ---- Tc[i,:] = sum_{j in list_i} S_row_j, S rows expanded on the fly --------
__global__ void adjS_sparse_kernel(const int* __restrict__ lst, const int* __restrict__ deg,
                                   const int* __restrict__ hasd, const float* __restrict__ d1,
                                   const float* __restrict__ ca, const float* __restrict__ srec,
                                   const int* __restrict__ ginv, const int* __restrict__ cnt,
                                   float* __restrict__ Tc) {
    __shared__ float acc[4][N_];
    int b = blockIdx.y, tid = threadIdx.x;   // 128 threads = 4 warps
    int w = tid >> 5, lane = tid & 31;
    int i = blockIdx.x * 4 + w;
    int cnp = (cnt[b] + 127) & ~127;
    float* a = acc[w];
    float4* a4 = (float4*)a;
    float4 z4 = make_float4(0.f, 0.f, 0.f, 0.f);
    for (int jc = lane; jc < (cnp >> 2); jc += 32) a4[jc] = z4;
    __syncwarp();
    int dgi = deg[b * N_ + i];
    const int* li = lst + ((size_t)(b * N_ + i)) * CAP;
    const int* gv = ginv + b * N_;
    for (int p = 0; p < dgi; p++) {
        int j = li[p];
        int dgj = deg[b * N_ + j];
        const int* lj = lst + ((size_t)(b * N_ + j)) * CAP;
        float sr = srec[b * N_ + j];
        for (int q = lane; q < dgj; q += 32) {
            int m = lj[q];
            int jc = gv[m];
            if (jc >= 0) {
                float coef = (m == j) ? 2.f : 1.f;
                a[jc] += sr * d1[b * N_ + m] * ca[b * N_ + m] * coef;
            }
        }
        __syncwarp();
        if (lane == 0 && !hasd[b * N_ + j]) {
            int jc = gv[j];
            if (jc >= 0) a[jc] += sr * d1[b * N_ + j] * ca[b * N_ + j];
        }
        __syncwarp();
    }
    float4* trow4 = (float4*)(Tc + (size_t)b * N_ * N_ + (size_t)i * cnp);
    for (int jc = lane; jc < (cnp >> 2); jc += 32) trow4[jc] = a4[jc];
}

// -- Ac[ic,:] = floorq(sum_n S[n,m]*Tc[n,:]); fused bf16 split + d2/rz2 -------
__global__ void STT_kernel(const int* __restrict__ lst, const int* __restrict__ deg,
                           const int* __restrict__ hasd, const float* __restrict__ d1,
                           const float* __restrict__ ca, const float* __restrict__ srec,
                           const int* __restrict__ idx, const int* __restrict__ cnt,
                           const float* __restrict__ Tc, float* __restrict__ Ac,
                           __nv_bfloat16* __restrict__ Achi, __nv_bfloat16* __restrict__ Aclo,
                           float* __restrict__ d2out, float* __restrict__ rz2out) {
    __shared__ float4 acc4[N_ / 4];
    __shared__ float red[256];
    int b = blockIdx.y, ic = blockIdx.x, tid = threadIdx.x;
    int cn = cnt[b], cnp = (cn + 127) & ~127, cnp4 = cnp >> 2;
    if (ic >= cnp) return;
    size_t rowoff = ((size_t)(b * N_ + ic)) * N_;
    float4* orow4 = (float4*)(Ac + rowoff);
    __nv_bfloat162* ohi = (__nv_bfloat162*)(Achi + rowoff);
    __nv_bfloat162* olo = (__nv_bfloat162*)(Aclo + rowoff);
    float4 z4 = make_float4(0.f, 0.f, 0.f, 0.f);
    if (ic >= cn) {
        __nv_bfloat162 zb; zb.x = __float2bfloat16(0.f); zb.y = zb.x;
        for (int jc = tid; jc < cnp4; jc += 256) {
            orow4[jc] = z4;
            ohi[jc * 2] = zb; ohi[jc * 2 + 1] = zb;
            olo[jc * 2] = zb; olo[jc * 2 + 1] = zb;
        }
        if (tid == 0) { d2out[b * N_ + ic] = 1.f; rz2out[b * N_ + ic] = 0.f; }
        return;
    }
    int m = idx[b * N_ + ic];
    float dmcam = d1[b * N_ + m] * ca[b * N_ + m];
    for (int jc = tid; jc < cnp4; jc += 256) acc4[jc] = z4;
    __syncthreads();
    int dg = deg[b * N_ + m];
    const int* l = lst + ((size_t)(b * N_ + m)) * CAP;
    const float* Tb = Tc + (size_t)b * N_ * N_;
    for (int p = 0; p < dg; p++) {
        int n = l[p];
        float coef = (n == m) ? 2.f : 1.f;
        float sv = srec[b * N_ + n] * dmcam * coef;
        if (sv != 0.f) {
            const float4* trow = (const float4*)(Tb + (size_t)n * cnp);
            for (int jc = tid; jc < cnp4; jc += 256) {
                float4 t = trow[jc], a = acc4[jc];
                a.x = fmaf(sv, t.x, a.x); a.y = fmaf(sv, t.y, a.y);
                a.z = fmaf(sv, t.z, a.z); a.w = fmaf(sv, t.w, a.w);
                acc4[jc] = a;
            }
        }
    }
    if (!hasd[b * N_ + m]) {
        float sv = srec[b * N_ + m] * dmcam;
        if (sv != 0.f) {
            const float4* trow = (const float4*)(Tb + (size_t)m * cnp);
            for (int jc = tid; jc < cnp4; jc += 256) {
                float4 t = trow[jc], a = acc4[jc];
                a.x = fmaf(sv, t.x, a.x); a.y = fmaf(sv, t.y, a.y);
                a.z = fmaf(sv, t.z, a.z); a.w = fmaf(sv, t.w, a.w);
                acc4[jc] = a;
            }
        }
    }
    __syncthreads();
    float part = 0.f;
    for (int jc = tid; jc < cnp4; jc += 256) {
        float4 a = acc4[jc];
        a.x = floorf(a.x * 10000.f) / 10000.f;
        a.y = floorf(a.y * 10000.f) / 10000.f;
        a.z = floorf(a.z * 10000.f) / 10000.f;
        a.w = floorf(a.w * 10000.f) / 10000.f;
        orow4[jc] = a;
        part += (a.x + a.y) + (a.z + a.w);
        __nv_bfloat162 h01 = split_hi2(a.x, a.y), h23 = split_hi2(a.z, a.w);
        ohi[jc * 2] = h01; ohi[jc * 2 + 1] = h23;
        olo[jc * 2] = split_lo2(a.x, a.y, h01); olo[jc * 2 + 1] = split_lo2(a.z, a.w, h23);
    }
    red[tid] = part; __syncthreads();
    for (int o = 128; o > 0; o >>= 1) { if (tid < o) red[tid] += red[tid + o]; __syncthreads(); }
    if (tid == 0) {
        float sum = red[0];
        d2out[b * N_ + ic] = rsqrtf(fmaxf(sum + 1.f, 1.f));
        rz2out[b * N_ + ic] = (sum > 0.f) ? 1.f : 0.f;
    }
}

// ---------------- layer-2 / final helpers (read Ac/A3 directly) --------------
__global__ void rowstats_c_kernel(const float* __restrict__ A, const int* __restrict__ cnt,
                                  float* __restrict__ dout, float* __restrict__ rnz, int mode) {
    int b = blockIdx.y, i = blockIdx.x, tid = threadIdx.x;
    int cnp = (cnt[b] + 127) & ~127;
    if (i >= cnp) return;
    const float* row = A + ((size_t)(b * N_ + i)) * N_;
    const float4* row4 = (const float4*)row;
    float s = 0.f;
    for (int j = tid; j < (cnp >> 2); j += 256) {
        float4 a = row4[j]; s += (a.x + a.y) + (a.z + a.w);
    }
    __shared__ float red[256];
    red[tid] = s; __syncthreads();
    for (int o = 128; o > 0; o >>= 1) { if (tid < o) red[tid] += red[tid + o]; __syncthreads(); }
    if (tid == 0) {
        float sum = red[0];
        if (mode == 0) {
            dout[b * N_ + i] = rsqrtf(fmaxf(sum - row[i] + 1.f, 1.f));
        } else {
            dout[b * N_ + i] = rsqrtf(fmaxf(sum + 1.f, 1.f));
            rnz[b * N_ + i] = (sum > 0.f) ? 1.f : 0.f;
        }
    }
}

__global__ void alpha2d_kernel(const float* __restrict__ Ac, const float* __restrict__ d2,
                               const float* __restrict__ rz2, const float* __restrict__ v,
                               const int* __restrict__ cnt, float* __restrict__ alp) {
    __shared__ float dv[N_];
    __shared__ float red[256];
    int b = blockIdx.y, n = blockIdx.x, tid = threadIdx.x;
    int cnp = (cnt[b] + 127) & ~127;
    if (n >= cnp) { if (tid == 0) alp[b * N_ + n] = 0.5f; return; }
    for (int m = tid; m < cnp; m += 256) dv[m] = d2[b * N_ + m] * v[b * N_ + m];
    __syncthreads();
    const float4* row4 = (const float4*)(Ac + ((size_t)(b * N_ + n)) * N_);
    const float4* dv4 = (const float4*)dv;
    float s = 0.f;
    for (int m = tid; m < (cnp >> 2); m += 256) {
        float4 a = row4[m], w = dv4[m];
        s += a.x * w.x + a.y * w.y + a.z * w.z + a.w * w.w;
    }
    red[tid] = s; __syncthreads();
    for (int o = 128; o > 0; o >>= 1) { if (tid < o) red[tid] += red[tid + o]; __syncthreads(); }
    if (tid == 0) {
        float r = rz2[b * N_ + n] * d2[b * N_ + n] * (red[0] + dv[n]);
        alp[b * N_ + n] = 1.f / (1.f + expf(-r * r));
    }
}

// sinv[n] = f / max(f * sum_m (Ac[n][m]+delta)*dca[m], 1e-12), f = rz2*d2
__global__ void s2inv_kernel(const float* __restrict__ Ac, const float* __restrict__ d2,
                             const float* __restrict__ rz2, const float* __restrict__ ca,
                             const int* __restrict__ cnt, float* __restrict__ sinv) {
    __shared__ float dca[N_];
    __shared__ float red[256];
    int b = blockIdx.y, n = blockIdx.x, tid = threadIdx.x;
    int cnp = (cnt[b] + 127) & ~127;
    if (n >= cnp) return;
    for (int m = tid; m < cnp; m += 256) dca[m] = d2[b * N_ + m] * ca[b * N_ + m];
    __syncthreads();
    const float4* row4 = (const float4*)(Ac + ((size_t)(b * N_ + n)) * N_);
    const float4* dca4 = (const float4*)dca;
    float s = 0.f;
    for (int m = tid; m < (cnp >> 2); m += 256) {
        float4 a = row4[m], w = dca4[m];
        s += a.x * w.x + a.y * w.y + a.z * w.z + a.w * w.w;
    }
    red[tid] = s; __syncthreads();
    for (int o = 128; o > 0; o >>= 1) { if (tid < o) red[tid] += red[tid + o]; __syncthreads(); }
    if (tid == 0) {
        float sum = red[0] + dca[n];
        float f = rz2[b * N_ + n] * d2[b * N_ + n];
        sinv[b * N_ + n] = f / fmaxf(f * sum, 1e-12f);
    }
}

// ST[m][n] = S2[n][m] = (Ac[m][n] + (m==n)) * dca[m] * sinv[n]  (Ac symmetric)
__global__ void buildST_kernel(const float* __restrict__ Ac, const float* __restrict__ d2,
                               const float* __restrict__ ca, const float* __restrict__ sinv,
                               const int* __restrict__ cnt,
                               __nv_bfloat16* __restrict__ SThi, __nv_bfloat16* __restrict__ STlo) {
    __shared__ float siv[N_];
    int b = blockIdx.y, m = blockIdx.x, tid = threadIdx.x;
    int cnp = (cnt[b] + 127) & ~127;
    if (m >= cnp) return;
    for (int n = tid; n < cnp; n += 256) siv[n] = sinv[b * N_ + n];
    __syncthreads();
    float dcam = d2[b * N_ + m] * ca[b * N_ + m];
    size_t ro = ((size_t)(b * N_ + m)) * N_;
    const float4* row4 = (const float4*)(Ac + ro);
    __nv_bfloat162* ohi = (__nv_bfloat162*)(SThi + ro);
    __nv_bfloat162* olo = (__nv_bfloat162*)(STlo + ro);
    for (int q = tid; q < (cnp >> 2); q += 256) {
        float4 a = row4[q];
        int n = q << 2;
        float v0 = (a.x + ((n    ) == m ? 1.f : 0.f)) * dcam * siv[n];
        float v1 = (a.y + ((n + 1) == m ? 1.f : 0.f)) * dcam * siv[n + 1];
        float v2 = (a.z + ((n + 2) == m ? 1.f : 0.f)) * dcam * siv[n + 2];
        float v3 = (a.w + ((n + 3) == m ? 1.f : 0.f)) * dcam * siv[n + 3];
        __nv_bfloat162 h01 = split_hi2(v0, v1), h23 = split_hi2(v2, v3);
        ohi[q * 2] = h01; ohi[q * 2 + 1] = h23;
        olo[q * 2] = split_lo2(v0, v1, h01); olo[q * 2 + 1] = split_lo2(v2, v3, h23);
    }
}

// w[k] = d2[k] * (sum_m A3[k][m]*dv[m] - A3[k][k]*dv[k] + dv[k]), dv = d2*maskc
__global__ void wvec_kernel(const float* __restrict__ A3, const float* __restrict__ d2,
                            const float* __restrict__ maskc, const int* __restrict__ cnt,
                            float* __restrict__ wv) {
    __shared__ float dv[N_];
    __shared__ float red[256];
    int b = blockIdx.y, k = blockIdx.x, tid = threadIdx.x;
    int cnp = (cnt[b] + 127) & ~127;
    if (k >= cnp) return;
    for (int m = tid; m < cnp; m += 256) dv[m] = d2[b * N_ + m] * maskc[b * N_ + m];
    __syncthreads();
    const float* row = A3 + ((size_t)(b * N_ + k)) * N_;
    const float4* row4 = (const float4*)row;
    const float4* dv4 = (const float4*)dv;
    float s = 0.f;
    for (int m = tid; m < (cnp >> 2); m += 256) {
        float4 a = row4[m], w = dv4[m];
        s += a.x * w.x + a.y * w.y + a.z * w.z + a.w * w.w;
    }
    red[tid] = s; __syncthreads();
    for (int o = 128; o > 0; o >>= 1) { if (tid < o) red[tid] += red[tid + o]; __syncthreads(); }
    if (tid == 0)
        wv[b * N_ + k] = d2[b * N_ + k] * (red[0] - row[k] * dv[k] + dv[k]);
}

// p2 partial: sum_k wv[k]*xW[k,:] over k-chunk q
__global__ void out2_part_kernel(const float* __restrict__ xW, const float* __restrict__ wv,
                                 const int* __restrict__ cnt, float* __restrict__ p2) {
    int b = blockIdx.y, q = blockIdx.x, c = threadIdx.x;   // 256 threads
    int cnp = (cnt[b] + 127) & ~127;
    int lo = q * 512, hi = (q + 1) * 512; if (hi > cnp) hi = cnp;
    float s = 0.f;
    for (int k = lo; k < hi; k++)
        s = fmaf(wv[b * N_ + k], xW[((size_t)(b * N_ + k)) * F_ + c], s);
    p2[(b * 4 + q) * F_ + c] = s;
}

// generic transposed split: out[j][i] = in[i][j]; in R x C (ld), out stride N_
__global__ void split_tr_kernel(const float* __restrict__ in, __nv_bfloat16* __restrict__ hi,
                                __nv_bfloat16* __restrict__ lo, const int* __restrict__ cnt,
                                int Rfixed, int Cfixed, int ld, long sIn, long sOut) {
    __shared__ float tile[32][33];
    int b = blockIdx.z;
    int cnp = (cnt[b] + 127) & ~127;
    int R = Rfixed ? Rfixed : cnp;
    int C = Cfixed ? Cfixed : cnp;
    int i0 = blockIdx.y * 32, j0 = blockIdx.x * 32;
    if (i0 >= R || j0 >= C) return;
    const float* inb = in + (size_t)b * sIn;
    size_t boff = (size_t)b * sOut;
    int tx = threadIdx.x, ty = threadIdx.y;   // (32, 8)
    #pragma unroll
    for (int r = 0; r < 4; r++) {
        int i = ty + r * 8;
        tile[i][tx] = inb[(size_t)(i0 + i) * ld + j0 + tx];
    }
    __syncthreads();
    #pragma unroll
    for (int r = 0; r < 4; r++) {
        int j = ty + r * 8;
        float v = tile[tx][j];
        __nv_bfloat16 h = __float2bfloat16(v);
        size_t o = boff + (size_t)(j0 + j) * N_ + i0 + tx;
        hi[o] = h;
        lo[o] = __float2bfloat16(v - __bfloat162float(h));
    }
}

// ---------------- bf16-split tensor GEMM, single-K-pass ----------------------
// C = A @ B: hi*hi + hi*lo + lo*hi accumulated per k-tile (fp32 accum).
// A row-major [m][k] stride N_; BT [n][k] stride N_.  M = K = cnp.
// EPI 4: row-major bf16 hi/lo split out; PLUS merged second region:
//        the LAST grid column reads B2 (H_ rows, stride N_) and writes fp32 C2.
// EPI 5: floor-quant + SYMMETRIC output (upper blocks only, mirror write).
#define TSZ (128 * 40)
template<int EPI>
__global__ void __launch_bounds__(256, 2) gemm_bf16_kernel(
    const __nv_bfloat16* __restrict__ Ahi, const __nv_bfloat16* __restrict__ Alo,
    const __nv_bfloat16* __restrict__ BThi, const __nv_bfloat16* __restrict__ BTlo,
    float* __restrict__ C, const int* __restrict__ cnt,
    int ldc, long sC,
    __nv_bfloat16* __restrict__ Chi, __nv_bfloat16* __restrict__ Clo,
    const __nv_bfloat16* __restrict__ B2hi, const __nv_bfloat16* __restrict__ B2lo,
    float* __restrict__ C2, int ldc2, long sC2) {
    extern __shared__ __nv_bfloat16 sm[];   // [2 stages][4 tiles][128*40]
    const int b = blockIdx.z;
    const int cnp = (cnt[b] + 127) & ~127;
    const int m0 = blockIdx.y * 128;
    const int n0 = blockIdx.x * 128;
    const bool reg2 = (EPI == 4) && (blockIdx.x == gridDim.x - 1);
    if (m0 >= cnp) return;
    if (!reg2) {
        if (n0 >= cnp) return;
        if (EPI == 5 && m0 > n0) return;   // symmetric: upper-triangle blocks only
    }
    const size_t boff = (size_t)b * N_ * N_;
    const int tid = threadIdx.x;
    const int wid = tid >> 5, lane = tid & 31;
    const int wm = wid >> 1, wn = wid & 1;     // warps 4 x 2 -> warp tile 32 x 64
    const int g = lane >> 2, t4 = lane & 3;
    const int a_row = lane & 15;
    const int a_k   = (lane & 16) ? 8 : 0;
    const int b_row = (lane & 7) + ((lane & 16) ? 8 : 0);
    const int b_k   = (lane & 8) ? 8 : 0;
    const int KT = cnp >> 5;

    float acc[2][8][4];
    #pragma unroll
    for (int fm = 0; fm < 2; fm++)
        #pragma unroll
        for (int fn = 0; fn < 8; fn++)
            #pragma unroll
            for (int r = 0; r < 4; r++) acc[fm][fn][r] = 0.f;

    const __nv_bfloat16* gsrc[4];
    auto stage = [&](int kt, int buf) {
        gsrc[0] = Ahi + boff + (size_t)m0 * N_ + kt * 32;
        gsrc[1] = Alo + boff + (size_t)m0 * N_ + kt * 32;
        if (reg2) {
            gsrc[2] = B2hi + (size_t)b * H_ * N_ + kt * 32;
            gsrc[3] = B2lo + (size_t)b * H_ * N_ + kt * 32;
        } else {
            gsrc[2] = BThi + boff + (size_t)n0 * N_ + kt * 32;
            gsrc[3] = BTlo + boff + (size_t)n0 * N_ + kt * 32;
        }
        int row = tid >> 2, cc = (tid & 3) * 8;
        #pragma unroll
        for (int w = 0; w < 4; w++) {
            __nv_bfloat16* dst = sm + (size_t)(buf * 4 + w) * TSZ;
            CP16(dst + row * 40 + cc,        gsrc[w] + (size_t)row * N_ + cc);
            CP16(dst + (row + 64) * 40 + cc, gsrc[w] + (size_t)(row + 64) * N_ + cc);
        }
    };

    stage(0, 0);
    CP_COMMIT();

    for (int t = 0; t < KT; t++) {
        CP_WAIT0();
        __syncthreads();
        if (t + 1 < KT) { stage(t + 1, (t + 1) & 1); CP_COMMIT(); }
        const __nv_bfloat16* Ah = sm + (size_t)((t & 1) * 4 + 0) * TSZ;
        const __nv_bfloat16* Al = sm + (size_t)((t & 1) * 4 + 1) * TSZ;
        const __nv_bfloat16* Bh = sm + (size_t)((t & 1) * 4 + 2) * TSZ;
        const __nv_bfloat16* Bl = sm + (size_t)((t & 1) * 4 + 3) * TSZ;
        #pragma unroll
        for (int kh = 0; kh < 32; kh += 16) {
            uint32_t ah[2][4], al[2][4];
            #pragma unroll
            for (int fm = 0; fm < 2; fm++) {
                int ao = (wm * 32 + fm * 16 + a_row) * 40 + kh + a_k;
                ldsm4(ah[fm], Ah + ao);
                ldsm4(al[fm], Al + ao);
            }
            #pragma unroll
            for (int fn2 = 0; fn2 < 4; fn2++) {
                int bo = (wn * 64 + fn2 * 16 + b_row) * 40 + kh + b_k;
                uint32_t bh[4], bl[4];
                ldsm4(bh, Bh + bo);
                ldsm4(bl, Bl + bo);
                #pragma unroll
                for (int fm = 0; fm < 2; fm++) {
                    mma_bf16(acc[fm][2 * fn2],     ah[fm], bh[0], bh[1]);
                    mma_bf16(acc[fm][2 * fn2],     ah[fm], bl[0], bl[1]);
                    mma_bf16(acc[fm][2 * fn2],     al[fm], bh[0], bh[1]);
                    mma_bf16(acc[fm][2 * fn2 + 1], ah[fm], bh[2], bh[3]);
                    mma_bf16(acc[fm][2 * fn2 + 1], ah[fm], bl[2], bl[3]);
                    mma_bf16(acc[fm][2 * fn2 + 1], al[fm], bh[2], bh[3]);
                }
            }
        }
        __syncthreads();
    }

    float* smf = (float*)sm;   // EPI==5: 128x133 fp32 transpose staging (68KB <= 80KB)
    #pragma unroll
    for (int fm = 0; fm < 2; fm++) {
        int mr = m0 + wm * 32 + fm * 16 + g;
        #pragma unroll
        for (int fn = 0; fn < 8; fn++) {
            int lc = wn * 64 + fn * 8 + t4 * 2;   // local col
            float v0 = acc[fm][fn][0], v1 = acc[fm][fn][1];
            float v2 = acc[fm][fn][2], v3 = acc[fm][fn][3];
            if (reg2) {
                float* p0 = C2 + (size_t)b * sC2 + (size_t)mr * ldc2 + lc;
                p0[0] = v0; p0[1] = v1;
                float* p1 = p0 + 8 * (size_t)ldc2;
                p1[0] = v2; p1[1] = v3;
            } else if (EPI == 5) {
                v0 = floorf(v0 * 10000.f) / 10000.f;
                v1 = floorf(v1 * 10000.f) / 10000.f;
                v2 = floorf(v2 * 10000.f) / 10000.f;
                v3 = floorf(v3 * 10000.f) / 10000.f;
                int r = wm * 32 + fm * 16 + g;
                smf[(lc    ) * 133 + r]     = v0;
                smf[(lc + 1) * 133 + r]     = v1;
                smf[(lc    ) * 133 + r + 8] = v2;
                smf[(lc + 1) * 133 + r + 8] = v3;
                int n = n0 + lc;
                float* p0 = C + (size_t)b * sC + (size_t)mr * ldc + n;
                p0[0] = v0; p0[1] = v1;
                float* p1 = p0 + 8 * (size_t)ldc;
                p1[0] = v2; p1[1] = v3;
            } else {   // EPI 4 region 1: bf16 split out
                int n = n0 + lc;
                size_t o0 = (size_t)b * sC + (size_t)mr * ldc + n;
                size_t o1 = o0 + 8 * (size_t)ldc;
                __nv_bfloat162 h0 = split_hi2(v0, v1), h1 = split_hi2(v2, v3);
                *(__nv_bfloat162*)(Chi + o0) = h0;
                *(__nv_bfloat162*)(Chi + o1) = h1;
                *(__nv_bfloat162*)(Clo + o0) = split_lo2(v0, v1, h0);
                *(__nv_bfloat162*)(Clo + o1) = split_lo2(v2, v3, h1);
            }
        }
    }
    if (EPI == 5 && m0 != n0) {
        __syncthreads();
        float* Cb = C + (size_t)b * sC;
        for (int e = tid; e < 128 * 128; e += 256) {
            int r2 = e >> 7, c2 = e & 127;
            Cb[(size_t)(n0 + r2) * ldc + m0 + c2] = smf[r2 * 133 + c2];
        }
    }
}

// ---------------- double-buffered cp.async SIMT GEMM (small GEMMs) -----------
template<int TRANSA, int EPI>
__global__ void __launch_bounds__(256, 2) gemm2_kernel(
    const float* __restrict__ A, const float* __restrict__ Bm, float* __restrict__ C,
    int M, int Kd, int Nc, int lda, int ldb, int ldc,
    long sA, long sB, long sC,
    const float* __restrict__ bias, const float* __restrict__ mask,
    const int* __restrict__ cnt, int dynM, int dynK, int dynN) {
    __shared__ float As[2][128 * 16];
    __shared__ float Bs[2][16 * 128];
    const int b = blockIdx.z;
    int Mp = M, Kp = Kd, Np = Nc;
    if (cnt) {
        int p = (cnt[b] + 127) & ~127;
        if (dynM) Mp = p; if (dynK) Kp = p; if (dynN) Np = p;
    }
    const int n0 = blockIdx.x * 128, m0 = blockIdx.y * 128;
    if (m0 >= Mp || n0 >= Np) return;
    A  += (size_t)b * sA;
    Bm += (size_t)b * sB;
    C  += (size_t)b * sC;
    const int tid = threadIdx.x, tx = tid & 15, ty = tid >> 4;
    float acc[8][8];
    #pragma unroll
    for (int i = 0; i < 8; i++)
        #pragma unroll
        for (int j = 0; j < 8; j++) acc[i][j] = 0.f;

    const int Kt = Kp >> 4;

    auto load_tiles = [&](int k0, int buf) {
        if (!TRANSA) {
            #pragma unroll
            for (int q = 0; q < 2; q++) {
                int c = tid + q * 256;
                int row = c >> 2, col4 = (c & 3) * 4;
                const float* src = A + (size_t)(m0 + row) * lda + k0 + col4;
                CP16(&As[buf][row * 16 + col4], src);
            }
        } else {
            #pragma unroll
            for (int q = 0; q < 2; q++) {
                int c = tid + q * 256;
                int row = c >> 5, col4 = (c & 31) * 4;
                const float* src = A + (size_t)(k0 + row) * lda + m0 + col4;
                CP16(&As[buf][row * 128 + col4], src);
            }
        }
        #pragma unroll
        for (int q = 0; q < 2; q++) {
            int c = tid + q * 256;
            int row = c >> 5, col4 = (c & 31) * 4;
            const float* src = Bm + (size_t)(k0 + row) * ldb + n0 + col4;
            CP16(&Bs[buf][row * 128 + col4], src);
        }
    };

    load_tiles(0, 0);
    CP_COMMIT();

    for (int t = 0; t < Kt; t++) {
        CP_WAIT0();
        __syncthreads();
        if (t + 1 < Kt) { load_tiles((t + 1) << 4, (t + 1) & 1); CP_COMMIT(); }
        const int buf = t & 1;
        #pragma unroll
        for (int k = 0; k < 16; k++) {
            float a[8], bv[8];
            if (!TRANSA) {
                #pragma unroll
                for (int i = 0; i < 8; i++) a[i] = As[buf][(ty * 8 + i) * 16 + k];
            } else {
                *(float4*)(a)     = *(const float4*)&As[buf][k * 128 + ty * 8];
                *(float4*)(a + 4) = *(const float4*)&As[buf][k * 128 + ty * 8 + 4];
            }
            *(float4*)(bv)     = *(const float4*)&Bs[buf][k * 128 + tx * 8];
            *(float4*)(bv + 4) = *(const float4*)&Bs[buf][k * 128 + tx * 8 + 4];
            #pragma unroll
            for (int i = 0; i < 8; i++)
                #pragma unroll
                for (int j = 0; j < 8; j++) acc[i][j] = fmaf(a[i], bv[j], acc[i][j]);
        }
        __syncthreads();
    }
    #pragma unroll
    for (int i = 0; i < 8; i++) {
        int m = m0 + ty * 8 + i;
        float mk = (EPI == 2) ? mask[(size_t)b * N_ + m] : 1.f;
        #pragma unroll
        for (int j = 0; j < 8; j++) {
            int n = n0 + tx * 8 + j;
            float v = acc[i][j];
            if (EPI == 2)      { v = (v + bias[n]) * mk; }
            else if (EPI == 3) { v = floorf(v * 10000.f) / 10000.f; }
            C[(size_t)m * ldc + n] = v;
        }
    }
}

// ---------------- output means (two-stage, deterministic) --------------------
__global__ void mean1_part_kernel(const float* __restrict__ x1, float* __restrict__ p1) {
    int b = blockIdx.y, q = blockIdx.x, c = threadIdx.x;   // 128 threads
    float s = 0.f;
    for (int n = q * 512; n < (q + 1) * 512; n++) s += x1[((size_t)(b * N_ + n)) * H_ + c];
    p1[(b * 4 + q) * H_ + c] = s;
}

__global__ void mean_combine_kernel(const float* __restrict__ p1, const float* __restrict__ p2,
                                    const float* __restrict__ b2, const float* __restrict__ smask,
                                    float* __restrict__ out) {
    int b = blockIdx.x, c = threadIdx.x;   // 384 threads
    if (c < H_) {
        float s = 0.f;
        for (int q = 0; q < 4; q++) s += p1[(b * 4 + q) * H_ + c];
        out[b * OUTC + c] = s / (float)N_;
    } else {
        int cc = c - H_;
        float s = b2[cc] * smask[b];
        for (int q = 0; q < 4; q++) s += p2[(b * 4 + q) * F_ + cc];
        out[b * OUTC + c] = s / (float)N_;
    }
}

extern "C" void kernel_launch(void* const* d_in, const int* in_sizes, int n_in,
                              void* d_out, int out_size) {
    const float* x    = (const float*)d_in[0];
    const float* adj  = (const float*)d_in[1];
    const float* mask = (const float*)d_in[2];
    const float* W1   = (const float*)d_in[3];
    const float* b1   = (const float*)d_in[4];
    const float* Watt = (const float*)d_in[5];
    const float* batt = (const float*)d_in[6];
    const float* W2   = (const float*)d_in[7];
    const float* b2   = (const float*)d_in[8];
    float* out = (float*)d_out;

    float *pT,*pAc,*pA3,*pxW,*px1,*pxc,*px3;
    float *pv,*palp,*pca,*psrec,*pd0,*pd1,*prnz,*pd2,*prz2,*pcut,*pmaskc,*pmrest,*pp1,*pp2;
    __nv_bfloat16 *pAhi,*pAlo,*pSThi,*pSTlo,*pTThi,*pTTlo,*pxTh,*pxTl;
    int *plst,*pdeg,*phasd,*pidx,*pginv,*pcnt;
    cudaGetSymbolAddress((void**)&pT,   g_T);
    cudaGetSymbolAddress((void**)&pAc,  g_Ac);
    cudaGetSymbolAddress((void**)&pA3,  g_A3);
    cudaGetSymbolAddress((void**)&pAhi, g_Ahi);
    cudaGetSymbolAddress((void**)&pAlo, g_Alo);
    cudaGetSymbolAddress((void**)&pSThi,g_SThi);
    cudaGetSymbolAddress((void**)&pSTlo,g_STlo);
    cudaGetSymbolAddress((void**)&pTThi,g_TThi);
    cudaGetSymbolAddress((void**)&pTTlo,g_TTlo);
    cudaGetSymbolAddress((void**)&pxTh, g_xTh);
    cudaGetSymbolAddress((void**)&pxTl, g_xTl);
    cudaGetSymbolAddress((void**)&pxW,  g_xW);
    cudaGetSymbolAddress((void**)&px1,  g_x1);
    cudaGetSymbolAddress((void**)&pxc,  g_xc);
    cudaGetSymbolAddress((void**)&px3,  g_x3);
    cudaGetSymbolAddress((void**)&pv,   g_v);
    cudaGetSymbolAddress((void**)&palp, g_alp);
    cudaGetSymbolAddress((void**)&pca,  g_ca);
    cudaGetSymbolAddress((void**)&psrec,g_srec);
    cudaGetSymbolAddress((void**)&pd0,  g_d0);
    cudaGetSymbolAddress((void**)&pd1,  g_d1);
    cudaGetSymbolAddress((void**)&prnz, g_rnz);
    cudaGetSymbolAddress((void**)&pd2,  g_d2);
    cudaGetSymbolAddress((void**)&prz2, g_rz2);
    cudaGetSymbolAddress((void**)&pcut, g_cut);
    cudaGetSymbolAddress((void**)&pmaskc, g_maskc);
    cudaGetSymbolAddress((void**)&pmrest, g_mrest);
    cudaGetSymbolAddress((void**)&pp1,  g_p1);
    cudaGetSymbolAddress((void**)&pp2,  g_p2);
    cudaGetSymbolAddress((void**)&plst, g_lst);
    cudaGetSymbolAddress((void**)&pdeg, g_deg);
    cudaGetSymbolAddress((void**)&phasd,g_hasd);
    cudaGetSymbolAddress((void**)&pidx, g_idx);
    cudaGetSymbolAddress((void**)&pginv,g_ginv);
    cudaGetSymbolAddress((void**)&pcnt, g_cnt);

    const int BF16_SMEM = 2 * 4 * TSZ * 2;   // 81920 bytes
    cudaFuncSetAttribute(gemm_bf16_kernel<4>, cudaFuncAttributeMaxDynamicSharedMemorySize, BF16_SMEM);
    cudaFuncSetAttribute(gemm_bf16_kernel<5>, cudaFuncAttributeMaxDynamicSharedMemorySize, BF16_SMEM);

    // ---- CSR + degree stats (single adj scan) ----
    csr_build_kernel<<<dim3(N_, B_), 256>>>(adj, plst, pdeg, phasd, pd0, pd1, prnz);

    // ---- GCN layer 1 (sparse aggregation) ----
    gemm2_kernel<0,0><<<dim3(1,16,B_),256>>>(x, W1, pxW, N_, F_, H_, F_, H_, H_,
        (long)N_*F_, 0, (long)N_*H_, nullptr, nullptr, nullptr, 0,0,0);
    gcn1_kernel<<<dim3(N_, B_), 128>>>(plst, pdeg, pd0, pxW, b1, mask, px1);

    // ---- coarsen layer 1 (sparse, no dense S anywhere) ----
    gemv_watt_kernel<<<(B_*N_)/8, 256>>>(px1, Watt, batt, pv);
    alpha1_kernel<<<dim3(N_/8, B_), 256>>>(plst, pdeg, pd1, prnz, pv, palp);
    topk_cut_kernel<<<B_, 1024>>>(palp, pcut);
    ca_kernel<<<(B_*N_)/256, 256>>>(palp, pcut, pca);
    compact_kernel<<<B_, 1024>>>(pca, pidx, pginv, pcnt);
    compact_mask_kernel<<<B_, 256>>>(mask, pidx, pcnt, pmaskc, pmrest);
    srec_kernel<<<dim3(N_/8, B_), 256>>>(plst, pdeg, pd1, prnz, pca, psrec);
    xupd_kernel<<<dim3(N_, B_), 128>>>(plst, pdeg, phasd, pd1, pca, psrec, pidx, pcnt, px1, pxc);
    adjS_sparse_kernel<<<dim3(N_/4, B_), 128>>>(plst, pdeg, phasd, pd1, pca, psrec,
                                                pginv, pcnt, pT);
    // Ac + fused bf16 split + fused d2/rz2 row stats
    STT_kernel<<<dim3(N_, B_), 256>>>(plst, pdeg, phasd, pd1, pca, psrec, pidx, pcnt,
                                      pT, pAc, pAhi, pAlo, pd2, prz2);

    // ---- coarsen layer 2 (symmetric Ac: direct row-major ST build) ----
    gemv_watt_kernel<<<(B_*N_)/8, 256>>>(pxc, Watt, batt, pv);
    alpha2d_kernel<<<dim3(N_, B_), 256>>>(pAc, pd2, prz2, pv, pcnt, palp);
    topk_cut_kernel<<<B_, 1024>>>(palp, pcut);
    ca_kernel<<<(B_*N_)/256, 256>>>(palp, pcut, pca);
    s2inv_kernel<<<dim3(N_, B_), 256>>>(pAc, pd2, prz2, pca, pcnt, psrec);
    buildST_kernel<<<dim3(N_, B_), 256>>>(pAc, pd2, pca, psrec, pcnt, pSThi, pSTlo);
    // xc^T split (B2 operand for the merged GEMM)
    split_tr_kernel<<<dim3(4, 64, B_), dim3(32, 8)>>>(pxc, pxTh, pxTl, pcnt,
        0, H_, H_, (long)N_*H_, (long)H_*N_);
    // MERGED: T2^T = ST @ Ac^T (bf16 split -> TT)  AND  x3 = ST @ xc (fp32)
    gemm_bf16_kernel<4><<<dim3(17,16,B_),256,BF16_SMEM>>>(pSThi, pSTlo, pAhi, pAlo,
        nullptr, pcnt, N_, (long)N_*N_, pTThi, pTTlo,
        pxTh, pxTl, px3, H_, (long)N_*H_);
    // A3 = ST @ T2 (symmetric): upper blocks only, floor-quant, mirror write
    gemm_bf16_kernel<5><<<dim3(16,16,B_),256,BF16_SMEM>>>(pSThi, pSTlo, pTThi, pTTlo,
        pA3, pcnt, N_, (long)N_*N_, nullptr, nullptr,
        nullptr, nullptr, nullptr, 0, 0);

    // ---- final GCN: only the column mean is needed ----
    rowstats_c_kernel<<<dim3(N_, B_), 256>>>(pA3, pcnt, pd2, nullptr, 0);
    gemm2_kernel<0,0><<<dim3(2,16,B_),256>>>(px3, W2, pxW, N_, H_, F_, H_, F_, F_,
        (long)N_*H_, 0, (long)N_*F_, nullptr, nullptr, pcnt, 1,0,0);
    wvec_kernel<<<dim3(N_, B_), 256>>>(pA3, pd2, pmaskc, pcnt, pv);
    out2_part_kernel<<<dim3(4, B_), 256>>>(pxW, pv, pcnt, pp2);

    // ---- concat means ----
    mean1_part_kernel<<<dim3(4, B_), 128>>>(px1, pp1);
    mean_combine_kernel<<<B_, 384>>>(pp1, pp2, b2, pmrest, out);
}